// round 1
// baseline (speedup 1.0000x reference)
#include <cuda_runtime.h>
#include <math.h>

// Problem constants
#define NL 4
#define B_ 2
#define L_ 2048
#define S_ 256
#define D_ 1024
#define F_ 4096
#define H_ 16
#define HD_ 64
#define M_ (B_*L_)          // 4096 token rows

// ---------------------------------------------------------------------------
// Scratch (device globals; no allocations allowed)
// ---------------------------------------------------------------------------
__device__ float g_x  [M_*D_];        // residual stream
__device__ float g_h  [M_*D_];        // normed activations
__device__ float g_qkv[M_*3*D_];      // fused qkv
__device__ float g_att[M_*D_];        // self-attn out / qc
__device__ float g_co [M_*D_];        // cross-attn out
__device__ float g_kvc[B_*S_*2*D_];   // cross k/v projections
__device__ float g_g  [M_*F_];        // gate
__device__ float g_u  [M_*F_];        // up
__device__ float g_cos[L_*32];
__device__ float g_sin[L_*32];

// ---------------------------------------------------------------------------
// RoPE cache (double precision phase; computed every launch, trivial cost)
// ---------------------------------------------------------------------------
__global__ void rope_cache_k() {
    int idx = blockIdx.x * blockDim.x + threadIdx.x;   // L_*32 = 65536
    int l = idx >> 5, i = idx & 31;
    double inv = exp(-log(10000.0) * (double)i / 32.0);
    double f = (double)l * inv;
    g_cos[idx] = (float)cos(f);
    g_sin[idx] = (float)sin(f);
}

__global__ void copy_x_k(const float* __restrict__ x) {
    size_t i = (size_t)blockIdx.x * blockDim.x + threadIdx.x;
    if (i < (size_t)M_ * D_) g_x[i] = x[i];
}

// ---------------------------------------------------------------------------
// RMSNorm: one block per row, D=1024, 256 threads x float4
// ---------------------------------------------------------------------------
__global__ void rmsnorm_k(const float* __restrict__ x, const float* __restrict__ w,
                          float* __restrict__ o) {
    int row = blockIdx.x;
    int t = threadIdx.x;                 // 256
    const float4* xr = (const float4*)(x + (size_t)row * D_);
    float4 v = xr[t];
    float ss = v.x*v.x + v.y*v.y + v.z*v.z + v.w*v.w;
    #pragma unroll
    for (int off = 16; off; off >>= 1) ss += __shfl_xor_sync(0xffffffffu, ss, off);
    __shared__ float red[8];
    if ((t & 31) == 0) red[t >> 5] = ss;
    __syncthreads();
    float tot = red[0]+red[1]+red[2]+red[3]+red[4]+red[5]+red[6]+red[7];
    float rs = rsqrtf(tot * (1.0f / (float)D_) + 1e-6f);
    float4 wv = ((const float4*)w)[t];
    float4 out;
    out.x = v.x * rs * wv.x; out.y = v.y * rs * wv.y;
    out.z = v.z * rs * wv.z; out.w = v.w * rs * wv.w;
    ((float4*)(o + (size_t)row * D_))[t] = out;
}

// ---------------------------------------------------------------------------
// SGEMM (NT): C[m,n] = sum_k A[m,k] * W[n,k] (+bias[n]) (+C residual)
// 128x128 tile, BK=8, 256 threads, 8x8 per thread. All dims multiples of 128/8.
// ---------------------------------------------------------------------------
template <bool HAS_BIAS, bool RESIDUAL>
__global__ void __launch_bounds__(256, 2)
gemm_nt(const float* __restrict__ A, const float* __restrict__ W,
        const float* __restrict__ bias, float* __restrict__ C,
        int M, int N, int K) {
    __shared__ float As[8][128];
    __shared__ float Bs[8][128];
    const int tid = threadIdx.x;
    const int bn = blockIdx.x, bm = blockIdx.y;
    const float* Ab = A + (size_t)bm * 128 * K;
    const float* Wb = W + (size_t)bn * 128 * K;
    const int lrow = tid >> 1;
    const int lcol = (tid & 1) * 4;
    const int ty = tid >> 4, tx = tid & 15;

    float acc[8][8];
    #pragma unroll
    for (int i = 0; i < 8; i++)
        #pragma unroll
        for (int j = 0; j < 8; j++) acc[i][j] = 0.f;

    for (int k0 = 0; k0 < K; k0 += 8) {
        float4 av = *(const float4*)(Ab + (size_t)lrow * K + k0 + lcol);
        float4 bv = *(const float4*)(Wb + (size_t)lrow * K + k0 + lcol);
        As[lcol+0][lrow] = av.x; As[lcol+1][lrow] = av.y;
        As[lcol+2][lrow] = av.z; As[lcol+3][lrow] = av.w;
        Bs[lcol+0][lrow] = bv.x; Bs[lcol+1][lrow] = bv.y;
        Bs[lcol+2][lrow] = bv.z; Bs[lcol+3][lrow] = bv.w;
        __syncthreads();
        #pragma unroll
        for (int kk = 0; kk < 8; kk++) {
            float ar[8], br[8];
            #pragma unroll
            for (int i = 0; i < 8; i++) ar[i] = As[kk][ty*8 + i];
            #pragma unroll
            for (int j = 0; j < 8; j++) br[j] = Bs[kk][tx*8 + j];
            #pragma unroll
            for (int i = 0; i < 8; i++)
                #pragma unroll
                for (int j = 0; j < 8; j++) acc[i][j] = fmaf(ar[i], br[j], acc[i][j]);
        }
        __syncthreads();
    }

    const int row0 = bm * 128 + ty * 8;
    const int col0 = bn * 128 + tx * 8;
    #pragma unroll
    for (int i = 0; i < 8; i++) {
        float* crow = C + (size_t)(row0 + i) * N + col0;
        #pragma unroll
        for (int jj = 0; jj < 8; jj += 4) {
            float4 c = make_float4(acc[i][jj], acc[i][jj+1], acc[i][jj+2], acc[i][jj+3]);
            if (HAS_BIAS) {
                float4 bb = *(const float4*)(bias + col0 + jj);
                c.x += bb.x; c.y += bb.y; c.z += bb.z; c.w += bb.w;
            }
            if (RESIDUAL) {
                float4 r = *(const float4*)(crow + jj);
                c.x += r.x; c.y += r.y; c.z += r.z; c.w += r.w;
            }
            *(float4*)(crow + jj) = c;
        }
    }
}

// ---------------------------------------------------------------------------
// RoPE applied in place to q and k slices of qkv. grid = B*L, block 512.
// ---------------------------------------------------------------------------
__global__ void rope_apply_k(float* __restrict__ qkv) {
    int bl = blockIdx.x;
    int l = bl & (L_ - 1);
    int h = threadIdx.x >> 5;
    int i = threadIdx.x & 31;
    float c = g_cos[l*32 + i];
    float s = g_sin[l*32 + i];
    float* base = qkv + (size_t)bl * (3*D_) + h * HD_;
    // q
    float x1 = base[i], x2 = base[i+32];
    base[i]    = x1 * c - x2 * s;
    base[i+32] = x2 * c + x1 * s;
    // k
    float* kb = base + D_;
    x1 = kb[i]; x2 = kb[i+32];
    kb[i]    = x1 * c - x2 * s;
    kb[i+32] = x2 * c + x1 * s;
}

// ---------------------------------------------------------------------------
// Self-attention, causal, flash-style. grid (L/8, H, B); 256 threads = 8 warps,
// one warp per query. K/V tiles (64 keys) staged in smem, shared by 8 queries.
// ---------------------------------------------------------------------------
__global__ void __launch_bounds__(256)
self_attn_k(const float* __restrict__ qkv, float* __restrict__ out) {
    __shared__ float Ks[64][64];
    __shared__ float Vs[64][64];
    const int tid = threadIdx.x;
    const int warp = tid >> 5, lane = tid & 31;
    const int h = blockIdx.y, b = blockIdx.z;
    const int q = blockIdx.x * 8 + warp;
    const int qmax = blockIdx.x * 8 + 7;

    const float* qrow = qkv + ((size_t)(b*L_ + q)) * (3*D_) + h * HD_;
    const float qv0 = qrow[lane]      * 0.125f;   // hd^-0.5
    const float qv1 = qrow[lane + 32] * 0.125f;

    float m = -1e30f, lsum = 0.f, a0 = 0.f, a1 = 0.f;

    for (int kt = 0; kt <= qmax; kt += 64) {
        int cnt = qmax + 1 - kt; if (cnt > 64) cnt = 64;
        // cooperative load of K/V tile (float4 granularity)
        for (int idx = tid; idx < cnt * 16; idx += 256) {
            int r = idx >> 4, cc = (idx & 15) * 4;
            const float* base = qkv + ((size_t)(b*L_ + kt + r)) * (3*D_) + h * HD_ + cc;
            *(float4*)&Ks[r][cc] = *(const float4*)(base + D_);
            *(float4*)&Vs[r][cc] = *(const float4*)(base + 2*D_);
        }
        __syncthreads();
        int kend = q - kt + 1;
        if (kend > cnt) kend = cnt;
        for (int j = 0; j < kend; j++) {
            float s = qv0 * Ks[j][lane] + qv1 * Ks[j][lane + 32];
            #pragma unroll
            for (int off = 16; off; off >>= 1) s += __shfl_xor_sync(0xffffffffu, s, off);
            float nm = fmaxf(m, s);
            float sc = __expf(m - nm);
            float p  = __expf(s - nm);
            lsum = lsum * sc + p;
            a0 = fmaf(p, Vs[j][lane],      a0 * sc);
            a1 = fmaf(p, Vs[j][lane + 32], a1 * sc);
            m = nm;
        }
        __syncthreads();
    }
    float invs = 1.0f / lsum;
    float* orow = out + ((size_t)(b*L_ + q)) * D_ + h * HD_;
    orow[lane]      = a0 * invs;
    orow[lane + 32] = a1 * invs;
}

// ---------------------------------------------------------------------------
// Cross-attention with lookback window. Each query attends memory positions
// j in [max(0, seg-127), seg]. Warp per query, keys from L2.
// ---------------------------------------------------------------------------
__global__ void __launch_bounds__(256)
cross_attn_k(const float* __restrict__ qc, const float* __restrict__ kvc,
             const int* __restrict__ seg_ids, float* __restrict__ out) {
    const int tid = threadIdx.x;
    const int warp = tid >> 5, lane = tid & 31;
    const int h = blockIdx.y, b = blockIdx.z;
    const int l = blockIdx.x * 8 + warp;

    const int seg = seg_ids[b * L_ + l];
    int j0 = seg - 127; if (j0 < 0) j0 = 0;
    const int j1 = seg;

    const float* qrow = qc + ((size_t)(b*L_ + l)) * D_ + h * HD_;
    const float qv0 = qrow[lane]      * 0.125f;
    const float qv1 = qrow[lane + 32] * 0.125f;

    float m = -1e30f, lsum = 0.f, a0 = 0.f, a1 = 0.f;
    for (int j = j0; j <= j1; j++) {
        const float* krow = kvc + ((size_t)(b*S_ + j)) * (2*D_) + h * HD_;
        float s = qv0 * krow[lane] + qv1 * krow[lane + 32];
        #pragma unroll
        for (int off = 16; off; off >>= 1) s += __shfl_xor_sync(0xffffffffu, s, off);
        float nm = fmaxf(m, s);
        float sc = __expf(m - nm);
        float p  = __expf(s - nm);
        lsum = lsum * sc + p;
        const float* vrow = krow + D_;
        a0 = fmaf(p, vrow[lane],      a0 * sc);
        a1 = fmaf(p, vrow[lane + 32], a1 * sc);
        m = nm;
    }
    float invs = 1.0f / lsum;
    float* orow = out + ((size_t)(b*L_ + l)) * D_ + h * HD_;
    orow[lane]      = a0 * invs;
    orow[lane + 32] = a1 * invs;
}

// ---------------------------------------------------------------------------
// SwiGLU elementwise: g = silu(g) * u
// ---------------------------------------------------------------------------
__global__ void silu_mul_k(float* __restrict__ g, const float* __restrict__ u) {
    size_t i = (size_t)blockIdx.x * blockDim.x + threadIdx.x;
    if (i < (size_t)M_ * F_) {
        float gv = g[i];
        float s = gv / (1.0f + expf(-gv));
        g[i] = s * u[i];
    }
}

// ---------------------------------------------------------------------------
// Launch
// ---------------------------------------------------------------------------
extern "C" void kernel_launch(void* const* d_in, const int* in_sizes, int n_in,
                              void* d_out, int out_size) {
    const float* x      = (const float*)d_in[0];
    const float* memory = (const float*)d_in[1];
    const int*   seg    = (const int*)  d_in[2];
    const float* Wqkv   = (const float*)d_in[3];
    const float* bqkv   = (const float*)d_in[4];
    const float* Wo     = (const float*)d_in[5];
    const float* bo     = (const float*)d_in[6];
    const float* Wq_c   = (const float*)d_in[7];
    const float* Wkv_c  = (const float*)d_in[8];
    const float* Wo_c   = (const float*)d_in[9];
    const float* Wg     = (const float*)d_in[10];
    const float* Wu     = (const float*)d_in[11];
    const float* Wd     = (const float*)d_in[12];
    const float* n1     = (const float*)d_in[13];
    const float* n2     = (const float*)d_in[14];
    const float* n3     = (const float*)d_in[15];
    const float* nf     = (const float*)d_in[16];

    float *xb, *hb, *qkvb, *ab, *cob, *kvcb, *gb, *ub;
    cudaGetSymbolAddress((void**)&xb,   g_x);
    cudaGetSymbolAddress((void**)&hb,   g_h);
    cudaGetSymbolAddress((void**)&qkvb, g_qkv);
    cudaGetSymbolAddress((void**)&ab,   g_att);
    cudaGetSymbolAddress((void**)&cob,  g_co);
    cudaGetSymbolAddress((void**)&kvcb, g_kvc);
    cudaGetSymbolAddress((void**)&gb,   g_g);
    cudaGetSymbolAddress((void**)&ub,   g_u);

    rope_cache_k<<<256, 256>>>();
    copy_x_k<<<(M_*D_)/256, 256>>>(x);

    const dim3 attn_grid(L_/8, H_, B_);

    for (int l = 0; l < NL; l++) {
        const float* wqkv_l = Wqkv  + (size_t)l * 3*D_ * D_;
        const float* bqkv_l = bqkv  + (size_t)l * 3*D_;
        const float* wo_l   = Wo    + (size_t)l * D_ * D_;
        const float* bo_l   = bo    + (size_t)l * D_;
        const float* wqc_l  = Wq_c  + (size_t)l * D_ * D_;
        const float* wkvc_l = Wkv_c + (size_t)l * 2*D_ * D_;
        const float* woc_l  = Wo_c  + (size_t)l * D_ * D_;
        const float* wg_l   = Wg    + (size_t)l * F_ * D_;
        const float* wu_l   = Wu    + (size_t)l * F_ * D_;
        const float* wd_l   = Wd    + (size_t)l * D_ * F_;

        // --- self attention block ---
        rmsnorm_k<<<M_, 256>>>(xb, n1 + l*D_, hb);
        gemm_nt<true, false><<<dim3(3*D_/128, M_/128), 256>>>(hb, wqkv_l, bqkv_l, qkvb, M_, 3*D_, D_);
        rope_apply_k<<<M_, 512>>>(qkvb);
        self_attn_k<<<attn_grid, 256>>>(qkvb, ab);
        gemm_nt<true, true><<<dim3(D_/128, M_/128), 256>>>(ab, wo_l, bo_l, xb, M_, D_, D_);

        // --- cross attention block ---
        rmsnorm_k<<<M_, 256>>>(xb, n2 + l*D_, hb);
        gemm_nt<false, false><<<dim3(D_/128, M_/128), 256>>>(hb, wqc_l, nullptr, ab, M_, D_, D_);
        gemm_nt<false, false><<<dim3(2*D_/128, (B_*S_)/128), 256>>>(memory, wkvc_l, nullptr, kvcb, B_*S_, 2*D_, D_);
        cross_attn_k<<<attn_grid, 256>>>(ab, kvcb, seg, cob);
        gemm_nt<false, true><<<dim3(D_/128, M_/128), 256>>>(cob, woc_l, nullptr, xb, M_, D_, D_);

        // --- MLP block ---
        rmsnorm_k<<<M_, 256>>>(xb, n3 + l*D_, hb);
        gemm_nt<false, false><<<dim3(F_/128, M_/128), 256>>>(hb, wg_l, nullptr, gb, M_, F_, D_);
        gemm_nt<false, false><<<dim3(F_/128, M_/128), 256>>>(hb, wu_l, nullptr, ub, M_, F_, D_);
        silu_mul_k<<<(M_*F_)/256, 256>>>(gb, ub);
        gemm_nt<false, true><<<dim3(D_/128, M_/128), 256>>>(gb, wd_l, nullptr, xb, M_, D_, F_);
    }

    rmsnorm_k<<<M_, 256>>>(xb, nf, (float*)d_out);
}

// round 2
// speedup vs baseline: 1.3420x; 1.3420x over previous
#include <cuda_runtime.h>
#include <math.h>
#include <stdint.h>

// Problem constants
#define NL 4
#define B_ 2
#define L_ 2048
#define S_ 256
#define D_ 1024
#define F_ 4096
#define H_ 16
#define HD_ 64
#define M_ (B_*L_)          // 4096 token rows

// ---------------------------------------------------------------------------
// Scratch (device globals; no allocations allowed)
// ---------------------------------------------------------------------------
__device__ float g_x  [M_*D_];        // residual stream
__device__ float g_h  [M_*D_];        // normed activations
__device__ float g_qkv[M_*3*D_];      // fused qkv
__device__ float g_att[M_*D_];        // self-attn out / qc
__device__ float g_co [M_*D_];        // cross-attn out
__device__ float g_kvc[B_*S_*2*D_];   // cross k/v projections
__device__ float g_g  [M_*F_];        // gate
__device__ float g_u  [M_*F_];        // up
__device__ float g_cos[L_*32];
__device__ float g_sin[L_*32];

// ---------------------------------------------------------------------------
// RoPE cache
// ---------------------------------------------------------------------------
__global__ void rope_cache_k() {
    int idx = blockIdx.x * blockDim.x + threadIdx.x;   // L_*32 = 65536
    int l = idx >> 5, i = idx & 31;
    double inv = exp(-log(10000.0) * (double)i / 32.0);
    double f = (double)l * inv;
    g_cos[idx] = (float)cos(f);
    g_sin[idx] = (float)sin(f);
}

__global__ void copy_x_k(const float* __restrict__ x) {
    size_t i = (size_t)blockIdx.x * blockDim.x + threadIdx.x;
    if (i < (size_t)M_ * D_) g_x[i] = x[i];
}

// ---------------------------------------------------------------------------
// RMSNorm: one block per row, D=1024, 256 threads x float4
// ---------------------------------------------------------------------------
__global__ void rmsnorm_k(const float* __restrict__ x, const float* __restrict__ w,
                          float* __restrict__ o) {
    int row = blockIdx.x;
    int t = threadIdx.x;                 // 256
    const float4* xr = (const float4*)(x + (size_t)row * D_);
    float4 v = xr[t];
    float ss = v.x*v.x + v.y*v.y + v.z*v.z + v.w*v.w;
    #pragma unroll
    for (int off = 16; off; off >>= 1) ss += __shfl_xor_sync(0xffffffffu, ss, off);
    __shared__ float red[8];
    if ((t & 31) == 0) red[t >> 5] = ss;
    __syncthreads();
    float tot = red[0]+red[1]+red[2]+red[3]+red[4]+red[5]+red[6]+red[7];
    float rs = rsqrtf(tot * (1.0f / (float)D_) + 1e-6f);
    float4 wv = ((const float4*)w)[t];
    float4 out;
    out.x = v.x * rs * wv.x; out.y = v.y * rs * wv.y;
    out.z = v.z * rs * wv.z; out.w = v.w * rs * wv.w;
    ((float4*)(o + (size_t)row * D_))[t] = out;
}

// ---------------------------------------------------------------------------
// tf32 helpers
// ---------------------------------------------------------------------------
__device__ __forceinline__ float to_tf32(float x) {
    float r;
    asm("cvt.rna.tf32.f32 %0, %1;" : "=f"(r) : "f"(x));
    return r;
}

__device__ __forceinline__ void mma_tf32(float* c, const uint32_t* a, const uint32_t* b) {
    asm volatile(
        "mma.sync.aligned.m16n8k8.row.col.f32.tf32.tf32.f32 "
        "{%0,%1,%2,%3}, {%4,%5,%6,%7}, {%8,%9}, {%0,%1,%2,%3};"
        : "+f"(c[0]), "+f"(c[1]), "+f"(c[2]), "+f"(c[3])
        : "r"(a[0]), "r"(a[1]), "r"(a[2]), "r"(a[3]), "r"(b[0]), "r"(b[1]));
}

// ---------------------------------------------------------------------------
// Tensor-core GEMM (NT) with 3-term tf32 split for ~fp32 accuracy:
//   C = Ah*Bh + Ah*Bl + Al*Bh   (A = Ah + Al, B = Bh + Bl, tf32 split)
// C[m,n] = sum_k A[m,k]*W[n,k] (+bias) (+residual). 128x128 block, BK=16,
// 256 threads (8 warps of 64x32), m16n8k8 tiles.
// ---------------------------------------------------------------------------
#define BKG 16
template <bool HAS_BIAS, bool RESIDUAL>
__global__ void __launch_bounds__(256, 2)
gemm_tf32(const float* __restrict__ A, const float* __restrict__ W,
          const float* __restrict__ bias, float* __restrict__ C,
          int M, int N, int K) {
    __shared__ float Ahs[BKG][132];
    __shared__ float Als[BKG][132];
    __shared__ float Bhs[BKG][132];
    __shared__ float Bls[BKG][132];

    const int tid  = threadIdx.x;
    const int warp = tid >> 5, lane = tid & 31;
    const int wm = warp & 1;        // 0..1 : 64-row slab
    const int wn = warp >> 1;       // 0..3 : 32-col slab
    const int g  = lane >> 2;       // group id 0..7
    const int t  = lane & 3;        // thread-in-group 0..3

    const int bm = blockIdx.y, bn = blockIdx.x;
    const float* Abase = A + (size_t)bm * 128 * K;
    const float* Wbase = W + (size_t)bn * 128 * K;

    const int lrow = tid >> 2;          // 0..63
    const int lc   = (tid & 3) * 4;     // 0,4,8,12

    float acc[4][4][4];
    #pragma unroll
    for (int i = 0; i < 4; i++)
        #pragma unroll
        for (int j = 0; j < 4; j++)
            #pragma unroll
            for (int r = 0; r < 4; r++) acc[i][j][r] = 0.f;

    for (int k0 = 0; k0 < K; k0 += BKG) {
        // ---- load gmem tiles, split hi/lo tf32, store to smem ----
        #pragma unroll
        for (int p = 0; p < 2; p++) {
            int r = lrow + p * 64;
            float4 av = *(const float4*)(Abase + (size_t)r * K + k0 + lc);
            float4 bv = *(const float4*)(Wbase + (size_t)r * K + k0 + lc);
            float a4[4] = {av.x, av.y, av.z, av.w};
            float b4[4] = {bv.x, bv.y, bv.z, bv.w};
            #pragma unroll
            for (int i = 0; i < 4; i++) {
                float ah = to_tf32(a4[i]);
                float bh = to_tf32(b4[i]);
                Ahs[lc+i][r] = ah;  Als[lc+i][r] = to_tf32(a4[i] - ah);
                Bhs[lc+i][r] = bh;  Bls[lc+i][r] = to_tf32(b4[i] - bh);
            }
        }
        __syncthreads();

        #pragma unroll
        for (int ks = 0; ks < 2; ks++) {
            const int kb = ks * 8;
            // B fragments (hi and lo)
            uint32_t bh[4][2], bl[4][2];
            #pragma unroll
            for (int nt = 0; nt < 4; nt++) {
                int n = wn * 32 + nt * 8 + g;
                bh[nt][0] = __float_as_uint(Bhs[kb + t    ][n]);
                bh[nt][1] = __float_as_uint(Bhs[kb + t + 4][n]);
                bl[nt][0] = __float_as_uint(Bls[kb + t    ][n]);
                bl[nt][1] = __float_as_uint(Bls[kb + t + 4][n]);
            }
            // A hi fragments
            uint32_t af[4][4];
            #pragma unroll
            for (int mt = 0; mt < 4; mt++) {
                int m = wm * 64 + mt * 16 + g;
                af[mt][0] = __float_as_uint(Ahs[kb + t    ][m    ]);
                af[mt][1] = __float_as_uint(Ahs[kb + t    ][m + 8]);
                af[mt][2] = __float_as_uint(Ahs[kb + t + 4][m    ]);
                af[mt][3] = __float_as_uint(Ahs[kb + t + 4][m + 8]);
            }
            #pragma unroll
            for (int mt = 0; mt < 4; mt++)
                #pragma unroll
                for (int nt = 0; nt < 4; nt++)
                    mma_tf32(acc[mt][nt], af[mt], bh[nt]);
            #pragma unroll
            for (int mt = 0; mt < 4; mt++)
                #pragma unroll
                for (int nt = 0; nt < 4; nt++)
                    mma_tf32(acc[mt][nt], af[mt], bl[nt]);
            // A lo fragments (overwrite af)
            #pragma unroll
            for (int mt = 0; mt < 4; mt++) {
                int m = wm * 64 + mt * 16 + g;
                af[mt][0] = __float_as_uint(Als[kb + t    ][m    ]);
                af[mt][1] = __float_as_uint(Als[kb + t    ][m + 8]);
                af[mt][2] = __float_as_uint(Als[kb + t + 4][m    ]);
                af[mt][3] = __float_as_uint(Als[kb + t + 4][m + 8]);
            }
            #pragma unroll
            for (int mt = 0; mt < 4; mt++)
                #pragma unroll
                for (int nt = 0; nt < 4; nt++)
                    mma_tf32(acc[mt][nt], af[mt], bh[nt]);
        }
        __syncthreads();
    }

    // ---- epilogue ----
    #pragma unroll
    for (int mt = 0; mt < 4; mt++) {
        #pragma unroll
        for (int half = 0; half < 2; half++) {
            int row = bm * 128 + wm * 64 + mt * 16 + g + half * 8;
            #pragma unroll
            for (int nt = 0; nt < 4; nt++) {
                int col = bn * 128 + wn * 32 + nt * 8 + 2 * t;
                float c0 = acc[mt][nt][half * 2 + 0];
                float c1 = acc[mt][nt][half * 2 + 1];
                float* dst = C + (size_t)row * N + col;
                if (HAS_BIAS) { c0 += bias[col]; c1 += bias[col + 1]; }
                if (RESIDUAL) {
                    float2 r = *(const float2*)dst;
                    c0 += r.x; c1 += r.y;
                }
                float2 o2 = make_float2(c0, c1);
                *(float2*)dst = o2;
            }
        }
    }
}

// ---------------------------------------------------------------------------
// RoPE applied in place to q and k slices of qkv. grid = B*L, block 512.
// ---------------------------------------------------------------------------
__global__ void rope_apply_k(float* __restrict__ qkv) {
    int bl = blockIdx.x;
    int l = bl & (L_ - 1);
    int h = threadIdx.x >> 5;
    int i = threadIdx.x & 31;
    float c = g_cos[l*32 + i];
    float s = g_sin[l*32 + i];
    float* base = qkv + (size_t)bl * (3*D_) + h * HD_;
    // q
    float x1 = base[i], x2 = base[i+32];
    base[i]    = x1 * c - x2 * s;
    base[i+32] = x2 * c + x1 * s;
    // k
    float* kb = base + D_;
    x1 = kb[i]; x2 = kb[i+32];
    kb[i]    = x1 * c - x2 * s;
    kb[i+32] = x2 * c + x1 * s;
}

// ---------------------------------------------------------------------------
// Self-attention, causal, flash-style, lane-parallel scoring.
// grid (L/8, H, B); 256 threads = 8 warps, one warp per query.
// K tile stored transposed (Kt[d][key], pad 68 -> bank (4d+key)%32, lanes
// key-parallel conflict-free). V tile row-major.
// ---------------------------------------------------------------------------
__global__ void __launch_bounds__(256)
self_attn_k(const float* __restrict__ qkv, float* __restrict__ out) {
    __shared__ float Kt[64][68];      // [d][key]
    __shared__ float Vs[64][68];      // [key][d]
    __shared__ float Qs[8][64];
    __shared__ float Ps[8][64];
    const int tid = threadIdx.x;
    const int warp = tid >> 5, lane = tid & 31;
    const int h = blockIdx.y, b = blockIdx.z;
    const int q = blockIdx.x * 8 + warp;
    const int qmax = blockIdx.x * 8 + 7;

    const float* qrow = qkv + ((size_t)(b*L_ + q)) * (3*D_) + h * HD_;
    Qs[warp][lane]      = qrow[lane]      * 0.125f;
    Qs[warp][lane + 32] = qrow[lane + 32] * 0.125f;

    float m = -1e30f, lsum = 0.f, a0 = 0.f, a1 = 0.f;

    for (int kt = 0; kt <= qmax; kt += 64) {
        __syncthreads();
        // cooperative fill: K transposed, V row-major (rows always in-bounds)
        for (int idx = tid; idx < 64 * 16; idx += 256) {
            int r = idx >> 4, c4 = (idx & 15) * 4;
            const float* base = qkv + ((size_t)(b*L_ + kt + r)) * (3*D_) + h * HD_ + c4;
            float4 kv = *(const float4*)(base + D_);
            float4 vv = *(const float4*)(base + 2*D_);
            Kt[c4+0][r] = kv.x; Kt[c4+1][r] = kv.y;
            Kt[c4+2][r] = kv.z; Kt[c4+3][r] = kv.w;
            *(float4*)&Vs[r][c4] = vv;
        }
        __syncthreads();

        // scores: each lane handles keys (kt+lane) and (kt+lane+32)
        float s0 = 0.f, s1 = 0.f;
        #pragma unroll 16
        for (int d = 0; d < 64; d++) {
            float qv = Qs[warp][d];
            s0 = fmaf(qv, Kt[d][lane],      s0);
            s1 = fmaf(qv, Kt[d][lane + 32], s1);
        }
        if (kt + lane      > q) s0 = -1e30f;
        if (kt + lane + 32 > q) s1 = -1e30f;

        float tm = fmaxf(s0, s1);
        #pragma unroll
        for (int off = 16; off; off >>= 1) tm = fmaxf(tm, __shfl_xor_sync(0xffffffffu, tm, off));
        float nm = fmaxf(m, tm);
        float sc = __expf(m - nm);
        float p0 = __expf(s0 - nm);
        float p1 = __expf(s1 - nm);
        float ts = p0 + p1;
        #pragma unroll
        for (int off = 16; off; off >>= 1) ts += __shfl_xor_sync(0xffffffffu, ts, off);
        lsum = lsum * sc + ts;
        a0 *= sc; a1 *= sc;
        Ps[warp][lane] = p0; Ps[warp][lane + 32] = p1;
        __syncwarp();
        #pragma unroll 8
        for (int j = 0; j < 64; j++) {
            float p = Ps[warp][j];
            a0 = fmaf(p, Vs[j][lane],      a0);
            a1 = fmaf(p, Vs[j][lane + 32], a1);
        }
        m = nm;
    }
    float invs = 1.0f / lsum;
    float* orow = out + ((size_t)(b*L_ + q)) * D_ + h * HD_;
    orow[lane]      = a0 * invs;
    orow[lane + 32] = a1 * invs;
}

// ---------------------------------------------------------------------------
// Cross-attention with lookback window (<=128 keys per query).
// ---------------------------------------------------------------------------
__global__ void __launch_bounds__(256)
cross_attn_k(const float* __restrict__ qc, const float* __restrict__ kvc,
             const int* __restrict__ seg_ids, float* __restrict__ out) {
    const int tid = threadIdx.x;
    const int warp = tid >> 5, lane = tid & 31;
    const int h = blockIdx.y, b = blockIdx.z;
    const int l = blockIdx.x * 8 + warp;

    const int seg = seg_ids[b * L_ + l];
    int j0 = seg - 127; if (j0 < 0) j0 = 0;
    const int j1 = seg;

    const float* qrow = qc + ((size_t)(b*L_ + l)) * D_ + h * HD_;
    const float qv0 = qrow[lane]      * 0.125f;
    const float qv1 = qrow[lane + 32] * 0.125f;

    float m = -1e30f, lsum = 0.f, a0 = 0.f, a1 = 0.f;
    for (int j = j0; j <= j1; j++) {
        const float* krow = kvc + ((size_t)(b*S_ + j)) * (2*D_) + h * HD_;
        float s = qv0 * krow[lane] + qv1 * krow[lane + 32];
        #pragma unroll
        for (int off = 16; off; off >>= 1) s += __shfl_xor_sync(0xffffffffu, s, off);
        float nm = fmaxf(m, s);
        float sc = __expf(m - nm);
        float p  = __expf(s - nm);
        lsum = lsum * sc + p;
        const float* vrow = krow + D_;
        a0 = fmaf(p, vrow[lane],      a0 * sc);
        a1 = fmaf(p, vrow[lane + 32], a1 * sc);
        m = nm;
    }
    float invs = 1.0f / lsum;
    float* orow = out + ((size_t)(b*L_ + l)) * D_ + h * HD_;
    orow[lane]      = a0 * invs;
    orow[lane + 32] = a1 * invs;
}

// ---------------------------------------------------------------------------
// SwiGLU elementwise: g = silu(g) * u
// ---------------------------------------------------------------------------
__global__ void silu_mul_k(float* __restrict__ g, const float* __restrict__ u) {
    size_t i = (size_t)blockIdx.x * blockDim.x + threadIdx.x;
    if (i < (size_t)M_ * F_) {
        float gv = g[i];
        float s = gv / (1.0f + expf(-gv));
        g[i] = s * u[i];
    }
}

// ---------------------------------------------------------------------------
// Launch
// ---------------------------------------------------------------------------
extern "C" void kernel_launch(void* const* d_in, const int* in_sizes, int n_in,
                              void* d_out, int out_size) {
    const float* x      = (const float*)d_in[0];
    const float* memory = (const float*)d_in[1];
    const int*   seg    = (const int*)  d_in[2];
    const float* Wqkv   = (const float*)d_in[3];
    const float* bqkv   = (const float*)d_in[4];
    const float* Wo     = (const float*)d_in[5];
    const float* bo     = (const float*)d_in[6];
    const float* Wq_c   = (const float*)d_in[7];
    const float* Wkv_c  = (const float*)d_in[8];
    const float* Wo_c   = (const float*)d_in[9];
    const float* Wg     = (const float*)d_in[10];
    const float* Wu     = (const float*)d_in[11];
    const float* Wd     = (const float*)d_in[12];
    const float* n1     = (const float*)d_in[13];
    const float* n2     = (const float*)d_in[14];
    const float* n3     = (const float*)d_in[15];
    const float* nf     = (const float*)d_in[16];

    float *xb, *hb, *qkvb, *ab, *cob, *kvcb, *gb, *ub;
    cudaGetSymbolAddress((void**)&xb,   g_x);
    cudaGetSymbolAddress((void**)&hb,   g_h);
    cudaGetSymbolAddress((void**)&qkvb, g_qkv);
    cudaGetSymbolAddress((void**)&ab,   g_att);
    cudaGetSymbolAddress((void**)&cob,  g_co);
    cudaGetSymbolAddress((void**)&kvcb, g_kvc);
    cudaGetSymbolAddress((void**)&gb,   g_g);
    cudaGetSymbolAddress((void**)&ub,   g_u);

    rope_cache_k<<<256, 256>>>();
    copy_x_k<<<(M_*D_)/256, 256>>>(x);

    const dim3 attn_grid(L_/8, H_, B_);

    for (int l = 0; l < NL; l++) {
        const float* wqkv_l = Wqkv  + (size_t)l * 3*D_ * D_;
        const float* bqkv_l = bqkv  + (size_t)l * 3*D_;
        const float* wo_l   = Wo    + (size_t)l * D_ * D_;
        const float* bo_l   = bo    + (size_t)l * D_;
        const float* wqc_l  = Wq_c  + (size_t)l * D_ * D_;
        const float* wkvc_l = Wkv_c + (size_t)l * 2*D_ * D_;
        const float* woc_l  = Wo_c  + (size_t)l * D_ * D_;
        const float* wg_l   = Wg    + (size_t)l * F_ * D_;
        const float* wu_l   = Wu    + (size_t)l * F_ * D_;
        const float* wd_l   = Wd    + (size_t)l * D_ * F_;

        // --- self attention block ---
        rmsnorm_k<<<M_, 256>>>(xb, n1 + l*D_, hb);
        gemm_tf32<true, false><<<dim3(3*D_/128, M_/128), 256>>>(hb, wqkv_l, bqkv_l, qkvb, M_, 3*D_, D_);
        rope_apply_k<<<M_, 512>>>(qkvb);
        self_attn_k<<<attn_grid, 256>>>(qkvb, ab);
        gemm_tf32<true, true><<<dim3(D_/128, M_/128), 256>>>(ab, wo_l, bo_l, xb, M_, D_, D_);

        // --- cross attention block ---
        rmsnorm_k<<<M_, 256>>>(xb, n2 + l*D_, hb);
        gemm_tf32<false, false><<<dim3(D_/128, M_/128), 256>>>(hb, wqc_l, nullptr, ab, M_, D_, D_);
        gemm_tf32<false, false><<<dim3(2*D_/128, (B_*S_)/128), 256>>>(memory, wkvc_l, nullptr, kvcb, B_*S_, 2*D_, D_);
        cross_attn_k<<<attn_grid, 256>>>(ab, kvcb, seg, cob);
        gemm_tf32<false, true><<<dim3(D_/128, M_/128), 256>>>(cob, woc_l, nullptr, xb, M_, D_, D_);

        // --- MLP block ---
        rmsnorm_k<<<M_, 256>>>(xb, n3 + l*D_, hb);
        gemm_tf32<false, false><<<dim3(F_/128, M_/128), 256>>>(hb, wg_l, nullptr, gb, M_, F_, D_);
        gemm_tf32<false, false><<<dim3(F_/128, M_/128), 256>>>(hb, wu_l, nullptr, ub, M_, F_, D_);
        silu_mul_k<<<(M_*F_)/256, 256>>>(gb, ub);
        gemm_tf32<false, true><<<dim3(D_/128, M_/128), 256>>>(gb, wd_l, nullptr, xb, M_, D_, F_);
    }

    rmsnorm_k<<<M_, 256>>>(xb, nf, (float*)d_out);
}

// round 3
// speedup vs baseline: 2.0111x; 1.4986x over previous
#include <cuda_runtime.h>
#include <cuda_bf16.h>
#include <math.h>
#include <stdint.h>

// Problem constants
#define NL 4
#define B_ 2
#define L_ 2048
#define S_ 256
#define D_ 1024
#define F_ 4096
#define H_ 16
#define HD_ 64
#define M_ (B_*L_)          // 4096 token rows

// Weight region sizes (elements) and offsets in the concatenated split buffer
#define SZ_WQKV ((size_t)3*D_*D_)
#define SZ_WO   ((size_t)D_*D_)
#define SZ_WQC  ((size_t)D_*D_)
#define SZ_WKVC ((size_t)2*D_*D_)
#define SZ_WOC  ((size_t)D_*D_)
#define SZ_WG   ((size_t)F_*D_)
#define SZ_WU   ((size_t)F_*D_)
#define SZ_WD   ((size_t)D_*F_)
static const size_t O_WQKV = 0;
static const size_t O_WO   = O_WQKV + NL*SZ_WQKV;
static const size_t O_WQC  = O_WO   + NL*SZ_WO;
static const size_t O_WKVC = O_WQC  + NL*SZ_WQC;
static const size_t O_WOC  = O_WKVC + NL*SZ_WKVC;
static const size_t O_WG   = O_WOC  + NL*SZ_WOC;
static const size_t O_WU   = O_WG   + NL*SZ_WG;
static const size_t O_WD   = O_WU   + NL*SZ_WU;
#define WTOT (O_WD + NL*SZ_WD)   // 83,886,080 elements

// ---------------------------------------------------------------------------
// Scratch (device globals; no allocations allowed)
// ---------------------------------------------------------------------------
__device__ float g_x  [M_*D_];        // residual stream (fp32)
__device__ float g_qkv[M_*3*D_];      // fused qkv (fp32)
__device__ float g_qc [M_*D_];        // cross-attn q proj (fp32)
__device__ float g_kvc[B_*S_*2*D_];   // cross k/v projections (fp32)
__device__ float g_g  [M_*F_];        // gate (fp32, GEMM out)
__device__ float g_u  [M_*F_];        // up (fp32, GEMM out)
__device__ float g_cos[L_*32];
__device__ float g_sin[L_*32];

// bf16 hi/lo split buffers (GEMM A operands)
__device__ __nv_bfloat16 g_h_hi [M_*D_],  g_h_lo [M_*D_];
__device__ __nv_bfloat16 g_at_hi[M_*D_],  g_at_lo[M_*D_];
__device__ __nv_bfloat16 g_co_hi[M_*D_],  g_co_lo[M_*D_];
__device__ __nv_bfloat16 g_gs_hi[M_*F_],  g_gs_lo[M_*F_];
__device__ __nv_bfloat16 g_m_hi [B_*S_*D_], g_m_lo[B_*S_*D_];
// bf16 hi/lo split weights (all tensors concatenated)
__device__ __nv_bfloat16 g_w_hi[WTOT], g_w_lo[WTOT];

// ---------------------------------------------------------------------------
// bf16 split helpers
// ---------------------------------------------------------------------------
__device__ __forceinline__ void split1(float v, unsigned short& h, unsigned short& l) {
    __nv_bfloat16 hb = __float2bfloat16_rn(v);
    float r = v - __bfloat162float(hb);
    __nv_bfloat16 lb = __float2bfloat16_rn(r);
    h = __bfloat16_as_ushort(hb);
    l = __bfloat16_as_ushort(lb);
}
__device__ __forceinline__ void split_pack4(float4 v, uint2& ph, uint2& pl) {
    unsigned short h0,h1,h2,h3,l0,l1,l2,l3;
    split1(v.x,h0,l0); split1(v.y,h1,l1); split1(v.z,h2,l2); split1(v.w,h3,l3);
    ph.x = (uint32_t)h0 | ((uint32_t)h1 << 16);
    ph.y = (uint32_t)h2 | ((uint32_t)h3 << 16);
    pl.x = (uint32_t)l0 | ((uint32_t)l1 << 16);
    pl.y = (uint32_t)l2 | ((uint32_t)l3 << 16);
}

// Generic fp32 -> bf16 hi/lo split (grid-stride not needed; exact grids)
__global__ void split_k(const float* __restrict__ in, __nv_bfloat16* __restrict__ hi,
                        __nv_bfloat16* __restrict__ lo, int n4) {
    int i = blockIdx.x * blockDim.x + threadIdx.x;
    if (i >= n4) return;
    float4 v = ((const float4*)in)[i];
    uint2 ph, pl; split_pack4(v, ph, pl);
    ((uint2*)hi)[i] = ph;
    ((uint2*)lo)[i] = pl;
}

// ---------------------------------------------------------------------------
// RoPE cache
// ---------------------------------------------------------------------------
__global__ void rope_cache_k() {
    int idx = blockIdx.x * blockDim.x + threadIdx.x;   // L_*32
    int l = idx >> 5, i = idx & 31;
    double inv = exp(-log(10000.0) * (double)i / 32.0);
    double f = (double)l * inv;
    g_cos[idx] = (float)cos(f);
    g_sin[idx] = (float)sin(f);
}

__global__ void copy_x_k(const float* __restrict__ x) {
    size_t i = (size_t)blockIdx.x * blockDim.x + threadIdx.x;
    if (i < (size_t)M_ * D_) g_x[i] = x[i];
}

// ---------------------------------------------------------------------------
// RMSNorm -> bf16 hi/lo split output
// ---------------------------------------------------------------------------
__global__ void rmsnorm_split_k(const float* __restrict__ x, const float* __restrict__ w,
                                __nv_bfloat16* __restrict__ hi, __nv_bfloat16* __restrict__ lo) {
    int row = blockIdx.x;
    int t = threadIdx.x;                 // 256
    const float4* xr = (const float4*)(x + (size_t)row * D_);
    float4 v = xr[t];
    float ss = v.x*v.x + v.y*v.y + v.z*v.z + v.w*v.w;
    #pragma unroll
    for (int off = 16; off; off >>= 1) ss += __shfl_xor_sync(0xffffffffu, ss, off);
    __shared__ float red[8];
    if ((t & 31) == 0) red[t >> 5] = ss;
    __syncthreads();
    float tot = red[0]+red[1]+red[2]+red[3]+red[4]+red[5]+red[6]+red[7];
    float rs = rsqrtf(tot * (1.0f / (float)D_) + 1e-6f);
    float4 wv = ((const float4*)w)[t];
    float4 o;
    o.x = v.x * rs * wv.x; o.y = v.y * rs * wv.y;
    o.z = v.z * rs * wv.z; o.w = v.w * rs * wv.w;
    uint2 ph, pl; split_pack4(o, ph, pl);
    ((uint2*)hi)[(size_t)row * 256 + t] = ph;
    ((uint2*)lo)[(size_t)row * 256 + t] = pl;
}

// Final RMSNorm -> fp32 output
__global__ void rmsnorm_k(const float* __restrict__ x, const float* __restrict__ w,
                          float* __restrict__ o) {
    int row = blockIdx.x;
    int t = threadIdx.x;
    const float4* xr = (const float4*)(x + (size_t)row * D_);
    float4 v = xr[t];
    float ss = v.x*v.x + v.y*v.y + v.z*v.z + v.w*v.w;
    #pragma unroll
    for (int off = 16; off; off >>= 1) ss += __shfl_xor_sync(0xffffffffu, ss, off);
    __shared__ float red[8];
    if ((t & 31) == 0) red[t >> 5] = ss;
    __syncthreads();
    float tot = red[0]+red[1]+red[2]+red[3]+red[4]+red[5]+red[6]+red[7];
    float rs = rsqrtf(tot * (1.0f / (float)D_) + 1e-6f);
    float4 wv = ((const float4*)w)[t];
    float4 out;
    out.x = v.x * rs * wv.x; out.y = v.y * rs * wv.y;
    out.z = v.z * rs * wv.z; out.w = v.w * rs * wv.w;
    ((float4*)(o + (size_t)row * D_))[t] = out;
}

// ---------------------------------------------------------------------------
// mma / ldmatrix helpers
// ---------------------------------------------------------------------------
__device__ __forceinline__ void mma_bf16(float* c, const uint32_t* a, const uint32_t* b) {
    asm volatile(
        "mma.sync.aligned.m16n8k16.row.col.f32.bf16.bf16.f32 "
        "{%0,%1,%2,%3}, {%4,%5,%6,%7}, {%8,%9}, {%0,%1,%2,%3};"
        : "+f"(c[0]), "+f"(c[1]), "+f"(c[2]), "+f"(c[3])
        : "r"(a[0]), "r"(a[1]), "r"(a[2]), "r"(a[3]), "r"(b[0]), "r"(b[1]));
}
__device__ __forceinline__ void ldsm_x4(uint32_t* r, uint32_t addr) {
    asm volatile("ldmatrix.sync.aligned.m8n8.x4.shared.b16 {%0,%1,%2,%3}, [%4];"
        : "=r"(r[0]), "=r"(r[1]), "=r"(r[2]), "=r"(r[3]) : "r"(addr));
}
__device__ __forceinline__ void ldsm_x2(uint32_t* r, uint32_t addr) {
    asm volatile("ldmatrix.sync.aligned.m8n8.x2.shared.b16 {%0,%1}, [%2];"
        : "=r"(r[0]), "=r"(r[1]) : "r"(addr));
}

// ---------------------------------------------------------------------------
// bf16 split-3 GEMM (NT): C[m,n] = sum_k A[m,k]*W[n,k] (+bias) (+residual)
//   A = Ah + Al, W = Wh + Wl (bf16 split); C = AhWh + AhWl + AlWh (fp32 acc)
// 128x128 block, BK=32, 256 threads (8 warps, 64x32 warp tiles), m16n8k16.
// 3-stage cp.async pipeline. Smem layout per stage: Ah|Al|Wh|Wl, each
// [128 rows][32 k] bf16 with 80B row stride ([row][k], 16B-aligned rows).
// ---------------------------------------------------------------------------
#define GSTAGE  40960     // 4 * 10240 bytes
#define GARR    10240     // 128 * 80
#define GSMEM   (3*GSTAGE)

template <bool HAS_BIAS, bool RESIDUAL>
__global__ void __launch_bounds__(256, 1)
gemm_bf16s(const __nv_bfloat16* __restrict__ Ah, const __nv_bfloat16* __restrict__ Al,
           const __nv_bfloat16* __restrict__ Wh, const __nv_bfloat16* __restrict__ Wl,
           const float* __restrict__ bias, float* __restrict__ C,
           int N, int K) {
    extern __shared__ char smem[];
    const uint32_t sbase = (uint32_t)__cvta_generic_to_shared(smem);
    const int tid  = threadIdx.x;
    const int warp = tid >> 5, lane = tid & 31;
    const int wm = warp & 1;        // 0..1 : 64-row slab
    const int wn = warp >> 1;       // 0..3 : 32-col slab
    const int g  = lane >> 2;
    const int t  = lane & 3;
    const int bm = blockIdx.y, bn = blockIdx.x;

    // cp.async chunk tables: 2048 16B-chunks per stage, 8 per thread
    const __nv_bfloat16* src[8];
    uint32_t dst[8];
    #pragma unroll
    for (int i = 0; i < 8; i++) {
        int id  = tid + 256 * i;
        int arr = id >> 9;          // 0:Ah 1:Al 2:Wh 3:Wl
        int rem = id & 511;
        int row = rem >> 2;
        int kc  = rem & 3;          // 16B chunk within row (8 bf16)
        const __nv_bfloat16* bp = (arr == 0) ? Ah : (arr == 1) ? Al : (arr == 2) ? Wh : Wl;
        int grow = ((arr < 2) ? bm : bn) * 128 + row;
        src[i] = bp + (size_t)grow * K + kc * 8;
        dst[i] = (uint32_t)(arr * GARR + row * 80 + kc * 16);
    }

    // ldmatrix base offsets (within an array region of a stage)
    const uint32_t arow = (uint32_t)((wm * 64 + (lane & 15)) * 80 + (lane >> 4) * 16);
    const uint32_t brow = (uint32_t)((wn * 32 + (lane & 7)) * 80 + ((lane >> 3) & 1) * 16);

    float acc[4][4][4];
    #pragma unroll
    for (int i = 0; i < 4; i++)
        #pragma unroll
        for (int j = 0; j < 4; j++)
            #pragma unroll
            for (int r = 0; r < 4; r++) acc[i][j][r] = 0.f;

    const int nk = K >> 5;

    // prologue: stages 0,1
    #pragma unroll
    for (int st = 0; st < 2; st++) {
        uint32_t s = sbase + st * GSTAGE;
        #pragma unroll
        for (int i = 0; i < 8; i++) {
            const void* p = src[i] + st * 32;
            asm volatile("cp.async.cg.shared.global [%0], [%1], 16;"
                         :: "r"(s + dst[i]), "l"(p) : "memory");
        }
        asm volatile("cp.async.commit_group;" ::: "memory");
    }

    for (int it = 0; it < nk; it++) {
        asm volatile("cp.async.wait_group 1;" ::: "memory");
        __syncthreads();
        uint32_t s = sbase + (uint32_t)(it % 3) * GSTAGE;

        #pragma unroll
        for (int ks = 0; ks < 2; ks++) {
            const uint32_t ko = ks * 32;   // 16 bf16 = 32 bytes per k-step
            uint32_t af[4][4], bh[4][2], bl[4][2];
            #pragma unroll
            for (int mt = 0; mt < 4; mt++) ldsm_x4(af[mt], s + 0*GARR + arow + mt*1280 + ko);
            #pragma unroll
            for (int nt = 0; nt < 4; nt++) ldsm_x2(bh[nt], s + 2*GARR + brow + nt*640 + ko);
            #pragma unroll
            for (int nt = 0; nt < 4; nt++) ldsm_x2(bl[nt], s + 3*GARR + brow + nt*640 + ko);
            #pragma unroll
            for (int mt = 0; mt < 4; mt++)
                #pragma unroll
                for (int nt = 0; nt < 4; nt++) mma_bf16(acc[mt][nt], af[mt], bh[nt]);
            #pragma unroll
            for (int mt = 0; mt < 4; mt++)
                #pragma unroll
                for (int nt = 0; nt < 4; nt++) mma_bf16(acc[mt][nt], af[mt], bl[nt]);
            #pragma unroll
            for (int mt = 0; mt < 4; mt++) ldsm_x4(af[mt], s + 1*GARR + arow + mt*1280 + ko);
            #pragma unroll
            for (int mt = 0; mt < 4; mt++)
                #pragma unroll
                for (int nt = 0; nt < 4; nt++) mma_bf16(acc[mt][nt], af[mt], bh[nt]);
        }

        if (it + 2 < nk) {
            uint32_t s2 = sbase + (uint32_t)((it + 2) % 3) * GSTAGE;
            int k0 = (it + 2) * 32;
            #pragma unroll
            for (int i = 0; i < 8; i++) {
                const void* p = src[i] + k0;
                asm volatile("cp.async.cg.shared.global [%0], [%1], 16;"
                             :: "r"(s2 + dst[i]), "l"(p) : "memory");
            }
        }
        asm volatile("cp.async.commit_group;" ::: "memory");
    }

    // ---- epilogue ----
    #pragma unroll
    for (int mt = 0; mt < 4; mt++) {
        #pragma unroll
        for (int half = 0; half < 2; half++) {
            int row = bm * 128 + wm * 64 + mt * 16 + g + half * 8;
            #pragma unroll
            for (int nt = 0; nt < 4; nt++) {
                int col = bn * 128 + wn * 32 + nt * 8 + 2 * t;
                float c0 = acc[mt][nt][half * 2 + 0];
                float c1 = acc[mt][nt][half * 2 + 1];
                float* dstp = C + (size_t)row * N + col;
                if (HAS_BIAS) { c0 += bias[col]; c1 += bias[col + 1]; }
                if (RESIDUAL) {
                    float2 r = *(const float2*)dstp;
                    c0 += r.x; c1 += r.y;
                }
                *(float2*)dstp = make_float2(c0, c1);
            }
        }
    }
}

// ---------------------------------------------------------------------------
// RoPE applied in place to q and k slices of qkv. grid = B*L, block 512.
// ---------------------------------------------------------------------------
__global__ void rope_apply_k(float* __restrict__ qkv) {
    int bl = blockIdx.x;
    int l = bl & (L_ - 1);
    int h = threadIdx.x >> 5;
    int i = threadIdx.x & 31;
    float c = g_cos[l*32 + i];
    float s = g_sin[l*32 + i];
    float* base = qkv + (size_t)bl * (3*D_) + h * HD_;
    float x1 = base[i], x2 = base[i+32];
    base[i]    = x1 * c - x2 * s;
    base[i+32] = x2 * c + x1 * s;
    float* kb = base + D_;
    x1 = kb[i]; x2 = kb[i+32];
    kb[i]    = x1 * c - x2 * s;
    kb[i+32] = x2 * c + x1 * s;
}

// ---------------------------------------------------------------------------
// Self-attention, causal, flash-style, lane-parallel scoring.
// Epilogue writes bf16 hi/lo split (feeds Wo GEMM).
// ---------------------------------------------------------------------------
__global__ void __launch_bounds__(256)
self_attn_k(const float* __restrict__ qkv,
            __nv_bfloat16* __restrict__ out_hi, __nv_bfloat16* __restrict__ out_lo) {
    __shared__ float Kt[64][68];      // [d][key]
    __shared__ float Vs[64][68];      // [key][d]
    __shared__ float Qs[8][64];
    __shared__ float Ps[8][64];
    const int tid = threadIdx.x;
    const int warp = tid >> 5, lane = tid & 31;
    const int h = blockIdx.y, b = blockIdx.z;
    const int q = blockIdx.x * 8 + warp;
    const int qmax = blockIdx.x * 8 + 7;

    const float* qrow = qkv + ((size_t)(b*L_ + q)) * (3*D_) + h * HD_;
    Qs[warp][lane]      = qrow[lane]      * 0.125f;
    Qs[warp][lane + 32] = qrow[lane + 32] * 0.125f;

    float m = -1e30f, lsum = 0.f, a0 = 0.f, a1 = 0.f;

    for (int kt = 0; kt <= qmax; kt += 64) {
        __syncthreads();
        for (int idx = tid; idx < 64 * 16; idx += 256) {
            int r = idx >> 4, c4 = (idx & 15) * 4;
            const float* base = qkv + ((size_t)(b*L_ + kt + r)) * (3*D_) + h * HD_ + c4;
            float4 kv = *(const float4*)(base + D_);
            float4 vv = *(const float4*)(base + 2*D_);
            Kt[c4+0][r] = kv.x; Kt[c4+1][r] = kv.y;
            Kt[c4+2][r] = kv.z; Kt[c4+3][r] = kv.w;
            *(float4*)&Vs[r][c4] = vv;
        }
        __syncthreads();

        float s0 = 0.f, s1 = 0.f;
        #pragma unroll 16
        for (int d = 0; d < 64; d++) {
            float qv = Qs[warp][d];
            s0 = fmaf(qv, Kt[d][lane],      s0);
            s1 = fmaf(qv, Kt[d][lane + 32], s1);
        }
        if (kt + lane      > q) s0 = -1e30f;
        if (kt + lane + 32 > q) s1 = -1e30f;

        float tm = fmaxf(s0, s1);
        #pragma unroll
        for (int off = 16; off; off >>= 1) tm = fmaxf(tm, __shfl_xor_sync(0xffffffffu, tm, off));
        float nm = fmaxf(m, tm);
        float sc = __expf(m - nm);
        float p0 = __expf(s0 - nm);
        float p1 = __expf(s1 - nm);
        float ts = p0 + p1;
        #pragma unroll
        for (int off = 16; off; off >>= 1) ts += __shfl_xor_sync(0xffffffffu, ts, off);
        lsum = lsum * sc + ts;
        a0 *= sc; a1 *= sc;
        Ps[warp][lane] = p0; Ps[warp][lane + 32] = p1;
        __syncwarp();
        #pragma unroll 8
        for (int j = 0; j < 64; j++) {
            float p = Ps[warp][j];
            a0 = fmaf(p, Vs[j][lane],      a0);
            a1 = fmaf(p, Vs[j][lane + 32], a1);
        }
        m = nm;
    }
    float invs = 1.0f / lsum;
    float v0 = a0 * invs, v1 = a1 * invs;
    size_t base = ((size_t)(b*L_ + q)) * D_ + h * HD_;
    unsigned short h0, l0, h1, l1;
    split1(v0, h0, l0); split1(v1, h1, l1);
    out_hi[base + lane]      = __ushort_as_bfloat16(h0);
    out_lo[base + lane]      = __ushort_as_bfloat16(l0);
    out_hi[base + lane + 32] = __ushort_as_bfloat16(h1);
    out_lo[base + lane + 32] = __ushort_as_bfloat16(l1);
}

// ---------------------------------------------------------------------------
// Cross-attention with lookback window (<=128 keys per query). bf16 split out.
// ---------------------------------------------------------------------------
__global__ void __launch_bounds__(256)
cross_attn_k(const float* __restrict__ qc, const float* __restrict__ kvc,
             const int* __restrict__ seg_ids,
             __nv_bfloat16* __restrict__ out_hi, __nv_bfloat16* __restrict__ out_lo) {
    const int tid = threadIdx.x;
    const int warp = tid >> 5, lane = tid & 31;
    const int h = blockIdx.y, b = blockIdx.z;
    const int l = blockIdx.x * 8 + warp;

    const int seg = seg_ids[b * L_ + l];
    int j0 = seg - 127; if (j0 < 0) j0 = 0;
    const int j1 = seg;

    const float* qrow = qc + ((size_t)(b*L_ + l)) * D_ + h * HD_;
    const float qv0 = qrow[lane]      * 0.125f;
    const float qv1 = qrow[lane + 32] * 0.125f;

    float m = -1e30f, lsum = 0.f, a0 = 0.f, a1 = 0.f;
    for (int j = j0; j <= j1; j++) {
        const float* krow = kvc + ((size_t)(b*S_ + j)) * (2*D_) + h * HD_;
        float s = qv0 * krow[lane] + qv1 * krow[lane + 32];
        #pragma unroll
        for (int off = 16; off; off >>= 1) s += __shfl_xor_sync(0xffffffffu, s, off);
        float nm = fmaxf(m, s);
        float sc = __expf(m - nm);
        float p  = __expf(s - nm);
        lsum = lsum * sc + p;
        const float* vrow = krow + D_;
        a0 = fmaf(p, vrow[lane],      a0 * sc);
        a1 = fmaf(p, vrow[lane + 32], a1 * sc);
        m = nm;
    }
    float invs = 1.0f / lsum;
    float v0 = a0 * invs, v1 = a1 * invs;
    size_t base = ((size_t)(b*L_ + l)) * D_ + h * HD_;
    unsigned short h0, l0s, h1, l1;
    split1(v0, h0, l0s); split1(v1, h1, l1);
    out_hi[base + lane]      = __ushort_as_bfloat16(h0);
    out_lo[base + lane]      = __ushort_as_bfloat16(l0s);
    out_hi[base + lane + 32] = __ushort_as_bfloat16(h1);
    out_lo[base + lane + 32] = __ushort_as_bfloat16(l1);
}

// ---------------------------------------------------------------------------
// SwiGLU: silu(g)*u -> bf16 hi/lo split
// ---------------------------------------------------------------------------
__global__ void silu_split_k(const float* __restrict__ g, const float* __restrict__ u,
                             __nv_bfloat16* __restrict__ hi, __nv_bfloat16* __restrict__ lo,
                             int n4) {
    int i = blockIdx.x * blockDim.x + threadIdx.x;
    if (i >= n4) return;
    float4 gv = ((const float4*)g)[i];
    float4 uv = ((const float4*)u)[i];
    float4 o;
    o.x = gv.x / (1.0f + expf(-gv.x)) * uv.x;
    o.y = gv.y / (1.0f + expf(-gv.y)) * uv.y;
    o.z = gv.z / (1.0f + expf(-gv.z)) * uv.z;
    o.w = gv.w / (1.0f + expf(-gv.w)) * uv.w;
    uint2 ph, pl; split_pack4(o, ph, pl);
    ((uint2*)hi)[i] = ph;
    ((uint2*)lo)[i] = pl;
}

// ---------------------------------------------------------------------------
// Launch
// ---------------------------------------------------------------------------
static inline void split_launch(const float* src, __nv_bfloat16* hi, __nv_bfloat16* lo, size_t n) {
    int n4 = (int)(n / 4);
    split_k<<<(n4 + 255) / 256, 256>>>(src, hi, lo, n4);
}

extern "C" void kernel_launch(void* const* d_in, const int* in_sizes, int n_in,
                              void* d_out, int out_size) {
    const float* x      = (const float*)d_in[0];
    const float* memory = (const float*)d_in[1];
    const int*   seg    = (const int*)  d_in[2];
    const float* Wqkv   = (const float*)d_in[3];
    const float* bqkv   = (const float*)d_in[4];
    const float* Wo     = (const float*)d_in[5];
    const float* bo     = (const float*)d_in[6];
    const float* Wq_c   = (const float*)d_in[7];
    const float* Wkv_c  = (const float*)d_in[8];
    const float* Wo_c   = (const float*)d_in[9];
    const float* Wg     = (const float*)d_in[10];
    const float* Wu     = (const float*)d_in[11];
    const float* Wd     = (const float*)d_in[12];
    const float* n1     = (const float*)d_in[13];
    const float* n2     = (const float*)d_in[14];
    const float* n3     = (const float*)d_in[15];
    const float* nf     = (const float*)d_in[16];

    cudaFuncSetAttribute(gemm_bf16s<true,  false>, cudaFuncAttributeMaxDynamicSharedMemorySize, GSMEM);
    cudaFuncSetAttribute(gemm_bf16s<true,  true >, cudaFuncAttributeMaxDynamicSharedMemorySize, GSMEM);
    cudaFuncSetAttribute(gemm_bf16s<false, false>, cudaFuncAttributeMaxDynamicSharedMemorySize, GSMEM);
    cudaFuncSetAttribute(gemm_bf16s<false, true >, cudaFuncAttributeMaxDynamicSharedMemorySize, GSMEM);

    float *xb, *qkvb, *qcb, *kvcb, *gb, *ub;
    __nv_bfloat16 *hhi, *hlo, *ahi, *alo, *chi, *clo, *gshi, *gslo, *mhi, *mlo, *whi, *wlo;
    cudaGetSymbolAddress((void**)&xb,   g_x);
    cudaGetSymbolAddress((void**)&qkvb, g_qkv);
    cudaGetSymbolAddress((void**)&qcb,  g_qc);
    cudaGetSymbolAddress((void**)&kvcb, g_kvc);
    cudaGetSymbolAddress((void**)&gb,   g_g);
    cudaGetSymbolAddress((void**)&ub,   g_u);
    cudaGetSymbolAddress((void**)&hhi,  g_h_hi);  cudaGetSymbolAddress((void**)&hlo,  g_h_lo);
    cudaGetSymbolAddress((void**)&ahi,  g_at_hi); cudaGetSymbolAddress((void**)&alo,  g_at_lo);
    cudaGetSymbolAddress((void**)&chi,  g_co_hi); cudaGetSymbolAddress((void**)&clo,  g_co_lo);
    cudaGetSymbolAddress((void**)&gshi, g_gs_hi); cudaGetSymbolAddress((void**)&gslo, g_gs_lo);
    cudaGetSymbolAddress((void**)&mhi,  g_m_hi);  cudaGetSymbolAddress((void**)&mlo,  g_m_lo);
    cudaGetSymbolAddress((void**)&whi,  g_w_hi);  cudaGetSymbolAddress((void**)&wlo,  g_w_lo);

    rope_cache_k<<<256, 256>>>();
    copy_x_k<<<(M_*D_)/256, 256>>>(x);

    // split all weights + memory into bf16 hi/lo
    split_launch(Wqkv,  whi + O_WQKV, wlo + O_WQKV, NL*SZ_WQKV);
    split_launch(Wo,    whi + O_WO,   wlo + O_WO,   NL*SZ_WO);
    split_launch(Wq_c,  whi + O_WQC,  wlo + O_WQC,  NL*SZ_WQC);
    split_launch(Wkv_c, whi + O_WKVC, wlo + O_WKVC, NL*SZ_WKVC);
    split_launch(Wo_c,  whi + O_WOC,  wlo + O_WOC,  NL*SZ_WOC);
    split_launch(Wg,    whi + O_WG,   wlo + O_WG,   NL*SZ_WG);
    split_launch(Wu,    whi + O_WU,   wlo + O_WU,   NL*SZ_WU);
    split_launch(Wd,    whi + O_WD,   wlo + O_WD,   NL*SZ_WD);
    split_launch(memory, mhi, mlo, (size_t)B_*S_*D_);

    const dim3 attn_grid(L_/8, H_, B_);

    for (int l = 0; l < NL; l++) {
        const __nv_bfloat16* wqkv_h = whi + O_WQKV + l*SZ_WQKV;
        const __nv_bfloat16* wqkv_l = wlo + O_WQKV + l*SZ_WQKV;
        const __nv_bfloat16* wo_h   = whi + O_WO   + l*SZ_WO;
        const __nv_bfloat16* wo_l   = wlo + O_WO   + l*SZ_WO;
        const __nv_bfloat16* wqc_h  = whi + O_WQC  + l*SZ_WQC;
        const __nv_bfloat16* wqc_l  = wlo + O_WQC  + l*SZ_WQC;
        const __nv_bfloat16* wkvc_h = whi + O_WKVC + l*SZ_WKVC;
        const __nv_bfloat16* wkvc_l = wlo + O_WKVC + l*SZ_WKVC;
        const __nv_bfloat16* woc_h  = whi + O_WOC  + l*SZ_WOC;
        const __nv_bfloat16* woc_l  = wlo + O_WOC  + l*SZ_WOC;
        const __nv_bfloat16* wg_h   = whi + O_WG   + l*SZ_WG;
        const __nv_bfloat16* wg_l   = wlo + O_WG   + l*SZ_WG;
        const __nv_bfloat16* wu_h   = whi + O_WU   + l*SZ_WU;
        const __nv_bfloat16* wu_l   = wlo + O_WU   + l*SZ_WU;
        const __nv_bfloat16* wd_h   = whi + O_WD   + l*SZ_WD;
        const __nv_bfloat16* wd_l   = wlo + O_WD   + l*SZ_WD;

        // --- self attention block ---
        rmsnorm_split_k<<<M_, 256>>>(xb, n1 + l*D_, hhi, hlo);
        gemm_bf16s<true, false><<<dim3(3*D_/128, M_/128), 256, GSMEM>>>(
            hhi, hlo, wqkv_h, wqkv_l, bqkv + l*3*D_, qkvb, 3*D_, D_);
        rope_apply_k<<<M_, 512>>>(qkvb);
        self_attn_k<<<attn_grid, 256>>>(qkvb, ahi, alo);
        gemm_bf16s<true, true><<<dim3(D_/128, M_/128), 256, GSMEM>>>(
            ahi, alo, wo_h, wo_l, bo + l*D_, xb, D_, D_);

        // --- cross attention block ---
        rmsnorm_split_k<<<M_, 256>>>(xb, n2 + l*D_, hhi, hlo);
        gemm_bf16s<false, false><<<dim3(D_/128, M_/128), 256, GSMEM>>>(
            hhi, hlo, wqc_h, wqc_l, nullptr, qcb, D_, D_);
        gemm_bf16s<false, false><<<dim3(2*D_/128, (B_*S_)/128), 256, GSMEM>>>(
            mhi, mlo, wkvc_h, wkvc_l, nullptr, kvcb, 2*D_, D_);
        cross_attn_k<<<attn_grid, 256>>>(qcb, kvcb, seg, chi, clo);
        gemm_bf16s<false, true><<<dim3(D_/128, M_/128), 256, GSMEM>>>(
            chi, clo, woc_h, woc_l, nullptr, xb, D_, D_);

        // --- MLP block ---
        rmsnorm_split_k<<<M_, 256>>>(xb, n3 + l*D_, hhi, hlo);
        gemm_bf16s<false, false><<<dim3(F_/128, M_/128), 256, GSMEM>>>(
            hhi, hlo, wg_h, wg_l, nullptr, gb, F_, D_);
        gemm_bf16s<false, false><<<dim3(F_/128, M_/128), 256, GSMEM>>>(
            hhi, hlo, wu_h, wu_l, nullptr, ub, F_, D_);
        silu_split_k<<<(M_*F_/4 + 255)/256, 256>>>(gb, ub, gshi, gslo, M_*F_/4);
        gemm_bf16s<false, true><<<dim3(D_/128, M_/128), 256, GSMEM>>>(
            gshi, gslo, wd_h, wd_l, nullptr, xb, D_, F_);
    }

    rmsnorm_k<<<M_, 256>>>(xb, nf, (float*)d_out);
}

// round 4
// speedup vs baseline: 2.0164x; 1.0027x over previous
#include <cuda_runtime.h>
#include <cuda_bf16.h>
#include <math.h>
#include <stdint.h>

// Problem constants
#define NL 4
#define B_ 2
#define L_ 2048
#define S_ 256
#define D_ 1024
#define F_ 4096
#define H_ 16
#define HD_ 64
#define M_ (B_*L_)          // 4096 token rows

// Weight region sizes (elements) and offsets in the concatenated split buffer
#define SZ_WQKV ((size_t)3*D_*D_)
#define SZ_WO   ((size_t)D_*D_)
#define SZ_WQC  ((size_t)D_*D_)
#define SZ_WKVC ((size_t)2*D_*D_)
#define SZ_WOC  ((size_t)D_*D_)
#define SZ_WG   ((size_t)F_*D_)
#define SZ_WU   ((size_t)F_*D_)
#define SZ_WD   ((size_t)D_*F_)
static const size_t O_WQKV = 0;
static const size_t O_WO   = O_WQKV + NL*SZ_WQKV;
static const size_t O_WQC  = O_WO   + NL*SZ_WO;
static const size_t O_WKVC = O_WQC  + NL*SZ_WQC;
static const size_t O_WOC  = O_WKVC + NL*SZ_WKVC;
static const size_t O_WG   = O_WOC  + NL*SZ_WOC;
static const size_t O_WU   = O_WG   + NL*SZ_WG;
static const size_t O_WD   = O_WU   + NL*SZ_WU;
#define WTOT (O_WD + NL*SZ_WD)   // 83,886,080 elements

// ---------------------------------------------------------------------------
// Scratch (device globals; no allocations allowed)
// ---------------------------------------------------------------------------
__device__ float g_x  [M_*D_];        // residual stream (fp32)
__device__ float g_qkv[M_*3*D_];      // fused qkv (fp32)
__device__ float g_qc [M_*D_];        // cross-attn q proj (fp32)
__device__ float g_kvc[B_*S_*2*D_];   // cross k/v projections (fp32)
__device__ float g_g  [M_*F_];        // gate (fp32, GEMM out)
__device__ float g_u  [M_*F_];        // up (fp32, GEMM out)
__device__ float g_cos[L_*32];
__device__ float g_sin[L_*32];

// bf16 hi/lo split buffers (GEMM A operands)
__device__ __nv_bfloat16 g_h_hi [M_*D_],  g_h_lo [M_*D_];
__device__ __nv_bfloat16 g_at_hi[M_*D_],  g_at_lo[M_*D_];
__device__ __nv_bfloat16 g_co_hi[M_*D_],  g_co_lo[M_*D_];
__device__ __nv_bfloat16 g_gs_hi[M_*F_],  g_gs_lo[M_*F_];
__device__ __nv_bfloat16 g_m_hi [B_*S_*D_], g_m_lo[B_*S_*D_];
// bf16 hi/lo split weights (all tensors concatenated)
__device__ __nv_bfloat16 g_w_hi[WTOT], g_w_lo[WTOT];

// ---------------------------------------------------------------------------
// bf16 split helpers
// ---------------------------------------------------------------------------
__device__ __forceinline__ void split1(float v, unsigned short& h, unsigned short& l) {
    __nv_bfloat16 hb = __float2bfloat16_rn(v);
    float r = v - __bfloat162float(hb);
    __nv_bfloat16 lb = __float2bfloat16_rn(r);
    h = __bfloat16_as_ushort(hb);
    l = __bfloat16_as_ushort(lb);
}
__device__ __forceinline__ void split_pack4(float4 v, uint2& ph, uint2& pl) {
    unsigned short h0,h1,h2,h3,l0,l1,l2,l3;
    split1(v.x,h0,l0); split1(v.y,h1,l1); split1(v.z,h2,l2); split1(v.w,h3,l3);
    ph.x = (uint32_t)h0 | ((uint32_t)h1 << 16);
    ph.y = (uint32_t)h2 | ((uint32_t)h3 << 16);
    pl.x = (uint32_t)l0 | ((uint32_t)l1 << 16);
    pl.y = (uint32_t)l2 | ((uint32_t)l3 << 16);
}

// Generic fp32 -> bf16 hi/lo split (grid-stride not needed; exact grids)
__global__ void split_k(const float* __restrict__ in, __nv_bfloat16* __restrict__ hi,
                        __nv_bfloat16* __restrict__ lo, int n4) {
    int i = blockIdx.x * blockDim.x + threadIdx.x;
    if (i >= n4) return;
    float4 v = ((const float4*)in)[i];
    uint2 ph, pl; split_pack4(v, ph, pl);
    ((uint2*)hi)[i] = ph;
    ((uint2*)lo)[i] = pl;
}

// ---------------------------------------------------------------------------
// RoPE cache
// ---------------------------------------------------------------------------
__global__ void rope_cache_k() {
    int idx = blockIdx.x * blockDim.x + threadIdx.x;   // L_*32
    int l = idx >> 5, i = idx & 31;
    double inv = exp(-log(10000.0) * (double)i / 32.0);
    double f = (double)l * inv;
    g_cos[idx] = (float)cos(f);
    g_sin[idx] = (float)sin(f);
}

__global__ void copy_x_k(const float* __restrict__ x) {
    size_t i = (size_t)blockIdx.x * blockDim.x + threadIdx.x;
    if (i < (size_t)M_ * D_) g_x[i] = x[i];
}

// ---------------------------------------------------------------------------
// RMSNorm -> bf16 hi/lo split output
// ---------------------------------------------------------------------------
__global__ void rmsnorm_split_k(const float* __restrict__ x, const float* __restrict__ w,
                                __nv_bfloat16* __restrict__ hi, __nv_bfloat16* __restrict__ lo) {
    int row = blockIdx.x;
    int t = threadIdx.x;                 // 256
    const float4* xr = (const float4*)(x + (size_t)row * D_);
    float4 v = xr[t];
    float ss = v.x*v.x + v.y*v.y + v.z*v.z + v.w*v.w;
    #pragma unroll
    for (int off = 16; off; off >>= 1) ss += __shfl_xor_sync(0xffffffffu, ss, off);
    __shared__ float red[8];
    if ((t & 31) == 0) red[t >> 5] = ss;
    __syncthreads();
    float tot = red[0]+red[1]+red[2]+red[3]+red[4]+red[5]+red[6]+red[7];
    float rs = rsqrtf(tot * (1.0f / (float)D_) + 1e-6f);
    float4 wv = ((const float4*)w)[t];
    float4 o;
    o.x = v.x * rs * wv.x; o.y = v.y * rs * wv.y;
    o.z = v.z * rs * wv.z; o.w = v.w * rs * wv.w;
    uint2 ph, pl; split_pack4(o, ph, pl);
    ((uint2*)hi)[(size_t)row * 256 + t] = ph;
    ((uint2*)lo)[(size_t)row * 256 + t] = pl;
}

// Final RMSNorm -> fp32 output
__global__ void rmsnorm_k(const float* __restrict__ x, const float* __restrict__ w,
                          float* __restrict__ o) {
    int row = blockIdx.x;
    int t = threadIdx.x;
    const float4* xr = (const float4*)(x + (size_t)row * D_);
    float4 v = xr[t];
    float ss = v.x*v.x + v.y*v.y + v.z*v.z + v.w*v.w;
    #pragma unroll
    for (int off = 16; off; off >>= 1) ss += __shfl_xor_sync(0xffffffffu, ss, off);
    __shared__ float red[8];
    if ((t & 31) == 0) red[t >> 5] = ss;
    __syncthreads();
    float tot = red[0]+red[1]+red[2]+red[3]+red[4]+red[5]+red[6]+red[7];
    float rs = rsqrtf(tot * (1.0f / (float)D_) + 1e-6f);
    float4 wv = ((const float4*)w)[t];
    float4 out;
    out.x = v.x * rs * wv.x; out.y = v.y * rs * wv.y;
    out.z = v.z * rs * wv.z; out.w = v.w * rs * wv.w;
    ((float4*)(o + (size_t)row * D_))[t] = out;
}

// ---------------------------------------------------------------------------
// mma / ldmatrix helpers
// ---------------------------------------------------------------------------
__device__ __forceinline__ void mma_bf16(float* c, const uint32_t* a, const uint32_t* b) {
    asm volatile(
        "mma.sync.aligned.m16n8k16.row.col.f32.bf16.bf16.f32 "
        "{%0,%1,%2,%3}, {%4,%5,%6,%7}, {%8,%9}, {%0,%1,%2,%3};"
        : "+f"(c[0]), "+f"(c[1]), "+f"(c[2]), "+f"(c[3])
        : "r"(a[0]), "r"(a[1]), "r"(a[2]), "r"(a[3]), "r"(b[0]), "r"(b[1]));
}
__device__ __forceinline__ void ldsm_x4(uint32_t* r, uint32_t addr) {
    asm volatile("ldmatrix.sync.aligned.m8n8.x4.shared.b16 {%0,%1,%2,%3}, [%4];"
        : "=r"(r[0]), "=r"(r[1]), "=r"(r[2]), "=r"(r[3]) : "r"(addr));
}
__device__ __forceinline__ void ldsm_x2(uint32_t* r, uint32_t addr) {
    asm volatile("ldmatrix.sync.aligned.m8n8.x2.shared.b16 {%0,%1}, [%2];"
        : "=r"(r[0]), "=r"(r[1]) : "r"(addr));
}

// ---------------------------------------------------------------------------
// bf16 split-3 GEMM (NT): C[m,n] = sum_k A[m,k]*W[n,k] (+bias) (+residual)
//   A = Ah + Al, W = Wh + Wl (bf16 split); C = AhWh + AhWl + AlWh (fp32 acc)
// 128x128 block, BK=32, 256 threads (8 warps, 64x32 warp tiles), m16n8k16.
// 3-stage cp.async pipeline. Smem layout per stage: Ah|Al|Wh|Wl, each
// [128 rows][32 k] bf16 with 80B row stride ([row][k], 16B-aligned rows).
// ---------------------------------------------------------------------------
#define GSTAGE  40960     // 4 * 10240 bytes
#define GARR    10240     // 128 * 80
#define GSMEM   (3*GSTAGE)

template <bool HAS_BIAS, bool RESIDUAL>
__global__ void __launch_bounds__(256, 1)
gemm_bf16s(const __nv_bfloat16* __restrict__ Ah, const __nv_bfloat16* __restrict__ Al,
           const __nv_bfloat16* __restrict__ Wh, const __nv_bfloat16* __restrict__ Wl,
           const float* __restrict__ bias, float* __restrict__ C,
           int N, int K) {
    extern __shared__ char smem[];
    const uint32_t sbase = (uint32_t)__cvta_generic_to_shared(smem);
    const int tid  = threadIdx.x;
    const int warp = tid >> 5, lane = tid & 31;
    const int wm = warp & 1;        // 0..1 : 64-row slab
    const int wn = warp >> 1;       // 0..3 : 32-col slab
    const int g  = lane >> 2;
    const int t  = lane & 3;
    const int bm = blockIdx.y, bn = blockIdx.x;

    // cp.async chunk tables: 2048 16B-chunks per stage, 8 per thread
    const __nv_bfloat16* src[8];
    uint32_t dst[8];
    #pragma unroll
    for (int i = 0; i < 8; i++) {
        int id  = tid + 256 * i;
        int arr = id >> 9;          // 0:Ah 1:Al 2:Wh 3:Wl
        int rem = id & 511;
        int row = rem >> 2;
        int kc  = rem & 3;          // 16B chunk within row (8 bf16)
        const __nv_bfloat16* bp = (arr == 0) ? Ah : (arr == 1) ? Al : (arr == 2) ? Wh : Wl;
        int grow = ((arr < 2) ? bm : bn) * 128 + row;
        src[i] = bp + (size_t)grow * K + kc * 8;
        dst[i] = (uint32_t)(arr * GARR + row * 80 + kc * 16);
    }

    // ldmatrix base offsets (within an array region of a stage)
    const uint32_t arow = (uint32_t)((wm * 64 + (lane & 15)) * 80 + (lane >> 4) * 16);
    const uint32_t brow = (uint32_t)((wn * 32 + (lane & 7)) * 80 + ((lane >> 3) & 1) * 16);

    float acc[4][4][4];
    #pragma unroll
    for (int i = 0; i < 4; i++)
        #pragma unroll
        for (int j = 0; j < 4; j++)
            #pragma unroll
            for (int r = 0; r < 4; r++) acc[i][j][r] = 0.f;

    const int nk = K >> 5;

    // prologue: stages 0,1
    #pragma unroll
    for (int st = 0; st < 2; st++) {
        uint32_t s = sbase + st * GSTAGE;
        #pragma unroll
        for (int i = 0; i < 8; i++) {
            const void* p = src[i] + st * 32;
            asm volatile("cp.async.cg.shared.global [%0], [%1], 16;"
                         :: "r"(s + dst[i]), "l"(p) : "memory");
        }
        asm volatile("cp.async.commit_group;" ::: "memory");
    }

    for (int it = 0; it < nk; it++) {
        asm volatile("cp.async.wait_group 1;" ::: "memory");
        __syncthreads();
        uint32_t s = sbase + (uint32_t)(it % 3) * GSTAGE;

        #pragma unroll
        for (int ks = 0; ks < 2; ks++) {
            const uint32_t ko = ks * 32;   // 16 bf16 = 32 bytes per k-step
            uint32_t af[4][4], bh[4][2], bl[4][2];
            #pragma unroll
            for (int mt = 0; mt < 4; mt++) ldsm_x4(af[mt], s + 0*GARR + arow + mt*1280 + ko);
            #pragma unroll
            for (int nt = 0; nt < 4; nt++) ldsm_x2(bh[nt], s + 2*GARR + brow + nt*640 + ko);
            #pragma unroll
            for (int nt = 0; nt < 4; nt++) ldsm_x2(bl[nt], s + 3*GARR + brow + nt*640 + ko);
            #pragma unroll
            for (int mt = 0; mt < 4; mt++)
                #pragma unroll
                for (int nt = 0; nt < 4; nt++) mma_bf16(acc[mt][nt], af[mt], bh[nt]);
            #pragma unroll
            for (int mt = 0; mt < 4; mt++)
                #pragma unroll
                for (int nt = 0; nt < 4; nt++) mma_bf16(acc[mt][nt], af[mt], bl[nt]);
            #pragma unroll
            for (int mt = 0; mt < 4; mt++) ldsm_x4(af[mt], s + 1*GARR + arow + mt*1280 + ko);
            #pragma unroll
            for (int mt = 0; mt < 4; mt++)
                #pragma unroll
                for (int nt = 0; nt < 4; nt++) mma_bf16(acc[mt][nt], af[mt], bh[nt]);
        }

        if (it + 2 < nk) {
            uint32_t s2 = sbase + (uint32_t)((it + 2) % 3) * GSTAGE;
            int k0 = (it + 2) * 32;
            #pragma unroll
            for (int i = 0; i < 8; i++) {
                const void* p = src[i] + k0;
                asm volatile("cp.async.cg.shared.global [%0], [%1], 16;"
                             :: "r"(s2 + dst[i]), "l"(p) : "memory");
            }
        }
        asm volatile("cp.async.commit_group;" ::: "memory");
    }

    // ---- epilogue ----
    #pragma unroll
    for (int mt = 0; mt < 4; mt++) {
        #pragma unroll
        for (int half = 0; half < 2; half++) {
            int row = bm * 128 + wm * 64 + mt * 16 + g + half * 8;
            #pragma unroll
            for (int nt = 0; nt < 4; nt++) {
                int col = bn * 128 + wn * 32 + nt * 8 + 2 * t;
                float c0 = acc[mt][nt][half * 2 + 0];
                float c1 = acc[mt][nt][half * 2 + 1];
                float* dstp = C + (size_t)row * N + col;
                if (HAS_BIAS) { c0 += bias[col]; c1 += bias[col + 1]; }
                if (RESIDUAL) {
                    float2 r = *(const float2*)dstp;
                    c0 += r.x; c1 += r.y;
                }
                *(float2*)dstp = make_float2(c0, c1);
            }
        }
    }
}

// ---------------------------------------------------------------------------
// RoPE applied in place to q and k slices of qkv. grid = B*L, block 512.
// ---------------------------------------------------------------------------
__global__ void rope_apply_k(float* __restrict__ qkv) {
    int bl = blockIdx.x;
    int l = bl & (L_ - 1);
    int h = threadIdx.x >> 5;
    int i = threadIdx.x & 31;
    float c = g_cos[l*32 + i];
    float s = g_sin[l*32 + i];
    float* base = qkv + (size_t)bl * (3*D_) + h * HD_;
    float x1 = base[i], x2 = base[i+32];
    base[i]    = x1 * c - x2 * s;
    base[i+32] = x2 * c + x1 * s;
    float* kb = base + D_;
    x1 = kb[i]; x2 = kb[i+32];
    kb[i]    = x1 * c - x2 * s;
    kb[i+32] = x2 * c + x1 * s;
}

// ---------------------------------------------------------------------------
// Self-attention, causal, flash-style, lane-parallel scoring.
// Epilogue writes bf16 hi/lo split (feeds Wo GEMM).
// ---------------------------------------------------------------------------
__global__ void __launch_bounds__(256)
self_attn_k(const float* __restrict__ qkv,
            __nv_bfloat16* __restrict__ out_hi, __nv_bfloat16* __restrict__ out_lo) {
    __shared__ float Kt[64][68];      // [d][key]
    __shared__ float Vs[64][68];      // [key][d]
    __shared__ float Qs[8][64];
    __shared__ float Ps[8][64];
    const int tid = threadIdx.x;
    const int warp = tid >> 5, lane = tid & 31;
    const int h = blockIdx.y, b = blockIdx.z;
    const int q = blockIdx.x * 8 + warp;
    const int qmax = blockIdx.x * 8 + 7;

    const float* qrow = qkv + ((size_t)(b*L_ + q)) * (3*D_) + h * HD_;
    Qs[warp][lane]      = qrow[lane]      * 0.125f;
    Qs[warp][lane + 32] = qrow[lane + 32] * 0.125f;

    float m = -1e30f, lsum = 0.f, a0 = 0.f, a1 = 0.f;

    for (int kt = 0; kt <= qmax; kt += 64) {
        __syncthreads();
        for (int idx = tid; idx < 64 * 16; idx += 256) {
            int r = idx >> 4, c4 = (idx & 15) * 4;
            const float* base = qkv + ((size_t)(b*L_ + kt + r)) * (3*D_) + h * HD_ + c4;
            float4 kv = *(const float4*)(base + D_);
            float4 vv = *(const float4*)(base + 2*D_);
            Kt[c4+0][r] = kv.x; Kt[c4+1][r] = kv.y;
            Kt[c4+2][r] = kv.z; Kt[c4+3][r] = kv.w;
            *(float4*)&Vs[r][c4] = vv;
        }
        __syncthreads();

        float s0 = 0.f, s1 = 0.f;
        #pragma unroll 16
        for (int d = 0; d < 64; d++) {
            float qv = Qs[warp][d];
            s0 = fmaf(qv, Kt[d][lane],      s0);
            s1 = fmaf(qv, Kt[d][lane + 32], s1);
        }
        if (kt + lane      > q) s0 = -1e30f;
        if (kt + lane + 32 > q) s1 = -1e30f;

        float tm = fmaxf(s0, s1);
        #pragma unroll
        for (int off = 16; off; off >>= 1) tm = fmaxf(tm, __shfl_xor_sync(0xffffffffu, tm, off));
        float nm = fmaxf(m, tm);
        float sc = __expf(m - nm);
        float p0 = __expf(s0 - nm);
        float p1 = __expf(s1 - nm);
        float ts = p0 + p1;
        #pragma unroll
        for (int off = 16; off; off >>= 1) ts += __shfl_xor_sync(0xffffffffu, ts, off);
        lsum = lsum * sc + ts;
        a0 *= sc; a1 *= sc;
        Ps[warp][lane] = p0; Ps[warp][lane + 32] = p1;
        __syncwarp();
        #pragma unroll 8
        for (int j = 0; j < 64; j++) {
            float p = Ps[warp][j];
            a0 = fmaf(p, Vs[j][lane],      a0);
            a1 = fmaf(p, Vs[j][lane + 32], a1);
        }
        m = nm;
    }
    float invs = 1.0f / lsum;
    float v0 = a0 * invs, v1 = a1 * invs;
    size_t base = ((size_t)(b*L_ + q)) * D_ + h * HD_;
    unsigned short h0, l0, h1, l1;
    split1(v0, h0, l0); split1(v1, h1, l1);
    out_hi[base + lane]      = __ushort_as_bfloat16(h0);
    out_lo[base + lane]      = __ushort_as_bfloat16(l0);
    out_hi[base + lane + 32] = __ushort_as_bfloat16(h1);
    out_lo[base + lane + 32] = __ushort_as_bfloat16(l1);
}

// ---------------------------------------------------------------------------
// Cross-attention with lookback window (<=128 keys per query). bf16 split out.
// ---------------------------------------------------------------------------
__global__ void __launch_bounds__(256)
cross_attn_k(const float* __restrict__ qc, const float* __restrict__ kvc,
             const int* __restrict__ seg_ids,
             __nv_bfloat16* __restrict__ out_hi, __nv_bfloat16* __restrict__ out_lo) {
    const int tid = threadIdx.x;
    const int warp = tid >> 5, lane = tid & 31;
    const int h = blockIdx.y, b = blockIdx.z;
    const int l = blockIdx.x * 8 + warp;

    const int seg = seg_ids[b * L_ + l];
    int j0 = seg - 127; if (j0 < 0) j0 = 0;
    const int j1 = seg;

    const float* qrow = qc + ((size_t)(b*L_ + l)) * D_ + h * HD_;
    const float qv0 = qrow[lane]      * 0.125f;
    const float qv1 = qrow[lane + 32] * 0.125f;

    float m = -1e30f, lsum = 0.f, a0 = 0.f, a1 = 0.f;
    for (int j = j0; j <= j1; j++) {
        const float* krow = kvc + ((size_t)(b*S_ + j)) * (2*D_) + h * HD_;
        float s = qv0 * krow[lane] + qv1 * krow[lane + 32];
        #pragma unroll
        for (int off = 16; off; off >>= 1) s += __shfl_xor_sync(0xffffffffu, s, off);
        float nm = fmaxf(m, s);
        float sc = __expf(m - nm);
        float p  = __expf(s - nm);
        lsum = lsum * sc + p;
        const float* vrow = krow + D_;
        a0 = fmaf(p, vrow[lane],      a0 * sc);
        a1 = fmaf(p, vrow[lane + 32], a1 * sc);
        m = nm;
    }
    float invs = 1.0f / lsum;
    float v0 = a0 * invs, v1 = a1 * invs;
    size_t base = ((size_t)(b*L_ + l)) * D_ + h * HD_;
    unsigned short h0, l0s, h1, l1;
    split1(v0, h0, l0s); split1(v1, h1, l1);
    out_hi[base + lane]      = __ushort_as_bfloat16(h0);
    out_lo[base + lane]      = __ushort_as_bfloat16(l0s);
    out_hi[base + lane + 32] = __ushort_as_bfloat16(h1);
    out_lo[base + lane + 32] = __ushort_as_bfloat16(l1);
}

// ---------------------------------------------------------------------------
// SwiGLU: silu(g)*u -> bf16 hi/lo split
// ---------------------------------------------------------------------------
__global__ void silu_split_k(const float* __restrict__ g, const float* __restrict__ u,
                             __nv_bfloat16* __restrict__ hi, __nv_bfloat16* __restrict__ lo,
                             int n4) {
    int i = blockIdx.x * blockDim.x + threadIdx.x;
    if (i >= n4) return;
    float4 gv = ((const float4*)g)[i];
    float4 uv = ((const float4*)u)[i];
    float4 o;
    o.x = gv.x / (1.0f + expf(-gv.x)) * uv.x;
    o.y = gv.y / (1.0f + expf(-gv.y)) * uv.y;
    o.z = gv.z / (1.0f + expf(-gv.z)) * uv.z;
    o.w = gv.w / (1.0f + expf(-gv.w)) * uv.w;
    uint2 ph, pl; split_pack4(o, ph, pl);
    ((uint2*)hi)[i] = ph;
    ((uint2*)lo)[i] = pl;
}

// ---------------------------------------------------------------------------
// Launch
// ---------------------------------------------------------------------------
static inline void split_launch(const float* src, __nv_bfloat16* hi, __nv_bfloat16* lo, size_t n) {
    int n4 = (int)(n / 4);
    split_k<<<(n4 + 255) / 256, 256>>>(src, hi, lo, n4);
}

extern "C" void kernel_launch(void* const* d_in, const int* in_sizes, int n_in,
                              void* d_out, int out_size) {
    const float* x      = (const float*)d_in[0];
    const float* memory = (const float*)d_in[1];
    const int*   seg    = (const int*)  d_in[2];
    const float* Wqkv   = (const float*)d_in[3];
    const float* bqkv   = (const float*)d_in[4];
    const float* Wo     = (const float*)d_in[5];
    const float* bo     = (const float*)d_in[6];
    const float* Wq_c   = (const float*)d_in[7];
    const float* Wkv_c  = (const float*)d_in[8];
    const float* Wo_c   = (const float*)d_in[9];
    const float* Wg     = (const float*)d_in[10];
    const float* Wu     = (const float*)d_in[11];
    const float* Wd     = (const float*)d_in[12];
    const float* n1     = (const float*)d_in[13];
    const float* n2     = (const float*)d_in[14];
    const float* n3     = (const float*)d_in[15];
    const float* nf     = (const float*)d_in[16];

    cudaFuncSetAttribute(gemm_bf16s<true,  false>, cudaFuncAttributeMaxDynamicSharedMemorySize, GSMEM);
    cudaFuncSetAttribute(gemm_bf16s<true,  true >, cudaFuncAttributeMaxDynamicSharedMemorySize, GSMEM);
    cudaFuncSetAttribute(gemm_bf16s<false, false>, cudaFuncAttributeMaxDynamicSharedMemorySize, GSMEM);
    cudaFuncSetAttribute(gemm_bf16s<false, true >, cudaFuncAttributeMaxDynamicSharedMemorySize, GSMEM);

    float *xb, *qkvb, *qcb, *kvcb, *gb, *ub;
    __nv_bfloat16 *hhi, *hlo, *ahi, *alo, *chi, *clo, *gshi, *gslo, *mhi, *mlo, *whi, *wlo;
    cudaGetSymbolAddress((void**)&xb,   g_x);
    cudaGetSymbolAddress((void**)&qkvb, g_qkv);
    cudaGetSymbolAddress((void**)&qcb,  g_qc);
    cudaGetSymbolAddress((void**)&kvcb, g_kvc);
    cudaGetSymbolAddress((void**)&gb,   g_g);
    cudaGetSymbolAddress((void**)&ub,   g_u);
    cudaGetSymbolAddress((void**)&hhi,  g_h_hi);  cudaGetSymbolAddress((void**)&hlo,  g_h_lo);
    cudaGetSymbolAddress((void**)&ahi,  g_at_hi); cudaGetSymbolAddress((void**)&alo,  g_at_lo);
    cudaGetSymbolAddress((void**)&chi,  g_co_hi); cudaGetSymbolAddress((void**)&clo,  g_co_lo);
    cudaGetSymbolAddress((void**)&gshi, g_gs_hi); cudaGetSymbolAddress((void**)&gslo, g_gs_lo);
    cudaGetSymbolAddress((void**)&mhi,  g_m_hi);  cudaGetSymbolAddress((void**)&mlo,  g_m_lo);
    cudaGetSymbolAddress((void**)&whi,  g_w_hi);  cudaGetSymbolAddress((void**)&wlo,  g_w_lo);

    rope_cache_k<<<256, 256>>>();
    copy_x_k<<<(M_*D_)/256, 256>>>(x);

    // split all weights + memory into bf16 hi/lo
    split_launch(Wqkv,  whi + O_WQKV, wlo + O_WQKV, NL*SZ_WQKV);
    split_launch(Wo,    whi + O_WO,   wlo + O_WO,   NL*SZ_WO);
    split_launch(Wq_c,  whi + O_WQC,  wlo + O_WQC,  NL*SZ_WQC);
    split_launch(Wkv_c, whi + O_WKVC, wlo + O_WKVC, NL*SZ_WKVC);
    split_launch(Wo_c,  whi + O_WOC,  wlo + O_WOC,  NL*SZ_WOC);
    split_launch(Wg,    whi + O_WG,   wlo + O_WG,   NL*SZ_WG);
    split_launch(Wu,    whi + O_WU,   wlo + O_WU,   NL*SZ_WU);
    split_launch(Wd,    whi + O_WD,   wlo + O_WD,   NL*SZ_WD);
    split_launch(memory, mhi, mlo, (size_t)B_*S_*D_);

    const dim3 attn_grid(L_/8, H_, B_);

    for (int l = 0; l < NL; l++) {
        const __nv_bfloat16* wqkv_h = whi + O_WQKV + l*SZ_WQKV;
        const __nv_bfloat16* wqkv_l = wlo + O_WQKV + l*SZ_WQKV;
        const __nv_bfloat16* wo_h   = whi + O_WO   + l*SZ_WO;
        const __nv_bfloat16* wo_l   = wlo + O_WO   + l*SZ_WO;
        const __nv_bfloat16* wqc_h  = whi + O_WQC  + l*SZ_WQC;
        const __nv_bfloat16* wqc_l  = wlo + O_WQC  + l*SZ_WQC;
        const __nv_bfloat16* wkvc_h = whi + O_WKVC + l*SZ_WKVC;
        const __nv_bfloat16* wkvc_l = wlo + O_WKVC + l*SZ_WKVC;
        const __nv_bfloat16* woc_h  = whi + O_WOC  + l*SZ_WOC;
        const __nv_bfloat16* woc_l  = wlo + O_WOC  + l*SZ_WOC;
        const __nv_bfloat16* wg_h   = whi + O_WG   + l*SZ_WG;
        const __nv_bfloat16* wg_l   = wlo + O_WG   + l*SZ_WG;
        const __nv_bfloat16* wu_h   = whi + O_WU   + l*SZ_WU;
        const __nv_bfloat16* wu_l   = wlo + O_WU   + l*SZ_WU;
        const __nv_bfloat16* wd_h   = whi + O_WD   + l*SZ_WD;
        const __nv_bfloat16* wd_l   = wlo + O_WD   + l*SZ_WD;

        // --- self attention block ---
        rmsnorm_split_k<<<M_, 256>>>(xb, n1 + l*D_, hhi, hlo);
        gemm_bf16s<true, false><<<dim3(3*D_/128, M_/128), 256, GSMEM>>>(
            hhi, hlo, wqkv_h, wqkv_l, bqkv + l*3*D_, qkvb, 3*D_, D_);
        rope_apply_k<<<M_, 512>>>(qkvb);
        self_attn_k<<<attn_grid, 256>>>(qkvb, ahi, alo);
        gemm_bf16s<true, true><<<dim3(D_/128, M_/128), 256, GSMEM>>>(
            ahi, alo, wo_h, wo_l, bo + l*D_, xb, D_, D_);

        // --- cross attention block ---
        rmsnorm_split_k<<<M_, 256>>>(xb, n2 + l*D_, hhi, hlo);
        gemm_bf16s<false, false><<<dim3(D_/128, M_/128), 256, GSMEM>>>(
            hhi, hlo, wqc_h, wqc_l, nullptr, qcb, D_, D_);
        gemm_bf16s<false, false><<<dim3(2*D_/128, (B_*S_)/128), 256, GSMEM>>>(
            mhi, mlo, wkvc_h, wkvc_l, nullptr, kvcb, 2*D_, D_);
        cross_attn_k<<<attn_grid, 256>>>(qcb, kvcb, seg, chi, clo);
        gemm_bf16s<false, true><<<dim3(D_/128, M_/128), 256, GSMEM>>>(
            chi, clo, woc_h, woc_l, nullptr, xb, D_, D_);

        // --- MLP block ---
        rmsnorm_split_k<<<M_, 256>>>(xb, n3 + l*D_, hhi, hlo);
        gemm_bf16s<false, false><<<dim3(F_/128, M_/128), 256, GSMEM>>>(
            hhi, hlo, wg_h, wg_l, nullptr, gb, F_, D_);
        gemm_bf16s<false, false><<<dim3(F_/128, M_/128), 256, GSMEM>>>(
            hhi, hlo, wu_h, wu_l, nullptr, ub, F_, D_);
        silu_split_k<<<(M_*F_/4 + 255)/256, 256>>>(gb, ub, gshi, gslo, M_*F_/4);
        gemm_bf16s<false, true><<<dim3(D_/128, M_/128), 256, GSMEM>>>(
            gshi, gslo, wd_h, wd_l, nullptr, xb, D_, F_);
    }

    rmsnorm_k<<<M_, 256>>>(xb, nf, (float*)d_out);
}

// round 6
// speedup vs baseline: 3.7943x; 1.8817x over previous
#include <cuda_runtime.h>
#include <cuda_bf16.h>
#include <math.h>
#include <stdint.h>

// Problem constants
#define NL 4
#define B_ 2
#define L_ 2048
#define S_ 256
#define D_ 1024
#define F_ 4096
#define H_ 16
#define HD_ 64
#define M_ (B_*L_)          // 4096 token rows

// Weight region sizes (elements) and offsets in the concatenated split buffer
#define SZ_WQKV ((size_t)3*D_*D_)
#define SZ_WO   ((size_t)D_*D_)
#define SZ_WQC  ((size_t)D_*D_)
#define SZ_WKVC ((size_t)2*D_*D_)
#define SZ_WOC  ((size_t)D_*D_)
#define SZ_WGU  ((size_t)2*F_*D_)     // fused [Wg; Wu] per layer
#define SZ_WD   ((size_t)D_*F_)
static const size_t O_WQKV = 0;
static const size_t O_WO   = O_WQKV + NL*SZ_WQKV;
static const size_t O_WQC  = O_WO   + NL*SZ_WO;
static const size_t O_WKVC = O_WQC  + NL*SZ_WQC;
static const size_t O_WOC  = O_WKVC + NL*SZ_WKVC;
static const size_t O_WGU  = O_WOC  + NL*SZ_WOC;
static const size_t O_WD   = O_WGU  + NL*SZ_WGU;
#define WTOT (O_WD + NL*SZ_WD)

// ---------------------------------------------------------------------------
// Scratch (device globals; no allocations allowed)
// ---------------------------------------------------------------------------
__device__ float g_x  [M_*D_];
__device__ float g_qkv[M_*3*D_];
__device__ float g_qc [M_*D_];
__device__ float g_kvc[B_*S_*2*D_];
__device__ float g_gu [M_*2*F_];      // fused gate|up GEMM output
__device__ float g_cos[L_*32];
__device__ float g_sin[L_*32];

__device__ __nv_bfloat16 g_h_hi [M_*D_],  g_h_lo [M_*D_];
__device__ __nv_bfloat16 g_at_hi[M_*D_],  g_at_lo[M_*D_];
__device__ __nv_bfloat16 g_co_hi[M_*D_],  g_co_lo[M_*D_];
__device__ __nv_bfloat16 g_gs_hi[M_*F_],  g_gs_lo[M_*F_];
__device__ __nv_bfloat16 g_m_hi [B_*S_*D_], g_m_lo[B_*S_*D_];
__device__ __nv_bfloat16 g_w_hi[WTOT], g_w_lo[WTOT];

// attention-layout split buffers: [B][H][L][64]
#define ATN ((size_t)B_*H_*L_*HD_)
__device__ __nv_bfloat16 g_sqh[ATN], g_sql[ATN];
__device__ __nv_bfloat16 g_skh[ATN], g_skl[ATN];
__device__ __nv_bfloat16 g_svh[ATN], g_svl[ATN];

// ---------------------------------------------------------------------------
// bf16 split helpers
// ---------------------------------------------------------------------------
__device__ __forceinline__ void split1(float v, unsigned short& h, unsigned short& l) {
    __nv_bfloat16 hb = __float2bfloat16_rn(v);
    float r = v - __bfloat162float(hb);
    __nv_bfloat16 lb = __float2bfloat16_rn(r);
    h = __bfloat16_as_ushort(hb);
    l = __bfloat16_as_ushort(lb);
}
__device__ __forceinline__ void split_pack4(float4 v, uint2& ph, uint2& pl) {
    unsigned short h0,h1,h2,h3,l0,l1,l2,l3;
    split1(v.x,h0,l0); split1(v.y,h1,l1); split1(v.z,h2,l2); split1(v.w,h3,l3);
    ph.x = (uint32_t)h0 | ((uint32_t)h1 << 16);
    ph.y = (uint32_t)h2 | ((uint32_t)h3 << 16);
    pl.x = (uint32_t)l0 | ((uint32_t)l1 << 16);
    pl.y = (uint32_t)l2 | ((uint32_t)l3 << 16);
}

__global__ void split_k(const float* __restrict__ in, __nv_bfloat16* __restrict__ hi,
                        __nv_bfloat16* __restrict__ lo, int n4) {
    int i = blockIdx.x * blockDim.x + threadIdx.x;
    if (i >= n4) return;
    float4 v = ((const float4*)in)[i];
    uint2 ph, pl; split_pack4(v, ph, pl);
    ((uint2*)hi)[i] = ph;
    ((uint2*)lo)[i] = pl;
}

// ---------------------------------------------------------------------------
// RoPE cache
// ---------------------------------------------------------------------------
__global__ void rope_cache_k() {
    int idx = blockIdx.x * blockDim.x + threadIdx.x;
    int l = idx >> 5, i = idx & 31;
    double inv = exp(-log(10000.0) * (double)i / 32.0);
    double f = (double)l * inv;
    g_cos[idx] = (float)cos(f);
    g_sin[idx] = (float)sin(f);
}

__global__ void copy_x_k(const float* __restrict__ x) {
    size_t i = (size_t)blockIdx.x * blockDim.x + threadIdx.x;
    if (i < (size_t)M_ * D_) g_x[i] = x[i];
}

// ---------------------------------------------------------------------------
// RMSNorm kernels
// ---------------------------------------------------------------------------
__global__ void rmsnorm_split_k(const float* __restrict__ x, const float* __restrict__ w,
                                __nv_bfloat16* __restrict__ hi, __nv_bfloat16* __restrict__ lo) {
    int row = blockIdx.x;
    int t = threadIdx.x;
    const float4* xr = (const float4*)(x + (size_t)row * D_);
    float4 v = xr[t];
    float ss = v.x*v.x + v.y*v.y + v.z*v.z + v.w*v.w;
    #pragma unroll
    for (int off = 16; off; off >>= 1) ss += __shfl_xor_sync(0xffffffffu, ss, off);
    __shared__ float red[8];
    if ((t & 31) == 0) red[t >> 5] = ss;
    __syncthreads();
    float tot = red[0]+red[1]+red[2]+red[3]+red[4]+red[5]+red[6]+red[7];
    float rs = rsqrtf(tot * (1.0f / (float)D_) + 1e-6f);
    float4 wv = ((const float4*)w)[t];
    float4 o;
    o.x = v.x * rs * wv.x; o.y = v.y * rs * wv.y;
    o.z = v.z * rs * wv.z; o.w = v.w * rs * wv.w;
    uint2 ph, pl; split_pack4(o, ph, pl);
    ((uint2*)hi)[(size_t)row * 256 + t] = ph;
    ((uint2*)lo)[(size_t)row * 256 + t] = pl;
}

__global__ void rmsnorm_k(const float* __restrict__ x, const float* __restrict__ w,
                          float* __restrict__ o) {
    int row = blockIdx.x;
    int t = threadIdx.x;
    const float4* xr = (const float4*)(x + (size_t)row * D_);
    float4 v = xr[t];
    float ss = v.x*v.x + v.y*v.y + v.z*v.z + v.w*v.w;
    #pragma unroll
    for (int off = 16; off; off >>= 1) ss += __shfl_xor_sync(0xffffffffu, ss, off);
    __shared__ float red[8];
    if ((t & 31) == 0) red[t >> 5] = ss;
    __syncthreads();
    float tot = red[0]+red[1]+red[2]+red[3]+red[4]+red[5]+red[6]+red[7];
    float rs = rsqrtf(tot * (1.0f / (float)D_) + 1e-6f);
    float4 wv = ((const float4*)w)[t];
    float4 out;
    out.x = v.x * rs * wv.x; out.y = v.y * rs * wv.y;
    out.z = v.z * rs * wv.z; out.w = v.w * rs * wv.w;
    ((float4*)(o + (size_t)row * D_))[t] = out;
}

// ---------------------------------------------------------------------------
// mma / ldmatrix helpers
// ---------------------------------------------------------------------------
__device__ __forceinline__ void mma_bf16(float* c, const uint32_t* a, const uint32_t* b) {
    asm volatile(
        "mma.sync.aligned.m16n8k16.row.col.f32.bf16.bf16.f32 "
        "{%0,%1,%2,%3}, {%4,%5,%6,%7}, {%8,%9}, {%0,%1,%2,%3};"
        : "+f"(c[0]), "+f"(c[1]), "+f"(c[2]), "+f"(c[3])
        : "r"(a[0]), "r"(a[1]), "r"(a[2]), "r"(a[3]), "r"(b[0]), "r"(b[1]));
}
__device__ __forceinline__ void ldsm_x4(uint32_t* r, uint32_t addr) {
    asm volatile("ldmatrix.sync.aligned.m8n8.x4.shared.b16 {%0,%1,%2,%3}, [%4];"
        : "=r"(r[0]), "=r"(r[1]), "=r"(r[2]), "=r"(r[3]) : "r"(addr));
}
__device__ __forceinline__ void ldsm_x4_t(uint32_t* r, uint32_t addr) {
    asm volatile("ldmatrix.sync.aligned.m8n8.x4.trans.shared.b16 {%0,%1,%2,%3}, [%4];"
        : "=r"(r[0]), "=r"(r[1]), "=r"(r[2]), "=r"(r[3]) : "r"(addr));
}
__device__ __forceinline__ void ldsm_x2(uint32_t* r, uint32_t addr) {
    asm volatile("ldmatrix.sync.aligned.m8n8.x2.shared.b16 {%0,%1}, [%2];"
        : "=r"(r[0]), "=r"(r[1]) : "r"(addr));
}
__device__ __forceinline__ uint32_t pack_bf16x2(float lo, float hi) {
    return (uint32_t)__bfloat16_as_ushort(__float2bfloat16_rn(lo)) |
           ((uint32_t)__bfloat16_as_ushort(__float2bfloat16_rn(hi)) << 16);
}

// ---------------------------------------------------------------------------
// bf16 split-3 GEMM (NT) — unchanged from Round 4 (known good)
// ---------------------------------------------------------------------------
#define GSTAGE  40960     // 4 * 10240 bytes
#define GARR    10240     // 128 * 80
#define GSMEM   (3*GSTAGE)

template <bool HAS_BIAS, bool RESIDUAL>
__global__ void __launch_bounds__(256, 1)
gemm_bf16s(const __nv_bfloat16* __restrict__ Ah, const __nv_bfloat16* __restrict__ Al,
           const __nv_bfloat16* __restrict__ Wh, const __nv_bfloat16* __restrict__ Wl,
           const float* __restrict__ bias, float* __restrict__ C,
           int N, int K) {
    extern __shared__ char smem[];
    const uint32_t sbase = (uint32_t)__cvta_generic_to_shared(smem);
    const int tid  = threadIdx.x;
    const int warp = tid >> 5, lane = tid & 31;
    const int wm = warp & 1;
    const int wn = warp >> 1;
    const int g  = lane >> 2;
    const int t  = lane & 3;
    const int bm = blockIdx.y, bn = blockIdx.x;

    const __nv_bfloat16* src[8];
    uint32_t dst[8];
    #pragma unroll
    for (int i = 0; i < 8; i++) {
        int id  = tid + 256 * i;
        int arr = id >> 9;
        int rem = id & 511;
        int row = rem >> 2;
        int kc  = rem & 3;
        const __nv_bfloat16* bp = (arr == 0) ? Ah : (arr == 1) ? Al : (arr == 2) ? Wh : Wl;
        int grow = ((arr < 2) ? bm : bn) * 128 + row;
        src[i] = bp + (size_t)grow * K + kc * 8;
        dst[i] = (uint32_t)(arr * GARR + row * 80 + kc * 16);
    }

    const uint32_t arow = (uint32_t)((wm * 64 + (lane & 15)) * 80 + (lane >> 4) * 16);
    const uint32_t brow = (uint32_t)((wn * 32 + (lane & 7)) * 80 + ((lane >> 3) & 1) * 16);

    float acc[4][4][4];
    #pragma unroll
    for (int i = 0; i < 4; i++)
        #pragma unroll
        for (int j = 0; j < 4; j++)
            #pragma unroll
            for (int r = 0; r < 4; r++) acc[i][j][r] = 0.f;

    const int nk = K >> 5;

    #pragma unroll
    for (int st = 0; st < 2; st++) {
        uint32_t s = sbase + st * GSTAGE;
        #pragma unroll
        for (int i = 0; i < 8; i++) {
            const void* p = src[i] + st * 32;
            asm volatile("cp.async.cg.shared.global [%0], [%1], 16;"
                         :: "r"(s + dst[i]), "l"(p) : "memory");
        }
        asm volatile("cp.async.commit_group;" ::: "memory");
    }

    for (int it = 0; it < nk; it++) {
        asm volatile("cp.async.wait_group 1;" ::: "memory");
        __syncthreads();
        uint32_t s = sbase + (uint32_t)(it % 3) * GSTAGE;

        #pragma unroll
        for (int ks = 0; ks < 2; ks++) {
            const uint32_t ko = ks * 32;
            uint32_t af[4][4], bh[4][2], bl[4][2];
            #pragma unroll
            for (int mt = 0; mt < 4; mt++) ldsm_x4(af[mt], s + 0*GARR + arow + mt*1280 + ko);
            #pragma unroll
            for (int nt = 0; nt < 4; nt++) ldsm_x2(bh[nt], s + 2*GARR + brow + nt*640 + ko);
            #pragma unroll
            for (int nt = 0; nt < 4; nt++) ldsm_x2(bl[nt], s + 3*GARR + brow + nt*640 + ko);
            #pragma unroll
            for (int mt = 0; mt < 4; mt++)
                #pragma unroll
                for (int nt = 0; nt < 4; nt++) mma_bf16(acc[mt][nt], af[mt], bh[nt]);
            #pragma unroll
            for (int mt = 0; mt < 4; mt++)
                #pragma unroll
                for (int nt = 0; nt < 4; nt++) mma_bf16(acc[mt][nt], af[mt], bl[nt]);
            #pragma unroll
            for (int mt = 0; mt < 4; mt++) ldsm_x4(af[mt], s + 1*GARR + arow + mt*1280 + ko);
            #pragma unroll
            for (int mt = 0; mt < 4; mt++)
                #pragma unroll
                for (int nt = 0; nt < 4; nt++) mma_bf16(acc[mt][nt], af[mt], bh[nt]);
        }

        if (it + 2 < nk) {
            uint32_t s2 = sbase + (uint32_t)((it + 2) % 3) * GSTAGE;
            int k0 = (it + 2) * 32;
            #pragma unroll
            for (int i = 0; i < 8; i++) {
                const void* p = src[i] + k0;
                asm volatile("cp.async.cg.shared.global [%0], [%1], 16;"
                             :: "r"(s2 + dst[i]), "l"(p) : "memory");
            }
        }
        asm volatile("cp.async.commit_group;" ::: "memory");
    }

    #pragma unroll
    for (int mt = 0; mt < 4; mt++) {
        #pragma unroll
        for (int half = 0; half < 2; half++) {
            int row = bm * 128 + wm * 64 + mt * 16 + g + half * 8;
            #pragma unroll
            for (int nt = 0; nt < 4; nt++) {
                int col = bn * 128 + wn * 32 + nt * 8 + 2 * t;
                float c0 = acc[mt][nt][half * 2 + 0];
                float c1 = acc[mt][nt][half * 2 + 1];
                float* dstp = C + (size_t)row * N + col;
                if (HAS_BIAS) { c0 += bias[col]; c1 += bias[col + 1]; }
                if (RESIDUAL) {
                    float2 r = *(const float2*)dstp;
                    c0 += r.x; c1 += r.y;
                }
                *(float2*)dstp = make_float2(c0, c1);
            }
        }
    }
}

// ---------------------------------------------------------------------------
// RoPE + bf16 hi/lo split of q,k,v into attention layout [B][H][L][64].
// grid = B*L, block 512 (warp = head). Q pre-scaled by 0.125.
// ---------------------------------------------------------------------------
__global__ void rope_split_k(const float* __restrict__ qkv) {
    int bl = blockIdx.x;
    int b = bl >> 11, l = bl & (L_ - 1);
    int hh = threadIdx.x >> 5;
    int i  = threadIdx.x & 31;
    float c = g_cos[l*32 + i];
    float s = g_sin[l*32 + i];
    const float* base = qkv + (size_t)bl * (3*D_) + hh * HD_;
    size_t orow = (((size_t)(b*H_ + hh)) * L_ + l) * HD_;
    unsigned short vh, vl;
    // q (scaled)
    float x1 = base[i], x2 = base[i+32];
    float q1 = (x1*c - x2*s) * 0.125f;
    float q2 = (x2*c + x1*s) * 0.125f;
    split1(q1, vh, vl); g_sqh[orow+i]    = __ushort_as_bfloat16(vh); g_sql[orow+i]    = __ushort_as_bfloat16(vl);
    split1(q2, vh, vl); g_sqh[orow+i+32] = __ushort_as_bfloat16(vh); g_sql[orow+i+32] = __ushort_as_bfloat16(vl);
    // k
    x1 = base[D_+i]; x2 = base[D_+i+32];
    float k1 = x1*c - x2*s;
    float k2 = x2*c + x1*s;
    split1(k1, vh, vl); g_skh[orow+i]    = __ushort_as_bfloat16(vh); g_skl[orow+i]    = __ushort_as_bfloat16(vl);
    split1(k2, vh, vl); g_skh[orow+i+32] = __ushort_as_bfloat16(vh); g_skl[orow+i+32] = __ushort_as_bfloat16(vl);
    // v
    split1(base[2*D_+i],    vh, vl); g_svh[orow+i]    = __ushort_as_bfloat16(vh); g_svl[orow+i]    = __ushort_as_bfloat16(vl);
    split1(base[2*D_+i+32], vh, vl); g_svh[orow+i+32] = __ushort_as_bfloat16(vh); g_svl[orow+i+32] = __ushort_as_bfloat16(vl);
}

// ---------------------------------------------------------------------------
// mma.sync flash self-attention. 64-query CTA, 4 warps (m16 each), 64-key
// tiles double-buffered via cp.async. Split-3 bf16 mma for S and P·V.
// Smem rows 144B stride (conflict-free ldsm). Output bf16 hi/lo [token][D].
// ---------------------------------------------------------------------------
#define AT_ROW  144
#define AT_ARR  (64*AT_ROW)          // 9216
#define AT_KV0  (2*AT_ARR)
#define AT_STG  (4*AT_ARR)           // 36864
#define AT_SMEM (2*AT_ARR + 2*AT_STG) // 92160

__global__ void __launch_bounds__(128, 2)
self_attn_mma(const __nv_bfloat16* __restrict__ Qh, const __nv_bfloat16* __restrict__ Ql,
              const __nv_bfloat16* __restrict__ Kh, const __nv_bfloat16* __restrict__ Kl,
              const __nv_bfloat16* __restrict__ Vh, const __nv_bfloat16* __restrict__ Vl,
              __nv_bfloat16* __restrict__ out_hi, __nv_bfloat16* __restrict__ out_lo) {
    extern __shared__ char smraw[];
    const uint32_t sb = (uint32_t)__cvta_generic_to_shared(smraw);
    const int tid = threadIdx.x, warp = tid >> 5, lane = tid & 31;
    const int h = blockIdx.y, b = blockIdx.z;
    const int qbi = (int)(gridDim.x - 1 - blockIdx.x);  // heavy blocks first
    const int qb = qbi * 64;
    const int ntiles = qbi + 1;
    const size_t hb = ((size_t)(b*H_ + h)) * L_;

    // ---- prologue: Q chunks + stage 0 (one commit group) ----
    #pragma unroll
    for (int i = 0; i < 8; i++) {
        int id = tid + i * 128;          // 0..1023
        int arr = id >> 9;               // 0:Qh 1:Ql
        int rem = id & 511;
        int row = rem >> 3, kc = rem & 7;
        const __nv_bfloat16* p = (arr ? Ql : Qh) + (hb + qb + row) * HD_ + kc * 8;
        uint32_t d = sb + (uint32_t)(arr * AT_ARR + row * AT_ROW + kc * 16);
        asm volatile("cp.async.cg.shared.global [%0], [%1], 16;" :: "r"(d), "l"(p) : "memory");
    }
    auto load_kv = [&](int t) {
        uint32_t base = sb + AT_KV0 + (uint32_t)(t & 1) * AT_STG;
        int k0 = t * 64;
        #pragma unroll
        for (int i = 0; i < 16; i++) {
            int id = tid + i * 128;      // 0..2047
            int arr = id >> 9;           // 0:Kh 1:Kl 2:Vh 3:Vl
            int rem = id & 511;
            int row = rem >> 3, kc = rem & 7;
            const __nv_bfloat16* p = (arr==0?Kh:arr==1?Kl:arr==2?Vh:Vl) + (hb + k0 + row) * HD_ + kc * 8;
            uint32_t d = base + (uint32_t)(arr * AT_ARR + row * AT_ROW + kc * 16);
            asm volatile("cp.async.cg.shared.global [%0], [%1], 16;" :: "r"(d), "l"(p) : "memory");
        }
        asm volatile("cp.async.commit_group;" ::: "memory");
    };
    load_kv(0);                      // group: Q + S0
    if (ntiles > 1) load_kv(1);      // group: S1

    uint32_t qh[4][4], ql[4][4];
    float o[8][4];
    #pragma unroll
    for (int i = 0; i < 8; i++)
        #pragma unroll
        for (int j = 0; j < 4; j++) o[i][j] = 0.f;
    float mA = -1e30f, mB = -1e30f, lA = 0.f, lB = 0.f;

    for (int t = 0; t < ntiles; t++) {
        if (t + 1 < ntiles) { asm volatile("cp.async.wait_group 1;" ::: "memory"); }
        else                { asm volatile("cp.async.wait_group 0;" ::: "memory"); }
        __syncthreads();
        if (t == 0) {
            #pragma unroll
            for (int ks = 0; ks < 4; ks++) {
                uint32_t a = sb + (uint32_t)((warp*16 + (lane & 15)) * AT_ROW + ks*32 + (lane >> 4) * 16);
                ldsm_x4(qh[ks], a);
                ldsm_x4(ql[ks], a + AT_ARR);
            }
        }
        const uint32_t kvb = sb + AT_KV0 + (uint32_t)(t & 1) * AT_STG;

        // ---- S = Q K^T (split-3) ----
        float s[8][4];
        #pragma unroll
        for (int i = 0; i < 8; i++)
            #pragma unroll
            for (int j = 0; j < 4; j++) s[i][j] = 0.f;
        #pragma unroll
        for (int ks = 0; ks < 4; ks++) {
            uint32_t kh4[4][4], kl4[4][4];
            #pragma unroll
            for (int ntp = 0; ntp < 4; ntp++) {
                uint32_t a = kvb + (uint32_t)((ntp*16 + (lane & 7) + ((lane >> 4) << 3)) * AT_ROW
                                              + ks*32 + (((lane >> 3) & 1) << 4));
                ldsm_x4(kh4[ntp], a);
                ldsm_x4(kl4[ntp], a + AT_ARR);
            }
            #pragma unroll
            for (int ntp = 0; ntp < 4; ntp++) {
                mma_bf16(s[2*ntp],   qh[ks], kh4[ntp]);
                mma_bf16(s[2*ntp+1], qh[ks], kh4[ntp] + 2);
                mma_bf16(s[2*ntp],   qh[ks], kl4[ntp]);
                mma_bf16(s[2*ntp+1], qh[ks], kl4[ntp] + 2);
                mma_bf16(s[2*ntp],   ql[ks], kh4[ntp]);
                mma_bf16(s[2*ntp+1], ql[ks], kh4[ntp] + 2);
            }
        }
        // ---- causal mask (diagonal tile only) ----
        if (t == ntiles - 1) {
            int rA = qb + warp*16 + (lane >> 2);
            int cbase = t*64 + 2*(lane & 3);
            #pragma unroll
            for (int nt = 0; nt < 8; nt++) {
                int c0 = cbase + nt*8, c1 = c0 + 1;
                if (c0 > rA)     s[nt][0] = -1e30f;
                if (c1 > rA)     s[nt][1] = -1e30f;
                if (c0 > rA + 8) s[nt][2] = -1e30f;
                if (c1 > rA + 8) s[nt][3] = -1e30f;
            }
        }
        // ---- online softmax ----
        float tmA = -1e30f, tmB = -1e30f;
        #pragma unroll
        for (int nt = 0; nt < 8; nt++) {
            tmA = fmaxf(tmA, fmaxf(s[nt][0], s[nt][1]));
            tmB = fmaxf(tmB, fmaxf(s[nt][2], s[nt][3]));
        }
        tmA = fmaxf(tmA, __shfl_xor_sync(0xffffffffu, tmA, 1));
        tmA = fmaxf(tmA, __shfl_xor_sync(0xffffffffu, tmA, 2));
        tmB = fmaxf(tmB, __shfl_xor_sync(0xffffffffu, tmB, 1));
        tmB = fmaxf(tmB, __shfl_xor_sync(0xffffffffu, tmB, 2));
        float nmA = fmaxf(mA, tmA), nmB = fmaxf(mB, tmB);
        float scA = __expf(mA - nmA), scB = __expf(mB - nmB);
        float tsA = 0.f, tsB = 0.f;
        #pragma unroll
        for (int nt = 0; nt < 8; nt++) {
            s[nt][0] = __expf(s[nt][0] - nmA);
            s[nt][1] = __expf(s[nt][1] - nmA);
            s[nt][2] = __expf(s[nt][2] - nmB);
            s[nt][3] = __expf(s[nt][3] - nmB);
            tsA += s[nt][0] + s[nt][1];
            tsB += s[nt][2] + s[nt][3];
        }
        tsA += __shfl_xor_sync(0xffffffffu, tsA, 1);
        tsA += __shfl_xor_sync(0xffffffffu, tsA, 2);
        tsB += __shfl_xor_sync(0xffffffffu, tsB, 1);
        tsB += __shfl_xor_sync(0xffffffffu, tsB, 2);
        lA = lA * scA + tsA;
        lB = lB * scB + tsB;
        #pragma unroll
        for (int nt = 0; nt < 8; nt++) {
            o[nt][0] *= scA; o[nt][1] *= scA;
            o[nt][2] *= scB; o[nt][3] *= scB;
        }
        mA = nmA; mB = nmB;
        // ---- O += P V (split-3) ----
        #pragma unroll
        for (int kk = 0; kk < 4; kk++) {
            uint32_t ph[4], pl[4];
            {
                float p0 = s[2*kk][0],   p1 = s[2*kk][1],   p2 = s[2*kk][2],   p3 = s[2*kk][3];
                float p4 = s[2*kk+1][0], p5 = s[2*kk+1][1], p6 = s[2*kk+1][2], p7 = s[2*kk+1][3];
                ph[0] = pack_bf16x2(p0, p1); ph[1] = pack_bf16x2(p2, p3);
                ph[2] = pack_bf16x2(p4, p5); ph[3] = pack_bf16x2(p6, p7);
                pl[0] = pack_bf16x2(p0 - __bfloat162float(__float2bfloat16_rn(p0)),
                                    p1 - __bfloat162float(__float2bfloat16_rn(p1)));
                pl[1] = pack_bf16x2(p2 - __bfloat162float(__float2bfloat16_rn(p2)),
                                    p3 - __bfloat162float(__float2bfloat16_rn(p3)));
                pl[2] = pack_bf16x2(p4 - __bfloat162float(__float2bfloat16_rn(p4)),
                                    p5 - __bfloat162float(__float2bfloat16_rn(p5)));
                pl[3] = pack_bf16x2(p6 - __bfloat162float(__float2bfloat16_rn(p6)),
                                    p7 - __bfloat162float(__float2bfloat16_rn(p7)));
            }
            #pragma unroll
            for (int ntp = 0; ntp < 4; ntp++) {
                uint32_t vh4[4], vl4[4];
                uint32_t a = kvb + 2*AT_ARR + (uint32_t)((kk*16 + (lane & 15)) * AT_ROW
                                                        + ntp*32 + ((lane >> 4) << 4));
                ldsm_x4_t(vh4, a);
                ldsm_x4_t(vl4, a + AT_ARR);
                mma_bf16(o[2*ntp],   ph, vh4);
                mma_bf16(o[2*ntp+1], ph, vh4 + 2);
                mma_bf16(o[2*ntp],   ph, vl4);
                mma_bf16(o[2*ntp+1], ph, vl4 + 2);
                mma_bf16(o[2*ntp],   pl, vh4);
                mma_bf16(o[2*ntp+1], pl, vh4 + 2);
            }
        }
        __syncthreads();
        if (t + 2 < ntiles) load_kv(t + 2);
    }

    // ---- epilogue: normalize, split, store ----
    float iA = 1.0f / lA, iB = 1.0f / lB;
    int qA = qb + warp*16 + (lane >> 2);
    size_t rowA = ((size_t)(b*L_ + qA)) * D_;
    size_t rowB = rowA + 8 * D_;
    int cb = h*HD_ + 2*(lane & 3);
    #pragma unroll
    for (int nt = 0; nt < 8; nt++) {
        int c = cb + nt*8;
        float a0 = o[nt][0]*iA, a1 = o[nt][1]*iA;
        float b0 = o[nt][2]*iB, b1 = o[nt][3]*iB;
        unsigned short h0,l0,h1,l1;
        split1(a0,h0,l0); split1(a1,h1,l1);
        *(uint32_t*)(out_hi + rowA + c) = (uint32_t)h0 | ((uint32_t)h1 << 16);
        *(uint32_t*)(out_lo + rowA + c) = (uint32_t)l0 | ((uint32_t)l1 << 16);
        split1(b0,h0,l0); split1(b1,h1,l1);
        *(uint32_t*)(out_hi + rowB + c) = (uint32_t)h0 | ((uint32_t)h1 << 16);
        *(uint32_t*)(out_lo + rowB + c) = (uint32_t)l0 | ((uint32_t)l1 << 16);
    }
}

// ---------------------------------------------------------------------------
// Cross-attention (scalar, <=128 keys per query) — unchanged.
// ---------------------------------------------------------------------------
__global__ void __launch_bounds__(256)
cross_attn_k(const float* __restrict__ qc, const float* __restrict__ kvc,
             const int* __restrict__ seg_ids,
             __nv_bfloat16* __restrict__ out_hi, __nv_bfloat16* __restrict__ out_lo) {
    const int tid = threadIdx.x;
    const int warp = tid >> 5, lane = tid & 31;
    const int h = blockIdx.y, b = blockIdx.z;
    const int l = blockIdx.x * 8 + warp;

    const int seg = seg_ids[b * L_ + l];
    int j0 = seg - 127; if (j0 < 0) j0 = 0;
    const int j1 = seg;

    const float* qrow = qc + ((size_t)(b*L_ + l)) * D_ + h * HD_;
    const float qv0 = qrow[lane]      * 0.125f;
    const float qv1 = qrow[lane + 32] * 0.125f;

    float m = -1e30f, lsum = 0.f, a0 = 0.f, a1 = 0.f;
    for (int j = j0; j <= j1; j++) {
        const float* krow = kvc + ((size_t)(b*S_ + j)) * (2*D_) + h * HD_;
        float s = qv0 * krow[lane] + qv1 * krow[lane + 32];
        #pragma unroll
        for (int off = 16; off; off >>= 1) s += __shfl_xor_sync(0xffffffffu, s, off);
        float nm = fmaxf(m, s);
        float sc = __expf(m - nm);
        float p  = __expf(s - nm);
        lsum = lsum * sc + p;
        const float* vrow = krow + D_;
        a0 = fmaf(p, vrow[lane],      a0 * sc);
        a1 = fmaf(p, vrow[lane + 32], a1 * sc);
        m = nm;
    }
    float invs = 1.0f / lsum;
    float v0 = a0 * invs, v1 = a1 * invs;
    size_t base = ((size_t)(b*L_ + l)) * D_ + h * HD_;
    unsigned short h0, l0s, h1, l1;
    split1(v0, h0, l0s); split1(v1, h1, l1);
    out_hi[base + lane]      = __ushort_as_bfloat16(h0);
    out_lo[base + lane]      = __ushort_as_bfloat16(l0s);
    out_hi[base + lane + 32] = __ushort_as_bfloat16(h1);
    out_lo[base + lane + 32] = __ushort_as_bfloat16(l1);
}

// ---------------------------------------------------------------------------
// SwiGLU from fused [g|u] buffer: silu(g)*u -> bf16 hi/lo split
// ---------------------------------------------------------------------------
__global__ void silu_split_k(const float* __restrict__ gu,
                             __nv_bfloat16* __restrict__ hi, __nv_bfloat16* __restrict__ lo) {
    int i = blockIdx.x * blockDim.x + threadIdx.x;      // over M*F/4
    int m = i / (F_/4), c4 = i % (F_/4);
    float4 gv = ((const float4*)gu)[(size_t)m * (2*F_/4) + c4];
    float4 uv = ((const float4*)gu)[(size_t)m * (2*F_/4) + F_/4 + c4];
    float4 o;
    o.x = gv.x / (1.0f + expf(-gv.x)) * uv.x;
    o.y = gv.y / (1.0f + expf(-gv.y)) * uv.y;
    o.z = gv.z / (1.0f + expf(-gv.z)) * uv.z;
    o.w = gv.w / (1.0f + expf(-gv.w)) * uv.w;
    uint2 ph, pl; split_pack4(o, ph, pl);
    ((uint2*)hi)[i] = ph;
    ((uint2*)lo)[i] = pl;
}

// ---------------------------------------------------------------------------
// Launch
// ---------------------------------------------------------------------------
static inline void split_launch(const float* src, __nv_bfloat16* hi, __nv_bfloat16* lo, size_t n) {
    int n4 = (int)(n / 4);
    split_k<<<(n4 + 255) / 256, 256>>>(src, hi, lo, n4);
}

extern "C" void kernel_launch(void* const* d_in, const int* in_sizes, int n_in,
                              void* d_out, int out_size) {
    const float* x      = (const float*)d_in[0];
    const float* memory = (const float*)d_in[1];
    const int*   seg    = (const int*)  d_in[2];
    const float* Wqkv   = (const float*)d_in[3];
    const float* bqkv   = (const float*)d_in[4];
    const float* Wo     = (const float*)d_in[5];
    const float* bo     = (const float*)d_in[6];
    const float* Wq_c   = (const float*)d_in[7];
    const float* Wkv_c  = (const float*)d_in[8];
    const float* Wo_c   = (const float*)d_in[9];
    const float* Wg     = (const float*)d_in[10];
    const float* Wu     = (const float*)d_in[11];
    const float* Wd     = (const float*)d_in[12];
    const float* n1     = (const float*)d_in[13];
    const float* n2     = (const float*)d_in[14];
    const float* n3     = (const float*)d_in[15];
    const float* nf     = (const float*)d_in[16];

    cudaFuncSetAttribute(gemm_bf16s<true,  false>, cudaFuncAttributeMaxDynamicSharedMemorySize, GSMEM);
    cudaFuncSetAttribute(gemm_bf16s<true,  true >, cudaFuncAttributeMaxDynamicSharedMemorySize, GSMEM);
    cudaFuncSetAttribute(gemm_bf16s<false, false>, cudaFuncAttributeMaxDynamicSharedMemorySize, GSMEM);
    cudaFuncSetAttribute(gemm_bf16s<false, true >, cudaFuncAttributeMaxDynamicSharedMemorySize, GSMEM);
    cudaFuncSetAttribute(self_attn_mma, cudaFuncAttributeMaxDynamicSharedMemorySize, AT_SMEM);

    float *xb, *qkvb, *qcb, *kvcb, *gub;
    __nv_bfloat16 *hhi, *hlo, *ahi, *alo, *chi, *clo, *gshi, *gslo, *mhi, *mlo, *whi, *wlo;
    __nv_bfloat16 *sqh, *sql, *skh, *skl, *svh, *svl;
    cudaGetSymbolAddress((void**)&xb,   g_x);
    cudaGetSymbolAddress((void**)&qkvb, g_qkv);
    cudaGetSymbolAddress((void**)&qcb,  g_qc);
    cudaGetSymbolAddress((void**)&kvcb, g_kvc);
    cudaGetSymbolAddress((void**)&gub,  g_gu);
    cudaGetSymbolAddress((void**)&hhi,  g_h_hi);  cudaGetSymbolAddress((void**)&hlo,  g_h_lo);
    cudaGetSymbolAddress((void**)&ahi,  g_at_hi); cudaGetSymbolAddress((void**)&alo,  g_at_lo);
    cudaGetSymbolAddress((void**)&chi,  g_co_hi); cudaGetSymbolAddress((void**)&clo,  g_co_lo);
    cudaGetSymbolAddress((void**)&gshi, g_gs_hi); cudaGetSymbolAddress((void**)&gslo, g_gs_lo);
    cudaGetSymbolAddress((void**)&mhi,  g_m_hi);  cudaGetSymbolAddress((void**)&mlo,  g_m_lo);
    cudaGetSymbolAddress((void**)&whi,  g_w_hi);  cudaGetSymbolAddress((void**)&wlo,  g_w_lo);
    cudaGetSymbolAddress((void**)&sqh,  g_sqh);   cudaGetSymbolAddress((void**)&sql,  g_sql);
    cudaGetSymbolAddress((void**)&skh,  g_skh);   cudaGetSymbolAddress((void**)&skl,  g_skl);
    cudaGetSymbolAddress((void**)&svh,  g_svh);   cudaGetSymbolAddress((void**)&svl,  g_svl);

    rope_cache_k<<<256, 256>>>();
    copy_x_k<<<(M_*D_)/256, 256>>>(x);

    split_launch(Wqkv,  whi + O_WQKV, wlo + O_WQKV, NL*SZ_WQKV);
    split_launch(Wo,    whi + O_WO,   wlo + O_WO,   NL*SZ_WO);
    split_launch(Wq_c,  whi + O_WQC,  wlo + O_WQC,  NL*SZ_WQC);
    split_launch(Wkv_c, whi + O_WKVC, wlo + O_WKVC, NL*SZ_WKVC);
    split_launch(Wo_c,  whi + O_WOC,  wlo + O_WOC,  NL*SZ_WOC);
    for (int l = 0; l < NL; l++) {   // interleave [Wg_l; Wu_l] per layer
        split_launch(Wg + (size_t)l*F_*D_, whi + O_WGU + l*SZ_WGU,            wlo + O_WGU + l*SZ_WGU,            (size_t)F_*D_);
        split_launch(Wu + (size_t)l*F_*D_, whi + O_WGU + l*SZ_WGU + (size_t)F_*D_, wlo + O_WGU + l*SZ_WGU + (size_t)F_*D_, (size_t)F_*D_);
    }
    split_launch(Wd,    whi + O_WD,   wlo + O_WD,   NL*SZ_WD);
    split_launch(memory, mhi, mlo, (size_t)B_*S_*D_);

    const dim3 self_grid(L_/64, H_, B_);
    const dim3 cross_grid(L_/8, H_, B_);

    for (int l = 0; l < NL; l++) {
        const __nv_bfloat16* wqkv_h = whi + O_WQKV + l*SZ_WQKV;
        const __nv_bfloat16* wqkv_l = wlo + O_WQKV + l*SZ_WQKV;
        const __nv_bfloat16* wo_h   = whi + O_WO   + l*SZ_WO;
        const __nv_bfloat16* wo_l   = wlo + O_WO   + l*SZ_WO;
        const __nv_bfloat16* wqc_h  = whi + O_WQC  + l*SZ_WQC;
        const __nv_bfloat16* wqc_l  = wlo + O_WQC  + l*SZ_WQC;
        const __nv_bfloat16* wkvc_h = whi + O_WKVC + l*SZ_WKVC;
        const __nv_bfloat16* wkvc_l = wlo + O_WKVC + l*SZ_WKVC;
        const __nv_bfloat16* woc_h  = whi + O_WOC  + l*SZ_WOC;
        const __nv_bfloat16* woc_l  = wlo + O_WOC  + l*SZ_WOC;
        const __nv_bfloat16* wgu_h  = whi + O_WGU  + l*SZ_WGU;
        const __nv_bfloat16* wgu_l  = wlo + O_WGU  + l*SZ_WGU;
        const __nv_bfloat16* wd_h   = whi + O_WD   + l*SZ_WD;
        const __nv_bfloat16* wd_l   = wlo + O_WD   + l*SZ_WD;

        // --- self attention block ---
        rmsnorm_split_k<<<M_, 256>>>(xb, n1 + l*D_, hhi, hlo);
        gemm_bf16s<true, false><<<dim3(3*D_/128, M_/128), 256, GSMEM>>>(
            hhi, hlo, wqkv_h, wqkv_l, bqkv + l*3*D_, qkvb, 3*D_, D_);
        rope_split_k<<<M_, 512>>>(qkvb);
        self_attn_mma<<<self_grid, 128, AT_SMEM>>>(sqh, sql, skh, skl, svh, svl, ahi, alo);
        gemm_bf16s<true, true><<<dim3(D_/128, M_/128), 256, GSMEM>>>(
            ahi, alo, wo_h, wo_l, bo + l*D_, xb, D_, D_);

        // --- cross attention block ---
        rmsnorm_split_k<<<M_, 256>>>(xb, n2 + l*D_, hhi, hlo);
        gemm_bf16s<false, false><<<dim3(D_/128, M_/128), 256, GSMEM>>>(
            hhi, hlo, wqc_h, wqc_l, nullptr, qcb, D_, D_);
        gemm_bf16s<false, false><<<dim3(2*D_/128, (B_*S_)/128), 256, GSMEM>>>(
            mhi, mlo, wkvc_h, wkvc_l, nullptr, kvcb, 2*D_, D_);
        cross_attn_k<<<cross_grid, 256>>>(qcb, kvcb, seg, chi, clo);
        gemm_bf16s<false, true><<<dim3(D_/128, M_/128), 256, GSMEM>>>(
            chi, clo, woc_h, woc_l, nullptr, xb, D_, D_);

        // --- MLP block (fused gate|up GEMM) ---
        rmsnorm_split_k<<<M_, 256>>>(xb, n3 + l*D_, hhi, hlo);
        gemm_bf16s<false, false><<<dim3(2*F_/128, M_/128), 256, GSMEM>>>(
            hhi, hlo, wgu_h, wgu_l, nullptr, gub, 2*F_, D_);
        silu_split_k<<<(M_*F_/4)/256, 256>>>(gub, gshi, gslo);
        gemm_bf16s<false, true><<<dim3(D_/128, M_/128), 256, GSMEM>>>(
            gshi, gslo, wd_h, wd_l, nullptr, xb, D_, F_);
    }

    rmsnorm_k<<<M_, 256>>>(xb, nf, (float*)d_out);
}

// round 7
// speedup vs baseline: 4.2375x; 1.1168x over previous
#include <cuda_runtime.h>
#include <cuda_bf16.h>
#include <math.h>
#include <stdint.h>

// Problem constants
#define NL 4
#define B_ 2
#define L_ 2048
#define S_ 256
#define D_ 1024
#define F_ 4096
#define H_ 16
#define HD_ 64
#define M_ (B_*L_)          // 4096 token rows

// Weight region sizes (elements) and offsets in the concatenated split buffer
#define SZ_WQKV ((size_t)3*D_*D_)
#define SZ_WO   ((size_t)D_*D_)
#define SZ_WQC  ((size_t)D_*D_)
#define SZ_WKVC ((size_t)2*D_*D_)
#define SZ_WOC  ((size_t)D_*D_)
#define SZ_WGU  ((size_t)2*F_*D_)     // interleaved [g0,u0,g1,u1,...] per layer
#define SZ_WD   ((size_t)D_*F_)
static const size_t O_WQKV = 0;
static const size_t O_WO   = O_WQKV + NL*SZ_WQKV;
static const size_t O_WQC  = O_WO   + NL*SZ_WO;
static const size_t O_WKVC = O_WQC  + NL*SZ_WQC;
static const size_t O_WOC  = O_WKVC + NL*SZ_WKVC;
static const size_t O_WGU  = O_WOC  + NL*SZ_WOC;
static const size_t O_WD   = O_WGU  + NL*SZ_WGU;
#define WTOT (O_WD + NL*SZ_WD)

// ---------------------------------------------------------------------------
// Scratch (device globals; no allocations allowed)
// ---------------------------------------------------------------------------
__device__ float g_x  [M_*D_];
__device__ float g_qkv[M_*3*D_];
__device__ float g_cos[L_*32];
__device__ float g_sin[L_*32];

__device__ __nv_bfloat16 g_h_hi [M_*D_],  g_h_lo [M_*D_];
__device__ __nv_bfloat16 g_at_hi[M_*D_],  g_at_lo[M_*D_];
__device__ __nv_bfloat16 g_co_hi[M_*D_],  g_co_lo[M_*D_];
__device__ __nv_bfloat16 g_gs_hi[M_*F_],  g_gs_lo[M_*F_];
__device__ __nv_bfloat16 g_m_hi [B_*S_*D_], g_m_lo[B_*S_*D_];
__device__ __nv_bfloat16 g_w_hi[WTOT], g_w_lo[WTOT];

// attention-layout split buffers: [B][H][L][64] (self q/k/v, cross reuses)
#define ATN ((size_t)B_*H_*L_*HD_)
__device__ __nv_bfloat16 g_sqh[ATN], g_sql[ATN];
__device__ __nv_bfloat16 g_skh[ATN], g_skl[ATN];
__device__ __nv_bfloat16 g_svh[ATN], g_svl[ATN];

// ---------------------------------------------------------------------------
// bf16 split helpers
// ---------------------------------------------------------------------------
__device__ __forceinline__ void split1(float v, unsigned short& h, unsigned short& l) {
    __nv_bfloat16 hb = __float2bfloat16_rn(v);
    float r = v - __bfloat162float(hb);
    __nv_bfloat16 lb = __float2bfloat16_rn(r);
    h = __bfloat16_as_ushort(hb);
    l = __bfloat16_as_ushort(lb);
}
__device__ __forceinline__ void split_pack4(float4 v, uint2& ph, uint2& pl) {
    unsigned short h0,h1,h2,h3,l0,l1,l2,l3;
    split1(v.x,h0,l0); split1(v.y,h1,l1); split1(v.z,h2,l2); split1(v.w,h3,l3);
    ph.x = (uint32_t)h0 | ((uint32_t)h1 << 16);
    ph.y = (uint32_t)h2 | ((uint32_t)h3 << 16);
    pl.x = (uint32_t)l0 | ((uint32_t)l1 << 16);
    pl.y = (uint32_t)l2 | ((uint32_t)l3 << 16);
}

__global__ void split_k(const float* __restrict__ in, __nv_bfloat16* __restrict__ hi,
                        __nv_bfloat16* __restrict__ lo, int n4) {
    int i = blockIdx.x * blockDim.x + threadIdx.x;
    if (i >= n4) return;
    float4 v = ((const float4*)in)[i];
    uint2 ph, pl; split_pack4(v, ph, pl);
    ((uint2*)hi)[i] = ph;
    ((uint2*)lo)[i] = pl;
}

// Interleaving split: source row r -> destination row 2r+off (rowQuads float4s per row)
__global__ void split_ilv_k(const float* __restrict__ in, __nv_bfloat16* __restrict__ hi,
                            __nv_bfloat16* __restrict__ lo, int n4, int rowQuads, int off) {
    int i = blockIdx.x * blockDim.x + threadIdx.x;
    if (i >= n4) return;
    int r = i / rowQuads, c = i % rowQuads;
    float4 v = ((const float4*)in)[i];
    uint2 ph, pl; split_pack4(v, ph, pl);
    size_t oi = (size_t)(2*r + off) * rowQuads + c;
    ((uint2*)hi)[oi] = ph;
    ((uint2*)lo)[oi] = pl;
}

// ---------------------------------------------------------------------------
// RoPE cache
// ---------------------------------------------------------------------------
__global__ void rope_cache_k() {
    int idx = blockIdx.x * blockDim.x + threadIdx.x;
    int l = idx >> 5, i = idx & 31;
    double inv = exp(-log(10000.0) * (double)i / 32.0);
    double f = (double)l * inv;
    g_cos[idx] = (float)cos(f);
    g_sin[idx] = (float)sin(f);
}

__global__ void copy_x_k(const float* __restrict__ x) {
    size_t i = (size_t)blockIdx.x * blockDim.x + threadIdx.x;
    if (i < (size_t)M_ * D_) g_x[i] = x[i];
}

// ---------------------------------------------------------------------------
// RMSNorm kernels
// ---------------------------------------------------------------------------
__global__ void rmsnorm_split_k(const float* __restrict__ x, const float* __restrict__ w,
                                __nv_bfloat16* __restrict__ hi, __nv_bfloat16* __restrict__ lo) {
    int row = blockIdx.x;
    int t = threadIdx.x;
    const float4* xr = (const float4*)(x + (size_t)row * D_);
    float4 v = xr[t];
    float ss = v.x*v.x + v.y*v.y + v.z*v.z + v.w*v.w;
    #pragma unroll
    for (int off = 16; off; off >>= 1) ss += __shfl_xor_sync(0xffffffffu, ss, off);
    __shared__ float red[8];
    if ((t & 31) == 0) red[t >> 5] = ss;
    __syncthreads();
    float tot = red[0]+red[1]+red[2]+red[3]+red[4]+red[5]+red[6]+red[7];
    float rs = rsqrtf(tot * (1.0f / (float)D_) + 1e-6f);
    float4 wv = ((const float4*)w)[t];
    float4 o;
    o.x = v.x * rs * wv.x; o.y = v.y * rs * wv.y;
    o.z = v.z * rs * wv.z; o.w = v.w * rs * wv.w;
    uint2 ph, pl; split_pack4(o, ph, pl);
    ((uint2*)hi)[(size_t)row * 256 + t] = ph;
    ((uint2*)lo)[(size_t)row * 256 + t] = pl;
}

__global__ void rmsnorm_k(const float* __restrict__ x, const float* __restrict__ w,
                          float* __restrict__ o) {
    int row = blockIdx.x;
    int t = threadIdx.x;
    const float4* xr = (const float4*)(x + (size_t)row * D_);
    float4 v = xr[t];
    float ss = v.x*v.x + v.y*v.y + v.z*v.z + v.w*v.w;
    #pragma unroll
    for (int off = 16; off; off >>= 1) ss += __shfl_xor_sync(0xffffffffu, ss, off);
    __shared__ float red[8];
    if ((t & 31) == 0) red[t >> 5] = ss;
    __syncthreads();
    float tot = red[0]+red[1]+red[2]+red[3]+red[4]+red[5]+red[6]+red[7];
    float rs = rsqrtf(tot * (1.0f / (float)D_) + 1e-6f);
    float4 wv = ((const float4*)w)[t];
    float4 out;
    out.x = v.x * rs * wv.x; out.y = v.y * rs * wv.y;
    out.z = v.z * rs * wv.z; out.w = v.w * rs * wv.w;
    ((float4*)(o + (size_t)row * D_))[t] = out;
}

// ---------------------------------------------------------------------------
// mma / ldmatrix helpers
// ---------------------------------------------------------------------------
__device__ __forceinline__ void mma_bf16(float* c, const uint32_t* a, const uint32_t* b) {
    asm volatile(
        "mma.sync.aligned.m16n8k16.row.col.f32.bf16.bf16.f32 "
        "{%0,%1,%2,%3}, {%4,%5,%6,%7}, {%8,%9}, {%0,%1,%2,%3};"
        : "+f"(c[0]), "+f"(c[1]), "+f"(c[2]), "+f"(c[3])
        : "r"(a[0]), "r"(a[1]), "r"(a[2]), "r"(a[3]), "r"(b[0]), "r"(b[1]));
}
__device__ __forceinline__ void ldsm_x4(uint32_t* r, uint32_t addr) {
    asm volatile("ldmatrix.sync.aligned.m8n8.x4.shared.b16 {%0,%1,%2,%3}, [%4];"
        : "=r"(r[0]), "=r"(r[1]), "=r"(r[2]), "=r"(r[3]) : "r"(addr));
}
__device__ __forceinline__ void ldsm_x4_t(uint32_t* r, uint32_t addr) {
    asm volatile("ldmatrix.sync.aligned.m8n8.x4.trans.shared.b16 {%0,%1,%2,%3}, [%4];"
        : "=r"(r[0]), "=r"(r[1]), "=r"(r[2]), "=r"(r[3]) : "r"(addr));
}
__device__ __forceinline__ void ldsm_x2(uint32_t* r, uint32_t addr) {
    asm volatile("ldmatrix.sync.aligned.m8n8.x2.shared.b16 {%0,%1}, [%2];"
        : "=r"(r[0]), "=r"(r[1]) : "r"(addr));
}
__device__ __forceinline__ uint32_t pack_bf16x2(float lo, float hi) {
    return (uint32_t)__bfloat16_as_ushort(__float2bfloat16_rn(lo)) |
           ((uint32_t)__bfloat16_as_ushort(__float2bfloat16_rn(hi)) << 16);
}

// ---------------------------------------------------------------------------
// bf16 split-3 GEMM (NT) with fused epilogues.
// MODE 0: +bias              -> fp32 C      (QKV)
// MODE 1: +bias +residual    -> fp32 C      (Wo)
// MODE 2: +residual          -> fp32 C      (Wo_c, Wd)
// MODE 3: swiglu (interleaved g|u cols) -> bf16 hi/lo [M][F]
// MODE 4: attn-q layout, x0.125         -> bf16 hi/lo [B][H][L][64]
// MODE 5: attn-kv layout (k|v)          -> bf16 hi/lo [B][H][S][64] x2
// ---------------------------------------------------------------------------
#define GSTAGE  40960     // 4 * 10240 bytes
#define GARR    10240     // 128 * 80
#define GSMEM   (3*GSTAGE)

template <int MODE>
__global__ void __launch_bounds__(256, 1)
gemm_bf16s(const __nv_bfloat16* __restrict__ Ah, const __nv_bfloat16* __restrict__ Al,
           const __nv_bfloat16* __restrict__ Wh, const __nv_bfloat16* __restrict__ Wl,
           const float* __restrict__ bias, float* __restrict__ C,
           __nv_bfloat16* __restrict__ o1h, __nv_bfloat16* __restrict__ o1l,
           __nv_bfloat16* __restrict__ o2h, __nv_bfloat16* __restrict__ o2l,
           int N, int K) {
    extern __shared__ char smem[];
    const uint32_t sbase = (uint32_t)__cvta_generic_to_shared(smem);
    const int tid  = threadIdx.x;
    const int warp = tid >> 5, lane = tid & 31;
    const int wm = warp & 1;
    const int wn = warp >> 1;
    const int g  = lane >> 2;
    const int t  = lane & 3;
    const int bm = blockIdx.y, bn = blockIdx.x;

    const __nv_bfloat16* src[8];
    uint32_t dst[8];
    #pragma unroll
    for (int i = 0; i < 8; i++) {
        int id  = tid + 256 * i;
        int arr = id >> 9;
        int rem = id & 511;
        int row = rem >> 2;
        int kc  = rem & 3;
        const __nv_bfloat16* bp = (arr == 0) ? Ah : (arr == 1) ? Al : (arr == 2) ? Wh : Wl;
        int grow = ((arr < 2) ? bm : bn) * 128 + row;
        src[i] = bp + (size_t)grow * K + kc * 8;
        dst[i] = (uint32_t)(arr * GARR + row * 80 + kc * 16);
    }

    const uint32_t arow = (uint32_t)((wm * 64 + (lane & 15)) * 80 + (lane >> 4) * 16);
    const uint32_t brow = (uint32_t)((wn * 32 + (lane & 7)) * 80 + ((lane >> 3) & 1) * 16);

    float acc[4][4][4];
    #pragma unroll
    for (int i = 0; i < 4; i++)
        #pragma unroll
        for (int j = 0; j < 4; j++)
            #pragma unroll
            for (int r = 0; r < 4; r++) acc[i][j][r] = 0.f;

    const int nk = K >> 5;

    #pragma unroll
    for (int st = 0; st < 2; st++) {
        uint32_t s = sbase + st * GSTAGE;
        #pragma unroll
        for (int i = 0; i < 8; i++) {
            const void* p = src[i] + st * 32;
            asm volatile("cp.async.cg.shared.global [%0], [%1], 16;"
                         :: "r"(s + dst[i]), "l"(p) : "memory");
        }
        asm volatile("cp.async.commit_group;" ::: "memory");
    }

    for (int it = 0; it < nk; it++) {
        asm volatile("cp.async.wait_group 1;" ::: "memory");
        __syncthreads();
        uint32_t s = sbase + (uint32_t)(it % 3) * GSTAGE;

        #pragma unroll
        for (int ks = 0; ks < 2; ks++) {
            const uint32_t ko = ks * 32;
            uint32_t af[4][4], bh[4][2], bl[4][2];
            #pragma unroll
            for (int mt = 0; mt < 4; mt++) ldsm_x4(af[mt], s + 0*GARR + arow + mt*1280 + ko);
            #pragma unroll
            for (int nt = 0; nt < 4; nt++) ldsm_x2(bh[nt], s + 2*GARR + brow + nt*640 + ko);
            #pragma unroll
            for (int nt = 0; nt < 4; nt++) ldsm_x2(bl[nt], s + 3*GARR + brow + nt*640 + ko);
            #pragma unroll
            for (int mt = 0; mt < 4; mt++)
                #pragma unroll
                for (int nt = 0; nt < 4; nt++) mma_bf16(acc[mt][nt], af[mt], bh[nt]);
            #pragma unroll
            for (int mt = 0; mt < 4; mt++)
                #pragma unroll
                for (int nt = 0; nt < 4; nt++) mma_bf16(acc[mt][nt], af[mt], bl[nt]);
            #pragma unroll
            for (int mt = 0; mt < 4; mt++) ldsm_x4(af[mt], s + 1*GARR + arow + mt*1280 + ko);
            #pragma unroll
            for (int mt = 0; mt < 4; mt++)
                #pragma unroll
                for (int nt = 0; nt < 4; nt++) mma_bf16(acc[mt][nt], af[mt], bh[nt]);
        }

        if (it + 2 < nk) {
            uint32_t s2 = sbase + (uint32_t)((it + 2) % 3) * GSTAGE;
            int k0 = (it + 2) * 32;
            #pragma unroll
            for (int i = 0; i < 8; i++) {
                const void* p = src[i] + k0;
                asm volatile("cp.async.cg.shared.global [%0], [%1], 16;"
                             :: "r"(s2 + dst[i]), "l"(p) : "memory");
            }
        }
        asm volatile("cp.async.commit_group;" ::: "memory");
    }

    #pragma unroll
    for (int mt = 0; mt < 4; mt++) {
        #pragma unroll
        for (int half = 0; half < 2; half++) {
            int row = bm * 128 + wm * 64 + mt * 16 + g + half * 8;
            #pragma unroll
            for (int nt = 0; nt < 4; nt++) {
                int col = bn * 128 + wn * 32 + nt * 8 + 2 * t;
                float c0 = acc[mt][nt][half * 2 + 0];
                float c1 = acc[mt][nt][half * 2 + 1];
                if (MODE <= 2) {
                    float* dstp = C + (size_t)row * N + col;
                    if (MODE == 0 || MODE == 1) { c0 += bias[col]; c1 += bias[col + 1]; }
                    if (MODE == 1 || MODE == 2) {
                        float2 r = *(const float2*)dstp;
                        c0 += r.x; c1 += r.y;
                    }
                    *(float2*)dstp = make_float2(c0, c1);
                } else if (MODE == 3) {
                    float sg = c0 / (1.0f + expf(-c0)) * c1;
                    unsigned short hh, ll; split1(sg, hh, ll);
                    size_t oi = (size_t)row * F_ + (col >> 1);
                    o1h[oi] = __ushort_as_bfloat16(hh);
                    o1l[oi] = __ushort_as_bfloat16(ll);
                } else if (MODE == 4) {
                    int b = row >> 11, ltok = row & (L_ - 1);
                    int hd = col >> 6, d = col & 63;
                    size_t oi = (((size_t)(b*H_ + hd)) * L_ + ltok) * HD_ + d;
                    unsigned short h0, l0, h1, l1;
                    split1(c0 * 0.125f, h0, l0); split1(c1 * 0.125f, h1, l1);
                    *(uint32_t*)(o1h + oi) = (uint32_t)h0 | ((uint32_t)h1 << 16);
                    *(uint32_t*)(o1l + oi) = (uint32_t)l0 | ((uint32_t)l1 << 16);
                } else { // MODE 5
                    int b = row >> 8, stok = row & (S_ - 1);
                    int hd = (col >> 6) & 15, d = col & 63;
                    size_t oi = (((size_t)(b*H_ + hd)) * S_ + stok) * HD_ + d;
                    unsigned short h0, l0, h1, l1;
                    split1(c0, h0, l0); split1(c1, h1, l1);
                    __nv_bfloat16* ph = (col < 1024) ? o1h : o2h;
                    __nv_bfloat16* pl = (col < 1024) ? o1l : o2l;
                    *(uint32_t*)(ph + oi) = (uint32_t)h0 | ((uint32_t)h1 << 16);
                    *(uint32_t*)(pl + oi) = (uint32_t)l0 | ((uint32_t)l1 << 16);
                }
            }
        }
    }
}

// ---------------------------------------------------------------------------
// RoPE + bf16 hi/lo split of q,k,v into attention layout [B][H][L][64].
// ---------------------------------------------------------------------------
__global__ void rope_split_k(const float* __restrict__ qkv) {
    int bl = blockIdx.x;
    int b = bl >> 11, l = bl & (L_ - 1);
    int hh = threadIdx.x >> 5;
    int i  = threadIdx.x & 31;
    float c = g_cos[l*32 + i];
    float s = g_sin[l*32 + i];
    const float* base = qkv + (size_t)bl * (3*D_) + hh * HD_;
    size_t orow = (((size_t)(b*H_ + hh)) * L_ + l) * HD_;
    unsigned short vh, vl;
    float x1 = base[i], x2 = base[i+32];
    float q1 = (x1*c - x2*s) * 0.125f;
    float q2 = (x2*c + x1*s) * 0.125f;
    split1(q1, vh, vl); g_sqh[orow+i]    = __ushort_as_bfloat16(vh); g_sql[orow+i]    = __ushort_as_bfloat16(vl);
    split1(q2, vh, vl); g_sqh[orow+i+32] = __ushort_as_bfloat16(vh); g_sql[orow+i+32] = __ushort_as_bfloat16(vl);
    x1 = base[D_+i]; x2 = base[D_+i+32];
    float k1 = x1*c - x2*s;
    float k2 = x2*c + x1*s;
    split1(k1, vh, vl); g_skh[orow+i]    = __ushort_as_bfloat16(vh); g_skl[orow+i]    = __ushort_as_bfloat16(vl);
    split1(k2, vh, vl); g_skh[orow+i+32] = __ushort_as_bfloat16(vh); g_skl[orow+i+32] = __ushort_as_bfloat16(vl);
    split1(base[2*D_+i],    vh, vl); g_svh[orow+i]    = __ushort_as_bfloat16(vh); g_svl[orow+i]    = __ushort_as_bfloat16(vl);
    split1(base[2*D_+i+32], vh, vl); g_svh[orow+i+32] = __ushort_as_bfloat16(vh); g_svl[orow+i+32] = __ushort_as_bfloat16(vl);
}

// ---------------------------------------------------------------------------
// mma.sync flash self-attention (as Round 6).
// ---------------------------------------------------------------------------
#define AT_ROW  144
#define AT_ARR  (64*AT_ROW)
#define AT_KV0  (2*AT_ARR)
#define AT_STG  (4*AT_ARR)
#define AT_SMEM (2*AT_ARR + 2*AT_STG)

__global__ void __launch_bounds__(128, 2)
self_attn_mma(const __nv_bfloat16* __restrict__ Qh, const __nv_bfloat16* __restrict__ Ql,
              const __nv_bfloat16* __restrict__ Kh, const __nv_bfloat16* __restrict__ Kl,
              const __nv_bfloat16* __restrict__ Vh, const __nv_bfloat16* __restrict__ Vl,
              __nv_bfloat16* __restrict__ out_hi, __nv_bfloat16* __restrict__ out_lo) {
    extern __shared__ char smraw[];
    const uint32_t sb = (uint32_t)__cvta_generic_to_shared(smraw);
    const int tid = threadIdx.x, warp = tid >> 5, lane = tid & 31;
    const int h = blockIdx.y, b = blockIdx.z;
    const int qbi = (int)(gridDim.x - 1 - blockIdx.x);
    const int qb = qbi * 64;
    const int ntiles = qbi + 1;
    const size_t hb = ((size_t)(b*H_ + h)) * L_;

    #pragma unroll
    for (int i = 0; i < 8; i++) {
        int id = tid + i * 128;
        int arr = id >> 9;
        int rem = id & 511;
        int row = rem >> 3, kc = rem & 7;
        const __nv_bfloat16* p = (arr ? Ql : Qh) + (hb + qb + row) * HD_ + kc * 8;
        uint32_t d = sb + (uint32_t)(arr * AT_ARR + row * AT_ROW + kc * 16);
        asm volatile("cp.async.cg.shared.global [%0], [%1], 16;" :: "r"(d), "l"(p) : "memory");
    }
    auto load_kv = [&](int t) {
        uint32_t base = sb + AT_KV0 + (uint32_t)(t & 1) * AT_STG;
        int k0 = t * 64;
        #pragma unroll
        for (int i = 0; i < 16; i++) {
            int id = tid + i * 128;
            int arr = id >> 9;
            int rem = id & 511;
            int row = rem >> 3, kc = rem & 7;
            const __nv_bfloat16* p = (arr==0?Kh:arr==1?Kl:arr==2?Vh:Vl) + (hb + k0 + row) * HD_ + kc * 8;
            uint32_t d = base + (uint32_t)(arr * AT_ARR + row * AT_ROW + kc * 16);
            asm volatile("cp.async.cg.shared.global [%0], [%1], 16;" :: "r"(d), "l"(p) : "memory");
        }
        asm volatile("cp.async.commit_group;" ::: "memory");
    };
    load_kv(0);
    if (ntiles > 1) load_kv(1);

    uint32_t qh[4][4], ql[4][4];
    float o[8][4];
    #pragma unroll
    for (int i = 0; i < 8; i++)
        #pragma unroll
        for (int j = 0; j < 4; j++) o[i][j] = 0.f;
    float mA = -1e30f, mB = -1e30f, lA = 0.f, lB = 0.f;

    for (int t = 0; t < ntiles; t++) {
        if (t + 1 < ntiles) { asm volatile("cp.async.wait_group 1;" ::: "memory"); }
        else                { asm volatile("cp.async.wait_group 0;" ::: "memory"); }
        __syncthreads();
        if (t == 0) {
            #pragma unroll
            for (int ks = 0; ks < 4; ks++) {
                uint32_t a = sb + (uint32_t)((warp*16 + (lane & 15)) * AT_ROW + ks*32 + (lane >> 4) * 16);
                ldsm_x4(qh[ks], a);
                ldsm_x4(ql[ks], a + AT_ARR);
            }
        }
        const uint32_t kvb = sb + AT_KV0 + (uint32_t)(t & 1) * AT_STG;

        float s[8][4];
        #pragma unroll
        for (int i = 0; i < 8; i++)
            #pragma unroll
            for (int j = 0; j < 4; j++) s[i][j] = 0.f;
        #pragma unroll
        for (int ks = 0; ks < 4; ks++) {
            uint32_t kh4[4][4], kl4[4][4];
            #pragma unroll
            for (int ntp = 0; ntp < 4; ntp++) {
                uint32_t a = kvb + (uint32_t)((ntp*16 + (lane & 7) + ((lane >> 4) << 3)) * AT_ROW
                                              + ks*32 + (((lane >> 3) & 1) << 4));
                ldsm_x4(kh4[ntp], a);
                ldsm_x4(kl4[ntp], a + AT_ARR);
            }
            #pragma unroll
            for (int ntp = 0; ntp < 4; ntp++) {
                mma_bf16(s[2*ntp],   qh[ks], kh4[ntp]);
                mma_bf16(s[2*ntp+1], qh[ks], kh4[ntp] + 2);
                mma_bf16(s[2*ntp],   qh[ks], kl4[ntp]);
                mma_bf16(s[2*ntp+1], qh[ks], kl4[ntp] + 2);
                mma_bf16(s[2*ntp],   ql[ks], kh4[ntp]);
                mma_bf16(s[2*ntp+1], ql[ks], kh4[ntp] + 2);
            }
        }
        if (t == ntiles - 1) {
            int rA = qb + warp*16 + (lane >> 2);
            int cbase = t*64 + 2*(lane & 3);
            #pragma unroll
            for (int nt = 0; nt < 8; nt++) {
                int c0 = cbase + nt*8, c1 = c0 + 1;
                if (c0 > rA)     s[nt][0] = -1e30f;
                if (c1 > rA)     s[nt][1] = -1e30f;
                if (c0 > rA + 8) s[nt][2] = -1e30f;
                if (c1 > rA + 8) s[nt][3] = -1e30f;
            }
        }
        float tmA = -1e30f, tmB = -1e30f;
        #pragma unroll
        for (int nt = 0; nt < 8; nt++) {
            tmA = fmaxf(tmA, fmaxf(s[nt][0], s[nt][1]));
            tmB = fmaxf(tmB, fmaxf(s[nt][2], s[nt][3]));
        }
        tmA = fmaxf(tmA, __shfl_xor_sync(0xffffffffu, tmA, 1));
        tmA = fmaxf(tmA, __shfl_xor_sync(0xffffffffu, tmA, 2));
        tmB = fmaxf(tmB, __shfl_xor_sync(0xffffffffu, tmB, 1));
        tmB = fmaxf(tmB, __shfl_xor_sync(0xffffffffu, tmB, 2));
        float nmA = fmaxf(mA, tmA), nmB = fmaxf(mB, tmB);
        float scA = __expf(mA - nmA), scB = __expf(mB - nmB);
        float tsA = 0.f, tsB = 0.f;
        #pragma unroll
        for (int nt = 0; nt < 8; nt++) {
            s[nt][0] = __expf(s[nt][0] - nmA);
            s[nt][1] = __expf(s[nt][1] - nmA);
            s[nt][2] = __expf(s[nt][2] - nmB);
            s[nt][3] = __expf(s[nt][3] - nmB);
            tsA += s[nt][0] + s[nt][1];
            tsB += s[nt][2] + s[nt][3];
        }
        tsA += __shfl_xor_sync(0xffffffffu, tsA, 1);
        tsA += __shfl_xor_sync(0xffffffffu, tsA, 2);
        tsB += __shfl_xor_sync(0xffffffffu, tsB, 1);
        tsB += __shfl_xor_sync(0xffffffffu, tsB, 2);
        lA = lA * scA + tsA;
        lB = lB * scB + tsB;
        #pragma unroll
        for (int nt = 0; nt < 8; nt++) {
            o[nt][0] *= scA; o[nt][1] *= scA;
            o[nt][2] *= scB; o[nt][3] *= scB;
        }
        mA = nmA; mB = nmB;
        #pragma unroll
        for (int kk = 0; kk < 4; kk++) {
            uint32_t ph[4], pl[4];
            {
                float p0 = s[2*kk][0],   p1 = s[2*kk][1],   p2 = s[2*kk][2],   p3 = s[2*kk][3];
                float p4 = s[2*kk+1][0], p5 = s[2*kk+1][1], p6 = s[2*kk+1][2], p7 = s[2*kk+1][3];
                ph[0] = pack_bf16x2(p0, p1); ph[1] = pack_bf16x2(p2, p3);
                ph[2] = pack_bf16x2(p4, p5); ph[3] = pack_bf16x2(p6, p7);
                pl[0] = pack_bf16x2(p0 - __bfloat162float(__float2bfloat16_rn(p0)),
                                    p1 - __bfloat162float(__float2bfloat16_rn(p1)));
                pl[1] = pack_bf16x2(p2 - __bfloat162float(__float2bfloat16_rn(p2)),
                                    p3 - __bfloat162float(__float2bfloat16_rn(p3)));
                pl[2] = pack_bf16x2(p4 - __bfloat162float(__float2bfloat16_rn(p4)),
                                    p5 - __bfloat162float(__float2bfloat16_rn(p5)));
                pl[3] = pack_bf16x2(p6 - __bfloat162float(__float2bfloat16_rn(p6)),
                                    p7 - __bfloat162float(__float2bfloat16_rn(p7)));
            }
            #pragma unroll
            for (int ntp = 0; ntp < 4; ntp++) {
                uint32_t vh4[4], vl4[4];
                uint32_t a = kvb + 2*AT_ARR + (uint32_t)((kk*16 + (lane & 15)) * AT_ROW
                                                        + ntp*32 + ((lane >> 4) << 4));
                ldsm_x4_t(vh4, a);
                ldsm_x4_t(vl4, a + AT_ARR);
                mma_bf16(o[2*ntp],   ph, vh4);
                mma_bf16(o[2*ntp+1], ph, vh4 + 2);
                mma_bf16(o[2*ntp],   ph, vl4);
                mma_bf16(o[2*ntp+1], ph, vl4 + 2);
                mma_bf16(o[2*ntp],   pl, vh4);
                mma_bf16(o[2*ntp+1], pl, vh4 + 2);
            }
        }
        __syncthreads();
        if (t + 2 < ntiles) load_kv(t + 2);
    }

    float iA = 1.0f / lA, iB = 1.0f / lB;
    int qA = qb + warp*16 + (lane >> 2);
    size_t rowA = ((size_t)(b*L_ + qA)) * D_;
    size_t rowB = rowA + 8 * D_;
    int cb = h*HD_ + 2*(lane & 3);
    #pragma unroll
    for (int nt = 0; nt < 8; nt++) {
        int c = cb + nt*8;
        float a0 = o[nt][0]*iA, a1 = o[nt][1]*iA;
        float b0 = o[nt][2]*iB, b1 = o[nt][3]*iB;
        unsigned short h0,l0,h1,l1;
        split1(a0,h0,l0); split1(a1,h1,l1);
        *(uint32_t*)(out_hi + rowA + c) = (uint32_t)h0 | ((uint32_t)h1 << 16);
        *(uint32_t*)(out_lo + rowA + c) = (uint32_t)l0 | ((uint32_t)l1 << 16);
        split1(b0,h0,l0); split1(b1,h1,l1);
        *(uint32_t*)(out_hi + rowB + c) = (uint32_t)h0 | ((uint32_t)h1 << 16);
        *(uint32_t*)(out_lo + rowB + c) = (uint32_t)l0 | ((uint32_t)l1 << 16);
    }
}

// ---------------------------------------------------------------------------
// mma.sync cross-attention: 64-query CTA, all 4 key tiles (S=256), window
// mask (seg-128, seg] per row. Same machinery as self-attention.
// ---------------------------------------------------------------------------
__global__ void __launch_bounds__(128, 2)
cross_attn_mma(const __nv_bfloat16* __restrict__ Qh, const __nv_bfloat16* __restrict__ Ql,
               const __nv_bfloat16* __restrict__ Kh, const __nv_bfloat16* __restrict__ Kl,
               const __nv_bfloat16* __restrict__ Vh, const __nv_bfloat16* __restrict__ Vl,
               const int* __restrict__ seg_ids,
               __nv_bfloat16* __restrict__ out_hi, __nv_bfloat16* __restrict__ out_lo) {
    extern __shared__ char smraw[];
    const uint32_t sb = (uint32_t)__cvta_generic_to_shared(smraw);
    const int tid = threadIdx.x, warp = tid >> 5, lane = tid & 31;
    const int h = blockIdx.y, b = blockIdx.z;
    const int qb = (int)blockIdx.x * 64;
    const int ntiles = S_ / 64;      // 4
    const size_t hbQ = ((size_t)(b*H_ + h)) * L_;
    const size_t hbK = ((size_t)(b*H_ + h)) * S_;

    const int rA = qb + warp*16 + (lane >> 2);
    const int segA = seg_ids[b*L_ + rA];
    const int segB = seg_ids[b*L_ + rA + 8];

    #pragma unroll
    for (int i = 0; i < 8; i++) {
        int id = tid + i * 128;
        int arr = id >> 9;
        int rem = id & 511;
        int row = rem >> 3, kc = rem & 7;
        const __nv_bfloat16* p = (arr ? Ql : Qh) + (hbQ + qb + row) * HD_ + kc * 8;
        uint32_t d = sb + (uint32_t)(arr * AT_ARR + row * AT_ROW + kc * 16);
        asm volatile("cp.async.cg.shared.global [%0], [%1], 16;" :: "r"(d), "l"(p) : "memory");
    }
    auto load_kv = [&](int t) {
        uint32_t base = sb + AT_KV0 + (uint32_t)(t & 1) * AT_STG;
        int k0 = t * 64;
        #pragma unroll
        for (int i = 0; i < 16; i++) {
            int id = tid + i * 128;
            int arr = id >> 9;
            int rem = id & 511;
            int row = rem >> 3, kc = rem & 7;
            const __nv_bfloat16* p = (arr==0?Kh:arr==1?Kl:arr==2?Vh:Vl) + (hbK + k0 + row) * HD_ + kc * 8;
            uint32_t d = base + (uint32_t)(arr * AT_ARR + row * AT_ROW + kc * 16);
            asm volatile("cp.async.cg.shared.global [%0], [%1], 16;" :: "r"(d), "l"(p) : "memory");
        }
        asm volatile("cp.async.commit_group;" ::: "memory");
    };
    load_kv(0);
    load_kv(1);

    uint32_t qh[4][4], ql[4][4];
    float o[8][4];
    #pragma unroll
    for (int i = 0; i < 8; i++)
        #pragma unroll
        for (int j = 0; j < 4; j++) o[i][j] = 0.f;
    float mA = -1e30f, mB = -1e30f, lA = 0.f, lB = 0.f;

    for (int t = 0; t < ntiles; t++) {
        if (t + 1 < ntiles) { asm volatile("cp.async.wait_group 1;" ::: "memory"); }
        else                { asm volatile("cp.async.wait_group 0;" ::: "memory"); }
        __syncthreads();
        if (t == 0) {
            #pragma unroll
            for (int ks = 0; ks < 4; ks++) {
                uint32_t a = sb + (uint32_t)((warp*16 + (lane & 15)) * AT_ROW + ks*32 + (lane >> 4) * 16);
                ldsm_x4(qh[ks], a);
                ldsm_x4(ql[ks], a + AT_ARR);
            }
        }
        const uint32_t kvb = sb + AT_KV0 + (uint32_t)(t & 1) * AT_STG;

        float s[8][4];
        #pragma unroll
        for (int i = 0; i < 8; i++)
            #pragma unroll
            for (int j = 0; j < 4; j++) s[i][j] = 0.f;
        #pragma unroll
        for (int ks = 0; ks < 4; ks++) {
            uint32_t kh4[4][4], kl4[4][4];
            #pragma unroll
            for (int ntp = 0; ntp < 4; ntp++) {
                uint32_t a = kvb + (uint32_t)((ntp*16 + (lane & 7) + ((lane >> 4) << 3)) * AT_ROW
                                              + ks*32 + (((lane >> 3) & 1) << 4));
                ldsm_x4(kh4[ntp], a);
                ldsm_x4(kl4[ntp], a + AT_ARR);
            }
            #pragma unroll
            for (int ntp = 0; ntp < 4; ntp++) {
                mma_bf16(s[2*ntp],   qh[ks], kh4[ntp]);
                mma_bf16(s[2*ntp+1], qh[ks], kh4[ntp] + 2);
                mma_bf16(s[2*ntp],   qh[ks], kl4[ntp]);
                mma_bf16(s[2*ntp+1], qh[ks], kl4[ntp] + 2);
                mma_bf16(s[2*ntp],   ql[ks], kh4[ntp]);
                mma_bf16(s[2*ntp+1], ql[ks], kh4[ntp] + 2);
            }
        }
        // window mask: allowed iff c <= seg && c > seg-128
        {
            int cbase = t*64 + 2*(lane & 3);
            #pragma unroll
            for (int nt = 0; nt < 8; nt++) {
                int c0 = cbase + nt*8, c1 = c0 + 1;
                if (c0 > segA || c0 <= segA - 128) s[nt][0] = -1e30f;
                if (c1 > segA || c1 <= segA - 128) s[nt][1] = -1e30f;
                if (c0 > segB || c0 <= segB - 128) s[nt][2] = -1e30f;
                if (c1 > segB || c1 <= segB - 128) s[nt][3] = -1e30f;
            }
        }
        float tmA = -1e30f, tmB = -1e30f;
        #pragma unroll
        for (int nt = 0; nt < 8; nt++) {
            tmA = fmaxf(tmA, fmaxf(s[nt][0], s[nt][1]));
            tmB = fmaxf(tmB, fmaxf(s[nt][2], s[nt][3]));
        }
        tmA = fmaxf(tmA, __shfl_xor_sync(0xffffffffu, tmA, 1));
        tmA = fmaxf(tmA, __shfl_xor_sync(0xffffffffu, tmA, 2));
        tmB = fmaxf(tmB, __shfl_xor_sync(0xffffffffu, tmB, 1));
        tmB = fmaxf(tmB, __shfl_xor_sync(0xffffffffu, tmB, 2));
        float nmA = fmaxf(mA, tmA), nmB = fmaxf(mB, tmB);
        float scA = __expf(mA - nmA), scB = __expf(mB - nmB);
        float tsA = 0.f, tsB = 0.f;
        #pragma unroll
        for (int nt = 0; nt < 8; nt++) {
            s[nt][0] = __expf(s[nt][0] - nmA);
            s[nt][1] = __expf(s[nt][1] - nmA);
            s[nt][2] = __expf(s[nt][2] - nmB);
            s[nt][3] = __expf(s[nt][3] - nmB);
            tsA += s[nt][0] + s[nt][1];
            tsB += s[nt][2] + s[nt][3];
        }
        tsA += __shfl_xor_sync(0xffffffffu, tsA, 1);
        tsA += __shfl_xor_sync(0xffffffffu, tsA, 2);
        tsB += __shfl_xor_sync(0xffffffffu, tsB, 1);
        tsB += __shfl_xor_sync(0xffffffffu, tsB, 2);
        lA = lA * scA + tsA;
        lB = lB * scB + tsB;
        #pragma unroll
        for (int nt = 0; nt < 8; nt++) {
            o[nt][0] *= scA; o[nt][1] *= scA;
            o[nt][2] *= scB; o[nt][3] *= scB;
        }
        mA = nmA; mB = nmB;
        #pragma unroll
        for (int kk = 0; kk < 4; kk++) {
            uint32_t ph[4], pl[4];
            {
                float p0 = s[2*kk][0],   p1 = s[2*kk][1],   p2 = s[2*kk][2],   p3 = s[2*kk][3];
                float p4 = s[2*kk+1][0], p5 = s[2*kk+1][1], p6 = s[2*kk+1][2], p7 = s[2*kk+1][3];
                ph[0] = pack_bf16x2(p0, p1); ph[1] = pack_bf16x2(p2, p3);
                ph[2] = pack_bf16x2(p4, p5); ph[3] = pack_bf16x2(p6, p7);
                pl[0] = pack_bf16x2(p0 - __bfloat162float(__float2bfloat16_rn(p0)),
                                    p1 - __bfloat162float(__float2bfloat16_rn(p1)));
                pl[1] = pack_bf16x2(p2 - __bfloat162float(__float2bfloat16_rn(p2)),
                                    p3 - __bfloat162float(__float2bfloat16_rn(p3)));
                pl[2] = pack_bf16x2(p4 - __bfloat162float(__float2bfloat16_rn(p4)),
                                    p5 - __bfloat162float(__float2bfloat16_rn(p5)));
                pl[3] = pack_bf16x2(p6 - __bfloat162float(__float2bfloat16_rn(p6)),
                                    p7 - __bfloat162float(__float2bfloat16_rn(p7)));
            }
            #pragma unroll
            for (int ntp = 0; ntp < 4; ntp++) {
                uint32_t vh4[4], vl4[4];
                uint32_t a = kvb + 2*AT_ARR + (uint32_t)((kk*16 + (lane & 15)) * AT_ROW
                                                        + ntp*32 + ((lane >> 4) << 4));
                ldsm_x4_t(vh4, a);
                ldsm_x4_t(vl4, a + AT_ARR);
                mma_bf16(o[2*ntp],   ph, vh4);
                mma_bf16(o[2*ntp+1], ph, vh4 + 2);
                mma_bf16(o[2*ntp],   ph, vl4);
                mma_bf16(o[2*ntp+1], ph, vl4 + 2);
                mma_bf16(o[2*ntp],   pl, vh4);
                mma_bf16(o[2*ntp+1], pl, vh4 + 2);
            }
        }
        __syncthreads();
        if (t + 2 < ntiles) load_kv(t + 2);
    }

    float iA = 1.0f / lA, iB = 1.0f / lB;
    size_t rowA = ((size_t)(b*L_ + rA)) * D_;
    size_t rowB = rowA + 8 * D_;
    int cb = h*HD_ + 2*(lane & 3);
    #pragma unroll
    for (int nt = 0; nt < 8; nt++) {
        int c = cb + nt*8;
        float a0 = o[nt][0]*iA, a1 = o[nt][1]*iA;
        float b0 = o[nt][2]*iB, b1 = o[nt][3]*iB;
        unsigned short h0,l0,h1,l1;
        split1(a0,h0,l0); split1(a1,h1,l1);
        *(uint32_t*)(out_hi + rowA + c) = (uint32_t)h0 | ((uint32_t)h1 << 16);
        *(uint32_t*)(out_lo + rowA + c) = (uint32_t)l0 | ((uint32_t)l1 << 16);
        split1(b0,h0,l0); split1(b1,h1,l1);
        *(uint32_t*)(out_hi + rowB + c) = (uint32_t)h0 | ((uint32_t)h1 << 16);
        *(uint32_t*)(out_lo + rowB + c) = (uint32_t)l0 | ((uint32_t)l1 << 16);
    }
}

// ---------------------------------------------------------------------------
// Launch
// ---------------------------------------------------------------------------
static inline void split_launch(const float* src, __nv_bfloat16* hi, __nv_bfloat16* lo, size_t n) {
    int n4 = (int)(n / 4);
    split_k<<<(n4 + 255) / 256, 256>>>(src, hi, lo, n4);
}

extern "C" void kernel_launch(void* const* d_in, const int* in_sizes, int n_in,
                              void* d_out, int out_size) {
    const float* x      = (const float*)d_in[0];
    const float* memory = (const float*)d_in[1];
    const int*   seg    = (const int*)  d_in[2];
    const float* Wqkv   = (const float*)d_in[3];
    const float* bqkv   = (const float*)d_in[4];
    const float* Wo     = (const float*)d_in[5];
    const float* bo     = (const float*)d_in[6];
    const float* Wq_c   = (const float*)d_in[7];
    const float* Wkv_c  = (const float*)d_in[8];
    const float* Wo_c   = (const float*)d_in[9];
    const float* Wg     = (const float*)d_in[10];
    const float* Wu     = (const float*)d_in[11];
    const float* Wd     = (const float*)d_in[12];
    const float* n1     = (const float*)d_in[13];
    const float* n2     = (const float*)d_in[14];
    const float* n3     = (const float*)d_in[15];
    const float* nf     = (const float*)d_in[16];

    cudaFuncSetAttribute(gemm_bf16s<0>, cudaFuncAttributeMaxDynamicSharedMemorySize, GSMEM);
    cudaFuncSetAttribute(gemm_bf16s<1>, cudaFuncAttributeMaxDynamicSharedMemorySize, GSMEM);
    cudaFuncSetAttribute(gemm_bf16s<2>, cudaFuncAttributeMaxDynamicSharedMemorySize, GSMEM);
    cudaFuncSetAttribute(gemm_bf16s<3>, cudaFuncAttributeMaxDynamicSharedMemorySize, GSMEM);
    cudaFuncSetAttribute(gemm_bf16s<4>, cudaFuncAttributeMaxDynamicSharedMemorySize, GSMEM);
    cudaFuncSetAttribute(gemm_bf16s<5>, cudaFuncAttributeMaxDynamicSharedMemorySize, GSMEM);
    cudaFuncSetAttribute(self_attn_mma,  cudaFuncAttributeMaxDynamicSharedMemorySize, AT_SMEM);
    cudaFuncSetAttribute(cross_attn_mma, cudaFuncAttributeMaxDynamicSharedMemorySize, AT_SMEM);

    float *xb, *qkvb;
    __nv_bfloat16 *hhi, *hlo, *ahi, *alo, *chi, *clo, *gshi, *gslo, *mhi, *mlo, *whi, *wlo;
    __nv_bfloat16 *sqh, *sql, *skh, *skl, *svh, *svl;
    cudaGetSymbolAddress((void**)&xb,   g_x);
    cudaGetSymbolAddress((void**)&qkvb, g_qkv);
    cudaGetSymbolAddress((void**)&hhi,  g_h_hi);  cudaGetSymbolAddress((void**)&hlo,  g_h_lo);
    cudaGetSymbolAddress((void**)&ahi,  g_at_hi); cudaGetSymbolAddress((void**)&alo,  g_at_lo);
    cudaGetSymbolAddress((void**)&chi,  g_co_hi); cudaGetSymbolAddress((void**)&clo,  g_co_lo);
    cudaGetSymbolAddress((void**)&gshi, g_gs_hi); cudaGetSymbolAddress((void**)&gslo, g_gs_lo);
    cudaGetSymbolAddress((void**)&mhi,  g_m_hi);  cudaGetSymbolAddress((void**)&mlo,  g_m_lo);
    cudaGetSymbolAddress((void**)&whi,  g_w_hi);  cudaGetSymbolAddress((void**)&wlo,  g_w_lo);
    cudaGetSymbolAddress((void**)&sqh,  g_sqh);   cudaGetSymbolAddress((void**)&sql,  g_sql);
    cudaGetSymbolAddress((void**)&skh,  g_skh);   cudaGetSymbolAddress((void**)&skl,  g_skl);
    cudaGetSymbolAddress((void**)&svh,  g_svh);   cudaGetSymbolAddress((void**)&svl,  g_svl);

    rope_cache_k<<<256, 256>>>();
    copy_x_k<<<(M_*D_)/256, 256>>>(x);

    split_launch(Wqkv,  whi + O_WQKV, wlo + O_WQKV, NL*SZ_WQKV);
    split_launch(Wo,    whi + O_WO,   wlo + O_WO,   NL*SZ_WO);
    split_launch(Wq_c,  whi + O_WQC,  wlo + O_WQC,  NL*SZ_WQC);
    split_launch(Wkv_c, whi + O_WKVC, wlo + O_WKVC, NL*SZ_WKVC);
    split_launch(Wo_c,  whi + O_WOC,  wlo + O_WOC,  NL*SZ_WOC);
    for (int l = 0; l < NL; l++) {
        int n4 = (int)((size_t)F_*D_/4);
        split_ilv_k<<<(n4 + 255)/256, 256>>>(Wg + (size_t)l*F_*D_,
            whi + O_WGU + l*SZ_WGU, wlo + O_WGU + l*SZ_WGU, n4, D_/4, 0);
        split_ilv_k<<<(n4 + 255)/256, 256>>>(Wu + (size_t)l*F_*D_,
            whi + O_WGU + l*SZ_WGU, wlo + O_WGU + l*SZ_WGU, n4, D_/4, 1);
    }
    split_launch(Wd,    whi + O_WD,   wlo + O_WD,   NL*SZ_WD);
    split_launch(memory, mhi, mlo, (size_t)B_*S_*D_);

    const dim3 self_grid(L_/64, H_, B_);
    const dim3 cross_grid(L_/64, H_, B_);

    for (int l = 0; l < NL; l++) {
        const __nv_bfloat16* wqkv_h = whi + O_WQKV + l*SZ_WQKV;
        const __nv_bfloat16* wqkv_l = wlo + O_WQKV + l*SZ_WQKV;
        const __nv_bfloat16* wo_h   = whi + O_WO   + l*SZ_WO;
        const __nv_bfloat16* wo_l   = wlo + O_WO   + l*SZ_WO;
        const __nv_bfloat16* wqc_h  = whi + O_WQC  + l*SZ_WQC;
        const __nv_bfloat16* wqc_l  = wlo + O_WQC  + l*SZ_WQC;
        const __nv_bfloat16* wkvc_h = whi + O_WKVC + l*SZ_WKVC;
        const __nv_bfloat16* wkvc_l = wlo + O_WKVC + l*SZ_WKVC;
        const __nv_bfloat16* woc_h  = whi + O_WOC  + l*SZ_WOC;
        const __nv_bfloat16* woc_l  = wlo + O_WOC  + l*SZ_WOC;
        const __nv_bfloat16* wgu_h  = whi + O_WGU  + l*SZ_WGU;
        const __nv_bfloat16* wgu_l  = wlo + O_WGU  + l*SZ_WGU;
        const __nv_bfloat16* wd_h   = whi + O_WD   + l*SZ_WD;
        const __nv_bfloat16* wd_l   = wlo + O_WD   + l*SZ_WD;

        // --- self attention block ---
        rmsnorm_split_k<<<M_, 256>>>(xb, n1 + l*D_, hhi, hlo);
        gemm_bf16s<0><<<dim3(3*D_/128, M_/128), 256, GSMEM>>>(
            hhi, hlo, wqkv_h, wqkv_l, bqkv + l*3*D_, qkvb,
            nullptr, nullptr, nullptr, nullptr, 3*D_, D_);
        rope_split_k<<<M_, 512>>>(qkvb);
        self_attn_mma<<<self_grid, 128, AT_SMEM>>>(sqh, sql, skh, skl, svh, svl, ahi, alo);
        gemm_bf16s<1><<<dim3(D_/128, M_/128), 256, GSMEM>>>(
            ahi, alo, wo_h, wo_l, bo + l*D_, xb,
            nullptr, nullptr, nullptr, nullptr, D_, D_);

        // --- cross attention block ---
        rmsnorm_split_k<<<M_, 256>>>(xb, n2 + l*D_, hhi, hlo);
        gemm_bf16s<4><<<dim3(D_/128, M_/128), 256, GSMEM>>>(
            hhi, hlo, wqc_h, wqc_l, nullptr, nullptr,
            sqh, sql, nullptr, nullptr, D_, D_);
        gemm_bf16s<5><<<dim3(2*D_/128, (B_*S_)/128), 256, GSMEM>>>(
            mhi, mlo, wkvc_h, wkvc_l, nullptr, nullptr,
            skh, skl, svh, svl, 2*D_, D_);
        cross_attn_mma<<<cross_grid, 128, AT_SMEM>>>(sqh, sql, skh, skl, svh, svl, seg, chi, clo);
        gemm_bf16s<2><<<dim3(D_/128, M_/128), 256, GSMEM>>>(
            chi, clo, woc_h, woc_l, nullptr, xb,
            nullptr, nullptr, nullptr, nullptr, D_, D_);

        // --- MLP block (fused gate|up GEMM with swiglu epilogue) ---
        rmsnorm_split_k<<<M_, 256>>>(xb, n3 + l*D_, hhi, hlo);
        gemm_bf16s<3><<<dim3(2*F_/128, M_/128), 256, GSMEM>>>(
            hhi, hlo, wgu_h, wgu_l, nullptr, nullptr,
            gshi, gslo, nullptr, nullptr, 2*F_, D_);
        gemm_bf16s<2><<<dim3(D_/128, M_/128), 256, GSMEM>>>(
            gshi, gslo, wd_h, wd_l, nullptr, xb,
            nullptr, nullptr, nullptr, nullptr, D_, F_);
    }

    rmsnorm_k<<<M_, 256>>>(xb, nf, (float*)d_out);
}

// round 8
// speedup vs baseline: 4.5140x; 1.0652x over previous
#include <cuda_runtime.h>
#include <cuda_bf16.h>
#include <math.h>
#include <stdint.h>

// Problem constants
#define NL 4
#define B_ 2
#define L_ 2048
#define S_ 256
#define D_ 1024
#define F_ 4096
#define H_ 16
#define HD_ 64
#define M_ (B_*L_)          // 4096 token rows

// Weight region sizes (elements) and offsets in the concatenated split buffer
#define SZ_WQKV ((size_t)3*D_*D_)
#define SZ_WO   ((size_t)D_*D_)
#define SZ_WQC  ((size_t)D_*D_)
#define SZ_WKVC ((size_t)2*D_*D_)
#define SZ_WOC  ((size_t)D_*D_)
#define SZ_WGU  ((size_t)2*F_*D_)     // interleaved [g0,u0,g1,u1,...] per layer
#define SZ_WD   ((size_t)D_*F_)
static const size_t O_WQKV = 0;
static const size_t O_WO   = O_WQKV + NL*SZ_WQKV;
static const size_t O_WQC  = O_WO   + NL*SZ_WO;
static const size_t O_WKVC = O_WQC  + NL*SZ_WQC;
static const size_t O_WOC  = O_WKVC + NL*SZ_WKVC;
static const size_t O_WGU  = O_WOC  + NL*SZ_WOC;
static const size_t O_WD   = O_WGU  + NL*SZ_WGU;
#define WTOT (O_WD + NL*SZ_WD)

// ---------------------------------------------------------------------------
// Scratch (device globals; no allocations allowed)
// ---------------------------------------------------------------------------
__device__ float g_x  [M_*D_];
__device__ float g_qkv[M_*3*D_];
__device__ float g_cos[L_*32];
__device__ float g_sin[L_*32];

__device__ __nv_bfloat16 g_h_hi [M_*D_],  g_h_lo [M_*D_];
__device__ __nv_bfloat16 g_at_hi[M_*D_],  g_at_lo[M_*D_];
__device__ __nv_bfloat16 g_co_hi[M_*D_],  g_co_lo[M_*D_];
__device__ __nv_bfloat16 g_gs_hi[M_*F_],  g_gs_lo[M_*F_];
__device__ __nv_bfloat16 g_m_hi [B_*S_*D_], g_m_lo[B_*S_*D_];
__device__ __nv_bfloat16 g_w_hi[WTOT], g_w_lo[WTOT];

// attention-layout split buffers: [B][H][L][64] (self q/k/v, cross reuses)
#define ATN ((size_t)B_*H_*L_*HD_)
__device__ __nv_bfloat16 g_sqh[ATN], g_sql[ATN];
__device__ __nv_bfloat16 g_skh[ATN], g_skl[ATN];
__device__ __nv_bfloat16 g_svh[ATN], g_svl[ATN];

// ---------------------------------------------------------------------------
// bf16 split helpers
// ---------------------------------------------------------------------------
__device__ __forceinline__ void split1(float v, unsigned short& h, unsigned short& l) {
    __nv_bfloat16 hb = __float2bfloat16_rn(v);
    float r = v - __bfloat162float(hb);
    __nv_bfloat16 lb = __float2bfloat16_rn(r);
    h = __bfloat16_as_ushort(hb);
    l = __bfloat16_as_ushort(lb);
}
__device__ __forceinline__ void split_pack4(float4 v, uint2& ph, uint2& pl) {
    unsigned short h0,h1,h2,h3,l0,l1,l2,l3;
    split1(v.x,h0,l0); split1(v.y,h1,l1); split1(v.z,h2,l2); split1(v.w,h3,l3);
    ph.x = (uint32_t)h0 | ((uint32_t)h1 << 16);
    ph.y = (uint32_t)h2 | ((uint32_t)h3 << 16);
    pl.x = (uint32_t)l0 | ((uint32_t)l1 << 16);
    pl.y = (uint32_t)l2 | ((uint32_t)l3 << 16);
}

__global__ void split_k(const float* __restrict__ in, __nv_bfloat16* __restrict__ hi,
                        __nv_bfloat16* __restrict__ lo, int n4) {
    int i = blockIdx.x * blockDim.x + threadIdx.x;
    if (i >= n4) return;
    float4 v = ((const float4*)in)[i];
    uint2 ph, pl; split_pack4(v, ph, pl);
    ((uint2*)hi)[i] = ph;
    ((uint2*)lo)[i] = pl;
}

// Interleaving split: source row r -> destination row 2r+off (rowQuads float4s per row)
__global__ void split_ilv_k(const float* __restrict__ in, __nv_bfloat16* __restrict__ hi,
                            __nv_bfloat16* __restrict__ lo, int n4, int rowQuads, int off) {
    int i = blockIdx.x * blockDim.x + threadIdx.x;
    if (i >= n4) return;
    int r = i / rowQuads, c = i % rowQuads;
    float4 v = ((const float4*)in)[i];
    uint2 ph, pl; split_pack4(v, ph, pl);
    size_t oi = (size_t)(2*r + off) * rowQuads + c;
    ((uint2*)hi)[oi] = ph;
    ((uint2*)lo)[oi] = pl;
}

// ---------------------------------------------------------------------------
// RoPE cache
// ---------------------------------------------------------------------------
__global__ void rope_cache_k() {
    int idx = blockIdx.x * blockDim.x + threadIdx.x;
    int l = idx >> 5, i = idx & 31;
    double inv = exp(-log(10000.0) * (double)i / 32.0);
    double f = (double)l * inv;
    g_cos[idx] = (float)cos(f);
    g_sin[idx] = (float)sin(f);
}

__global__ void copy_x_k(const float* __restrict__ x) {
    size_t i = (size_t)blockIdx.x * blockDim.x + threadIdx.x;
    if (i < (size_t)M_ * D_) g_x[i] = x[i];
}

// ---------------------------------------------------------------------------
// RMSNorm kernels
// ---------------------------------------------------------------------------
__global__ void rmsnorm_split_k(const float* __restrict__ x, const float* __restrict__ w,
                                __nv_bfloat16* __restrict__ hi, __nv_bfloat16* __restrict__ lo) {
    int row = blockIdx.x;
    int t = threadIdx.x;
    const float4* xr = (const float4*)(x + (size_t)row * D_);
    float4 v = xr[t];
    float ss = v.x*v.x + v.y*v.y + v.z*v.z + v.w*v.w;
    #pragma unroll
    for (int off = 16; off; off >>= 1) ss += __shfl_xor_sync(0xffffffffu, ss, off);
    __shared__ float red[8];
    if ((t & 31) == 0) red[t >> 5] = ss;
    __syncthreads();
    float tot = red[0]+red[1]+red[2]+red[3]+red[4]+red[5]+red[6]+red[7];
    float rs = rsqrtf(tot * (1.0f / (float)D_) + 1e-6f);
    float4 wv = ((const float4*)w)[t];
    float4 o;
    o.x = v.x * rs * wv.x; o.y = v.y * rs * wv.y;
    o.z = v.z * rs * wv.z; o.w = v.w * rs * wv.w;
    uint2 ph, pl; split_pack4(o, ph, pl);
    ((uint2*)hi)[(size_t)row * 256 + t] = ph;
    ((uint2*)lo)[(size_t)row * 256 + t] = pl;
}

__global__ void rmsnorm_k(const float* __restrict__ x, const float* __restrict__ w,
                          float* __restrict__ o) {
    int row = blockIdx.x;
    int t = threadIdx.x;
    const float4* xr = (const float4*)(x + (size_t)row * D_);
    float4 v = xr[t];
    float ss = v.x*v.x + v.y*v.y + v.z*v.z + v.w*v.w;
    #pragma unroll
    for (int off = 16; off; off >>= 1) ss += __shfl_xor_sync(0xffffffffu, ss, off);
    __shared__ float red[8];
    if ((t & 31) == 0) red[t >> 5] = ss;
    __syncthreads();
    float tot = red[0]+red[1]+red[2]+red[3]+red[4]+red[5]+red[6]+red[7];
    float rs = rsqrtf(tot * (1.0f / (float)D_) + 1e-6f);
    float4 wv = ((const float4*)w)[t];
    float4 out;
    out.x = v.x * rs * wv.x; out.y = v.y * rs * wv.y;
    out.z = v.z * rs * wv.z; out.w = v.w * rs * wv.w;
    ((float4*)(o + (size_t)row * D_))[t] = out;
}

// ---------------------------------------------------------------------------
// mma / ldmatrix helpers
// ---------------------------------------------------------------------------
__device__ __forceinline__ void mma_bf16(float* c, const uint32_t* a, const uint32_t* b) {
    asm volatile(
        "mma.sync.aligned.m16n8k16.row.col.f32.bf16.bf16.f32 "
        "{%0,%1,%2,%3}, {%4,%5,%6,%7}, {%8,%9}, {%0,%1,%2,%3};"
        : "+f"(c[0]), "+f"(c[1]), "+f"(c[2]), "+f"(c[3])
        : "r"(a[0]), "r"(a[1]), "r"(a[2]), "r"(a[3]), "r"(b[0]), "r"(b[1]));
}
__device__ __forceinline__ void ldsm_x4(uint32_t* r, uint32_t addr) {
    asm volatile("ldmatrix.sync.aligned.m8n8.x4.shared.b16 {%0,%1,%2,%3}, [%4];"
        : "=r"(r[0]), "=r"(r[1]), "=r"(r[2]), "=r"(r[3]) : "r"(addr));
}
__device__ __forceinline__ void ldsm_x4_t(uint32_t* r, uint32_t addr) {
    asm volatile("ldmatrix.sync.aligned.m8n8.x4.trans.shared.b16 {%0,%1,%2,%3}, [%4];"
        : "=r"(r[0]), "=r"(r[1]), "=r"(r[2]), "=r"(r[3]) : "r"(addr));
}
__device__ __forceinline__ uint32_t pack_bf16x2(float lo, float hi) {
    return (uint32_t)__bfloat16_as_ushort(__float2bfloat16_rn(lo)) |
           ((uint32_t)__bfloat16_as_ushort(__float2bfloat16_rn(hi)) << 16);
}

// ---------------------------------------------------------------------------
// bf16 split-3 GEMM (NT), 256x128 CTA tile, warp tile 64x64 (8 warps, 4x2).
// Per k16 step: 8 A-ldsm_x4 + 8 B-ldsm_x4 feed 96 HMMA (1:6 aux:mma ratio).
// MODE 0: +bias              -> fp32 C      (QKV)
// MODE 1: +bias +residual    -> fp32 C      (Wo)
// MODE 2: +residual          -> fp32 C      (Wo_c, Wd)
// MODE 3: swiglu (interleaved g|u cols) -> bf16 hi/lo [M][F]
// MODE 4: attn-q layout, x0.125         -> bf16 hi/lo [B][H][L][64]
// MODE 5: attn-kv layout (k|v)          -> bf16 hi/lo [B][H][S][64] x2
// Smem per stage: Ah(20480)|Al(20480)|Bh(10240)|Bl(10240) = 61440B, 3 stages.
// ---------------------------------------------------------------------------
#define G2STAGE 61440
#define G2_AL   20480
#define G2_B0   40960
#define G2_B1   51200
#define GSMEM   (3*G2STAGE)

template <int MODE>
__global__ void __launch_bounds__(256, 1)
gemm_bf16s(const __nv_bfloat16* __restrict__ Ah, const __nv_bfloat16* __restrict__ Al,
           const __nv_bfloat16* __restrict__ Wh, const __nv_bfloat16* __restrict__ Wl,
           const float* __restrict__ bias, float* __restrict__ C,
           __nv_bfloat16* __restrict__ o1h, __nv_bfloat16* __restrict__ o1l,
           __nv_bfloat16* __restrict__ o2h, __nv_bfloat16* __restrict__ o2l,
           int N, int K) {
    extern __shared__ char smem[];
    const uint32_t sbase = (uint32_t)__cvta_generic_to_shared(smem);
    const int tid  = threadIdx.x;
    const int warp = tid >> 5, lane = tid & 31;
    const int wr = warp >> 1;      // 0..3 : 64-row slab
    const int wc = warp & 1;       // 0..1 : 64-col slab
    const int g  = lane >> 2;
    const int t  = lane & 3;
    const int bm = blockIdx.y, bn = blockIdx.x;

    // cp.async chunk tables: 3072 16B-chunks per stage, 12 per thread
    const __nv_bfloat16* src[12];
    uint32_t dst[12];
    #pragma unroll
    for (int i = 0; i < 12; i++) {
        int id = tid + (i << 8);
        const __nv_bfloat16* bp;
        int grow; uint32_t off; int kc;
        if (id < 2048) {                       // A region: 2 arrays x 256 rows x 4 chunks
            int arr = id >> 10, rem = id & 1023;
            int row = rem >> 2; kc = rem & 3;
            bp = arr ? Al : Ah;
            grow = bm * 256 + row;
            off = (uint32_t)(arr * G2_AL + row * 80 + kc * 16);
        } else {                               // B region: 2 arrays x 128 rows x 4 chunks
            int id2 = id - 2048;
            int arr = id2 >> 9, rem = id2 & 511;
            int row = rem >> 2; kc = rem & 3;
            bp = arr ? Wl : Wh;
            grow = bn * 128 + row;
            off = (uint32_t)(G2_B0 + arr * 10240 + row * 80 + kc * 16);
        }
        src[i] = bp + (size_t)grow * K + kc * 8;
        dst[i] = off;
    }

    // ldmatrix base offsets
    const uint32_t arow = (uint32_t)((wr * 64 + (lane & 15)) * 80 + (lane >> 4) * 16);
    const uint32_t brow = (uint32_t)((wc * 64 + (lane & 7) + ((lane >> 4) << 3)) * 80
                                     + (((lane >> 3) & 1) << 4));

    float acc[4][8][4];
    #pragma unroll
    for (int i = 0; i < 4; i++)
        #pragma unroll
        for (int j = 0; j < 8; j++)
            #pragma unroll
            for (int r = 0; r < 4; r++) acc[i][j][r] = 0.f;

    const int nk = K >> 5;

    #pragma unroll
    for (int st = 0; st < 2; st++) {
        uint32_t s = sbase + st * G2STAGE;
        #pragma unroll
        for (int i = 0; i < 12; i++) {
            const void* p = src[i] + st * 32;
            asm volatile("cp.async.cg.shared.global [%0], [%1], 16;"
                         :: "r"(s + dst[i]), "l"(p) : "memory");
        }
        asm volatile("cp.async.commit_group;" ::: "memory");
    }

    for (int it = 0; it < nk; it++) {
        asm volatile("cp.async.wait_group 1;" ::: "memory");
        __syncthreads();
        uint32_t s = sbase + (uint32_t)(it % 3) * G2STAGE;

        #pragma unroll
        for (int ks = 0; ks < 2; ks++) {
            const uint32_t ko = ks * 32;
            uint32_t af[16], bh[16], bl[16];
            #pragma unroll
            for (int mt = 0; mt < 4; mt++) ldsm_x4(af + 4*mt, s + arow + mt*1280 + ko);
            #pragma unroll
            for (int p = 0; p < 4; p++) ldsm_x4(bh + 4*p, s + G2_B0 + brow + p*1280 + ko);
            #pragma unroll
            for (int p = 0; p < 4; p++) ldsm_x4(bl + 4*p, s + G2_B1 + brow + p*1280 + ko);
            #pragma unroll
            for (int mt = 0; mt < 4; mt++)
                #pragma unroll
                for (int nt = 0; nt < 8; nt++) mma_bf16(acc[mt][nt], af + 4*mt, bh + 2*nt);
            #pragma unroll
            for (int mt = 0; mt < 4; mt++)
                #pragma unroll
                for (int nt = 0; nt < 8; nt++) mma_bf16(acc[mt][nt], af + 4*mt, bl + 2*nt);
            #pragma unroll
            for (int mt = 0; mt < 4; mt++) ldsm_x4(af + 4*mt, s + G2_AL + arow + mt*1280 + ko);
            #pragma unroll
            for (int mt = 0; mt < 4; mt++)
                #pragma unroll
                for (int nt = 0; nt < 8; nt++) mma_bf16(acc[mt][nt], af + 4*mt, bh + 2*nt);
        }

        if (it + 2 < nk) {
            uint32_t s2 = sbase + (uint32_t)((it + 2) % 3) * G2STAGE;
            int k0 = (it + 2) * 32;
            #pragma unroll
            for (int i = 0; i < 12; i++) {
                const void* p = src[i] + k0;
                asm volatile("cp.async.cg.shared.global [%0], [%1], 16;"
                             :: "r"(s2 + dst[i]), "l"(p) : "memory");
            }
        }
        asm volatile("cp.async.commit_group;" ::: "memory");
    }

    #pragma unroll
    for (int mt = 0; mt < 4; mt++) {
        #pragma unroll
        for (int half = 0; half < 2; half++) {
            int row = bm * 256 + wr * 64 + mt * 16 + g + half * 8;
            #pragma unroll
            for (int nt = 0; nt < 8; nt++) {
                int col = bn * 128 + wc * 64 + nt * 8 + 2 * t;
                float c0 = acc[mt][nt][half * 2 + 0];
                float c1 = acc[mt][nt][half * 2 + 1];
                if (MODE <= 2) {
                    float* dstp = C + (size_t)row * N + col;
                    if (MODE == 0 || MODE == 1) { c0 += bias[col]; c1 += bias[col + 1]; }
                    if (MODE == 1 || MODE == 2) {
                        float2 r = *(const float2*)dstp;
                        c0 += r.x; c1 += r.y;
                    }
                    *(float2*)dstp = make_float2(c0, c1);
                } else if (MODE == 3) {
                    float sg = c0 / (1.0f + expf(-c0)) * c1;
                    unsigned short hh, ll; split1(sg, hh, ll);
                    size_t oi = (size_t)row * F_ + (col >> 1);
                    o1h[oi] = __ushort_as_bfloat16(hh);
                    o1l[oi] = __ushort_as_bfloat16(ll);
                } else if (MODE == 4) {
                    int b = row >> 11, ltok = row & (L_ - 1);
                    int hd = col >> 6, d = col & 63;
                    size_t oi = (((size_t)(b*H_ + hd)) * L_ + ltok) * HD_ + d;
                    unsigned short h0, l0, h1, l1;
                    split1(c0 * 0.125f, h0, l0); split1(c1 * 0.125f, h1, l1);
                    *(uint32_t*)(o1h + oi) = (uint32_t)h0 | ((uint32_t)h1 << 16);
                    *(uint32_t*)(o1l + oi) = (uint32_t)l0 | ((uint32_t)l1 << 16);
                } else { // MODE 5
                    int b = row >> 8, stok = row & (S_ - 1);
                    int hd = (col >> 6) & 15, d = col & 63;
                    size_t oi = (((size_t)(b*H_ + hd)) * S_ + stok) * HD_ + d;
                    unsigned short h0, l0, h1, l1;
                    split1(c0, h0, l0); split1(c1, h1, l1);
                    __nv_bfloat16* ph = (col < 1024) ? o1h : o2h;
                    __nv_bfloat16* pl = (col < 1024) ? o1l : o2l;
                    *(uint32_t*)(ph + oi) = (uint32_t)h0 | ((uint32_t)h1 << 16);
                    *(uint32_t*)(pl + oi) = (uint32_t)l0 | ((uint32_t)l1 << 16);
                }
            }
        }
    }
}

// ---------------------------------------------------------------------------
// RoPE + bf16 hi/lo split of q,k,v into attention layout [B][H][L][64].
// ---------------------------------------------------------------------------
__global__ void rope_split_k(const float* __restrict__ qkv) {
    int bl = blockIdx.x;
    int b = bl >> 11, l = bl & (L_ - 1);
    int hh = threadIdx.x >> 5;
    int i  = threadIdx.x & 31;
    float c = g_cos[l*32 + i];
    float s = g_sin[l*32 + i];
    const float* base = qkv + (size_t)bl * (3*D_) + hh * HD_;
    size_t orow = (((size_t)(b*H_ + hh)) * L_ + l) * HD_;
    unsigned short vh, vl;
    float x1 = base[i], x2 = base[i+32];
    float q1 = (x1*c - x2*s) * 0.125f;
    float q2 = (x2*c + x1*s) * 0.125f;
    split1(q1, vh, vl); g_sqh[orow+i]    = __ushort_as_bfloat16(vh); g_sql[orow+i]    = __ushort_as_bfloat16(vl);
    split1(q2, vh, vl); g_sqh[orow+i+32] = __ushort_as_bfloat16(vh); g_sql[orow+i+32] = __ushort_as_bfloat16(vl);
    x1 = base[D_+i]; x2 = base[D_+i+32];
    float k1 = x1*c - x2*s;
    float k2 = x2*c + x1*s;
    split1(k1, vh, vl); g_skh[orow+i]    = __ushort_as_bfloat16(vh); g_skl[orow+i]    = __ushort_as_bfloat16(vl);
    split1(k2, vh, vl); g_skh[orow+i+32] = __ushort_as_bfloat16(vh); g_skl[orow+i+32] = __ushort_as_bfloat16(vl);
    split1(base[2*D_+i],    vh, vl); g_svh[orow+i]    = __ushort_as_bfloat16(vh); g_svl[orow+i]    = __ushort_as_bfloat16(vl);
    split1(base[2*D_+i+32], vh, vl); g_svh[orow+i+32] = __ushort_as_bfloat16(vh); g_svl[orow+i+32] = __ushort_as_bfloat16(vl);
}

// ---------------------------------------------------------------------------
// mma.sync flash self-attention.
// ---------------------------------------------------------------------------
#define AT_ROW  144
#define AT_ARR  (64*AT_ROW)
#define AT_KV0  (2*AT_ARR)
#define AT_STG  (4*AT_ARR)
#define AT_SMEM (2*AT_ARR + 2*AT_STG)

__global__ void __launch_bounds__(128, 2)
self_attn_mma(const __nv_bfloat16* __restrict__ Qh, const __nv_bfloat16* __restrict__ Ql,
              const __nv_bfloat16* __restrict__ Kh, const __nv_bfloat16* __restrict__ Kl,
              const __nv_bfloat16* __restrict__ Vh, const __nv_bfloat16* __restrict__ Vl,
              __nv_bfloat16* __restrict__ out_hi, __nv_bfloat16* __restrict__ out_lo) {
    extern __shared__ char smraw[];
    const uint32_t sb = (uint32_t)__cvta_generic_to_shared(smraw);
    const int tid = threadIdx.x, warp = tid >> 5, lane = tid & 31;
    const int h = blockIdx.y, b = blockIdx.z;
    const int qbi = (int)(gridDim.x - 1 - blockIdx.x);
    const int qb = qbi * 64;
    const int ntiles = qbi + 1;
    const size_t hb = ((size_t)(b*H_ + h)) * L_;

    #pragma unroll
    for (int i = 0; i < 8; i++) {
        int id = tid + i * 128;
        int arr = id >> 9;
        int rem = id & 511;
        int row = rem >> 3, kc = rem & 7;
        const __nv_bfloat16* p = (arr ? Ql : Qh) + (hb + qb + row) * HD_ + kc * 8;
        uint32_t d = sb + (uint32_t)(arr * AT_ARR + row * AT_ROW + kc * 16);
        asm volatile("cp.async.cg.shared.global [%0], [%1], 16;" :: "r"(d), "l"(p) : "memory");
    }
    auto load_kv = [&](int t) {
        uint32_t base = sb + AT_KV0 + (uint32_t)(t & 1) * AT_STG;
        int k0 = t * 64;
        #pragma unroll
        for (int i = 0; i < 16; i++) {
            int id = tid + i * 128;
            int arr = id >> 9;
            int rem = id & 511;
            int row = rem >> 3, kc = rem & 7;
            const __nv_bfloat16* p = (arr==0?Kh:arr==1?Kl:arr==2?Vh:Vl) + (hb + k0 + row) * HD_ + kc * 8;
            uint32_t d = base + (uint32_t)(arr * AT_ARR + row * AT_ROW + kc * 16);
            asm volatile("cp.async.cg.shared.global [%0], [%1], 16;" :: "r"(d), "l"(p) : "memory");
        }
        asm volatile("cp.async.commit_group;" ::: "memory");
    };
    load_kv(0);
    if (ntiles > 1) load_kv(1);

    uint32_t qh[4][4], ql[4][4];
    float o[8][4];
    #pragma unroll
    for (int i = 0; i < 8; i++)
        #pragma unroll
        for (int j = 0; j < 4; j++) o[i][j] = 0.f;
    float mA = -1e30f, mB = -1e30f, lA = 0.f, lB = 0.f;

    for (int t = 0; t < ntiles; t++) {
        if (t + 1 < ntiles) { asm volatile("cp.async.wait_group 1;" ::: "memory"); }
        else                { asm volatile("cp.async.wait_group 0;" ::: "memory"); }
        __syncthreads();
        if (t == 0) {
            #pragma unroll
            for (int ks = 0; ks < 4; ks++) {
                uint32_t a = sb + (uint32_t)((warp*16 + (lane & 15)) * AT_ROW + ks*32 + (lane >> 4) * 16);
                ldsm_x4(qh[ks], a);
                ldsm_x4(ql[ks], a + AT_ARR);
            }
        }
        const uint32_t kvb = sb + AT_KV0 + (uint32_t)(t & 1) * AT_STG;

        float s[8][4];
        #pragma unroll
        for (int i = 0; i < 8; i++)
            #pragma unroll
            for (int j = 0; j < 4; j++) s[i][j] = 0.f;
        #pragma unroll
        for (int ks = 0; ks < 4; ks++) {
            uint32_t kh4[4][4], kl4[4][4];
            #pragma unroll
            for (int ntp = 0; ntp < 4; ntp++) {
                uint32_t a = kvb + (uint32_t)((ntp*16 + (lane & 7) + ((lane >> 4) << 3)) * AT_ROW
                                              + ks*32 + (((lane >> 3) & 1) << 4));
                ldsm_x4(kh4[ntp], a);
                ldsm_x4(kl4[ntp], a + AT_ARR);
            }
            #pragma unroll
            for (int ntp = 0; ntp < 4; ntp++) {
                mma_bf16(s[2*ntp],   qh[ks], kh4[ntp]);
                mma_bf16(s[2*ntp+1], qh[ks], kh4[ntp] + 2);
                mma_bf16(s[2*ntp],   qh[ks], kl4[ntp]);
                mma_bf16(s[2*ntp+1], qh[ks], kl4[ntp] + 2);
                mma_bf16(s[2*ntp],   ql[ks], kh4[ntp]);
                mma_bf16(s[2*ntp+1], ql[ks], kh4[ntp] + 2);
            }
        }
        if (t == ntiles - 1) {
            int rA = qb + warp*16 + (lane >> 2);
            int cbase = t*64 + 2*(lane & 3);
            #pragma unroll
            for (int nt = 0; nt < 8; nt++) {
                int c0 = cbase + nt*8, c1 = c0 + 1;
                if (c0 > rA)     s[nt][0] = -1e30f;
                if (c1 > rA)     s[nt][1] = -1e30f;
                if (c0 > rA + 8) s[nt][2] = -1e30f;
                if (c1 > rA + 8) s[nt][3] = -1e30f;
            }
        }
        float tmA = -1e30f, tmB = -1e30f;
        #pragma unroll
        for (int nt = 0; nt < 8; nt++) {
            tmA = fmaxf(tmA, fmaxf(s[nt][0], s[nt][1]));
            tmB = fmaxf(tmB, fmaxf(s[nt][2], s[nt][3]));
        }
        tmA = fmaxf(tmA, __shfl_xor_sync(0xffffffffu, tmA, 1));
        tmA = fmaxf(tmA, __shfl_xor_sync(0xffffffffu, tmA, 2));
        tmB = fmaxf(tmB, __shfl_xor_sync(0xffffffffu, tmB, 1));
        tmB = fmaxf(tmB, __shfl_xor_sync(0xffffffffu, tmB, 2));
        float nmA = fmaxf(mA, tmA), nmB = fmaxf(mB, tmB);
        float scA = __expf(mA - nmA), scB = __expf(mB - nmB);
        float tsA = 0.f, tsB = 0.f;
        #pragma unroll
        for (int nt = 0; nt < 8; nt++) {
            s[nt][0] = __expf(s[nt][0] - nmA);
            s[nt][1] = __expf(s[nt][1] - nmA);
            s[nt][2] = __expf(s[nt][2] - nmB);
            s[nt][3] = __expf(s[nt][3] - nmB);
            tsA += s[nt][0] + s[nt][1];
            tsB += s[nt][2] + s[nt][3];
        }
        tsA += __shfl_xor_sync(0xffffffffu, tsA, 1);
        tsA += __shfl_xor_sync(0xffffffffu, tsA, 2);
        tsB += __shfl_xor_sync(0xffffffffu, tsB, 1);
        tsB += __shfl_xor_sync(0xffffffffu, tsB, 2);
        lA = lA * scA + tsA;
        lB = lB * scB + tsB;
        #pragma unroll
        for (int nt = 0; nt < 8; nt++) {
            o[nt][0] *= scA; o[nt][1] *= scA;
            o[nt][2] *= scB; o[nt][3] *= scB;
        }
        mA = nmA; mB = nmB;
        #pragma unroll
        for (int kk = 0; kk < 4; kk++) {
            uint32_t ph[4], pl[4];
            {
                float p0 = s[2*kk][0],   p1 = s[2*kk][1],   p2 = s[2*kk][2],   p3 = s[2*kk][3];
                float p4 = s[2*kk+1][0], p5 = s[2*kk+1][1], p6 = s[2*kk+1][2], p7 = s[2*kk+1][3];
                ph[0] = pack_bf16x2(p0, p1); ph[1] = pack_bf16x2(p2, p3);
                ph[2] = pack_bf16x2(p4, p5); ph[3] = pack_bf16x2(p6, p7);
                pl[0] = pack_bf16x2(p0 - __bfloat162float(__float2bfloat16_rn(p0)),
                                    p1 - __bfloat162float(__float2bfloat16_rn(p1)));
                pl[1] = pack_bf16x2(p2 - __bfloat162float(__float2bfloat16_rn(p2)),
                                    p3 - __bfloat162float(__float2bfloat16_rn(p3)));
                pl[2] = pack_bf16x2(p4 - __bfloat162float(__float2bfloat16_rn(p4)),
                                    p5 - __bfloat162float(__float2bfloat16_rn(p5)));
                pl[3] = pack_bf16x2(p6 - __bfloat162float(__float2bfloat16_rn(p6)),
                                    p7 - __bfloat162float(__float2bfloat16_rn(p7)));
            }
            #pragma unroll
            for (int ntp = 0; ntp < 4; ntp++) {
                uint32_t vh4[4], vl4[4];
                uint32_t a = kvb + 2*AT_ARR + (uint32_t)((kk*16 + (lane & 15)) * AT_ROW
                                                        + ntp*32 + ((lane >> 4) << 4));
                ldsm_x4_t(vh4, a);
                ldsm_x4_t(vl4, a + AT_ARR);
                mma_bf16(o[2*ntp],   ph, vh4);
                mma_bf16(o[2*ntp+1], ph, vh4 + 2);
                mma_bf16(o[2*ntp],   ph, vl4);
                mma_bf16(o[2*ntp+1], ph, vl4 + 2);
                mma_bf16(o[2*ntp],   pl, vh4);
                mma_bf16(o[2*ntp+1], pl, vh4 + 2);
            }
        }
        __syncthreads();
        if (t + 2 < ntiles) load_kv(t + 2);
    }

    float iA = 1.0f / lA, iB = 1.0f / lB;
    int qA = qb + warp*16 + (lane >> 2);
    size_t rowA = ((size_t)(b*L_ + qA)) * D_;
    size_t rowB = rowA + 8 * D_;
    int cb = h*HD_ + 2*(lane & 3);
    #pragma unroll
    for (int nt = 0; nt < 8; nt++) {
        int c = cb + nt*8;
        float a0 = o[nt][0]*iA, a1 = o[nt][1]*iA;
        float b0 = o[nt][2]*iB, b1 = o[nt][3]*iB;
        unsigned short h0,l0,h1,l1;
        split1(a0,h0,l0); split1(a1,h1,l1);
        *(uint32_t*)(out_hi + rowA + c) = (uint32_t)h0 | ((uint32_t)h1 << 16);
        *(uint32_t*)(out_lo + rowA + c) = (uint32_t)l0 | ((uint32_t)l1 << 16);
        split1(b0,h0,l0); split1(b1,h1,l1);
        *(uint32_t*)(out_hi + rowB + c) = (uint32_t)h0 | ((uint32_t)h1 << 16);
        *(uint32_t*)(out_lo + rowB + c) = (uint32_t)l0 | ((uint32_t)l1 << 16);
    }
}

// ---------------------------------------------------------------------------
// mma.sync cross-attention: 64-query CTA, all 4 key tiles (S=256), window
// mask (seg-128, seg] per row.
// ---------------------------------------------------------------------------
__global__ void __launch_bounds__(128, 2)
cross_attn_mma(const __nv_bfloat16* __restrict__ Qh, const __nv_bfloat16* __restrict__ Ql,
               const __nv_bfloat16* __restrict__ Kh, const __nv_bfloat16* __restrict__ Kl,
               const __nv_bfloat16* __restrict__ Vh, const __nv_bfloat16* __restrict__ Vl,
               const int* __restrict__ seg_ids,
               __nv_bfloat16* __restrict__ out_hi, __nv_bfloat16* __restrict__ out_lo) {
    extern __shared__ char smraw[];
    const uint32_t sb = (uint32_t)__cvta_generic_to_shared(smraw);
    const int tid = threadIdx.x, warp = tid >> 5, lane = tid & 31;
    const int h = blockIdx.y, b = blockIdx.z;
    const int qb = (int)blockIdx.x * 64;
    const int ntiles = S_ / 64;
    const size_t hbQ = ((size_t)(b*H_ + h)) * L_;
    const size_t hbK = ((size_t)(b*H_ + h)) * S_;

    const int rA = qb + warp*16 + (lane >> 2);
    const int segA = seg_ids[b*L_ + rA];
    const int segB = seg_ids[b*L_ + rA + 8];

    #pragma unroll
    for (int i = 0; i < 8; i++) {
        int id = tid + i * 128;
        int arr = id >> 9;
        int rem = id & 511;
        int row = rem >> 3, kc = rem & 7;
        const __nv_bfloat16* p = (arr ? Ql : Qh) + (hbQ + qb + row) * HD_ + kc * 8;
        uint32_t d = sb + (uint32_t)(arr * AT_ARR + row * AT_ROW + kc * 16);
        asm volatile("cp.async.cg.shared.global [%0], [%1], 16;" :: "r"(d), "l"(p) : "memory");
    }
    auto load_kv = [&](int t) {
        uint32_t base = sb + AT_KV0 + (uint32_t)(t & 1) * AT_STG;
        int k0 = t * 64;
        #pragma unroll
        for (int i = 0; i < 16; i++) {
            int id = tid + i * 128;
            int arr = id >> 9;
            int rem = id & 511;
            int row = rem >> 3, kc = rem & 7;
            const __nv_bfloat16* p = (arr==0?Kh:arr==1?Kl:arr==2?Vh:Vl) + (hbK + k0 + row) * HD_ + kc * 8;
            uint32_t d = base + (uint32_t)(arr * AT_ARR + row * AT_ROW + kc * 16);
            asm volatile("cp.async.cg.shared.global [%0], [%1], 16;" :: "r"(d), "l"(p) : "memory");
        }
        asm volatile("cp.async.commit_group;" ::: "memory");
    };
    load_kv(0);
    load_kv(1);

    uint32_t qh[4][4], ql[4][4];
    float o[8][4];
    #pragma unroll
    for (int i = 0; i < 8; i++)
        #pragma unroll
        for (int j = 0; j < 4; j++) o[i][j] = 0.f;
    float mA = -1e30f, mB = -1e30f, lA = 0.f, lB = 0.f;

    for (int t = 0; t < ntiles; t++) {
        if (t + 1 < ntiles) { asm volatile("cp.async.wait_group 1;" ::: "memory"); }
        else                { asm volatile("cp.async.wait_group 0;" ::: "memory"); }
        __syncthreads();
        if (t == 0) {
            #pragma unroll
            for (int ks = 0; ks < 4; ks++) {
                uint32_t a = sb + (uint32_t)((warp*16 + (lane & 15)) * AT_ROW + ks*32 + (lane >> 4) * 16);
                ldsm_x4(qh[ks], a);
                ldsm_x4(ql[ks], a + AT_ARR);
            }
        }
        const uint32_t kvb = sb + AT_KV0 + (uint32_t)(t & 1) * AT_STG;

        float s[8][4];
        #pragma unroll
        for (int i = 0; i < 8; i++)
            #pragma unroll
            for (int j = 0; j < 4; j++) s[i][j] = 0.f;
        #pragma unroll
        for (int ks = 0; ks < 4; ks++) {
            uint32_t kh4[4][4], kl4[4][4];
            #pragma unroll
            for (int ntp = 0; ntp < 4; ntp++) {
                uint32_t a = kvb + (uint32_t)((ntp*16 + (lane & 7) + ((lane >> 4) << 3)) * AT_ROW
                                              + ks*32 + (((lane >> 3) & 1) << 4));
                ldsm_x4(kh4[ntp], a);
                ldsm_x4(kl4[ntp], a + AT_ARR);
            }
            #pragma unroll
            for (int ntp = 0; ntp < 4; ntp++) {
                mma_bf16(s[2*ntp],   qh[ks], kh4[ntp]);
                mma_bf16(s[2*ntp+1], qh[ks], kh4[ntp] + 2);
                mma_bf16(s[2*ntp],   qh[ks], kl4[ntp]);
                mma_bf16(s[2*ntp+1], qh[ks], kl4[ntp] + 2);
                mma_bf16(s[2*ntp],   ql[ks], kh4[ntp]);
                mma_bf16(s[2*ntp+1], ql[ks], kh4[ntp] + 2);
            }
        }
        {
            int cbase = t*64 + 2*(lane & 3);
            #pragma unroll
            for (int nt = 0; nt < 8; nt++) {
                int c0 = cbase + nt*8, c1 = c0 + 1;
                if (c0 > segA || c0 <= segA - 128) s[nt][0] = -1e30f;
                if (c1 > segA || c1 <= segA - 128) s[nt][1] = -1e30f;
                if (c0 > segB || c0 <= segB - 128) s[nt][2] = -1e30f;
                if (c1 > segB || c1 <= segB - 128) s[nt][3] = -1e30f;
            }
        }
        float tmA = -1e30f, tmB = -1e30f;
        #pragma unroll
        for (int nt = 0; nt < 8; nt++) {
            tmA = fmaxf(tmA, fmaxf(s[nt][0], s[nt][1]));
            tmB = fmaxf(tmB, fmaxf(s[nt][2], s[nt][3]));
        }
        tmA = fmaxf(tmA, __shfl_xor_sync(0xffffffffu, tmA, 1));
        tmA = fmaxf(tmA, __shfl_xor_sync(0xffffffffu, tmA, 2));
        tmB = fmaxf(tmB, __shfl_xor_sync(0xffffffffu, tmB, 1));
        tmB = fmaxf(tmB, __shfl_xor_sync(0xffffffffu, tmB, 2));
        float nmA = fmaxf(mA, tmA), nmB = fmaxf(mB, tmB);
        float scA = __expf(mA - nmA), scB = __expf(mB - nmB);
        float tsA = 0.f, tsB = 0.f;
        #pragma unroll
        for (int nt = 0; nt < 8; nt++) {
            s[nt][0] = __expf(s[nt][0] - nmA);
            s[nt][1] = __expf(s[nt][1] - nmA);
            s[nt][2] = __expf(s[nt][2] - nmB);
            s[nt][3] = __expf(s[nt][3] - nmB);
            tsA += s[nt][0] + s[nt][1];
            tsB += s[nt][2] + s[nt][3];
        }
        tsA += __shfl_xor_sync(0xffffffffu, tsA, 1);
        tsA += __shfl_xor_sync(0xffffffffu, tsA, 2);
        tsB += __shfl_xor_sync(0xffffffffu, tsB, 1);
        tsB += __shfl_xor_sync(0xffffffffu, tsB, 2);
        lA = lA * scA + tsA;
        lB = lB * scB + tsB;
        #pragma unroll
        for (int nt = 0; nt < 8; nt++) {
            o[nt][0] *= scA; o[nt][1] *= scA;
            o[nt][2] *= scB; o[nt][3] *= scB;
        }
        mA = nmA; mB = nmB;
        #pragma unroll
        for (int kk = 0; kk < 4; kk++) {
            uint32_t ph[4], pl[4];
            {
                float p0 = s[2*kk][0],   p1 = s[2*kk][1],   p2 = s[2*kk][2],   p3 = s[2*kk][3];
                float p4 = s[2*kk+1][0], p5 = s[2*kk+1][1], p6 = s[2*kk+1][2], p7 = s[2*kk+1][3];
                ph[0] = pack_bf16x2(p0, p1); ph[1] = pack_bf16x2(p2, p3);
                ph[2] = pack_bf16x2(p4, p5); ph[3] = pack_bf16x2(p6, p7);
                pl[0] = pack_bf16x2(p0 - __bfloat162float(__float2bfloat16_rn(p0)),
                                    p1 - __bfloat162float(__float2bfloat16_rn(p1)));
                pl[1] = pack_bf16x2(p2 - __bfloat162float(__float2bfloat16_rn(p2)),
                                    p3 - __bfloat162float(__float2bfloat16_rn(p3)));
                pl[2] = pack_bf16x2(p4 - __bfloat162float(__float2bfloat16_rn(p4)),
                                    p5 - __bfloat162float(__float2bfloat16_rn(p5)));
                pl[3] = pack_bf16x2(p6 - __bfloat162float(__float2bfloat16_rn(p6)),
                                    p7 - __bfloat162float(__float2bfloat16_rn(p7)));
            }
            #pragma unroll
            for (int ntp = 0; ntp < 4; ntp++) {
                uint32_t vh4[4], vl4[4];
                uint32_t a = kvb + 2*AT_ARR + (uint32_t)((kk*16 + (lane & 15)) * AT_ROW
                                                        + ntp*32 + ((lane >> 4) << 4));
                ldsm_x4_t(vh4, a);
                ldsm_x4_t(vl4, a + AT_ARR);
                mma_bf16(o[2*ntp],   ph, vh4);
                mma_bf16(o[2*ntp+1], ph, vh4 + 2);
                mma_bf16(o[2*ntp],   ph, vl4);
                mma_bf16(o[2*ntp+1], ph, vl4 + 2);
                mma_bf16(o[2*ntp],   pl, vh4);
                mma_bf16(o[2*ntp+1], pl, vh4 + 2);
            }
        }
        __syncthreads();
        if (t + 2 < ntiles) load_kv(t + 2);
    }

    float iA = 1.0f / lA, iB = 1.0f / lB;
    size_t rowA = ((size_t)(b*L_ + rA)) * D_;
    size_t rowB = rowA + 8 * D_;
    int cb = h*HD_ + 2*(lane & 3);
    #pragma unroll
    for (int nt = 0; nt < 8; nt++) {
        int c = cb + nt*8;
        float a0 = o[nt][0]*iA, a1 = o[nt][1]*iA;
        float b0 = o[nt][2]*iB, b1 = o[nt][3]*iB;
        unsigned short h0,l0,h1,l1;
        split1(a0,h0,l0); split1(a1,h1,l1);
        *(uint32_t*)(out_hi + rowA + c) = (uint32_t)h0 | ((uint32_t)h1 << 16);
        *(uint32_t*)(out_lo + rowA + c) = (uint32_t)l0 | ((uint32_t)l1 << 16);
        split1(b0,h0,l0); split1(b1,h1,l1);
        *(uint32_t*)(out_hi + rowB + c) = (uint32_t)h0 | ((uint32_t)h1 << 16);
        *(uint32_t*)(out_lo + rowB + c) = (uint32_t)l0 | ((uint32_t)l1 << 16);
    }
}

// ---------------------------------------------------------------------------
// Launch
// ---------------------------------------------------------------------------
static inline void split_launch(const float* src, __nv_bfloat16* hi, __nv_bfloat16* lo, size_t n) {
    int n4 = (int)(n / 4);
    split_k<<<(n4 + 255) / 256, 256>>>(src, hi, lo, n4);
}

extern "C" void kernel_launch(void* const* d_in, const int* in_sizes, int n_in,
                              void* d_out, int out_size) {
    const float* x      = (const float*)d_in[0];
    const float* memory = (const float*)d_in[1];
    const int*   seg    = (const int*)  d_in[2];
    const float* Wqkv   = (const float*)d_in[3];
    const float* bqkv   = (const float*)d_in[4];
    const float* Wo     = (const float*)d_in[5];
    const float* bo     = (const float*)d_in[6];
    const float* Wq_c   = (const float*)d_in[7];
    const float* Wkv_c  = (const float*)d_in[8];
    const float* Wo_c   = (const float*)d_in[9];
    const float* Wg     = (const float*)d_in[10];
    const float* Wu     = (const float*)d_in[11];
    const float* Wd     = (const float*)d_in[12];
    const float* n1     = (const float*)d_in[13];
    const float* n2     = (const float*)d_in[14];
    const float* n3     = (const float*)d_in[15];
    const float* nf     = (const float*)d_in[16];

    cudaFuncSetAttribute(gemm_bf16s<0>, cudaFuncAttributeMaxDynamicSharedMemorySize, GSMEM);
    cudaFuncSetAttribute(gemm_bf16s<1>, cudaFuncAttributeMaxDynamicSharedMemorySize, GSMEM);
    cudaFuncSetAttribute(gemm_bf16s<2>, cudaFuncAttributeMaxDynamicSharedMemorySize, GSMEM);
    cudaFuncSetAttribute(gemm_bf16s<3>, cudaFuncAttributeMaxDynamicSharedMemorySize, GSMEM);
    cudaFuncSetAttribute(gemm_bf16s<4>, cudaFuncAttributeMaxDynamicSharedMemorySize, GSMEM);
    cudaFuncSetAttribute(gemm_bf16s<5>, cudaFuncAttributeMaxDynamicSharedMemorySize, GSMEM);
    cudaFuncSetAttribute(self_attn_mma,  cudaFuncAttributeMaxDynamicSharedMemorySize, AT_SMEM);
    cudaFuncSetAttribute(cross_attn_mma, cudaFuncAttributeMaxDynamicSharedMemorySize, AT_SMEM);

    float *xb, *qkvb;
    __nv_bfloat16 *hhi, *hlo, *ahi, *alo, *chi, *clo, *gshi, *gslo, *mhi, *mlo, *whi, *wlo;
    __nv_bfloat16 *sqh, *sql, *skh, *skl, *svh, *svl;
    cudaGetSymbolAddress((void**)&xb,   g_x);
    cudaGetSymbolAddress((void**)&qkvb, g_qkv);
    cudaGetSymbolAddress((void**)&hhi,  g_h_hi);  cudaGetSymbolAddress((void**)&hlo,  g_h_lo);
    cudaGetSymbolAddress((void**)&ahi,  g_at_hi); cudaGetSymbolAddress((void**)&alo,  g_at_lo);
    cudaGetSymbolAddress((void**)&chi,  g_co_hi); cudaGetSymbolAddress((void**)&clo,  g_co_lo);
    cudaGetSymbolAddress((void**)&gshi, g_gs_hi); cudaGetSymbolAddress((void**)&gslo, g_gs_lo);
    cudaGetSymbolAddress((void**)&mhi,  g_m_hi);  cudaGetSymbolAddress((void**)&mlo,  g_m_lo);
    cudaGetSymbolAddress((void**)&whi,  g_w_hi);  cudaGetSymbolAddress((void**)&wlo,  g_w_lo);
    cudaGetSymbolAddress((void**)&sqh,  g_sqh);   cudaGetSymbolAddress((void**)&sql,  g_sql);
    cudaGetSymbolAddress((void**)&skh,  g_skh);   cudaGetSymbolAddress((void**)&skl,  g_skl);
    cudaGetSymbolAddress((void**)&svh,  g_svh);   cudaGetSymbolAddress((void**)&svl,  g_svl);

    rope_cache_k<<<256, 256>>>();
    copy_x_k<<<(M_*D_)/256, 256>>>(x);

    split_launch(Wqkv,  whi + O_WQKV, wlo + O_WQKV, NL*SZ_WQKV);
    split_launch(Wo,    whi + O_WO,   wlo + O_WO,   NL*SZ_WO);
    split_launch(Wq_c,  whi + O_WQC,  wlo + O_WQC,  NL*SZ_WQC);
    split_launch(Wkv_c, whi + O_WKVC, wlo + O_WKVC, NL*SZ_WKVC);
    split_launch(Wo_c,  whi + O_WOC,  wlo + O_WOC,  NL*SZ_WOC);
    for (int l = 0; l < NL; l++) {
        int n4 = (int)((size_t)F_*D_/4);
        split_ilv_k<<<(n4 + 255)/256, 256>>>(Wg + (size_t)l*F_*D_,
            whi + O_WGU + l*SZ_WGU, wlo + O_WGU + l*SZ_WGU, n4, D_/4, 0);
        split_ilv_k<<<(n4 + 255)/256, 256>>>(Wu + (size_t)l*F_*D_,
            whi + O_WGU + l*SZ_WGU, wlo + O_WGU + l*SZ_WGU, n4, D_/4, 1);
    }
    split_launch(Wd,    whi + O_WD,   wlo + O_WD,   NL*SZ_WD);
    split_launch(memory, mhi, mlo, (size_t)B_*S_*D_);

    const dim3 self_grid(L_/64, H_, B_);
    const dim3 cross_grid(L_/64, H_, B_);

    for (int l = 0; l < NL; l++) {
        const __nv_bfloat16* wqkv_h = whi + O_WQKV + l*SZ_WQKV;
        const __nv_bfloat16* wqkv_l = wlo + O_WQKV + l*SZ_WQKV;
        const __nv_bfloat16* wo_h   = whi + O_WO   + l*SZ_WO;
        const __nv_bfloat16* wo_l   = wlo + O_WO   + l*SZ_WO;
        const __nv_bfloat16* wqc_h  = whi + O_WQC  + l*SZ_WQC;
        const __nv_bfloat16* wqc_l  = wlo + O_WQC  + l*SZ_WQC;
        const __nv_bfloat16* wkvc_h = whi + O_WKVC + l*SZ_WKVC;
        const __nv_bfloat16* wkvc_l = wlo + O_WKVC + l*SZ_WKVC;
        const __nv_bfloat16* woc_h  = whi + O_WOC  + l*SZ_WOC;
        const __nv_bfloat16* woc_l  = wlo + O_WOC  + l*SZ_WOC;
        const __nv_bfloat16* wgu_h  = whi + O_WGU  + l*SZ_WGU;
        const __nv_bfloat16* wgu_l  = wlo + O_WGU  + l*SZ_WGU;
        const __nv_bfloat16* wd_h   = whi + O_WD   + l*SZ_WD;
        const __nv_bfloat16* wd_l   = wlo + O_WD   + l*SZ_WD;

        // --- self attention block ---
        rmsnorm_split_k<<<M_, 256>>>(xb, n1 + l*D_, hhi, hlo);
        gemm_bf16s<0><<<dim3(3*D_/128, M_/256), 256, GSMEM>>>(
            hhi, hlo, wqkv_h, wqkv_l, bqkv + l*3*D_, qkvb,
            nullptr, nullptr, nullptr, nullptr, 3*D_, D_);
        rope_split_k<<<M_, 512>>>(qkvb);
        self_attn_mma<<<self_grid, 128, AT_SMEM>>>(sqh, sql, skh, skl, svh, svl, ahi, alo);
        gemm_bf16s<1><<<dim3(D_/128, M_/256), 256, GSMEM>>>(
            ahi, alo, wo_h, wo_l, bo + l*D_, xb,
            nullptr, nullptr, nullptr, nullptr, D_, D_);

        // --- cross attention block ---
        rmsnorm_split_k<<<M_, 256>>>(xb, n2 + l*D_, hhi, hlo);
        gemm_bf16s<4><<<dim3(D_/128, M_/256), 256, GSMEM>>>(
            hhi, hlo, wqc_h, wqc_l, nullptr, nullptr,
            sqh, sql, nullptr, nullptr, D_, D_);
        gemm_bf16s<5><<<dim3(2*D_/128, (B_*S_)/256), 256, GSMEM>>>(
            mhi, mlo, wkvc_h, wkvc_l, nullptr, nullptr,
            skh, skl, svh, svl, 2*D_, D_);
        cross_attn_mma<<<cross_grid, 128, AT_SMEM>>>(sqh, sql, skh, skl, svh, svl, seg, chi, clo);
        gemm_bf16s<2><<<dim3(D_/128, M_/256), 256, GSMEM>>>(
            chi, clo, woc_h, woc_l, nullptr, xb,
            nullptr, nullptr, nullptr, nullptr, D_, D_);

        // --- MLP block (fused gate|up GEMM with swiglu epilogue) ---
        rmsnorm_split_k<<<M_, 256>>>(xb, n3 + l*D_, hhi, hlo);
        gemm_bf16s<3><<<dim3(2*F_/128, M_/256), 256, GSMEM>>>(
            hhi, hlo, wgu_h, wgu_l, nullptr, nullptr,
            gshi, gslo, nullptr, nullptr, 2*F_, D_);
        gemm_bf16s<2><<<dim3(D_/128, M_/256), 256, GSMEM>>>(
            gshi, gslo, wd_h, wd_l, nullptr, xb,
            nullptr, nullptr, nullptr, nullptr, D_, F_);
    }

    rmsnorm_k<<<M_, 256>>>(xb, nf, (float*)d_out);
}

// round 9
// speedup vs baseline: 4.6684x; 1.0342x over previous
#include <cuda_runtime.h>
#include <cuda_bf16.h>
#include <math.h>
#include <stdint.h>

// Problem constants
#define NL 4
#define B_ 2
#define L_ 2048
#define S_ 256
#define D_ 1024
#define F_ 4096
#define H_ 16
#define HD_ 64
#define M_ (B_*L_)          // 4096 token rows

// Weight region sizes (elements) and offsets in the concatenated split buffer
#define SZ_WQKV ((size_t)3*D_*D_)
#define SZ_WO   ((size_t)D_*D_)
#define SZ_WQC  ((size_t)D_*D_)
#define SZ_WKVC ((size_t)2*D_*D_)
#define SZ_WOC  ((size_t)D_*D_)
#define SZ_WGU  ((size_t)2*F_*D_)     // interleaved [g0,u0,g1,u1,...] per layer
#define SZ_WD   ((size_t)D_*F_)
static const size_t O_WQKV = 0;
static const size_t O_WO   = O_WQKV + NL*SZ_WQKV;
static const size_t O_WQC  = O_WO   + NL*SZ_WO;
static const size_t O_WKVC = O_WQC  + NL*SZ_WQC;
static const size_t O_WOC  = O_WKVC + NL*SZ_WKVC;
static const size_t O_WGU  = O_WOC  + NL*SZ_WOC;
static const size_t O_WD   = O_WGU  + NL*SZ_WGU;
#define WTOT (O_WD + NL*SZ_WD)

// ---------------------------------------------------------------------------
// Scratch (device globals; no allocations allowed)
// ---------------------------------------------------------------------------
__device__ float g_x  [M_*D_];
__device__ float g_cos[L_*32];
__device__ float g_sin[L_*32];

__device__ __nv_bfloat16 g_h_hi [M_*D_],  g_h_lo [M_*D_];
__device__ __nv_bfloat16 g_at_hi[M_*D_],  g_at_lo[M_*D_];
__device__ __nv_bfloat16 g_co_hi[M_*D_],  g_co_lo[M_*D_];
__device__ __nv_bfloat16 g_gs_hi[M_*F_],  g_gs_lo[M_*F_];
__device__ __nv_bfloat16 g_m_hi [B_*S_*D_], g_m_lo[B_*S_*D_];
__device__ __nv_bfloat16 g_w_hi[WTOT], g_w_lo[WTOT];

// attention-layout split buffers: [B][H][L][64] (self q/k/v; cross q reuses q)
#define ATN ((size_t)B_*H_*L_*HD_)
__device__ __nv_bfloat16 g_sqh[ATN], g_sql[ATN];
__device__ __nv_bfloat16 g_skh[ATN], g_skl[ATN];
__device__ __nv_bfloat16 g_svh[ATN], g_svl[ATN];

// per-layer cross K/V: [NL][B][H][S][64]
#define CATN ((size_t)B_*H_*S_*HD_)
__device__ __nv_bfloat16 g_ckh[NL*CATN], g_ckl[NL*CATN];
__device__ __nv_bfloat16 g_cvh[NL*CATN], g_cvl[NL*CATN];

// ---------------------------------------------------------------------------
// bf16 split helpers
// ---------------------------------------------------------------------------
__device__ __forceinline__ void split1(float v, unsigned short& h, unsigned short& l) {
    __nv_bfloat16 hb = __float2bfloat16_rn(v);
    float r = v - __bfloat162float(hb);
    __nv_bfloat16 lb = __float2bfloat16_rn(r);
    h = __bfloat16_as_ushort(hb);
    l = __bfloat16_as_ushort(lb);
}
__device__ __forceinline__ void split_pack4(float4 v, uint2& ph, uint2& pl) {
    unsigned short h0,h1,h2,h3,l0,l1,l2,l3;
    split1(v.x,h0,l0); split1(v.y,h1,l1); split1(v.z,h2,l2); split1(v.w,h3,l3);
    ph.x = (uint32_t)h0 | ((uint32_t)h1 << 16);
    ph.y = (uint32_t)h2 | ((uint32_t)h3 << 16);
    pl.x = (uint32_t)l0 | ((uint32_t)l1 << 16);
    pl.y = (uint32_t)l2 | ((uint32_t)l3 << 16);
}

__global__ void split_k(const float* __restrict__ in, __nv_bfloat16* __restrict__ hi,
                        __nv_bfloat16* __restrict__ lo, int n4) {
    int i = blockIdx.x * blockDim.x + threadIdx.x;
    if (i >= n4) return;
    float4 v = ((const float4*)in)[i];
    uint2 ph, pl; split_pack4(v, ph, pl);
    ((uint2*)hi)[i] = ph;
    ((uint2*)lo)[i] = pl;
}

// Interleaving split: source row r -> destination row 2r+off (rowQuads float4s per row)
__global__ void split_ilv_k(const float* __restrict__ in, __nv_bfloat16* __restrict__ hi,
                            __nv_bfloat16* __restrict__ lo, int n4, int rowQuads, int off) {
    int i = blockIdx.x * blockDim.x + threadIdx.x;
    if (i >= n4) return;
    int r = i / rowQuads, c = i % rowQuads;
    float4 v = ((const float4*)in)[i];
    uint2 ph, pl; split_pack4(v, ph, pl);
    size_t oi = (size_t)(2*r + off) * rowQuads + c;
    ((uint2*)hi)[oi] = ph;
    ((uint2*)lo)[oi] = pl;
}

// ---------------------------------------------------------------------------
// RoPE cache
// ---------------------------------------------------------------------------
__global__ void rope_cache_k() {
    int idx = blockIdx.x * blockDim.x + threadIdx.x;
    int l = idx >> 5, i = idx & 31;
    double inv = exp(-log(10000.0) * (double)i / 32.0);
    double f = (double)l * inv;
    g_cos[idx] = (float)cos(f);
    g_sin[idx] = (float)sin(f);
}

__global__ void copy_x_k(const float* __restrict__ x) {
    size_t i = (size_t)blockIdx.x * blockDim.x + threadIdx.x;
    if (i < (size_t)M_ * D_) g_x[i] = x[i];
}

// ---------------------------------------------------------------------------
// RMSNorm kernels
// ---------------------------------------------------------------------------
__global__ void rmsnorm_split_k(const float* __restrict__ x, const float* __restrict__ w,
                                __nv_bfloat16* __restrict__ hi, __nv_bfloat16* __restrict__ lo) {
    int row = blockIdx.x;
    int t = threadIdx.x;
    const float4* xr = (const float4*)(x + (size_t)row * D_);
    float4 v = xr[t];
    float ss = v.x*v.x + v.y*v.y + v.z*v.z + v.w*v.w;
    #pragma unroll
    for (int off = 16; off; off >>= 1) ss += __shfl_xor_sync(0xffffffffu, ss, off);
    __shared__ float red[8];
    if ((t & 31) == 0) red[t >> 5] = ss;
    __syncthreads();
    float tot = red[0]+red[1]+red[2]+red[3]+red[4]+red[5]+red[6]+red[7];
    float rs = rsqrtf(tot * (1.0f / (float)D_) + 1e-6f);
    float4 wv = ((const float4*)w)[t];
    float4 o;
    o.x = v.x * rs * wv.x; o.y = v.y * rs * wv.y;
    o.z = v.z * rs * wv.z; o.w = v.w * rs * wv.w;
    uint2 ph, pl; split_pack4(o, ph, pl);
    ((uint2*)hi)[(size_t)row * 256 + t] = ph;
    ((uint2*)lo)[(size_t)row * 256 + t] = pl;
}

__global__ void rmsnorm_k(const float* __restrict__ x, const float* __restrict__ w,
                          float* __restrict__ o) {
    int row = blockIdx.x;
    int t = threadIdx.x;
    const float4* xr = (const float4*)(x + (size_t)row * D_);
    float4 v = xr[t];
    float ss = v.x*v.x + v.y*v.y + v.z*v.z + v.w*v.w;
    #pragma unroll
    for (int off = 16; off; off >>= 1) ss += __shfl_xor_sync(0xffffffffu, ss, off);
    __shared__ float red[8];
    if ((t & 31) == 0) red[t >> 5] = ss;
    __syncthreads();
    float tot = red[0]+red[1]+red[2]+red[3]+red[4]+red[5]+red[6]+red[7];
    float rs = rsqrtf(tot * (1.0f / (float)D_) + 1e-6f);
    float4 wv = ((const float4*)w)[t];
    float4 out;
    out.x = v.x * rs * wv.x; out.y = v.y * rs * wv.y;
    out.z = v.z * rs * wv.z; out.w = v.w * rs * wv.w;
    ((float4*)(o + (size_t)row * D_))[t] = out;
}

// ---------------------------------------------------------------------------
// mma / ldmatrix helpers
// ---------------------------------------------------------------------------
__device__ __forceinline__ void mma_bf16(float* c, const uint32_t* a, const uint32_t* b) {
    asm volatile(
        "mma.sync.aligned.m16n8k16.row.col.f32.bf16.bf16.f32 "
        "{%0,%1,%2,%3}, {%4,%5,%6,%7}, {%8,%9}, {%0,%1,%2,%3};"
        : "+f"(c[0]), "+f"(c[1]), "+f"(c[2]), "+f"(c[3])
        : "r"(a[0]), "r"(a[1]), "r"(a[2]), "r"(a[3]), "r"(b[0]), "r"(b[1]));
}
__device__ __forceinline__ void ldsm_x4(uint32_t* r, uint32_t addr) {
    asm volatile("ldmatrix.sync.aligned.m8n8.x4.shared.b16 {%0,%1,%2,%3}, [%4];"
        : "=r"(r[0]), "=r"(r[1]), "=r"(r[2]), "=r"(r[3]) : "r"(addr));
}
__device__ __forceinline__ void ldsm_x4_t(uint32_t* r, uint32_t addr) {
    asm volatile("ldmatrix.sync.aligned.m8n8.x4.trans.shared.b16 {%0,%1,%2,%3}, [%4];"
        : "=r"(r[0]), "=r"(r[1]), "=r"(r[2]), "=r"(r[3]) : "r"(addr));
}
__device__ __forceinline__ uint32_t pack_bf16x2(float lo, float hi) {
    return (uint32_t)__bfloat16_as_ushort(__float2bfloat16_rn(lo)) |
           ((uint32_t)__bfloat16_as_ushort(__float2bfloat16_rn(hi)) << 16);
}

// ---------------------------------------------------------------------------
// bf16 split-3 GEMM (NT), 256x128 CTA tile, warp tile 64x64 (8 warps, 4x2).
// MODE 1: +bias +residual    -> fp32 C      (Wo)
// MODE 2: +residual          -> fp32 C      (Wo_c, Wd)
// MODE 3: swiglu (interleaved g|u cols) -> bf16 hi/lo [M][F]
// MODE 4: attn-q layout, x0.125         -> bf16 hi/lo [B][H][L][64]
// MODE 6: QKV: +bias, RoPE on q/k, q x0.125 -> q/k/v bf16 hi/lo [B][H][L][64]
// MODE 7: multi-layer cross-KV           -> per-layer k/v [NL][B][H][S][64]
// ---------------------------------------------------------------------------
#define G2STAGE 61440
#define G2_AL   20480
#define G2_B0   40960
#define G2_B1   51200
#define GSMEM   (3*G2STAGE)

template <int MODE>
__global__ void __launch_bounds__(256, 1)
gemm_bf16s(const __nv_bfloat16* __restrict__ Ah, const __nv_bfloat16* __restrict__ Al,
           const __nv_bfloat16* __restrict__ Wh, const __nv_bfloat16* __restrict__ Wl,
           const float* __restrict__ bias, float* __restrict__ C,
           __nv_bfloat16* __restrict__ o1h, __nv_bfloat16* __restrict__ o1l,
           __nv_bfloat16* __restrict__ o2h, __nv_bfloat16* __restrict__ o2l,
           __nv_bfloat16* __restrict__ o3h, __nv_bfloat16* __restrict__ o3l,
           int N, int K) {
    extern __shared__ char smem[];
    const uint32_t sbase = (uint32_t)__cvta_generic_to_shared(smem);
    const int tid  = threadIdx.x;
    const int warp = tid >> 5, lane = tid & 31;
    const int wr = warp >> 1;      // 0..3 : 64-row slab
    const int wc = warp & 1;       // 0..1 : 64-col slab
    const int g  = lane >> 2;
    const int t  = lane & 3;
    const int bm = blockIdx.y, bn = blockIdx.x;

    // cp.async chunk tables: 3072 16B-chunks per stage, 12 per thread
    const __nv_bfloat16* src[12];
    uint32_t dst[12];
    #pragma unroll
    for (int i = 0; i < 12; i++) {
        int id = tid + (i << 8);
        const __nv_bfloat16* bp;
        int grow; uint32_t off; int kc;
        if (id < 2048) {
            int arr = id >> 10, rem = id & 1023;
            int row = rem >> 2; kc = rem & 3;
            bp = arr ? Al : Ah;
            grow = bm * 256 + row;
            off = (uint32_t)(arr * G2_AL + row * 80 + kc * 16);
        } else {
            int id2 = id - 2048;
            int arr = id2 >> 9, rem = id2 & 511;
            int row = rem >> 2; kc = rem & 3;
            bp = arr ? Wl : Wh;
            grow = bn * 128 + row;
            off = (uint32_t)(G2_B0 + arr * 10240 + row * 80 + kc * 16);
        }
        src[i] = bp + (size_t)grow * K + kc * 8;
        dst[i] = off;
    }

    const uint32_t arow = (uint32_t)((wr * 64 + (lane & 15)) * 80 + (lane >> 4) * 16);
    const uint32_t brow = (uint32_t)((wc * 64 + (lane & 7) + ((lane >> 4) << 3)) * 80
                                     + (((lane >> 3) & 1) << 4));

    float acc[4][8][4];
    #pragma unroll
    for (int i = 0; i < 4; i++)
        #pragma unroll
        for (int j = 0; j < 8; j++)
            #pragma unroll
            for (int r = 0; r < 4; r++) acc[i][j][r] = 0.f;

    const int nk = K >> 5;

    #pragma unroll
    for (int st = 0; st < 2; st++) {
        uint32_t s = sbase + st * G2STAGE;
        #pragma unroll
        for (int i = 0; i < 12; i++) {
            const void* p = src[i] + st * 32;
            asm volatile("cp.async.cg.shared.global [%0], [%1], 16;"
                         :: "r"(s + dst[i]), "l"(p) : "memory");
        }
        asm volatile("cp.async.commit_group;" ::: "memory");
    }

    for (int it = 0; it < nk; it++) {
        asm volatile("cp.async.wait_group 1;" ::: "memory");
        __syncthreads();
        uint32_t s = sbase + (uint32_t)(it % 3) * G2STAGE;

        #pragma unroll
        for (int ks = 0; ks < 2; ks++) {
            const uint32_t ko = ks * 32;
            uint32_t af[16], bh[16], bl[16];
            #pragma unroll
            for (int mt = 0; mt < 4; mt++) ldsm_x4(af + 4*mt, s + arow + mt*1280 + ko);
            #pragma unroll
            for (int p = 0; p < 4; p++) ldsm_x4(bh + 4*p, s + G2_B0 + brow + p*1280 + ko);
            #pragma unroll
            for (int p = 0; p < 4; p++) ldsm_x4(bl + 4*p, s + G2_B1 + brow + p*1280 + ko);
            #pragma unroll
            for (int mt = 0; mt < 4; mt++)
                #pragma unroll
                for (int nt = 0; nt < 8; nt++) mma_bf16(acc[mt][nt], af + 4*mt, bh + 2*nt);
            #pragma unroll
            for (int mt = 0; mt < 4; mt++)
                #pragma unroll
                for (int nt = 0; nt < 8; nt++) mma_bf16(acc[mt][nt], af + 4*mt, bl + 2*nt);
            #pragma unroll
            for (int mt = 0; mt < 4; mt++) ldsm_x4(af + 4*mt, s + G2_AL + arow + mt*1280 + ko);
            #pragma unroll
            for (int mt = 0; mt < 4; mt++)
                #pragma unroll
                for (int nt = 0; nt < 8; nt++) mma_bf16(acc[mt][nt], af + 4*mt, bh + 2*nt);
        }

        if (it + 2 < nk) {
            uint32_t s2 = sbase + (uint32_t)((it + 2) % 3) * G2STAGE;
            int k0 = (it + 2) * 32;
            #pragma unroll
            for (int i = 0; i < 12; i++) {
                const void* p = src[i] + k0;
                asm volatile("cp.async.cg.shared.global [%0], [%1], 16;"
                             :: "r"(s2 + dst[i]), "l"(p) : "memory");
            }
        }
        asm volatile("cp.async.commit_group;" ::: "memory");
    }

    if (MODE == 6) {
        // QKV epilogue: bias + RoPE (q,k) + split into attention layout.
        // part: 0=q, 1=k, 2=v (64-col warp slabs never straddle parts).
        const int part = (bn * 128 + wc * 64) >> 10;
        #pragma unroll
        for (int mt = 0; mt < 4; mt++) {
            #pragma unroll
            for (int half = 0; half < 2; half++) {
                int row = bm * 256 + wr * 64 + mt * 16 + g + half * 8;
                int b = row >> 11, ltok = row & (L_ - 1);
                if (part < 2) {
                    #pragma unroll
                    for (int np = 0; np < 4; np++) {
                        int col = bn*128 + wc*64 + np*8 + 2*t;
                        int pcol = col & 1023;
                        int head = pcol >> 6;
                        int i = pcol & 31;                 // d for np; np+4 holds d+32
                        float c0 = g_cos[ltok*32 + i],     s0 = g_sin[ltok*32 + i];
                        float c1 = g_cos[ltok*32 + i + 1], s1 = g_sin[ltok*32 + i + 1];
                        float x1a = acc[mt][np  ][half*2+0] + bias[col];
                        float x1b = acc[mt][np  ][half*2+1] + bias[col+1];
                        float x2a = acc[mt][np+4][half*2+0] + bias[col+32];
                        float x2b = acc[mt][np+4][half*2+1] + bias[col+33];
                        float r1a = x1a*c0 - x2a*s0, r2a = x2a*c0 + x1a*s0;
                        float r1b = x1b*c1 - x2b*s1, r2b = x2b*c1 + x1b*s1;
                        __nv_bfloat16 *oh, *ol;
                        if (part == 0) {
                            r1a *= 0.125f; r1b *= 0.125f; r2a *= 0.125f; r2b *= 0.125f;
                            oh = o1h; ol = o1l;
                        } else { oh = o2h; ol = o2l; }
                        size_t oi = (((size_t)(b*H_ + head)) * L_ + ltok) * HD_ + i;
                        unsigned short h0, l0, h1, l1;
                        split1(r1a, h0, l0); split1(r1b, h1, l1);
                        *(uint32_t*)(oh + oi) = (uint32_t)h0 | ((uint32_t)h1 << 16);
                        *(uint32_t*)(ol + oi) = (uint32_t)l0 | ((uint32_t)l1 << 16);
                        split1(r2a, h0, l0); split1(r2b, h1, l1);
                        *(uint32_t*)(oh + oi + 32) = (uint32_t)h0 | ((uint32_t)h1 << 16);
                        *(uint32_t*)(ol + oi + 32) = (uint32_t)l0 | ((uint32_t)l1 << 16);
                    }
                } else {
                    #pragma unroll
                    for (int nt = 0; nt < 8; nt++) {
                        int col = bn*128 + wc*64 + nt*8 + 2*t;
                        int pcol = col & 1023;
                        int head = pcol >> 6, d = pcol & 63;
                        float c0 = acc[mt][nt][half*2+0] + bias[col];
                        float c1 = acc[mt][nt][half*2+1] + bias[col+1];
                        size_t oi = (((size_t)(b*H_ + head)) * L_ + ltok) * HD_ + d;
                        unsigned short h0, l0, h1, l1;
                        split1(c0, h0, l0); split1(c1, h1, l1);
                        *(uint32_t*)(o3h + oi) = (uint32_t)h0 | ((uint32_t)h1 << 16);
                        *(uint32_t*)(o3l + oi) = (uint32_t)l0 | ((uint32_t)l1 << 16);
                    }
                }
            }
        }
        return;
    }

    #pragma unroll
    for (int mt = 0; mt < 4; mt++) {
        #pragma unroll
        for (int half = 0; half < 2; half++) {
            int row = bm * 256 + wr * 64 + mt * 16 + g + half * 8;
            #pragma unroll
            for (int nt = 0; nt < 8; nt++) {
                int col = bn * 128 + wc * 64 + nt * 8 + 2 * t;
                float c0 = acc[mt][nt][half * 2 + 0];
                float c1 = acc[mt][nt][half * 2 + 1];
                if (MODE <= 2) {
                    float* dstp = C + (size_t)row * N + col;
                    if (MODE == 1) { c0 += bias[col]; c1 += bias[col + 1]; }
                    float2 r = *(const float2*)dstp;
                    c0 += r.x; c1 += r.y;
                    *(float2*)dstp = make_float2(c0, c1);
                } else if (MODE == 3) {
                    float sg = c0 / (1.0f + expf(-c0)) * c1;
                    unsigned short hh, ll; split1(sg, hh, ll);
                    size_t oi = (size_t)row * F_ + (col >> 1);
                    o1h[oi] = __ushort_as_bfloat16(hh);
                    o1l[oi] = __ushort_as_bfloat16(ll);
                } else if (MODE == 4) {
                    int b = row >> 11, ltok = row & (L_ - 1);
                    int hd = col >> 6, d = col & 63;
                    size_t oi = (((size_t)(b*H_ + hd)) * L_ + ltok) * HD_ + d;
                    unsigned short h0, l0, h1, l1;
                    split1(c0 * 0.125f, h0, l0); split1(c1 * 0.125f, h1, l1);
                    *(uint32_t*)(o1h + oi) = (uint32_t)h0 | ((uint32_t)h1 << 16);
                    *(uint32_t*)(o1l + oi) = (uint32_t)l0 | ((uint32_t)l1 << 16);
                } else { // MODE 7: multi-layer cross-KV
                    int layer = col >> 11;
                    int c2 = col & 2047;
                    int kv = c2 >> 10;
                    int hd = (c2 >> 6) & 15, d = c2 & 63;
                    int b = row >> 8, stok = row & (S_ - 1);
                    size_t oi = (size_t)layer * CATN
                              + (((size_t)(b*H_ + hd)) * S_ + stok) * HD_ + d;
                    unsigned short h0, l0, h1, l1;
                    split1(c0, h0, l0); split1(c1, h1, l1);
                    __nv_bfloat16* ph = kv ? o2h : o1h;
                    __nv_bfloat16* pl = kv ? o2l : o1l;
                    *(uint32_t*)(ph + oi) = (uint32_t)h0 | ((uint32_t)h1 << 16);
                    *(uint32_t*)(pl + oi) = (uint32_t)l0 | ((uint32_t)l1 << 16);
                }
            }
        }
    }
}

// ---------------------------------------------------------------------------
// mma.sync flash self-attention.
// ---------------------------------------------------------------------------
#define AT_ROW  144
#define AT_ARR  (64*AT_ROW)
#define AT_KV0  (2*AT_ARR)
#define AT_STG  (4*AT_ARR)
#define AT_SMEM (2*AT_ARR + 2*AT_STG)

__global__ void __launch_bounds__(128, 2)
self_attn_mma(const __nv_bfloat16* __restrict__ Qh, const __nv_bfloat16* __restrict__ Ql,
              const __nv_bfloat16* __restrict__ Kh, const __nv_bfloat16* __restrict__ Kl,
              const __nv_bfloat16* __restrict__ Vh, const __nv_bfloat16* __restrict__ Vl,
              __nv_bfloat16* __restrict__ out_hi, __nv_bfloat16* __restrict__ out_lo) {
    extern __shared__ char smraw[];
    const uint32_t sb = (uint32_t)__cvta_generic_to_shared(smraw);
    const int tid = threadIdx.x, warp = tid >> 5, lane = tid & 31;
    const int h = blockIdx.y, b = blockIdx.z;
    const int qbi = (int)(gridDim.x - 1 - blockIdx.x);
    const int qb = qbi * 64;
    const int ntiles = qbi + 1;
    const size_t hb = ((size_t)(b*H_ + h)) * L_;

    #pragma unroll
    for (int i = 0; i < 8; i++) {
        int id = tid + i * 128;
        int arr = id >> 9;
        int rem = id & 511;
        int row = rem >> 3, kc = rem & 7;
        const __nv_bfloat16* p = (arr ? Ql : Qh) + (hb + qb + row) * HD_ + kc * 8;
        uint32_t d = sb + (uint32_t)(arr * AT_ARR + row * AT_ROW + kc * 16);
        asm volatile("cp.async.cg.shared.global [%0], [%1], 16;" :: "r"(d), "l"(p) : "memory");
    }
    auto load_kv = [&](int t) {
        uint32_t base = sb + AT_KV0 + (uint32_t)(t & 1) * AT_STG;
        int k0 = t * 64;
        #pragma unroll
        for (int i = 0; i < 16; i++) {
            int id = tid + i * 128;
            int arr = id >> 9;
            int rem = id & 511;
            int row = rem >> 3, kc = rem & 7;
            const __nv_bfloat16* p = (arr==0?Kh:arr==1?Kl:arr==2?Vh:Vl) + (hb + k0 + row) * HD_ + kc * 8;
            uint32_t d = base + (uint32_t)(arr * AT_ARR + row * AT_ROW + kc * 16);
            asm volatile("cp.async.cg.shared.global [%0], [%1], 16;" :: "r"(d), "l"(p) : "memory");
        }
        asm volatile("cp.async.commit_group;" ::: "memory");
    };
    load_kv(0);
    if (ntiles > 1) load_kv(1);

    uint32_t qh[4][4], ql[4][4];
    float o[8][4];
    #pragma unroll
    for (int i = 0; i < 8; i++)
        #pragma unroll
        for (int j = 0; j < 4; j++) o[i][j] = 0.f;
    float mA = -1e30f, mB = -1e30f, lA = 0.f, lB = 0.f;

    for (int t = 0; t < ntiles; t++) {
        if (t + 1 < ntiles) { asm volatile("cp.async.wait_group 1;" ::: "memory"); }
        else                { asm volatile("cp.async.wait_group 0;" ::: "memory"); }
        __syncthreads();
        if (t == 0) {
            #pragma unroll
            for (int ks = 0; ks < 4; ks++) {
                uint32_t a = sb + (uint32_t)((warp*16 + (lane & 15)) * AT_ROW + ks*32 + (lane >> 4) * 16);
                ldsm_x4(qh[ks], a);
                ldsm_x4(ql[ks], a + AT_ARR);
            }
        }
        const uint32_t kvb = sb + AT_KV0 + (uint32_t)(t & 1) * AT_STG;

        float s[8][4];
        #pragma unroll
        for (int i = 0; i < 8; i++)
            #pragma unroll
            for (int j = 0; j < 4; j++) s[i][j] = 0.f;
        #pragma unroll
        for (int ks = 0; ks < 4; ks++) {
            uint32_t kh4[4][4], kl4[4][4];
            #pragma unroll
            for (int ntp = 0; ntp < 4; ntp++) {
                uint32_t a = kvb + (uint32_t)((ntp*16 + (lane & 7) + ((lane >> 4) << 3)) * AT_ROW
                                              + ks*32 + (((lane >> 3) & 1) << 4));
                ldsm_x4(kh4[ntp], a);
                ldsm_x4(kl4[ntp], a + AT_ARR);
            }
            #pragma unroll
            for (int ntp = 0; ntp < 4; ntp++) {
                mma_bf16(s[2*ntp],   qh[ks], kh4[ntp]);
                mma_bf16(s[2*ntp+1], qh[ks], kh4[ntp] + 2);
                mma_bf16(s[2*ntp],   qh[ks], kl4[ntp]);
                mma_bf16(s[2*ntp+1], qh[ks], kl4[ntp] + 2);
                mma_bf16(s[2*ntp],   ql[ks], kh4[ntp]);
                mma_bf16(s[2*ntp+1], ql[ks], kh4[ntp] + 2);
            }
        }
        if (t == ntiles - 1) {
            int rA = qb + warp*16 + (lane >> 2);
            int cbase = t*64 + 2*(lane & 3);
            #pragma unroll
            for (int nt = 0; nt < 8; nt++) {
                int c0 = cbase + nt*8, c1 = c0 + 1;
                if (c0 > rA)     s[nt][0] = -1e30f;
                if (c1 > rA)     s[nt][1] = -1e30f;
                if (c0 > rA + 8) s[nt][2] = -1e30f;
                if (c1 > rA + 8) s[nt][3] = -1e30f;
            }
        }
        float tmA = -1e30f, tmB = -1e30f;
        #pragma unroll
        for (int nt = 0; nt < 8; nt++) {
            tmA = fmaxf(tmA, fmaxf(s[nt][0], s[nt][1]));
            tmB = fmaxf(tmB, fmaxf(s[nt][2], s[nt][3]));
        }
        tmA = fmaxf(tmA, __shfl_xor_sync(0xffffffffu, tmA, 1));
        tmA = fmaxf(tmA, __shfl_xor_sync(0xffffffffu, tmA, 2));
        tmB = fmaxf(tmB, __shfl_xor_sync(0xffffffffu, tmB, 1));
        tmB = fmaxf(tmB, __shfl_xor_sync(0xffffffffu, tmB, 2));
        float nmA = fmaxf(mA, tmA), nmB = fmaxf(mB, tmB);
        float scA = __expf(mA - nmA), scB = __expf(mB - nmB);
        float tsA = 0.f, tsB = 0.f;
        #pragma unroll
        for (int nt = 0; nt < 8; nt++) {
            s[nt][0] = __expf(s[nt][0] - nmA);
            s[nt][1] = __expf(s[nt][1] - nmA);
            s[nt][2] = __expf(s[nt][2] - nmB);
            s[nt][3] = __expf(s[nt][3] - nmB);
            tsA += s[nt][0] + s[nt][1];
            tsB += s[nt][2] + s[nt][3];
        }
        tsA += __shfl_xor_sync(0xffffffffu, tsA, 1);
        tsA += __shfl_xor_sync(0xffffffffu, tsA, 2);
        tsB += __shfl_xor_sync(0xffffffffu, tsB, 1);
        tsB += __shfl_xor_sync(0xffffffffu, tsB, 2);
        lA = lA * scA + tsA;
        lB = lB * scB + tsB;
        #pragma unroll
        for (int nt = 0; nt < 8; nt++) {
            o[nt][0] *= scA; o[nt][1] *= scA;
            o[nt][2] *= scB; o[nt][3] *= scB;
        }
        mA = nmA; mB = nmB;
        #pragma unroll
        for (int kk = 0; kk < 4; kk++) {
            uint32_t ph[4], pl[4];
            {
                float p0 = s[2*kk][0],   p1 = s[2*kk][1],   p2 = s[2*kk][2],   p3 = s[2*kk][3];
                float p4 = s[2*kk+1][0], p5 = s[2*kk+1][1], p6 = s[2*kk+1][2], p7 = s[2*kk+1][3];
                ph[0] = pack_bf16x2(p0, p1); ph[1] = pack_bf16x2(p2, p3);
                ph[2] = pack_bf16x2(p4, p5); ph[3] = pack_bf16x2(p6, p7);
                pl[0] = pack_bf16x2(p0 - __bfloat162float(__float2bfloat16_rn(p0)),
                                    p1 - __bfloat162float(__float2bfloat16_rn(p1)));
                pl[1] = pack_bf16x2(p2 - __bfloat162float(__float2bfloat16_rn(p2)),
                                    p3 - __bfloat162float(__float2bfloat16_rn(p3)));
                pl[2] = pack_bf16x2(p4 - __bfloat162float(__float2bfloat16_rn(p4)),
                                    p5 - __bfloat162float(__float2bfloat16_rn(p5)));
                pl[3] = pack_bf16x2(p6 - __bfloat162float(__float2bfloat16_rn(p6)),
                                    p7 - __bfloat162float(__float2bfloat16_rn(p7)));
            }
            #pragma unroll
            for (int ntp = 0; ntp < 4; ntp++) {
                uint32_t vh4[4], vl4[4];
                uint32_t a = kvb + 2*AT_ARR + (uint32_t)((kk*16 + (lane & 15)) * AT_ROW
                                                        + ntp*32 + ((lane >> 4) << 4));
                ldsm_x4_t(vh4, a);
                ldsm_x4_t(vl4, a + AT_ARR);
                mma_bf16(o[2*ntp],   ph, vh4);
                mma_bf16(o[2*ntp+1], ph, vh4 + 2);
                mma_bf16(o[2*ntp],   ph, vl4);
                mma_bf16(o[2*ntp+1], ph, vl4 + 2);
                mma_bf16(o[2*ntp],   pl, vh4);
                mma_bf16(o[2*ntp+1], pl, vh4 + 2);
            }
        }
        __syncthreads();
        if (t + 2 < ntiles) load_kv(t + 2);
    }

    float iA = 1.0f / lA, iB = 1.0f / lB;
    int qA = qb + warp*16 + (lane >> 2);
    size_t rowA = ((size_t)(b*L_ + qA)) * D_;
    size_t rowB = rowA + 8 * D_;
    int cb = h*HD_ + 2*(lane & 3);
    #pragma unroll
    for (int nt = 0; nt < 8; nt++) {
        int c = cb + nt*8;
        float a0 = o[nt][0]*iA, a1 = o[nt][1]*iA;
        float b0 = o[nt][2]*iB, b1 = o[nt][3]*iB;
        unsigned short h0,l0,h1,l1;
        split1(a0,h0,l0); split1(a1,h1,l1);
        *(uint32_t*)(out_hi + rowA + c) = (uint32_t)h0 | ((uint32_t)h1 << 16);
        *(uint32_t*)(out_lo + rowA + c) = (uint32_t)l0 | ((uint32_t)l1 << 16);
        split1(b0,h0,l0); split1(b1,h1,l1);
        *(uint32_t*)(out_hi + rowB + c) = (uint32_t)h0 | ((uint32_t)h1 << 16);
        *(uint32_t*)(out_lo + rowB + c) = (uint32_t)l0 | ((uint32_t)l1 << 16);
    }
}

// ---------------------------------------------------------------------------
// mma.sync cross-attention: 64-query CTA, all 4 key tiles (S=256), window
// mask (seg-128, seg] per row.
// ---------------------------------------------------------------------------
__global__ void __launch_bounds__(128, 2)
cross_attn_mma(const __nv_bfloat16* __restrict__ Qh, const __nv_bfloat16* __restrict__ Ql,
               const __nv_bfloat16* __restrict__ Kh, const __nv_bfloat16* __restrict__ Kl,
               const __nv_bfloat16* __restrict__ Vh, const __nv_bfloat16* __restrict__ Vl,
               const int* __restrict__ seg_ids,
               __nv_bfloat16* __restrict__ out_hi, __nv_bfloat16* __restrict__ out_lo) {
    extern __shared__ char smraw[];
    const uint32_t sb = (uint32_t)__cvta_generic_to_shared(smraw);
    const int tid = threadIdx.x, warp = tid >> 5, lane = tid & 31;
    const int h = blockIdx.y, b = blockIdx.z;
    const int qb = (int)blockIdx.x * 64;
    const int ntiles = S_ / 64;
    const size_t hbQ = ((size_t)(b*H_ + h)) * L_;
    const size_t hbK = ((size_t)(b*H_ + h)) * S_;

    const int rA = qb + warp*16 + (lane >> 2);
    const int segA = seg_ids[b*L_ + rA];
    const int segB = seg_ids[b*L_ + rA + 8];

    #pragma unroll
    for (int i = 0; i < 8; i++) {
        int id = tid + i * 128;
        int arr = id >> 9;
        int rem = id & 511;
        int row = rem >> 3, kc = rem & 7;
        const __nv_bfloat16* p = (arr ? Ql : Qh) + (hbQ + qb + row) * HD_ + kc * 8;
        uint32_t d = sb + (uint32_t)(arr * AT_ARR + row * AT_ROW + kc * 16);
        asm volatile("cp.async.cg.shared.global [%0], [%1], 16;" :: "r"(d), "l"(p) : "memory");
    }
    auto load_kv = [&](int t) {
        uint32_t base = sb + AT_KV0 + (uint32_t)(t & 1) * AT_STG;
        int k0 = t * 64;
        #pragma unroll
        for (int i = 0; i < 16; i++) {
            int id = tid + i * 128;
            int arr = id >> 9;
            int rem = id & 511;
            int row = rem >> 3, kc = rem & 7;
            const __nv_bfloat16* p = (arr==0?Kh:arr==1?Kl:arr==2?Vh:Vl) + (hbK + k0 + row) * HD_ + kc * 8;
            uint32_t d = base + (uint32_t)(arr * AT_ARR + row * AT_ROW + kc * 16);
            asm volatile("cp.async.cg.shared.global [%0], [%1], 16;" :: "r"(d), "l"(p) : "memory");
        }
        asm volatile("cp.async.commit_group;" ::: "memory");
    };
    load_kv(0);
    load_kv(1);

    uint32_t qh[4][4], ql[4][4];
    float o[8][4];
    #pragma unroll
    for (int i = 0; i < 8; i++)
        #pragma unroll
        for (int j = 0; j < 4; j++) o[i][j] = 0.f;
    float mA = -1e30f, mB = -1e30f, lA = 0.f, lB = 0.f;

    for (int t = 0; t < ntiles; t++) {
        if (t + 1 < ntiles) { asm volatile("cp.async.wait_group 1;" ::: "memory"); }
        else                { asm volatile("cp.async.wait_group 0;" ::: "memory"); }
        __syncthreads();
        if (t == 0) {
            #pragma unroll
            for (int ks = 0; ks < 4; ks++) {
                uint32_t a = sb + (uint32_t)((warp*16 + (lane & 15)) * AT_ROW + ks*32 + (lane >> 4) * 16);
                ldsm_x4(qh[ks], a);
                ldsm_x4(ql[ks], a + AT_ARR);
            }
        }
        const uint32_t kvb = sb + AT_KV0 + (uint32_t)(t & 1) * AT_STG;

        float s[8][4];
        #pragma unroll
        for (int i = 0; i < 8; i++)
            #pragma unroll
            for (int j = 0; j < 4; j++) s[i][j] = 0.f;
        #pragma unroll
        for (int ks = 0; ks < 4; ks++) {
            uint32_t kh4[4][4], kl4[4][4];
            #pragma unroll
            for (int ntp = 0; ntp < 4; ntp++) {
                uint32_t a = kvb + (uint32_t)((ntp*16 + (lane & 7) + ((lane >> 4) << 3)) * AT_ROW
                                              + ks*32 + (((lane >> 3) & 1) << 4));
                ldsm_x4(kh4[ntp], a);
                ldsm_x4(kl4[ntp], a + AT_ARR);
            }
            #pragma unroll
            for (int ntp = 0; ntp < 4; ntp++) {
                mma_bf16(s[2*ntp],   qh[ks], kh4[ntp]);
                mma_bf16(s[2*ntp+1], qh[ks], kh4[ntp] + 2);
                mma_bf16(s[2*ntp],   qh[ks], kl4[ntp]);
                mma_bf16(s[2*ntp+1], qh[ks], kl4[ntp] + 2);
                mma_bf16(s[2*ntp],   ql[ks], kh4[ntp]);
                mma_bf16(s[2*ntp+1], ql[ks], kh4[ntp] + 2);
            }
        }
        {
            int cbase = t*64 + 2*(lane & 3);
            #pragma unroll
            for (int nt = 0; nt < 8; nt++) {
                int c0 = cbase + nt*8, c1 = c0 + 1;
                if (c0 > segA || c0 <= segA - 128) s[nt][0] = -1e30f;
                if (c1 > segA || c1 <= segA - 128) s[nt][1] = -1e30f;
                if (c0 > segB || c0 <= segB - 128) s[nt][2] = -1e30f;
                if (c1 > segB || c1 <= segB - 128) s[nt][3] = -1e30f;
            }
        }
        float tmA = -1e30f, tmB = -1e30f;
        #pragma unroll
        for (int nt = 0; nt < 8; nt++) {
            tmA = fmaxf(tmA, fmaxf(s[nt][0], s[nt][1]));
            tmB = fmaxf(tmB, fmaxf(s[nt][2], s[nt][3]));
        }
        tmA = fmaxf(tmA, __shfl_xor_sync(0xffffffffu, tmA, 1));
        tmA = fmaxf(tmA, __shfl_xor_sync(0xffffffffu, tmA, 2));
        tmB = fmaxf(tmB, __shfl_xor_sync(0xffffffffu, tmB, 1));
        tmB = fmaxf(tmB, __shfl_xor_sync(0xffffffffu, tmB, 2));
        float nmA = fmaxf(mA, tmA), nmB = fmaxf(mB, tmB);
        float scA = __expf(mA - nmA), scB = __expf(mB - nmB);
        float tsA = 0.f, tsB = 0.f;
        #pragma unroll
        for (int nt = 0; nt < 8; nt++) {
            s[nt][0] = __expf(s[nt][0] - nmA);
            s[nt][1] = __expf(s[nt][1] - nmA);
            s[nt][2] = __expf(s[nt][2] - nmB);
            s[nt][3] = __expf(s[nt][3] - nmB);
            tsA += s[nt][0] + s[nt][1];
            tsB += s[nt][2] + s[nt][3];
        }
        tsA += __shfl_xor_sync(0xffffffffu, tsA, 1);
        tsA += __shfl_xor_sync(0xffffffffu, tsA, 2);
        tsB += __shfl_xor_sync(0xffffffffu, tsB, 1);
        tsB += __shfl_xor_sync(0xffffffffu, tsB, 2);
        lA = lA * scA + tsA;
        lB = lB * scB + tsB;
        #pragma unroll
        for (int nt = 0; nt < 8; nt++) {
            o[nt][0] *= scA; o[nt][1] *= scA;
            o[nt][2] *= scB; o[nt][3] *= scB;
        }
        mA = nmA; mB = nmB;
        #pragma unroll
        for (int kk = 0; kk < 4; kk++) {
            uint32_t ph[4], pl[4];
            {
                float p0 = s[2*kk][0],   p1 = s[2*kk][1],   p2 = s[2*kk][2],   p3 = s[2*kk][3];
                float p4 = s[2*kk+1][0], p5 = s[2*kk+1][1], p6 = s[2*kk+1][2], p7 = s[2*kk+1][3];
                ph[0] = pack_bf16x2(p0, p1); ph[1] = pack_bf16x2(p2, p3);
                ph[2] = pack_bf16x2(p4, p5); ph[3] = pack_bf16x2(p6, p7);
                pl[0] = pack_bf16x2(p0 - __bfloat162float(__float2bfloat16_rn(p0)),
                                    p1 - __bfloat162float(__float2bfloat16_rn(p1)));
                pl[1] = pack_bf16x2(p2 - __bfloat162float(__float2bfloat16_rn(p2)),
                                    p3 - __bfloat162float(__float2bfloat16_rn(p3)));
                pl[2] = pack_bf16x2(p4 - __bfloat162float(__float2bfloat16_rn(p4)),
                                    p5 - __bfloat162float(__float2bfloat16_rn(p5)));
                pl[3] = pack_bf16x2(p6 - __bfloat162float(__float2bfloat16_rn(p6)),
                                    p7 - __bfloat162float(__float2bfloat16_rn(p7)));
            }
            #pragma unroll
            for (int ntp = 0; ntp < 4; ntp++) {
                uint32_t vh4[4], vl4[4];
                uint32_t a = kvb + 2*AT_ARR + (uint32_t)((kk*16 + (lane & 15)) * AT_ROW
                                                        + ntp*32 + ((lane >> 4) << 4));
                ldsm_x4_t(vh4, a);
                ldsm_x4_t(vl4, a + AT_ARR);
                mma_bf16(o[2*ntp],   ph, vh4);
                mma_bf16(o[2*ntp+1], ph, vh4 + 2);
                mma_bf16(o[2*ntp],   ph, vl4);
                mma_bf16(o[2*ntp+1], ph, vl4 + 2);
                mma_bf16(o[2*ntp],   pl, vh4);
                mma_bf16(o[2*ntp+1], pl, vh4 + 2);
            }
        }
        __syncthreads();
        if (t + 2 < ntiles) load_kv(t + 2);
    }

    float iA = 1.0f / lA, iB = 1.0f / lB;
    size_t rowA = ((size_t)(b*L_ + rA)) * D_;
    size_t rowB = rowA + 8 * D_;
    int cb = h*HD_ + 2*(lane & 3);
    #pragma unroll
    for (int nt = 0; nt < 8; nt++) {
        int c = cb + nt*8;
        float a0 = o[nt][0]*iA, a1 = o[nt][1]*iA;
        float b0 = o[nt][2]*iB, b1 = o[nt][3]*iB;
        unsigned short h0,l0,h1,l1;
        split1(a0,h0,l0); split1(a1,h1,l1);
        *(uint32_t*)(out_hi + rowA + c) = (uint32_t)h0 | ((uint32_t)h1 << 16);
        *(uint32_t*)(out_lo + rowA + c) = (uint32_t)l0 | ((uint32_t)l1 << 16);
        split1(b0,h0,l0); split1(b1,h1,l1);
        *(uint32_t*)(out_hi + rowB + c) = (uint32_t)h0 | ((uint32_t)h1 << 16);
        *(uint32_t*)(out_lo + rowB + c) = (uint32_t)l0 | ((uint32_t)l1 << 16);
    }
}

// ---------------------------------------------------------------------------
// Launch
// ---------------------------------------------------------------------------
static inline void split_launch(const float* src, __nv_bfloat16* hi, __nv_bfloat16* lo, size_t n) {
    int n4 = (int)(n / 4);
    split_k<<<(n4 + 255) / 256, 256>>>(src, hi, lo, n4);
}

extern "C" void kernel_launch(void* const* d_in, const int* in_sizes, int n_in,
                              void* d_out, int out_size) {
    const float* x      = (const float*)d_in[0];
    const float* memory = (const float*)d_in[1];
    const int*   seg    = (const int*)  d_in[2];
    const float* Wqkv   = (const float*)d_in[3];
    const float* bqkv   = (const float*)d_in[4];
    const float* Wo     = (const float*)d_in[5];
    const float* bo     = (const float*)d_in[6];
    const float* Wq_c   = (const float*)d_in[7];
    const float* Wkv_c  = (const float*)d_in[8];
    const float* Wo_c   = (const float*)d_in[9];
    const float* Wg     = (const float*)d_in[10];
    const float* Wu     = (const float*)d_in[11];
    const float* Wd     = (const float*)d_in[12];
    const float* n1     = (const float*)d_in[13];
    const float* n2     = (const float*)d_in[14];
    const float* n3     = (const float*)d_in[15];
    const float* nf     = (const float*)d_in[16];

    cudaFuncSetAttribute(gemm_bf16s<1>, cudaFuncAttributeMaxDynamicSharedMemorySize, GSMEM);
    cudaFuncSetAttribute(gemm_bf16s<2>, cudaFuncAttributeMaxDynamicSharedMemorySize, GSMEM);
    cudaFuncSetAttribute(gemm_bf16s<3>, cudaFuncAttributeMaxDynamicSharedMemorySize, GSMEM);
    cudaFuncSetAttribute(gemm_bf16s<4>, cudaFuncAttributeMaxDynamicSharedMemorySize, GSMEM);
    cudaFuncSetAttribute(gemm_bf16s<6>, cudaFuncAttributeMaxDynamicSharedMemorySize, GSMEM);
    cudaFuncSetAttribute(gemm_bf16s<7>, cudaFuncAttributeMaxDynamicSharedMemorySize, GSMEM);
    cudaFuncSetAttribute(self_attn_mma,  cudaFuncAttributeMaxDynamicSharedMemorySize, AT_SMEM);
    cudaFuncSetAttribute(cross_attn_mma, cudaFuncAttributeMaxDynamicSharedMemorySize, AT_SMEM);

    float *xb;
    __nv_bfloat16 *hhi, *hlo, *ahi, *alo, *chi, *clo, *gshi, *gslo, *mhi, *mlo, *whi, *wlo;
    __nv_bfloat16 *sqh, *sql, *skh, *skl, *svh, *svl;
    __nv_bfloat16 *ckh, *ckl, *cvh, *cvl;
    cudaGetSymbolAddress((void**)&xb,   g_x);
    cudaGetSymbolAddress((void**)&hhi,  g_h_hi);  cudaGetSymbolAddress((void**)&hlo,  g_h_lo);
    cudaGetSymbolAddress((void**)&ahi,  g_at_hi); cudaGetSymbolAddress((void**)&alo,  g_at_lo);
    cudaGetSymbolAddress((void**)&chi,  g_co_hi); cudaGetSymbolAddress((void**)&clo,  g_co_lo);
    cudaGetSymbolAddress((void**)&gshi, g_gs_hi); cudaGetSymbolAddress((void**)&gslo, g_gs_lo);
    cudaGetSymbolAddress((void**)&mhi,  g_m_hi);  cudaGetSymbolAddress((void**)&mlo,  g_m_lo);
    cudaGetSymbolAddress((void**)&whi,  g_w_hi);  cudaGetSymbolAddress((void**)&wlo,  g_w_lo);
    cudaGetSymbolAddress((void**)&sqh,  g_sqh);   cudaGetSymbolAddress((void**)&sql,  g_sql);
    cudaGetSymbolAddress((void**)&skh,  g_skh);   cudaGetSymbolAddress((void**)&skl,  g_skl);
    cudaGetSymbolAddress((void**)&svh,  g_svh);   cudaGetSymbolAddress((void**)&svl,  g_svl);
    cudaGetSymbolAddress((void**)&ckh,  g_ckh);   cudaGetSymbolAddress((void**)&ckl,  g_ckl);
    cudaGetSymbolAddress((void**)&cvh,  g_cvh);   cudaGetSymbolAddress((void**)&cvl,  g_cvl);

    rope_cache_k<<<256, 256>>>();
    copy_x_k<<<(M_*D_)/256, 256>>>(x);

    split_launch(Wqkv,  whi + O_WQKV, wlo + O_WQKV, NL*SZ_WQKV);
    split_launch(Wo,    whi + O_WO,   wlo + O_WO,   NL*SZ_WO);
    split_launch(Wq_c,  whi + O_WQC,  wlo + O_WQC,  NL*SZ_WQC);
    split_launch(Wkv_c, whi + O_WKVC, wlo + O_WKVC, NL*SZ_WKVC);
    split_launch(Wo_c,  whi + O_WOC,  wlo + O_WOC,  NL*SZ_WOC);
    for (int l = 0; l < NL; l++) {
        int n4 = (int)((size_t)F_*D_/4);
        split_ilv_k<<<(n4 + 255)/256, 256>>>(Wg + (size_t)l*F_*D_,
            whi + O_WGU + l*SZ_WGU, wlo + O_WGU + l*SZ_WGU, n4, D_/4, 0);
        split_ilv_k<<<(n4 + 255)/256, 256>>>(Wu + (size_t)l*F_*D_,
            whi + O_WGU + l*SZ_WGU, wlo + O_WGU + l*SZ_WGU, n4, D_/4, 1);
    }
    split_launch(Wd,    whi + O_WD,   wlo + O_WD,   NL*SZ_WD);
    split_launch(memory, mhi, mlo, (size_t)B_*S_*D_);

    // upfront: all 4 layers' cross K/V in one GEMM (layer-independent)
    gemm_bf16s<7><<<dim3(NL*2*D_/128, (B_*S_)/256), 256, GSMEM>>>(
        mhi, mlo, whi + O_WKVC, wlo + O_WKVC, nullptr, nullptr,
        ckh, ckl, cvh, cvl, nullptr, nullptr, NL*2*D_, D_);

    const dim3 self_grid(L_/64, H_, B_);
    const dim3 cross_grid(L_/64, H_, B_);

    for (int l = 0; l < NL; l++) {
        const __nv_bfloat16* wqkv_h = whi + O_WQKV + l*SZ_WQKV;
        const __nv_bfloat16* wqkv_l = wlo + O_WQKV + l*SZ_WQKV;
        const __nv_bfloat16* wo_h   = whi + O_WO   + l*SZ_WO;
        const __nv_bfloat16* wo_l   = wlo + O_WO   + l*SZ_WO;
        const __nv_bfloat16* wqc_h  = whi + O_WQC  + l*SZ_WQC;
        const __nv_bfloat16* wqc_l  = wlo + O_WQC  + l*SZ_WQC;
        const __nv_bfloat16* woc_h  = whi + O_WOC  + l*SZ_WOC;
        const __nv_bfloat16* woc_l  = wlo + O_WOC  + l*SZ_WOC;
        const __nv_bfloat16* wgu_h  = whi + O_WGU  + l*SZ_WGU;
        const __nv_bfloat16* wgu_l  = wlo + O_WGU  + l*SZ_WGU;
        const __nv_bfloat16* wd_h   = whi + O_WD   + l*SZ_WD;
        const __nv_bfloat16* wd_l   = wlo + O_WD   + l*SZ_WD;

        // --- self attention block (QKV GEMM fuses bias+RoPE+split) ---
        rmsnorm_split_k<<<M_, 256>>>(xb, n1 + l*D_, hhi, hlo);
        gemm_bf16s<6><<<dim3(3*D_/128, M_/256), 256, GSMEM>>>(
            hhi, hlo, wqkv_h, wqkv_l, bqkv + l*3*D_, nullptr,
            sqh, sql, skh, skl, svh, svl, 3*D_, D_);
        self_attn_mma<<<self_grid, 128, AT_SMEM>>>(sqh, sql, skh, skl, svh, svl, ahi, alo);
        gemm_bf16s<1><<<dim3(D_/128, M_/256), 256, GSMEM>>>(
            ahi, alo, wo_h, wo_l, bo + l*D_, xb,
            nullptr, nullptr, nullptr, nullptr, nullptr, nullptr, D_, D_);

        // --- cross attention block ---
        rmsnorm_split_k<<<M_, 256>>>(xb, n2 + l*D_, hhi, hlo);
        gemm_bf16s<4><<<dim3(D_/128, M_/256), 256, GSMEM>>>(
            hhi, hlo, wqc_h, wqc_l, nullptr, nullptr,
            sqh, sql, nullptr, nullptr, nullptr, nullptr, D_, D_);
        cross_attn_mma<<<cross_grid, 128, AT_SMEM>>>(
            sqh, sql, ckh + l*CATN, ckl + l*CATN, cvh + l*CATN, cvl + l*CATN,
            seg, chi, clo);
        gemm_bf16s<2><<<dim3(D_/128, M_/256), 256, GSMEM>>>(
            chi, clo, woc_h, woc_l, nullptr, xb,
            nullptr, nullptr, nullptr, nullptr, nullptr, nullptr, D_, D_);

        // --- MLP block (fused gate|up GEMM with swiglu epilogue) ---
        rmsnorm_split_k<<<M_, 256>>>(xb, n3 + l*D_, hhi, hlo);
        gemm_bf16s<3><<<dim3(2*F_/128, M_/256), 256, GSMEM>>>(
            hhi, hlo, wgu_h, wgu_l, nullptr, nullptr,
            gshi, gslo, nullptr, nullptr, nullptr, nullptr, 2*F_, D_);
        gemm_bf16s<2><<<dim3(D_/128, M_/256), 256, GSMEM>>>(
            gshi, gslo, wd_h, wd_l, nullptr, xb,
            nullptr, nullptr, nullptr, nullptr, nullptr, nullptr, D_, F_);
    }

    rmsnorm_k<<<M_, 256>>>(xb, nf, (float*)d_out);
}

// round 10
// speedup vs baseline: 4.7361x; 1.0145x over previous
#include <cuda_runtime.h>
#include <cuda_bf16.h>
#include <math.h>
#include <stdint.h>

// Problem constants
#define NL 4
#define B_ 2
#define L_ 2048
#define S_ 256
#define D_ 1024
#define F_ 4096
#define H_ 16
#define HD_ 64
#define M_ (B_*L_)          // 4096 token rows

// Weight region sizes (elements) and offsets in the concatenated split buffer
#define SZ_WQKV ((size_t)3*D_*D_)
#define SZ_WO   ((size_t)D_*D_)
#define SZ_WQC  ((size_t)D_*D_)
#define SZ_WKVC ((size_t)2*D_*D_)
#define SZ_WOC  ((size_t)D_*D_)
#define SZ_WGU  ((size_t)2*F_*D_)     // interleaved [g0,u0,g1,u1,...] per layer
#define SZ_WD   ((size_t)D_*F_)
static const size_t O_WQKV = 0;
static const size_t O_WO   = O_WQKV + NL*SZ_WQKV;
static const size_t O_WQC  = O_WO   + NL*SZ_WO;
static const size_t O_WKVC = O_WQC  + NL*SZ_WQC;
static const size_t O_WOC  = O_WKVC + NL*SZ_WKVC;
static const size_t O_WGU  = O_WOC  + NL*SZ_WOC;
static const size_t O_WD   = O_WGU  + NL*SZ_WGU;
#define WTOT (O_WD + NL*SZ_WD)

// ---------------------------------------------------------------------------
// Scratch (device globals; no allocations allowed)
// ---------------------------------------------------------------------------
__device__ float g_x  [M_*D_];
__device__ float g_cos[L_*32];
__device__ float g_sin[L_*32];

__device__ __nv_bfloat16 g_h_hi [M_*D_],  g_h_lo [M_*D_];
__device__ __nv_bfloat16 g_at_hi[M_*D_],  g_at_lo[M_*D_];
__device__ __nv_bfloat16 g_co_hi[M_*D_],  g_co_lo[M_*D_];
__device__ __nv_bfloat16 g_gs_hi[M_*F_],  g_gs_lo[M_*F_];
__device__ __nv_bfloat16 g_m_hi [B_*S_*D_], g_m_lo[B_*S_*D_];
__device__ __nv_bfloat16 g_w_hi[WTOT], g_w_lo[WTOT];

// attention-layout split buffers: [B][H][L][64] (self q/k/v; cross q reuses q)
#define ATN ((size_t)B_*H_*L_*HD_)
__device__ __nv_bfloat16 g_sqh[ATN], g_sql[ATN];
__device__ __nv_bfloat16 g_skh[ATN], g_skl[ATN];
__device__ __nv_bfloat16 g_svh[ATN], g_svl[ATN];

// per-layer cross K/V: [NL][B][H][S][64]
#define CATN ((size_t)B_*H_*S_*HD_)
__device__ __nv_bfloat16 g_ckh[NL*CATN], g_ckl[NL*CATN];
__device__ __nv_bfloat16 g_cvh[NL*CATN], g_cvl[NL*CATN];

// ---------------------------------------------------------------------------
// bf16 split helpers
// ---------------------------------------------------------------------------
__device__ __forceinline__ void split1(float v, unsigned short& h, unsigned short& l) {
    __nv_bfloat16 hb = __float2bfloat16_rn(v);
    float r = v - __bfloat162float(hb);
    __nv_bfloat16 lb = __float2bfloat16_rn(r);
    h = __bfloat16_as_ushort(hb);
    l = __bfloat16_as_ushort(lb);
}
__device__ __forceinline__ void split_pack4(float4 v, uint2& ph, uint2& pl) {
    unsigned short h0,h1,h2,h3,l0,l1,l2,l3;
    split1(v.x,h0,l0); split1(v.y,h1,l1); split1(v.z,h2,l2); split1(v.w,h3,l3);
    ph.x = (uint32_t)h0 | ((uint32_t)h1 << 16);
    ph.y = (uint32_t)h2 | ((uint32_t)h3 << 16);
    pl.x = (uint32_t)l0 | ((uint32_t)l1 << 16);
    pl.y = (uint32_t)l2 | ((uint32_t)l3 << 16);
}

__global__ void split_k(const float* __restrict__ in, __nv_bfloat16* __restrict__ hi,
                        __nv_bfloat16* __restrict__ lo, int n4) {
    int i = blockIdx.x * blockDim.x + threadIdx.x;
    if (i >= n4) return;
    float4 v = ((const float4*)in)[i];
    uint2 ph, pl; split_pack4(v, ph, pl);
    ((uint2*)hi)[i] = ph;
    ((uint2*)lo)[i] = pl;
}

// Interleaving split: source row r -> destination row 2r+off (rowQuads float4s per row)
__global__ void split_ilv_k(const float* __restrict__ in, __nv_bfloat16* __restrict__ hi,
                            __nv_bfloat16* __restrict__ lo, int n4, int rowQuads, int off) {
    int i = blockIdx.x * blockDim.x + threadIdx.x;
    if (i >= n4) return;
    int r = i / rowQuads, c = i % rowQuads;
    float4 v = ((const float4*)in)[i];
    uint2 ph, pl; split_pack4(v, ph, pl);
    size_t oi = (size_t)(2*r + off) * rowQuads + c;
    ((uint2*)hi)[oi] = ph;
    ((uint2*)lo)[oi] = pl;
}

// ---------------------------------------------------------------------------
// RoPE cache
// ---------------------------------------------------------------------------
__global__ void rope_cache_k() {
    int idx = blockIdx.x * blockDim.x + threadIdx.x;
    int l = idx >> 5, i = idx & 31;
    double inv = exp(-log(10000.0) * (double)i / 32.0);
    double f = (double)l * inv;
    g_cos[idx] = (float)cos(f);
    g_sin[idx] = (float)sin(f);
}

__global__ void copy_x_k(const float* __restrict__ x) {
    size_t i = (size_t)blockIdx.x * blockDim.x + threadIdx.x;
    if (i < (size_t)M_ * D_) g_x[i] = x[i];
}

// ---------------------------------------------------------------------------
// RMSNorm kernels
// ---------------------------------------------------------------------------
__global__ void rmsnorm_split_k(const float* __restrict__ x, const float* __restrict__ w,
                                __nv_bfloat16* __restrict__ hi, __nv_bfloat16* __restrict__ lo) {
    int row = blockIdx.x;
    int t = threadIdx.x;
    const float4* xr = (const float4*)(x + (size_t)row * D_);
    float4 v = xr[t];
    float ss = v.x*v.x + v.y*v.y + v.z*v.z + v.w*v.w;
    #pragma unroll
    for (int off = 16; off; off >>= 1) ss += __shfl_xor_sync(0xffffffffu, ss, off);
    __shared__ float red[8];
    if ((t & 31) == 0) red[t >> 5] = ss;
    __syncthreads();
    float tot = red[0]+red[1]+red[2]+red[3]+red[4]+red[5]+red[6]+red[7];
    float rs = rsqrtf(tot * (1.0f / (float)D_) + 1e-6f);
    float4 wv = ((const float4*)w)[t];
    float4 o;
    o.x = v.x * rs * wv.x; o.y = v.y * rs * wv.y;
    o.z = v.z * rs * wv.z; o.w = v.w * rs * wv.w;
    uint2 ph, pl; split_pack4(o, ph, pl);
    ((uint2*)hi)[(size_t)row * 256 + t] = ph;
    ((uint2*)lo)[(size_t)row * 256 + t] = pl;
}

__global__ void rmsnorm_k(const float* __restrict__ x, const float* __restrict__ w,
                          float* __restrict__ o) {
    int row = blockIdx.x;
    int t = threadIdx.x;
    const float4* xr = (const float4*)(x + (size_t)row * D_);
    float4 v = xr[t];
    float ss = v.x*v.x + v.y*v.y + v.z*v.z + v.w*v.w;
    #pragma unroll
    for (int off = 16; off; off >>= 1) ss += __shfl_xor_sync(0xffffffffu, ss, off);
    __shared__ float red[8];
    if ((t & 31) == 0) red[t >> 5] = ss;
    __syncthreads();
    float tot = red[0]+red[1]+red[2]+red[3]+red[4]+red[5]+red[6]+red[7];
    float rs = rsqrtf(tot * (1.0f / (float)D_) + 1e-6f);
    float4 wv = ((const float4*)w)[t];
    float4 out;
    out.x = v.x * rs * wv.x; out.y = v.y * rs * wv.y;
    out.z = v.z * rs * wv.z; out.w = v.w * rs * wv.w;
    ((float4*)(o + (size_t)row * D_))[t] = out;
}

// ---------------------------------------------------------------------------
// mma / ldmatrix helpers
// ---------------------------------------------------------------------------
__device__ __forceinline__ void mma_bf16(float* c, const uint32_t* a, const uint32_t* b) {
    asm volatile(
        "mma.sync.aligned.m16n8k16.row.col.f32.bf16.bf16.f32 "
        "{%0,%1,%2,%3}, {%4,%5,%6,%7}, {%8,%9}, {%0,%1,%2,%3};"
        : "+f"(c[0]), "+f"(c[1]), "+f"(c[2]), "+f"(c[3])
        : "r"(a[0]), "r"(a[1]), "r"(a[2]), "r"(a[3]), "r"(b[0]), "r"(b[1]));
}
__device__ __forceinline__ void ldsm_x4(uint32_t* r, uint32_t addr) {
    asm volatile("ldmatrix.sync.aligned.m8n8.x4.shared.b16 {%0,%1,%2,%3}, [%4];"
        : "=r"(r[0]), "=r"(r[1]), "=r"(r[2]), "=r"(r[3]) : "r"(addr));
}
__device__ __forceinline__ void ldsm_x4_t(uint32_t* r, uint32_t addr) {
    asm volatile("ldmatrix.sync.aligned.m8n8.x4.trans.shared.b16 {%0,%1,%2,%3}, [%4];"
        : "=r"(r[0]), "=r"(r[1]), "=r"(r[2]), "=r"(r[3]) : "r"(addr));
}
__device__ __forceinline__ uint32_t pack_bf16x2(float lo, float hi) {
    return (uint32_t)__bfloat16_as_ushort(__float2bfloat16_rn(lo)) |
           ((uint32_t)__bfloat16_as_ushort(__float2bfloat16_rn(hi)) << 16);
}

// ---------------------------------------------------------------------------
// bf16 split-3 GEMM (NT), 256x128 CTA tile, warp tile 64x64 (8 warps, 4x2).
// MODE 1: +bias +residual    -> fp32 C      (Wo)
// MODE 2: +residual          -> fp32 C      (Wo_c, Wd)
// MODE 3: swiglu (interleaved g|u cols) -> bf16 hi/lo [M][F]
// MODE 4: attn-q layout, x0.125         -> bf16 hi/lo [B][H][L][64]
// MODE 6: QKV: +bias, RoPE on q/k, q x0.125 -> q/k/v bf16 hi/lo [B][H][L][64]
// MODE 7: multi-layer cross-KV           -> per-layer k/v [NL][B][H][S][64]
// ---------------------------------------------------------------------------
#define G2STAGE 61440
#define G2_AL   20480
#define G2_B0   40960
#define G2_B1   51200
#define GSMEM   (3*G2STAGE)

template <int MODE>
__global__ void __launch_bounds__(256, 1)
gemm_bf16s(const __nv_bfloat16* __restrict__ Ah, const __nv_bfloat16* __restrict__ Al,
           const __nv_bfloat16* __restrict__ Wh, const __nv_bfloat16* __restrict__ Wl,
           const float* __restrict__ bias, float* __restrict__ C,
           __nv_bfloat16* __restrict__ o1h, __nv_bfloat16* __restrict__ o1l,
           __nv_bfloat16* __restrict__ o2h, __nv_bfloat16* __restrict__ o2l,
           __nv_bfloat16* __restrict__ o3h, __nv_bfloat16* __restrict__ o3l,
           int N, int K) {
    extern __shared__ char smem[];
    const uint32_t sbase = (uint32_t)__cvta_generic_to_shared(smem);
    const int tid  = threadIdx.x;
    const int warp = tid >> 5, lane = tid & 31;
    const int wr = warp >> 1;      // 0..3 : 64-row slab
    const int wc = warp & 1;       // 0..1 : 64-col slab
    const int g  = lane >> 2;
    const int t  = lane & 3;
    const int bm = blockIdx.y, bn = blockIdx.x;

    // cp.async chunk tables: 3072 16B-chunks per stage, 12 per thread
    const __nv_bfloat16* src[12];
    uint32_t dst[12];
    #pragma unroll
    for (int i = 0; i < 12; i++) {
        int id = tid + (i << 8);
        const __nv_bfloat16* bp;
        int grow; uint32_t off; int kc;
        if (id < 2048) {
            int arr = id >> 10, rem = id & 1023;
            int row = rem >> 2; kc = rem & 3;
            bp = arr ? Al : Ah;
            grow = bm * 256 + row;
            off = (uint32_t)(arr * G2_AL + row * 80 + kc * 16);
        } else {
            int id2 = id - 2048;
            int arr = id2 >> 9, rem = id2 & 511;
            int row = rem >> 2; kc = rem & 3;
            bp = arr ? Wl : Wh;
            grow = bn * 128 + row;
            off = (uint32_t)(G2_B0 + arr * 10240 + row * 80 + kc * 16);
        }
        src[i] = bp + (size_t)grow * K + kc * 8;
        dst[i] = off;
    }

    const uint32_t arow = (uint32_t)((wr * 64 + (lane & 15)) * 80 + (lane >> 4) * 16);
    const uint32_t brow = (uint32_t)((wc * 64 + (lane & 7) + ((lane >> 4) << 3)) * 80
                                     + (((lane >> 3) & 1) << 4));

    float acc[4][8][4];
    #pragma unroll
    for (int i = 0; i < 4; i++)
        #pragma unroll
        for (int j = 0; j < 8; j++)
            #pragma unroll
            for (int r = 0; r < 4; r++) acc[i][j][r] = 0.f;

    const int nk = K >> 5;

    #pragma unroll
    for (int st = 0; st < 2; st++) {
        uint32_t s = sbase + st * G2STAGE;
        #pragma unroll
        for (int i = 0; i < 12; i++) {
            const void* p = src[i] + st * 32;
            asm volatile("cp.async.cg.shared.global [%0], [%1], 16;"
                         :: "r"(s + dst[i]), "l"(p) : "memory");
        }
        asm volatile("cp.async.commit_group;" ::: "memory");
    }

    for (int it = 0; it < nk; it++) {
        asm volatile("cp.async.wait_group 1;" ::: "memory");
        __syncthreads();
        uint32_t s = sbase + (uint32_t)(it % 3) * G2STAGE;

        #pragma unroll
        for (int ks = 0; ks < 2; ks++) {
            const uint32_t ko = ks * 32;
            uint32_t af[16], bh[16], bl[16];
            #pragma unroll
            for (int mt = 0; mt < 4; mt++) ldsm_x4(af + 4*mt, s + arow + mt*1280 + ko);
            #pragma unroll
            for (int p = 0; p < 4; p++) ldsm_x4(bh + 4*p, s + G2_B0 + brow + p*1280 + ko);
            #pragma unroll
            for (int p = 0; p < 4; p++) ldsm_x4(bl + 4*p, s + G2_B1 + brow + p*1280 + ko);
            #pragma unroll
            for (int mt = 0; mt < 4; mt++)
                #pragma unroll
                for (int nt = 0; nt < 8; nt++) mma_bf16(acc[mt][nt], af + 4*mt, bh + 2*nt);
            #pragma unroll
            for (int mt = 0; mt < 4; mt++)
                #pragma unroll
                for (int nt = 0; nt < 8; nt++) mma_bf16(acc[mt][nt], af + 4*mt, bl + 2*nt);
            #pragma unroll
            for (int mt = 0; mt < 4; mt++) ldsm_x4(af + 4*mt, s + G2_AL + arow + mt*1280 + ko);
            #pragma unroll
            for (int mt = 0; mt < 4; mt++)
                #pragma unroll
                for (int nt = 0; nt < 8; nt++) mma_bf16(acc[mt][nt], af + 4*mt, bh + 2*nt);
        }

        if (it + 2 < nk) {
            uint32_t s2 = sbase + (uint32_t)((it + 2) % 3) * G2STAGE;
            int k0 = (it + 2) * 32;
            #pragma unroll
            for (int i = 0; i < 12; i++) {
                const void* p = src[i] + k0;
                asm volatile("cp.async.cg.shared.global [%0], [%1], 16;"
                             :: "r"(s2 + dst[i]), "l"(p) : "memory");
            }
        }
        asm volatile("cp.async.commit_group;" ::: "memory");
    }

    if (MODE == 6) {
        // QKV epilogue: bias + RoPE (q,k) + split into attention layout.
        const int part = (bn * 128 + wc * 64) >> 10;
        #pragma unroll
        for (int mt = 0; mt < 4; mt++) {
            #pragma unroll
            for (int half = 0; half < 2; half++) {
                int row = bm * 256 + wr * 64 + mt * 16 + g + half * 8;
                int b = row >> 11, ltok = row & (L_ - 1);
                if (part < 2) {
                    #pragma unroll
                    for (int np = 0; np < 4; np++) {
                        int col = bn*128 + wc*64 + np*8 + 2*t;
                        int pcol = col & 1023;
                        int head = pcol >> 6;
                        int i = pcol & 31;
                        float c0 = g_cos[ltok*32 + i],     s0 = g_sin[ltok*32 + i];
                        float c1 = g_cos[ltok*32 + i + 1], s1 = g_sin[ltok*32 + i + 1];
                        float x1a = acc[mt][np  ][half*2+0] + bias[col];
                        float x1b = acc[mt][np  ][half*2+1] + bias[col+1];
                        float x2a = acc[mt][np+4][half*2+0] + bias[col+32];
                        float x2b = acc[mt][np+4][half*2+1] + bias[col+33];
                        float r1a = x1a*c0 - x2a*s0, r2a = x2a*c0 + x1a*s0;
                        float r1b = x1b*c1 - x2b*s1, r2b = x2b*c1 + x1b*s1;
                        __nv_bfloat16 *oh, *ol;
                        if (part == 0) {
                            r1a *= 0.125f; r1b *= 0.125f; r2a *= 0.125f; r2b *= 0.125f;
                            oh = o1h; ol = o1l;
                        } else { oh = o2h; ol = o2l; }
                        size_t oi = (((size_t)(b*H_ + head)) * L_ + ltok) * HD_ + i;
                        unsigned short h0, l0, h1, l1;
                        split1(r1a, h0, l0); split1(r1b, h1, l1);
                        *(uint32_t*)(oh + oi) = (uint32_t)h0 | ((uint32_t)h1 << 16);
                        *(uint32_t*)(ol + oi) = (uint32_t)l0 | ((uint32_t)l1 << 16);
                        split1(r2a, h0, l0); split1(r2b, h1, l1);
                        *(uint32_t*)(oh + oi + 32) = (uint32_t)h0 | ((uint32_t)h1 << 16);
                        *(uint32_t*)(ol + oi + 32) = (uint32_t)l0 | ((uint32_t)l1 << 16);
                    }
                } else {
                    #pragma unroll
                    for (int nt = 0; nt < 8; nt++) {
                        int col = bn*128 + wc*64 + nt*8 + 2*t;
                        int pcol = col & 1023;
                        int head = pcol >> 6, d = pcol & 63;
                        float c0 = acc[mt][nt][half*2+0] + bias[col];
                        float c1 = acc[mt][nt][half*2+1] + bias[col+1];
                        size_t oi = (((size_t)(b*H_ + head)) * L_ + ltok) * HD_ + d;
                        unsigned short h0, l0, h1, l1;
                        split1(c0, h0, l0); split1(c1, h1, l1);
                        *(uint32_t*)(o3h + oi) = (uint32_t)h0 | ((uint32_t)h1 << 16);
                        *(uint32_t*)(o3l + oi) = (uint32_t)l0 | ((uint32_t)l1 << 16);
                    }
                }
            }
        }
        return;
    }

    #pragma unroll
    for (int mt = 0; mt < 4; mt++) {
        #pragma unroll
        for (int half = 0; half < 2; half++) {
            int row = bm * 256 + wr * 64 + mt * 16 + g + half * 8;
            #pragma unroll
            for (int nt = 0; nt < 8; nt++) {
                int col = bn * 128 + wc * 64 + nt * 8 + 2 * t;
                float c0 = acc[mt][nt][half * 2 + 0];
                float c1 = acc[mt][nt][half * 2 + 1];
                if (MODE <= 2) {
                    float* dstp = C + (size_t)row * N + col;
                    if (MODE == 1) { c0 += bias[col]; c1 += bias[col + 1]; }
                    float2 r = *(const float2*)dstp;
                    c0 += r.x; c1 += r.y;
                    *(float2*)dstp = make_float2(c0, c1);
                } else if (MODE == 3) {
                    float sg = c0 / (1.0f + expf(-c0)) * c1;
                    unsigned short hh, ll; split1(sg, hh, ll);
                    size_t oi = (size_t)row * F_ + (col >> 1);
                    o1h[oi] = __ushort_as_bfloat16(hh);
                    o1l[oi] = __ushort_as_bfloat16(ll);
                } else if (MODE == 4) {
                    int b = row >> 11, ltok = row & (L_ - 1);
                    int hd = col >> 6, d = col & 63;
                    size_t oi = (((size_t)(b*H_ + hd)) * L_ + ltok) * HD_ + d;
                    unsigned short h0, l0, h1, l1;
                    split1(c0 * 0.125f, h0, l0); split1(c1 * 0.125f, h1, l1);
                    *(uint32_t*)(o1h + oi) = (uint32_t)h0 | ((uint32_t)h1 << 16);
                    *(uint32_t*)(o1l + oi) = (uint32_t)l0 | ((uint32_t)l1 << 16);
                } else { // MODE 7: multi-layer cross-KV
                    int layer = col >> 11;
                    int c2 = col & 2047;
                    int kv = c2 >> 10;
                    int hd = (c2 >> 6) & 15, d = c2 & 63;
                    int b = row >> 8, stok = row & (S_ - 1);
                    size_t oi = (size_t)layer * CATN
                              + (((size_t)(b*H_ + hd)) * S_ + stok) * HD_ + d;
                    unsigned short h0, l0, h1, l1;
                    split1(c0, h0, l0); split1(c1, h1, l1);
                    __nv_bfloat16* ph = kv ? o2h : o1h;
                    __nv_bfloat16* pl = kv ? o2l : o1l;
                    *(uint32_t*)(ph + oi) = (uint32_t)h0 | ((uint32_t)h1 << 16);
                    *(uint32_t*)(pl + oi) = (uint32_t)l0 | ((uint32_t)l1 << 16);
                }
            }
        }
    }
}

// ---------------------------------------------------------------------------
// mma.sync flash self-attention. P·V uses Ph·Vh + Ph·Vl (Pl term dropped;
// P in [0,1] positive-sum, error ~1e-4 on output, within 1e-3 budget).
// ---------------------------------------------------------------------------
#define AT_ROW  144
#define AT_ARR  (64*AT_ROW)
#define AT_KV0  (2*AT_ARR)
#define AT_STG  (4*AT_ARR)
#define AT_SMEM (2*AT_ARR + 2*AT_STG)

__global__ void __launch_bounds__(128, 2)
self_attn_mma(const __nv_bfloat16* __restrict__ Qh, const __nv_bfloat16* __restrict__ Ql,
              const __nv_bfloat16* __restrict__ Kh, const __nv_bfloat16* __restrict__ Kl,
              const __nv_bfloat16* __restrict__ Vh, const __nv_bfloat16* __restrict__ Vl,
              __nv_bfloat16* __restrict__ out_hi, __nv_bfloat16* __restrict__ out_lo) {
    extern __shared__ char smraw[];
    const uint32_t sb = (uint32_t)__cvta_generic_to_shared(smraw);
    const int tid = threadIdx.x, warp = tid >> 5, lane = tid & 31;
    const int h = blockIdx.y, b = blockIdx.z;
    const int qbi = (int)(gridDim.x - 1 - blockIdx.x);
    const int qb = qbi * 64;
    const int ntiles = qbi + 1;
    const size_t hb = ((size_t)(b*H_ + h)) * L_;

    #pragma unroll
    for (int i = 0; i < 8; i++) {
        int id = tid + i * 128;
        int arr = id >> 9;
        int rem = id & 511;
        int row = rem >> 3, kc = rem & 7;
        const __nv_bfloat16* p = (arr ? Ql : Qh) + (hb + qb + row) * HD_ + kc * 8;
        uint32_t d = sb + (uint32_t)(arr * AT_ARR + row * AT_ROW + kc * 16);
        asm volatile("cp.async.cg.shared.global [%0], [%1], 16;" :: "r"(d), "l"(p) : "memory");
    }
    auto load_kv = [&](int t) {
        uint32_t base = sb + AT_KV0 + (uint32_t)(t & 1) * AT_STG;
        int k0 = t * 64;
        #pragma unroll
        for (int i = 0; i < 16; i++) {
            int id = tid + i * 128;
            int arr = id >> 9;
            int rem = id & 511;
            int row = rem >> 3, kc = rem & 7;
            const __nv_bfloat16* p = (arr==0?Kh:arr==1?Kl:arr==2?Vh:Vl) + (hb + k0 + row) * HD_ + kc * 8;
            uint32_t d = base + (uint32_t)(arr * AT_ARR + row * AT_ROW + kc * 16);
            asm volatile("cp.async.cg.shared.global [%0], [%1], 16;" :: "r"(d), "l"(p) : "memory");
        }
        asm volatile("cp.async.commit_group;" ::: "memory");
    };
    load_kv(0);
    if (ntiles > 1) load_kv(1);

    uint32_t qh[4][4], ql[4][4];
    float o[8][4];
    #pragma unroll
    for (int i = 0; i < 8; i++)
        #pragma unroll
        for (int j = 0; j < 4; j++) o[i][j] = 0.f;
    float mA = -1e30f, mB = -1e30f, lA = 0.f, lB = 0.f;

    for (int t = 0; t < ntiles; t++) {
        if (t + 1 < ntiles) { asm volatile("cp.async.wait_group 1;" ::: "memory"); }
        else                { asm volatile("cp.async.wait_group 0;" ::: "memory"); }
        __syncthreads();
        if (t == 0) {
            #pragma unroll
            for (int ks = 0; ks < 4; ks++) {
                uint32_t a = sb + (uint32_t)((warp*16 + (lane & 15)) * AT_ROW + ks*32 + (lane >> 4) * 16);
                ldsm_x4(qh[ks], a);
                ldsm_x4(ql[ks], a + AT_ARR);
            }
        }
        const uint32_t kvb = sb + AT_KV0 + (uint32_t)(t & 1) * AT_STG;

        float s[8][4];
        #pragma unroll
        for (int i = 0; i < 8; i++)
            #pragma unroll
            for (int j = 0; j < 4; j++) s[i][j] = 0.f;
        #pragma unroll
        for (int ks = 0; ks < 4; ks++) {
            uint32_t kh4[4][4], kl4[4][4];
            #pragma unroll
            for (int ntp = 0; ntp < 4; ntp++) {
                uint32_t a = kvb + (uint32_t)((ntp*16 + (lane & 7) + ((lane >> 4) << 3)) * AT_ROW
                                              + ks*32 + (((lane >> 3) & 1) << 4));
                ldsm_x4(kh4[ntp], a);
                ldsm_x4(kl4[ntp], a + AT_ARR);
            }
            #pragma unroll
            for (int ntp = 0; ntp < 4; ntp++) {
                mma_bf16(s[2*ntp],   qh[ks], kh4[ntp]);
                mma_bf16(s[2*ntp+1], qh[ks], kh4[ntp] + 2);
                mma_bf16(s[2*ntp],   qh[ks], kl4[ntp]);
                mma_bf16(s[2*ntp+1], qh[ks], kl4[ntp] + 2);
                mma_bf16(s[2*ntp],   ql[ks], kh4[ntp]);
                mma_bf16(s[2*ntp+1], ql[ks], kh4[ntp] + 2);
            }
        }
        if (t == ntiles - 1) {
            int rA = qb + warp*16 + (lane >> 2);
            int cbase = t*64 + 2*(lane & 3);
            #pragma unroll
            for (int nt = 0; nt < 8; nt++) {
                int c0 = cbase + nt*8, c1 = c0 + 1;
                if (c0 > rA)     s[nt][0] = -1e30f;
                if (c1 > rA)     s[nt][1] = -1e30f;
                if (c0 > rA + 8) s[nt][2] = -1e30f;
                if (c1 > rA + 8) s[nt][3] = -1e30f;
            }
        }
        float tmA = -1e30f, tmB = -1e30f;
        #pragma unroll
        for (int nt = 0; nt < 8; nt++) {
            tmA = fmaxf(tmA, fmaxf(s[nt][0], s[nt][1]));
            tmB = fmaxf(tmB, fmaxf(s[nt][2], s[nt][3]));
        }
        tmA = fmaxf(tmA, __shfl_xor_sync(0xffffffffu, tmA, 1));
        tmA = fmaxf(tmA, __shfl_xor_sync(0xffffffffu, tmA, 2));
        tmB = fmaxf(tmB, __shfl_xor_sync(0xffffffffu, tmB, 1));
        tmB = fmaxf(tmB, __shfl_xor_sync(0xffffffffu, tmB, 2));
        float nmA = fmaxf(mA, tmA), nmB = fmaxf(mB, tmB);
        float scA = __expf(mA - nmA), scB = __expf(mB - nmB);
        float tsA = 0.f, tsB = 0.f;
        #pragma unroll
        for (int nt = 0; nt < 8; nt++) {
            s[nt][0] = __expf(s[nt][0] - nmA);
            s[nt][1] = __expf(s[nt][1] - nmA);
            s[nt][2] = __expf(s[nt][2] - nmB);
            s[nt][3] = __expf(s[nt][3] - nmB);
            tsA += s[nt][0] + s[nt][1];
            tsB += s[nt][2] + s[nt][3];
        }
        tsA += __shfl_xor_sync(0xffffffffu, tsA, 1);
        tsA += __shfl_xor_sync(0xffffffffu, tsA, 2);
        tsB += __shfl_xor_sync(0xffffffffu, tsB, 1);
        tsB += __shfl_xor_sync(0xffffffffu, tsB, 2);
        lA = lA * scA + tsA;
        lB = lB * scB + tsB;
        #pragma unroll
        for (int nt = 0; nt < 8; nt++) {
            o[nt][0] *= scA; o[nt][1] *= scA;
            o[nt][2] *= scB; o[nt][3] *= scB;
        }
        mA = nmA; mB = nmB;
        #pragma unroll
        for (int kk = 0; kk < 4; kk++) {
            uint32_t ph[4];
            ph[0] = pack_bf16x2(s[2*kk][0],   s[2*kk][1]);
            ph[1] = pack_bf16x2(s[2*kk][2],   s[2*kk][3]);
            ph[2] = pack_bf16x2(s[2*kk+1][0], s[2*kk+1][1]);
            ph[3] = pack_bf16x2(s[2*kk+1][2], s[2*kk+1][3]);
            #pragma unroll
            for (int ntp = 0; ntp < 4; ntp++) {
                uint32_t vh4[4], vl4[4];
                uint32_t a = kvb + 2*AT_ARR + (uint32_t)((kk*16 + (lane & 15)) * AT_ROW
                                                        + ntp*32 + ((lane >> 4) << 4));
                ldsm_x4_t(vh4, a);
                ldsm_x4_t(vl4, a + AT_ARR);
                mma_bf16(o[2*ntp],   ph, vh4);
                mma_bf16(o[2*ntp+1], ph, vh4 + 2);
                mma_bf16(o[2*ntp],   ph, vl4);
                mma_bf16(o[2*ntp+1], ph, vl4 + 2);
            }
        }
        __syncthreads();
        if (t + 2 < ntiles) load_kv(t + 2);
    }

    float iA = 1.0f / lA, iB = 1.0f / lB;
    int qA = qb + warp*16 + (lane >> 2);
    size_t rowA = ((size_t)(b*L_ + qA)) * D_;
    size_t rowB = rowA + 8 * D_;
    int cb = h*HD_ + 2*(lane & 3);
    #pragma unroll
    for (int nt = 0; nt < 8; nt++) {
        int c = cb + nt*8;
        float a0 = o[nt][0]*iA, a1 = o[nt][1]*iA;
        float b0 = o[nt][2]*iB, b1 = o[nt][3]*iB;
        unsigned short h0,l0,h1,l1;
        split1(a0,h0,l0); split1(a1,h1,l1);
        *(uint32_t*)(out_hi + rowA + c) = (uint32_t)h0 | ((uint32_t)h1 << 16);
        *(uint32_t*)(out_lo + rowA + c) = (uint32_t)l0 | ((uint32_t)l1 << 16);
        split1(b0,h0,l0); split1(b1,h1,l1);
        *(uint32_t*)(out_hi + rowB + c) = (uint32_t)h0 | ((uint32_t)h1 << 16);
        *(uint32_t*)(out_lo + rowB + c) = (uint32_t)l0 | ((uint32_t)l1 << 16);
    }
}

// ---------------------------------------------------------------------------
// mma.sync cross-attention: 64-query CTA, all 4 key tiles (S=256), window
// mask (seg-128, seg] per row. P·V drops Pl term (same budget as self-attn).
// ---------------------------------------------------------------------------
__global__ void __launch_bounds__(128, 2)
cross_attn_mma(const __nv_bfloat16* __restrict__ Qh, const __nv_bfloat16* __restrict__ Ql,
               const __nv_bfloat16* __restrict__ Kh, const __nv_bfloat16* __restrict__ Kl,
               const __nv_bfloat16* __restrict__ Vh, const __nv_bfloat16* __restrict__ Vl,
               const int* __restrict__ seg_ids,
               __nv_bfloat16* __restrict__ out_hi, __nv_bfloat16* __restrict__ out_lo) {
    extern __shared__ char smraw[];
    const uint32_t sb = (uint32_t)__cvta_generic_to_shared(smraw);
    const int tid = threadIdx.x, warp = tid >> 5, lane = tid & 31;
    const int h = blockIdx.y, b = blockIdx.z;
    const int qb = (int)blockIdx.x * 64;
    const int ntiles = S_ / 64;
    const size_t hbQ = ((size_t)(b*H_ + h)) * L_;
    const size_t hbK = ((size_t)(b*H_ + h)) * S_;

    const int rA = qb + warp*16 + (lane >> 2);
    const int segA = seg_ids[b*L_ + rA];
    const int segB = seg_ids[b*L_ + rA + 8];

    #pragma unroll
    for (int i = 0; i < 8; i++) {
        int id = tid + i * 128;
        int arr = id >> 9;
        int rem = id & 511;
        int row = rem >> 3, kc = rem & 7;
        const __nv_bfloat16* p = (arr ? Ql : Qh) + (hbQ + qb + row) * HD_ + kc * 8;
        uint32_t d = sb + (uint32_t)(arr * AT_ARR + row * AT_ROW + kc * 16);
        asm volatile("cp.async.cg.shared.global [%0], [%1], 16;" :: "r"(d), "l"(p) : "memory");
    }
    auto load_kv = [&](int t) {
        uint32_t base = sb + AT_KV0 + (uint32_t)(t & 1) * AT_STG;
        int k0 = t * 64;
        #pragma unroll
        for (int i = 0; i < 16; i++) {
            int id = tid + i * 128;
            int arr = id >> 9;
            int rem = id & 511;
            int row = rem >> 3, kc = rem & 7;
            const __nv_bfloat16* p = (arr==0?Kh:arr==1?Kl:arr==2?Vh:Vl) + (hbK + k0 + row) * HD_ + kc * 8;
            uint32_t d = base + (uint32_t)(arr * AT_ARR + row * AT_ROW + kc * 16);
            asm volatile("cp.async.cg.shared.global [%0], [%1], 16;" :: "r"(d), "l"(p) : "memory");
        }
        asm volatile("cp.async.commit_group;" ::: "memory");
    };
    load_kv(0);
    load_kv(1);

    uint32_t qh[4][4], ql[4][4];
    float o[8][4];
    #pragma unroll
    for (int i = 0; i < 8; i++)
        #pragma unroll
        for (int j = 0; j < 4; j++) o[i][j] = 0.f;
    float mA = -1e30f, mB = -1e30f, lA = 0.f, lB = 0.f;

    for (int t = 0; t < ntiles; t++) {
        if (t + 1 < ntiles) { asm volatile("cp.async.wait_group 1;" ::: "memory"); }
        else                { asm volatile("cp.async.wait_group 0;" ::: "memory"); }
        __syncthreads();
        if (t == 0) {
            #pragma unroll
            for (int ks = 0; ks < 4; ks++) {
                uint32_t a = sb + (uint32_t)((warp*16 + (lane & 15)) * AT_ROW + ks*32 + (lane >> 4) * 16);
                ldsm_x4(qh[ks], a);
                ldsm_x4(ql[ks], a + AT_ARR);
            }
        }
        const uint32_t kvb = sb + AT_KV0 + (uint32_t)(t & 1) * AT_STG;

        float s[8][4];
        #pragma unroll
        for (int i = 0; i < 8; i++)
            #pragma unroll
            for (int j = 0; j < 4; j++) s[i][j] = 0.f;
        #pragma unroll
        for (int ks = 0; ks < 4; ks++) {
            uint32_t kh4[4][4], kl4[4][4];
            #pragma unroll
            for (int ntp = 0; ntp < 4; ntp++) {
                uint32_t a = kvb + (uint32_t)((ntp*16 + (lane & 7) + ((lane >> 4) << 3)) * AT_ROW
                                              + ks*32 + (((lane >> 3) & 1) << 4));
                ldsm_x4(kh4[ntp], a);
                ldsm_x4(kl4[ntp], a + AT_ARR);
            }
            #pragma unroll
            for (int ntp = 0; ntp < 4; ntp++) {
                mma_bf16(s[2*ntp],   qh[ks], kh4[ntp]);
                mma_bf16(s[2*ntp+1], qh[ks], kh4[ntp] + 2);
                mma_bf16(s[2*ntp],   qh[ks], kl4[ntp]);
                mma_bf16(s[2*ntp+1], qh[ks], kl4[ntp] + 2);
                mma_bf16(s[2*ntp],   ql[ks], kh4[ntp]);
                mma_bf16(s[2*ntp+1], ql[ks], kh4[ntp] + 2);
            }
        }
        {
            int cbase = t*64 + 2*(lane & 3);
            #pragma unroll
            for (int nt = 0; nt < 8; nt++) {
                int c0 = cbase + nt*8, c1 = c0 + 1;
                if (c0 > segA || c0 <= segA - 128) s[nt][0] = -1e30f;
                if (c1 > segA || c1 <= segA - 128) s[nt][1] = -1e30f;
                if (c0 > segB || c0 <= segB - 128) s[nt][2] = -1e30f;
                if (c1 > segB || c1 <= segB - 128) s[nt][3] = -1e30f;
            }
        }
        float tmA = -1e30f, tmB = -1e30f;
        #pragma unroll
        for (int nt = 0; nt < 8; nt++) {
            tmA = fmaxf(tmA, fmaxf(s[nt][0], s[nt][1]));
            tmB = fmaxf(tmB, fmaxf(s[nt][2], s[nt][3]));
        }
        tmA = fmaxf(tmA, __shfl_xor_sync(0xffffffffu, tmA, 1));
        tmA = fmaxf(tmA, __shfl_xor_sync(0xffffffffu, tmA, 2));
        tmB = fmaxf(tmB, __shfl_xor_sync(0xffffffffu, tmB, 1));
        tmB = fmaxf(tmB, __shfl_xor_sync(0xffffffffu, tmB, 2));
        float nmA = fmaxf(mA, tmA), nmB = fmaxf(mB, tmB);
        float scA = __expf(mA - nmA), scB = __expf(mB - nmB);
        float tsA = 0.f, tsB = 0.f;
        #pragma unroll
        for (int nt = 0; nt < 8; nt++) {
            s[nt][0] = __expf(s[nt][0] - nmA);
            s[nt][1] = __expf(s[nt][1] - nmA);
            s[nt][2] = __expf(s[nt][2] - nmB);
            s[nt][3] = __expf(s[nt][3] - nmB);
            tsA += s[nt][0] + s[nt][1];
            tsB += s[nt][2] + s[nt][3];
        }
        tsA += __shfl_xor_sync(0xffffffffu, tsA, 1);
        tsA += __shfl_xor_sync(0xffffffffu, tsA, 2);
        tsB += __shfl_xor_sync(0xffffffffu, tsB, 1);
        tsB += __shfl_xor_sync(0xffffffffu, tsB, 2);
        lA = lA * scA + tsA;
        lB = lB * scB + tsB;
        #pragma unroll
        for (int nt = 0; nt < 8; nt++) {
            o[nt][0] *= scA; o[nt][1] *= scA;
            o[nt][2] *= scB; o[nt][3] *= scB;
        }
        mA = nmA; mB = nmB;
        #pragma unroll
        for (int kk = 0; kk < 4; kk++) {
            uint32_t ph[4];
            ph[0] = pack_bf16x2(s[2*kk][0],   s[2*kk][1]);
            ph[1] = pack_bf16x2(s[2*kk][2],   s[2*kk][3]);
            ph[2] = pack_bf16x2(s[2*kk+1][0], s[2*kk+1][1]);
            ph[3] = pack_bf16x2(s[2*kk+1][2], s[2*kk+1][3]);
            #pragma unroll
            for (int ntp = 0; ntp < 4; ntp++) {
                uint32_t vh4[4], vl4[4];
                uint32_t a = kvb + 2*AT_ARR + (uint32_t)((kk*16 + (lane & 15)) * AT_ROW
                                                        + ntp*32 + ((lane >> 4) << 4));
                ldsm_x4_t(vh4, a);
                ldsm_x4_t(vl4, a + AT_ARR);
                mma_bf16(o[2*ntp],   ph, vh4);
                mma_bf16(o[2*ntp+1], ph, vh4 + 2);
                mma_bf16(o[2*ntp],   ph, vl4);
                mma_bf16(o[2*ntp+1], ph, vl4 + 2);
            }
        }
        __syncthreads();
        if (t + 2 < ntiles) load_kv(t + 2);
    }

    float iA = 1.0f / lA, iB = 1.0f / lB;
    size_t rowA = ((size_t)(b*L_ + rA)) * D_;
    size_t rowB = rowA + 8 * D_;
    int cb = h*HD_ + 2*(lane & 3);
    #pragma unroll
    for (int nt = 0; nt < 8; nt++) {
        int c = cb + nt*8;
        float a0 = o[nt][0]*iA, a1 = o[nt][1]*iA;
        float b0 = o[nt][2]*iB, b1 = o[nt][3]*iB;
        unsigned short h0,l0,h1,l1;
        split1(a0,h0,l0); split1(a1,h1,l1);
        *(uint32_t*)(out_hi + rowA + c) = (uint32_t)h0 | ((uint32_t)h1 << 16);
        *(uint32_t*)(out_lo + rowA + c) = (uint32_t)l0 | ((uint32_t)l1 << 16);
        split1(b0,h0,l0); split1(b1,h1,l1);
        *(uint32_t*)(out_hi + rowB + c) = (uint32_t)h0 | ((uint32_t)h1 << 16);
        *(uint32_t*)(out_lo + rowB + c) = (uint32_t)l0 | ((uint32_t)l1 << 16);
    }
}

// ---------------------------------------------------------------------------
// Launch
// ---------------------------------------------------------------------------
static inline void split_launch(const float* src, __nv_bfloat16* hi, __nv_bfloat16* lo, size_t n) {
    int n4 = (int)(n / 4);
    split_k<<<(n4 + 255) / 256, 256>>>(src, hi, lo, n4);
}

extern "C" void kernel_launch(void* const* d_in, const int* in_sizes, int n_in,
                              void* d_out, int out_size) {
    const float* x      = (const float*)d_in[0];
    const float* memory = (const float*)d_in[1];
    const int*   seg    = (const int*)  d_in[2];
    const float* Wqkv   = (const float*)d_in[3];
    const float* bqkv   = (const float*)d_in[4];
    const float* Wo     = (const float*)d_in[5];
    const float* bo     = (const float*)d_in[6];
    const float* Wq_c   = (const float*)d_in[7];
    const float* Wkv_c  = (const float*)d_in[8];
    const float* Wo_c   = (const float*)d_in[9];
    const float* Wg     = (const float*)d_in[10];
    const float* Wu     = (const float*)d_in[11];
    const float* Wd     = (const float*)d_in[12];
    const float* n1     = (const float*)d_in[13];
    const float* n2     = (const float*)d_in[14];
    const float* n3     = (const float*)d_in[15];
    const float* nf     = (const float*)d_in[16];

    cudaFuncSetAttribute(gemm_bf16s<1>, cudaFuncAttributeMaxDynamicSharedMemorySize, GSMEM);
    cudaFuncSetAttribute(gemm_bf16s<2>, cudaFuncAttributeMaxDynamicSharedMemorySize, GSMEM);
    cudaFuncSetAttribute(gemm_bf16s<3>, cudaFuncAttributeMaxDynamicSharedMemorySize, GSMEM);
    cudaFuncSetAttribute(gemm_bf16s<4>, cudaFuncAttributeMaxDynamicSharedMemorySize, GSMEM);
    cudaFuncSetAttribute(gemm_bf16s<6>, cudaFuncAttributeMaxDynamicSharedMemorySize, GSMEM);
    cudaFuncSetAttribute(gemm_bf16s<7>, cudaFuncAttributeMaxDynamicSharedMemorySize, GSMEM);
    cudaFuncSetAttribute(self_attn_mma,  cudaFuncAttributeMaxDynamicSharedMemorySize, AT_SMEM);
    cudaFuncSetAttribute(cross_attn_mma, cudaFuncAttributeMaxDynamicSharedMemorySize, AT_SMEM);

    float *xb;
    __nv_bfloat16 *hhi, *hlo, *ahi, *alo, *chi, *clo, *gshi, *gslo, *mhi, *mlo, *whi, *wlo;
    __nv_bfloat16 *sqh, *sql, *skh, *skl, *svh, *svl;
    __nv_bfloat16 *ckh, *ckl, *cvh, *cvl;
    cudaGetSymbolAddress((void**)&xb,   g_x);
    cudaGetSymbolAddress((void**)&hhi,  g_h_hi);  cudaGetSymbolAddress((void**)&hlo,  g_h_lo);
    cudaGetSymbolAddress((void**)&ahi,  g_at_hi); cudaGetSymbolAddress((void**)&alo,  g_at_lo);
    cudaGetSymbolAddress((void**)&chi,  g_co_hi); cudaGetSymbolAddress((void**)&clo,  g_co_lo);
    cudaGetSymbolAddress((void**)&gshi, g_gs_hi); cudaGetSymbolAddress((void**)&gslo, g_gs_lo);
    cudaGetSymbolAddress((void**)&mhi,  g_m_hi);  cudaGetSymbolAddress((void**)&mlo,  g_m_lo);
    cudaGetSymbolAddress((void**)&whi,  g_w_hi);  cudaGetSymbolAddress((void**)&wlo,  g_w_lo);
    cudaGetSymbolAddress((void**)&sqh,  g_sqh);   cudaGetSymbolAddress((void**)&sql,  g_sql);
    cudaGetSymbolAddress((void**)&skh,  g_skh);   cudaGetSymbolAddress((void**)&skl,  g_skl);
    cudaGetSymbolAddress((void**)&svh,  g_svh);   cudaGetSymbolAddress((void**)&svl,  g_svl);
    cudaGetSymbolAddress((void**)&ckh,  g_ckh);   cudaGetSymbolAddress((void**)&ckl,  g_ckl);
    cudaGetSymbolAddress((void**)&cvh,  g_cvh);   cudaGetSymbolAddress((void**)&cvl,  g_cvl);

    rope_cache_k<<<256, 256>>>();
    copy_x_k<<<(M_*D_)/256, 256>>>(x);

    split_launch(Wqkv,  whi + O_WQKV, wlo + O_WQKV, NL*SZ_WQKV);
    split_launch(Wo,    whi + O_WO,   wlo + O_WO,   NL*SZ_WO);
    split_launch(Wq_c,  whi + O_WQC,  wlo + O_WQC,  NL*SZ_WQC);
    split_launch(Wkv_c, whi + O_WKVC, wlo + O_WKVC, NL*SZ_WKVC);
    split_launch(Wo_c,  whi + O_WOC,  wlo + O_WOC,  NL*SZ_WOC);
    for (int l = 0; l < NL; l++) {
        int n4 = (int)((size_t)F_*D_/4);
        split_ilv_k<<<(n4 + 255)/256, 256>>>(Wg + (size_t)l*F_*D_,
            whi + O_WGU + l*SZ_WGU, wlo + O_WGU + l*SZ_WGU, n4, D_/4, 0);
        split_ilv_k<<<(n4 + 255)/256, 256>>>(Wu + (size_t)l*F_*D_,
            whi + O_WGU + l*SZ_WGU, wlo + O_WGU + l*SZ_WGU, n4, D_/4, 1);
    }
    split_launch(Wd,    whi + O_WD,   wlo + O_WD,   NL*SZ_WD);
    split_launch(memory, mhi, mlo, (size_t)B_*S_*D_);

    // upfront: all 4 layers' cross K/V in one GEMM (layer-independent)
    gemm_bf16s<7><<<dim3(NL*2*D_/128, (B_*S_)/256), 256, GSMEM>>>(
        mhi, mlo, whi + O_WKVC, wlo + O_WKVC, nullptr, nullptr,
        ckh, ckl, cvh, cvl, nullptr, nullptr, NL*2*D_, D_);

    const dim3 self_grid(L_/64, H_, B_);
    const dim3 cross_grid(L_/64, H_, B_);

    for (int l = 0; l < NL; l++) {
        const __nv_bfloat16* wqkv_h = whi + O_WQKV + l*SZ_WQKV;
        const __nv_bfloat16* wqkv_l = wlo + O_WQKV + l*SZ_WQKV;
        const __nv_bfloat16* wo_h   = whi + O_WO   + l*SZ_WO;
        const __nv_bfloat16* wo_l   = wlo + O_WO   + l*SZ_WO;
        const __nv_bfloat16* wqc_h  = whi + O_WQC  + l*SZ_WQC;
        const __nv_bfloat16* wqc_l  = wlo + O_WQC  + l*SZ_WQC;
        const __nv_bfloat16* woc_h  = whi + O_WOC  + l*SZ_WOC;
        const __nv_bfloat16* woc_l  = wlo + O_WOC  + l*SZ_WOC;
        const __nv_bfloat16* wgu_h  = whi + O_WGU  + l*SZ_WGU;
        const __nv_bfloat16* wgu_l  = wlo + O_WGU  + l*SZ_WGU;
        const __nv_bfloat16* wd_h   = whi + O_WD   + l*SZ_WD;
        const __nv_bfloat16* wd_l   = wlo + O_WD   + l*SZ_WD;

        // --- self attention block (QKV GEMM fuses bias+RoPE+split) ---
        rmsnorm_split_k<<<M_, 256>>>(xb, n1 + l*D_, hhi, hlo);
        gemm_bf16s<6><<<dim3(3*D_/128, M_/256), 256, GSMEM>>>(
            hhi, hlo, wqkv_h, wqkv_l, bqkv + l*3*D_, nullptr,
            sqh, sql, skh, skl, svh, svl, 3*D_, D_);
        self_attn_mma<<<self_grid, 128, AT_SMEM>>>(sqh, sql, skh, skl, svh, svl, ahi, alo);
        gemm_bf16s<1><<<dim3(D_/128, M_/256), 256, GSMEM>>>(
            ahi, alo, wo_h, wo_l, bo + l*D_, xb,
            nullptr, nullptr, nullptr, nullptr, nullptr, nullptr, D_, D_);

        // --- cross attention block ---
        rmsnorm_split_k<<<M_, 256>>>(xb, n2 + l*D_, hhi, hlo);
        gemm_bf16s<4><<<dim3(D_/128, M_/256), 256, GSMEM>>>(
            hhi, hlo, wqc_h, wqc_l, nullptr, nullptr,
            sqh, sql, nullptr, nullptr, nullptr, nullptr, D_, D_);
        cross_attn_mma<<<cross_grid, 128, AT_SMEM>>>(
            sqh, sql, ckh + l*CATN, ckl + l*CATN, cvh + l*CATN, cvl + l*CATN,
            seg, chi, clo);
        gemm_bf16s<2><<<dim3(D_/128, M_/256), 256, GSMEM>>>(
            chi, clo, woc_h, woc_l, nullptr, xb,
            nullptr, nullptr, nullptr, nullptr, nullptr, nullptr, D_, D_);

        // --- MLP block (fused gate|up GEMM with swiglu epilogue) ---
        rmsnorm_split_k<<<M_, 256>>>(xb, n3 + l*D_, hhi, hlo);
        gemm_bf16s<3><<<dim3(2*F_/128, M_/256), 256, GSMEM>>>(
            hhi, hlo, wgu_h, wgu_l, nullptr, nullptr,
            gshi, gslo, nullptr, nullptr, nullptr, nullptr, 2*F_, D_);
        gemm_bf16s<2><<<dim3(D_/128, M_/256), 256, GSMEM>>>(
            gshi, gslo, wd_h, wd_l, nullptr, xb,
            nullptr, nullptr, nullptr, nullptr, nullptr, nullptr, D_, F_);
    }

    rmsnorm_k<<<M_, 256>>>(xb, nf, (float*)d_out);
}

// round 12
// speedup vs baseline: 4.7676x; 1.0066x over previous
#include <cuda_runtime.h>
#include <cuda_bf16.h>
#include <math.h>
#include <stdint.h>

// Problem constants
#define NL 4
#define B_ 2
#define L_ 2048
#define S_ 256
#define D_ 1024
#define F_ 4096
#define H_ 16
#define HD_ 64
#define M_ (B_*L_)          // 4096 token rows

// Weight region sizes (elements) and offsets in the concatenated split buffer
#define SZ_WQKV ((size_t)3*D_*D_)
#define SZ_WO   ((size_t)D_*D_)
#define SZ_WQC  ((size_t)D_*D_)
#define SZ_WKVC ((size_t)2*D_*D_)
#define SZ_WOC  ((size_t)D_*D_)
#define SZ_WGU  ((size_t)2*F_*D_)     // interleaved [g0,u0,g1,u1,...] per layer
#define SZ_WD   ((size_t)D_*F_)
static const size_t O_WQKV = 0;
static const size_t O_WO   = O_WQKV + NL*SZ_WQKV;
static const size_t O_WQC  = O_WO   + NL*SZ_WO;
static const size_t O_WKVC = O_WQC  + NL*SZ_WQC;
static const size_t O_WOC  = O_WKVC + NL*SZ_WKVC;
static const size_t O_WGU  = O_WOC  + NL*SZ_WOC;
static const size_t O_WD   = O_WGU  + NL*SZ_WGU;
#define WTOT (O_WD + NL*SZ_WD)

// ---------------------------------------------------------------------------
// Scratch (device globals; no allocations allowed)
// ---------------------------------------------------------------------------
__device__ float g_x  [M_*D_];
__device__ float g_cos[L_*32];
__device__ float g_sin[L_*32];

__device__ __nv_bfloat16 g_h_hi [M_*D_],  g_h_lo [M_*D_];
__device__ __nv_bfloat16 g_at_hi[M_*D_],  g_at_lo[M_*D_];
__device__ __nv_bfloat16 g_co_hi[M_*D_],  g_co_lo[M_*D_];
__device__ __nv_bfloat16 g_gs_hi[M_*F_],  g_gs_lo[M_*F_];
__device__ __nv_bfloat16 g_m_hi [B_*S_*D_], g_m_lo[B_*S_*D_];
__device__ __nv_bfloat16 g_w_hi[WTOT], g_w_lo[WTOT];

// attention-layout split buffers: [B][H][L][64] (self q/k/v; cross q reuses q)
#define ATN ((size_t)B_*H_*L_*HD_)
__device__ __nv_bfloat16 g_sqh[ATN], g_sql[ATN];
__device__ __nv_bfloat16 g_skh[ATN], g_skl[ATN];
__device__ __nv_bfloat16 g_svh[ATN], g_svl[ATN];

// per-layer cross K/V: [NL][B][H][S][64]
#define CATN ((size_t)B_*H_*S_*HD_)
__device__ __nv_bfloat16 g_ckh[NL*CATN], g_ckl[NL*CATN];
__device__ __nv_bfloat16 g_cvh[NL*CATN], g_cvl[NL*CATN];

// ---------------------------------------------------------------------------
// bf16 split helpers
// ---------------------------------------------------------------------------
__device__ __forceinline__ void split1(float v, unsigned short& h, unsigned short& l) {
    __nv_bfloat16 hb = __float2bfloat16_rn(v);
    float r = v - __bfloat162float(hb);
    __nv_bfloat16 lb = __float2bfloat16_rn(r);
    h = __bfloat16_as_ushort(hb);
    l = __bfloat16_as_ushort(lb);
}
__device__ __forceinline__ void split_pack4(float4 v, uint2& ph, uint2& pl) {
    unsigned short h0,h1,h2,h3,l0,l1,l2,l3;
    split1(v.x,h0,l0); split1(v.y,h1,l1); split1(v.z,h2,l2); split1(v.w,h3,l3);
    ph.x = (uint32_t)h0 | ((uint32_t)h1 << 16);
    ph.y = (uint32_t)h2 | ((uint32_t)h3 << 16);
    pl.x = (uint32_t)l0 | ((uint32_t)l1 << 16);
    pl.y = (uint32_t)l2 | ((uint32_t)l3 << 16);
}

__global__ void split_k(const float* __restrict__ in, __nv_bfloat16* __restrict__ hi,
                        __nv_bfloat16* __restrict__ lo, int n4) {
    int i = blockIdx.x * blockDim.x + threadIdx.x;
    if (i >= n4) return;
    float4 v = ((const float4*)in)[i];
    uint2 ph, pl; split_pack4(v, ph, pl);
    ((uint2*)hi)[i] = ph;
    ((uint2*)lo)[i] = pl;
}

// Interleaving split: source row r -> destination row 2r+off (rowQuads float4s per row)
__global__ void split_ilv_k(const float* __restrict__ in, __nv_bfloat16* __restrict__ hi,
                            __nv_bfloat16* __restrict__ lo, int n4, int rowQuads, int off) {
    int i = blockIdx.x * blockDim.x + threadIdx.x;
    if (i >= n4) return;
    int r = i / rowQuads, c = i % rowQuads;
    float4 v = ((const float4*)in)[i];
    uint2 ph, pl; split_pack4(v, ph, pl);
    size_t oi = (size_t)(2*r + off) * rowQuads + c;
    ((uint2*)hi)[oi] = ph;
    ((uint2*)lo)[oi] = pl;
}

// ---------------------------------------------------------------------------
// RoPE cache
// ---------------------------------------------------------------------------
__global__ void rope_cache_k() {
    int idx = blockIdx.x * blockDim.x + threadIdx.x;
    int l = idx >> 5, i = idx & 31;
    double inv = exp(-log(10000.0) * (double)i / 32.0);
    double f = (double)l * inv;
    g_cos[idx] = (float)cos(f);
    g_sin[idx] = (float)sin(f);
}

__global__ void copy_x_k(const float* __restrict__ x) {
    size_t i = (size_t)blockIdx.x * blockDim.x + threadIdx.x;
    if (i < (size_t)M_ * D_) g_x[i] = x[i];
}

// ---------------------------------------------------------------------------
// RMSNorm kernels
// ---------------------------------------------------------------------------
__global__ void rmsnorm_split_k(const float* __restrict__ x, const float* __restrict__ w,
                                __nv_bfloat16* __restrict__ hi, __nv_bfloat16* __restrict__ lo) {
    int row = blockIdx.x;
    int t = threadIdx.x;
    const float4* xr = (const float4*)(x + (size_t)row * D_);
    float4 v = xr[t];
    float ss = v.x*v.x + v.y*v.y + v.z*v.z + v.w*v.w;
    #pragma unroll
    for (int off = 16; off; off >>= 1) ss += __shfl_xor_sync(0xffffffffu, ss, off);
    __shared__ float red[8];
    if ((t & 31) == 0) red[t >> 5] = ss;
    __syncthreads();
    float tot = red[0]+red[1]+red[2]+red[3]+red[4]+red[5]+red[6]+red[7];
    float rs = rsqrtf(tot * (1.0f / (float)D_) + 1e-6f);
    float4 wv = ((const float4*)w)[t];
    float4 o;
    o.x = v.x * rs * wv.x; o.y = v.y * rs * wv.y;
    o.z = v.z * rs * wv.z; o.w = v.w * rs * wv.w;
    uint2 ph, pl; split_pack4(o, ph, pl);
    ((uint2*)hi)[(size_t)row * 256 + t] = ph;
    ((uint2*)lo)[(size_t)row * 256 + t] = pl;
}

__global__ void rmsnorm_k(const float* __restrict__ x, const float* __restrict__ w,
                          float* __restrict__ o) {
    int row = blockIdx.x;
    int t = threadIdx.x;
    const float4* xr = (const float4*)(x + (size_t)row * D_);
    float4 v = xr[t];
    float ss = v.x*v.x + v.y*v.y + v.z*v.z + v.w*v.w;
    #pragma unroll
    for (int off = 16; off; off >>= 1) ss += __shfl_xor_sync(0xffffffffu, ss, off);
    __shared__ float red[8];
    if ((t & 31) == 0) red[t >> 5] = ss;
    __syncthreads();
    float tot = red[0]+red[1]+red[2]+red[3]+red[4]+red[5]+red[6]+red[7];
    float rs = rsqrtf(tot * (1.0f / (float)D_) + 1e-6f);
    float4 wv = ((const float4*)w)[t];
    float4 out;
    out.x = v.x * rs * wv.x; out.y = v.y * rs * wv.y;
    out.z = v.z * rs * wv.z; out.w = v.w * rs * wv.w;
    ((float4*)(o + (size_t)row * D_))[t] = out;
}

// ---------------------------------------------------------------------------
// mma / ldmatrix helpers
// ---------------------------------------------------------------------------
__device__ __forceinline__ void mma_bf16(float* c, const uint32_t* a, const uint32_t* b) {
    asm volatile(
        "mma.sync.aligned.m16n8k16.row.col.f32.bf16.bf16.f32 "
        "{%0,%1,%2,%3}, {%4,%5,%6,%7}, {%8,%9}, {%0,%1,%2,%3};"
        : "+f"(c[0]), "+f"(c[1]), "+f"(c[2]), "+f"(c[3])
        : "r"(a[0]), "r"(a[1]), "r"(a[2]), "r"(a[3]), "r"(b[0]), "r"(b[1]));
}
__device__ __forceinline__ void ldsm_x4(uint32_t* r, uint32_t addr) {
    asm volatile("ldmatrix.sync.aligned.m8n8.x4.shared.b16 {%0,%1,%2,%3}, [%4];"
        : "=r"(r[0]), "=r"(r[1]), "=r"(r[2]), "=r"(r[3]) : "r"(addr));
}
__device__ __forceinline__ void ldsm_x4_t(uint32_t* r, uint32_t addr) {
    asm volatile("ldmatrix.sync.aligned.m8n8.x4.trans.shared.b16 {%0,%1,%2,%3}, [%4];"
        : "=r"(r[0]), "=r"(r[1]), "=r"(r[2]), "=r"(r[3]) : "r"(addr));
}
__device__ __forceinline__ uint32_t pack_bf16x2(float lo, float hi) {
    return (uint32_t)__bfloat16_as_ushort(__float2bfloat16_rn(lo)) |
           ((uint32_t)__bfloat16_as_ushort(__float2bfloat16_rn(hi)) << 16);
}

// ---------------------------------------------------------------------------
// bf16 split-3 GEMM (NT), 256x128 CTA tile, warp tile 64x64 (8 warps, 4x2).
// MODE 1: +bias +residual    -> fp32 C      (Wo)
// MODE 2: +residual          -> fp32 C      (Wo_c, Wd)
// MODE 3: swiglu (interleaved g|u cols) -> bf16 hi/lo [M][F]
// MODE 4: attn-q layout, x0.125         -> bf16 hi/lo [B][H][L][64]
// MODE 6: QKV: +bias, RoPE on q/k, q x0.125 -> q/k/v bf16 hi/lo [B][H][L][64]
// MODE 7: multi-layer cross-KV           -> per-layer k/v [NL][B][H][S][64]
// ---------------------------------------------------------------------------
#define G2STAGE 61440
#define G2_AL   20480
#define G2_B0   40960
#define G2_B1   51200
#define GSMEM   (3*G2STAGE)

template <int MODE>
__global__ void __launch_bounds__(256, 1)
gemm_bf16s(const __nv_bfloat16* __restrict__ Ah, const __nv_bfloat16* __restrict__ Al,
           const __nv_bfloat16* __restrict__ Wh, const __nv_bfloat16* __restrict__ Wl,
           const float* __restrict__ bias, float* __restrict__ C,
           __nv_bfloat16* __restrict__ o1h, __nv_bfloat16* __restrict__ o1l,
           __nv_bfloat16* __restrict__ o2h, __nv_bfloat16* __restrict__ o2l,
           __nv_bfloat16* __restrict__ o3h, __nv_bfloat16* __restrict__ o3l,
           int N, int K) {
    extern __shared__ char smem[];
    const uint32_t sbase = (uint32_t)__cvta_generic_to_shared(smem);
    const int tid  = threadIdx.x;
    const int warp = tid >> 5, lane = tid & 31;
    const int wr = warp >> 1;      // 0..3 : 64-row slab
    const int wc = warp & 1;       // 0..1 : 64-col slab
    const int g  = lane >> 2;
    const int t  = lane & 3;
    const int bm = blockIdx.y, bn = blockIdx.x;

    // cp.async chunk tables: 3072 16B-chunks per stage, 12 per thread
    const __nv_bfloat16* src[12];
    uint32_t dst[12];
    #pragma unroll
    for (int i = 0; i < 12; i++) {
        int id = tid + (i << 8);
        const __nv_bfloat16* bp;
        int grow; uint32_t off; int kc;
        if (id < 2048) {
            int arr = id >> 10, rem = id & 1023;
            int row = rem >> 2; kc = rem & 3;
            bp = arr ? Al : Ah;
            grow = bm * 256 + row;
            off = (uint32_t)(arr * G2_AL + row * 80 + kc * 16);
        } else {
            int id2 = id - 2048;
            int arr = id2 >> 9, rem = id2 & 511;
            int row = rem >> 2; kc = rem & 3;
            bp = arr ? Wl : Wh;
            grow = bn * 128 + row;
            off = (uint32_t)(G2_B0 + arr * 10240 + row * 80 + kc * 16);
        }
        src[i] = bp + (size_t)grow * K + kc * 8;
        dst[i] = off;
    }

    const uint32_t arow = (uint32_t)((wr * 64 + (lane & 15)) * 80 + (lane >> 4) * 16);
    const uint32_t brow = (uint32_t)((wc * 64 + (lane & 7) + ((lane >> 4) << 3)) * 80
                                     + (((lane >> 3) & 1) << 4));

    float acc[4][8][4];
    #pragma unroll
    for (int i = 0; i < 4; i++)
        #pragma unroll
        for (int j = 0; j < 8; j++)
            #pragma unroll
            for (int r = 0; r < 4; r++) acc[i][j][r] = 0.f;

    const int nk = K >> 5;

    #pragma unroll
    for (int st = 0; st < 2; st++) {
        uint32_t s = sbase + st * G2STAGE;
        #pragma unroll
        for (int i = 0; i < 12; i++) {
            const void* p = src[i] + st * 32;
            asm volatile("cp.async.cg.shared.global [%0], [%1], 16;"
                         :: "r"(s + dst[i]), "l"(p) : "memory");
        }
        asm volatile("cp.async.commit_group;" ::: "memory");
    }

    for (int it = 0; it < nk; it++) {
        asm volatile("cp.async.wait_group 1;" ::: "memory");
        __syncthreads();
        uint32_t s = sbase + (uint32_t)(it % 3) * G2STAGE;

        #pragma unroll
        for (int ks = 0; ks < 2; ks++) {
            const uint32_t ko = ks * 32;
            uint32_t af[16], bh[16], bl[16];
            #pragma unroll
            for (int mt = 0; mt < 4; mt++) ldsm_x4(af + 4*mt, s + arow + mt*1280 + ko);
            #pragma unroll
            for (int p = 0; p < 4; p++) ldsm_x4(bh + 4*p, s + G2_B0 + brow + p*1280 + ko);
            #pragma unroll
            for (int p = 0; p < 4; p++) ldsm_x4(bl + 4*p, s + G2_B1 + brow + p*1280 + ko);
            #pragma unroll
            for (int mt = 0; mt < 4; mt++)
                #pragma unroll
                for (int nt = 0; nt < 8; nt++) mma_bf16(acc[mt][nt], af + 4*mt, bh + 2*nt);
            #pragma unroll
            for (int mt = 0; mt < 4; mt++)
                #pragma unroll
                for (int nt = 0; nt < 8; nt++) mma_bf16(acc[mt][nt], af + 4*mt, bl + 2*nt);
            #pragma unroll
            for (int mt = 0; mt < 4; mt++) ldsm_x4(af + 4*mt, s + G2_AL + arow + mt*1280 + ko);
            #pragma unroll
            for (int mt = 0; mt < 4; mt++)
                #pragma unroll
                for (int nt = 0; nt < 8; nt++) mma_bf16(acc[mt][nt], af + 4*mt, bh + 2*nt);
        }

        if (it + 2 < nk) {
            uint32_t s2 = sbase + (uint32_t)((it + 2) % 3) * G2STAGE;
            int k0 = (it + 2) * 32;
            #pragma unroll
            for (int i = 0; i < 12; i++) {
                const void* p = src[i] + k0;
                asm volatile("cp.async.cg.shared.global [%0], [%1], 16;"
                             :: "r"(s2 + dst[i]), "l"(p) : "memory");
            }
        }
        asm volatile("cp.async.commit_group;" ::: "memory");
    }

    if (MODE == 6) {
        // QKV epilogue: bias + RoPE (q,k) + split into attention layout.
        const int part = (bn * 128 + wc * 64) >> 10;
        #pragma unroll
        for (int mt = 0; mt < 4; mt++) {
            #pragma unroll
            for (int half = 0; half < 2; half++) {
                int row = bm * 256 + wr * 64 + mt * 16 + g + half * 8;
                int b = row >> 11, ltok = row & (L_ - 1);
                if (part < 2) {
                    #pragma unroll
                    for (int np = 0; np < 4; np++) {
                        int col = bn*128 + wc*64 + np*8 + 2*t;
                        int pcol = col & 1023;
                        int head = pcol >> 6;
                        int i = pcol & 31;
                        float c0 = g_cos[ltok*32 + i],     s0 = g_sin[ltok*32 + i];
                        float c1 = g_cos[ltok*32 + i + 1], s1 = g_sin[ltok*32 + i + 1];
                        float x1a = acc[mt][np  ][half*2+0] + bias[col];
                        float x1b = acc[mt][np  ][half*2+1] + bias[col+1];
                        float x2a = acc[mt][np+4][half*2+0] + bias[col+32];
                        float x2b = acc[mt][np+4][half*2+1] + bias[col+33];
                        float r1a = x1a*c0 - x2a*s0, r2a = x2a*c0 + x1a*s0;
                        float r1b = x1b*c1 - x2b*s1, r2b = x2b*c1 + x1b*s1;
                        __nv_bfloat16 *oh, *ol;
                        if (part == 0) {
                            r1a *= 0.125f; r1b *= 0.125f; r2a *= 0.125f; r2b *= 0.125f;
                            oh = o1h; ol = o1l;
                        } else { oh = o2h; ol = o2l; }
                        size_t oi = (((size_t)(b*H_ + head)) * L_ + ltok) * HD_ + i;
                        unsigned short h0, l0, h1, l1;
                        split1(r1a, h0, l0); split1(r1b, h1, l1);
                        *(uint32_t*)(oh + oi) = (uint32_t)h0 | ((uint32_t)h1 << 16);
                        *(uint32_t*)(ol + oi) = (uint32_t)l0 | ((uint32_t)l1 << 16);
                        split1(r2a, h0, l0); split1(r2b, h1, l1);
                        *(uint32_t*)(oh + oi + 32) = (uint32_t)h0 | ((uint32_t)h1 << 16);
                        *(uint32_t*)(ol + oi + 32) = (uint32_t)l0 | ((uint32_t)l1 << 16);
                    }
                } else {
                    #pragma unroll
                    for (int nt = 0; nt < 8; nt++) {
                        int col = bn*128 + wc*64 + nt*8 + 2*t;
                        int pcol = col & 1023;
                        int head = pcol >> 6, d = pcol & 63;
                        float c0 = acc[mt][nt][half*2+0] + bias[col];
                        float c1 = acc[mt][nt][half*2+1] + bias[col+1];
                        size_t oi = (((size_t)(b*H_ + head)) * L_ + ltok) * HD_ + d;
                        unsigned short h0, l0, h1, l1;
                        split1(c0, h0, l0); split1(c1, h1, l1);
                        *(uint32_t*)(o3h + oi) = (uint32_t)h0 | ((uint32_t)h1 << 16);
                        *(uint32_t*)(o3l + oi) = (uint32_t)l0 | ((uint32_t)l1 << 16);
                    }
                }
            }
        }
        return;
    }

    #pragma unroll
    for (int mt = 0; mt < 4; mt++) {
        #pragma unroll
        for (int half = 0; half < 2; half++) {
            int row = bm * 256 + wr * 64 + mt * 16 + g + half * 8;
            #pragma unroll
            for (int nt = 0; nt < 8; nt++) {
                int col = bn * 128 + wc * 64 + nt * 8 + 2 * t;
                float c0 = acc[mt][nt][half * 2 + 0];
                float c1 = acc[mt][nt][half * 2 + 1];
                if (MODE <= 2) {
                    float* dstp = C + (size_t)row * N + col;
                    if (MODE == 1) { c0 += bias[col]; c1 += bias[col + 1]; }
                    float2 r = *(const float2*)dstp;
                    c0 += r.x; c1 += r.y;
                    *(float2*)dstp = make_float2(c0, c1);
                } else if (MODE == 3) {
                    float sg = c0 / (1.0f + expf(-c0)) * c1;
                    unsigned short hh, ll; split1(sg, hh, ll);
                    size_t oi = (size_t)row * F_ + (col >> 1);
                    o1h[oi] = __ushort_as_bfloat16(hh);
                    o1l[oi] = __ushort_as_bfloat16(ll);
                } else if (MODE == 4) {
                    int b = row >> 11, ltok = row & (L_ - 1);
                    int hd = col >> 6, d = col & 63;
                    size_t oi = (((size_t)(b*H_ + hd)) * L_ + ltok) * HD_ + d;
                    unsigned short h0, l0, h1, l1;
                    split1(c0 * 0.125f, h0, l0); split1(c1 * 0.125f, h1, l1);
                    *(uint32_t*)(o1h + oi) = (uint32_t)h0 | ((uint32_t)h1 << 16);
                    *(uint32_t*)(o1l + oi) = (uint32_t)l0 | ((uint32_t)l1 << 16);
                } else { // MODE 7: multi-layer cross-KV
                    int layer = col >> 11;
                    int c2 = col & 2047;
                    int kv = c2 >> 10;
                    int hd = (c2 >> 6) & 15, d = c2 & 63;
                    int b = row >> 8, stok = row & (S_ - 1);
                    size_t oi = (size_t)layer * CATN
                              + (((size_t)(b*H_ + hd)) * S_ + stok) * HD_ + d;
                    unsigned short h0, l0, h1, l1;
                    split1(c0, h0, l0); split1(c1, h1, l1);
                    __nv_bfloat16* ph = kv ? o2h : o1h;
                    __nv_bfloat16* pl = kv ? o2l : o1l;
                    *(uint32_t*)(ph + oi) = (uint32_t)h0 | ((uint32_t)h1 << 16);
                    *(uint32_t*)(pl + oi) = (uint32_t)l0 | ((uint32_t)l1 << 16);
                }
            }
        }
    }
}

// ---------------------------------------------------------------------------
// mma.sync flash self-attention. P·V uses Ph·Vh + Ph·Vl (Pl term dropped;
// P in [0,1] positive-sum, ~1e-4 output error, within budget).
// ---------------------------------------------------------------------------
#define AT_ROW  144
#define AT_ARR  (64*AT_ROW)
#define AT_KV0  (2*AT_ARR)
#define AT_STG  (4*AT_ARR)
#define AT_SMEM (2*AT_ARR + 2*AT_STG)

__global__ void __launch_bounds__(128, 2)
self_attn_mma(const __nv_bfloat16* __restrict__ Qh, const __nv_bfloat16* __restrict__ Ql,
              const __nv_bfloat16* __restrict__ Kh, const __nv_bfloat16* __restrict__ Kl,
              const __nv_bfloat16* __restrict__ Vh, const __nv_bfloat16* __restrict__ Vl,
              __nv_bfloat16* __restrict__ out_hi, __nv_bfloat16* __restrict__ out_lo) {
    extern __shared__ char smraw[];
    const uint32_t sb = (uint32_t)__cvta_generic_to_shared(smraw);
    const int tid = threadIdx.x, warp = tid >> 5, lane = tid & 31;
    const int h = blockIdx.y, b = blockIdx.z;
    const int qbi = (int)(gridDim.x - 1 - blockIdx.x);
    const int qb = qbi * 64;
    const int ntiles = qbi + 1;
    const size_t hb = ((size_t)(b*H_ + h)) * L_;

    #pragma unroll
    for (int i = 0; i < 8; i++) {
        int id = tid + i * 128;
        int arr = id >> 9;
        int rem = id & 511;
        int row = rem >> 3, kc = rem & 7;
        const __nv_bfloat16* p = (arr ? Ql : Qh) + (hb + qb + row) * HD_ + kc * 8;
        uint32_t d = sb + (uint32_t)(arr * AT_ARR + row * AT_ROW + kc * 16);
        asm volatile("cp.async.cg.shared.global [%0], [%1], 16;" :: "r"(d), "l"(p) : "memory");
    }
    auto load_kv = [&](int t, int slot) {
        uint32_t base = sb + AT_KV0 + (uint32_t)(slot & 1) * AT_STG;
        int k0 = t * 64;
        #pragma unroll
        for (int i = 0; i < 16; i++) {
            int id = tid + i * 128;
            int arr = id >> 9;
            int rem = id & 511;
            int row = rem >> 3, kc = rem & 7;
            const __nv_bfloat16* p = (arr==0?Kh:arr==1?Kl:arr==2?Vh:Vl) + (hb + k0 + row) * HD_ + kc * 8;
            uint32_t d = base + (uint32_t)(arr * AT_ARR + row * AT_ROW + kc * 16);
            asm volatile("cp.async.cg.shared.global [%0], [%1], 16;" :: "r"(d), "l"(p) : "memory");
        }
        asm volatile("cp.async.commit_group;" ::: "memory");
    };
    load_kv(0, 0);
    if (ntiles > 1) load_kv(1, 1);

    uint32_t qh[4][4], ql[4][4];
    float o[8][4];
    #pragma unroll
    for (int i = 0; i < 8; i++)
        #pragma unroll
        for (int j = 0; j < 4; j++) o[i][j] = 0.f;
    float mA = -1e30f, mB = -1e30f, lA = 0.f, lB = 0.f;

    for (int t = 0; t < ntiles; t++) {
        if (t + 1 < ntiles) { asm volatile("cp.async.wait_group 1;" ::: "memory"); }
        else                { asm volatile("cp.async.wait_group 0;" ::: "memory"); }
        __syncthreads();
        if (t == 0) {
            #pragma unroll
            for (int ks = 0; ks < 4; ks++) {
                uint32_t a = sb + (uint32_t)((warp*16 + (lane & 15)) * AT_ROW + ks*32 + (lane >> 4) * 16);
                ldsm_x4(qh[ks], a);
                ldsm_x4(ql[ks], a + AT_ARR);
            }
        }
        const uint32_t kvb = sb + AT_KV0 + (uint32_t)(t & 1) * AT_STG;

        float s[8][4];
        #pragma unroll
        for (int i = 0; i < 8; i++)
            #pragma unroll
            for (int j = 0; j < 4; j++) s[i][j] = 0.f;
        #pragma unroll
        for (int ks = 0; ks < 4; ks++) {
            uint32_t kh4[4][4], kl4[4][4];
            #pragma unroll
            for (int ntp = 0; ntp < 4; ntp++) {
                uint32_t a = kvb + (uint32_t)((ntp*16 + (lane & 7) + ((lane >> 4) << 3)) * AT_ROW
                                              + ks*32 + (((lane >> 3) & 1) << 4));
                ldsm_x4(kh4[ntp], a);
                ldsm_x4(kl4[ntp], a + AT_ARR);
            }
            #pragma unroll
            for (int ntp = 0; ntp < 4; ntp++) {
                mma_bf16(s[2*ntp],   qh[ks], kh4[ntp]);
                mma_bf16(s[2*ntp+1], qh[ks], kh4[ntp] + 2);
                mma_bf16(s[2*ntp],   qh[ks], kl4[ntp]);
                mma_bf16(s[2*ntp+1], qh[ks], kl4[ntp] + 2);
                mma_bf16(s[2*ntp],   ql[ks], kh4[ntp]);
                mma_bf16(s[2*ntp+1], ql[ks], kh4[ntp] + 2);
            }
        }
        if (t == ntiles - 1) {
            int rA = qb + warp*16 + (lane >> 2);
            int cbase = t*64 + 2*(lane & 3);
            #pragma unroll
            for (int nt = 0; nt < 8; nt++) {
                int c0 = cbase + nt*8, c1 = c0 + 1;
                if (c0 > rA)     s[nt][0] = -1e30f;
                if (c1 > rA)     s[nt][1] = -1e30f;
                if (c0 > rA + 8) s[nt][2] = -1e30f;
                if (c1 > rA + 8) s[nt][3] = -1e30f;
            }
        }
        float tmA = -1e30f, tmB = -1e30f;
        #pragma unroll
        for (int nt = 0; nt < 8; nt++) {
            tmA = fmaxf(tmA, fmaxf(s[nt][0], s[nt][1]));
            tmB = fmaxf(tmB, fmaxf(s[nt][2], s[nt][3]));
        }
        tmA = fmaxf(tmA, __shfl_xor_sync(0xffffffffu, tmA, 1));
        tmA = fmaxf(tmA, __shfl_xor_sync(0xffffffffu, tmA, 2));
        tmB = fmaxf(tmB, __shfl_xor_sync(0xffffffffu, tmB, 1));
        tmB = fmaxf(tmB, __shfl_xor_sync(0xffffffffu, tmB, 2));
        float nmA = fmaxf(mA, tmA), nmB = fmaxf(mB, tmB);
        float scA = __expf(mA - nmA), scB = __expf(mB - nmB);
        float tsA = 0.f, tsB = 0.f;
        #pragma unroll
        for (int nt = 0; nt < 8; nt++) {
            s[nt][0] = __expf(s[nt][0] - nmA);
            s[nt][1] = __expf(s[nt][1] - nmA);
            s[nt][2] = __expf(s[nt][2] - nmB);
            s[nt][3] = __expf(s[nt][3] - nmB);
            tsA += s[nt][0] + s[nt][1];
            tsB += s[nt][2] + s[nt][3];
        }
        tsA += __shfl_xor_sync(0xffffffffu, tsA, 1);
        tsA += __shfl_xor_sync(0xffffffffu, tsA, 2);
        tsB += __shfl_xor_sync(0xffffffffu, tsB, 1);
        tsB += __shfl_xor_sync(0xffffffffu, tsB, 2);
        lA = lA * scA + tsA;
        lB = lB * scB + tsB;
        #pragma unroll
        for (int nt = 0; nt < 8; nt++) {
            o[nt][0] *= scA; o[nt][1] *= scA;
            o[nt][2] *= scB; o[nt][3] *= scB;
        }
        mA = nmA; mB = nmB;
        #pragma unroll
        for (int kk = 0; kk < 4; kk++) {
            uint32_t ph[4];
            ph[0] = pack_bf16x2(s[2*kk][0],   s[2*kk][1]);
            ph[1] = pack_bf16x2(s[2*kk][2],   s[2*kk][3]);
            ph[2] = pack_bf16x2(s[2*kk+1][0], s[2*kk+1][1]);
            ph[3] = pack_bf16x2(s[2*kk+1][2], s[2*kk+1][3]);
            #pragma unroll
            for (int ntp = 0; ntp < 4; ntp++) {
                uint32_t vh4[4], vl4[4];
                uint32_t a = kvb + 2*AT_ARR + (uint32_t)((kk*16 + (lane & 15)) * AT_ROW
                                                        + ntp*32 + ((lane >> 4) << 4));
                ldsm_x4_t(vh4, a);
                ldsm_x4_t(vl4, a + AT_ARR);
                mma_bf16(o[2*ntp],   ph, vh4);
                mma_bf16(o[2*ntp+1], ph, vh4 + 2);
                mma_bf16(o[2*ntp],   ph, vl4);
                mma_bf16(o[2*ntp+1], ph, vl4 + 2);
            }
        }
        __syncthreads();
        if (t + 2 < ntiles) load_kv(t + 2, t + 2);
    }

    float iA = 1.0f / lA, iB = 1.0f / lB;
    int qA = qb + warp*16 + (lane >> 2);
    size_t rowA = ((size_t)(b*L_ + qA)) * D_;
    size_t rowB = rowA + 8 * D_;
    int cb = h*HD_ + 2*(lane & 3);
    #pragma unroll
    for (int nt = 0; nt < 8; nt++) {
        int c = cb + nt*8;
        float a0 = o[nt][0]*iA, a1 = o[nt][1]*iA;
        float b0 = o[nt][2]*iB, b1 = o[nt][3]*iB;
        unsigned short h0,l0,h1,l1;
        split1(a0,h0,l0); split1(a1,h1,l1);
        *(uint32_t*)(out_hi + rowA + c) = (uint32_t)h0 | ((uint32_t)h1 << 16);
        *(uint32_t*)(out_lo + rowA + c) = (uint32_t)l0 | ((uint32_t)l1 << 16);
        split1(b0,h0,l0); split1(b1,h1,l1);
        *(uint32_t*)(out_hi + rowB + c) = (uint32_t)h0 | ((uint32_t)h1 << 16);
        *(uint32_t*)(out_lo + rowB + c) = (uint32_t)l0 | ((uint32_t)l1 << 16);
    }
}

// ---------------------------------------------------------------------------
// mma.sync cross-attention with tile-range skipping: seg_ids sorted per batch,
// so this CTA's window lies in [segF-127, segL] -> tiles [t0, t1] (<=3 of 4).
// Masking inside unchanged; skipped tiles were fully masked anyway.
// ---------------------------------------------------------------------------
__global__ void __launch_bounds__(128, 2)
cross_attn_mma(const __nv_bfloat16* __restrict__ Qh, const __nv_bfloat16* __restrict__ Ql,
               const __nv_bfloat16* __restrict__ Kh, const __nv_bfloat16* __restrict__ Kl,
               const __nv_bfloat16* __restrict__ Vh, const __nv_bfloat16* __restrict__ Vl,
               const int* __restrict__ seg_ids,
               __nv_bfloat16* __restrict__ out_hi, __nv_bfloat16* __restrict__ out_lo) {
    extern __shared__ char smraw[];
    const uint32_t sb = (uint32_t)__cvta_generic_to_shared(smraw);
    const int tid = threadIdx.x, warp = tid >> 5, lane = tid & 31;
    const int h = blockIdx.y, b = blockIdx.z;
    const int qb = (int)blockIdx.x * 64;
    const size_t hbQ = ((size_t)(b*H_ + h)) * L_;
    const size_t hbK = ((size_t)(b*H_ + h)) * S_;

    const int rA = qb + warp*16 + (lane >> 2);
    const int segA = seg_ids[b*L_ + rA];
    const int segB = seg_ids[b*L_ + rA + 8];

    // tile range for this CTA (seg_ids sorted ascending within batch)
    const int segF = seg_ids[b*L_ + qb];
    const int segL = seg_ids[b*L_ + qb + 63];
    int t0 = (segF - 127) >> 6; if (t0 < 0) t0 = 0;
    int t1 = segL >> 6;
    const int nte = t1 - t0 + 1;

    #pragma unroll
    for (int i = 0; i < 8; i++) {
        int id = tid + i * 128;
        int arr = id >> 9;
        int rem = id & 511;
        int row = rem >> 3, kc = rem & 7;
        const __nv_bfloat16* p = (arr ? Ql : Qh) + (hbQ + qb + row) * HD_ + kc * 8;
        uint32_t d = sb + (uint32_t)(arr * AT_ARR + row * AT_ROW + kc * 16);
        asm volatile("cp.async.cg.shared.global [%0], [%1], 16;" :: "r"(d), "l"(p) : "memory");
    }
    auto load_kv = [&](int t, int slot) {
        uint32_t base = sb + AT_KV0 + (uint32_t)(slot & 1) * AT_STG;
        int k0 = t * 64;
        #pragma unroll
        for (int i = 0; i < 16; i++) {
            int id = tid + i * 128;
            int arr = id >> 9;
            int rem = id & 511;
            int row = rem >> 3, kc = rem & 7;
            const __nv_bfloat16* p = (arr==0?Kh:arr==1?Kl:arr==2?Vh:Vl) + (hbK + k0 + row) * HD_ + kc * 8;
            uint32_t d = base + (uint32_t)(arr * AT_ARR + row * AT_ROW + kc * 16);
            asm volatile("cp.async.cg.shared.global [%0], [%1], 16;" :: "r"(d), "l"(p) : "memory");
        }
        asm volatile("cp.async.commit_group;" ::: "memory");
    };
    load_kv(t0, 0);
    if (nte > 1) load_kv(t0 + 1, 1);

    uint32_t qh[4][4], ql[4][4];
    float o[8][4];
    #pragma unroll
    for (int i = 0; i < 8; i++)
        #pragma unroll
        for (int j = 0; j < 4; j++) o[i][j] = 0.f;
    float mA = -1e30f, mB = -1e30f, lA = 0.f, lB = 0.f;

    for (int tt = 0; tt < nte; tt++) {
        const int t = t0 + tt;
        if (tt + 1 < nte) { asm volatile("cp.async.wait_group 1;" ::: "memory"); }
        else              { asm volatile("cp.async.wait_group 0;" ::: "memory"); }
        __syncthreads();
        if (tt == 0) {
            #pragma unroll
            for (int ks = 0; ks < 4; ks++) {
                uint32_t a = sb + (uint32_t)((warp*16 + (lane & 15)) * AT_ROW + ks*32 + (lane >> 4) * 16);
                ldsm_x4(qh[ks], a);
                ldsm_x4(ql[ks], a + AT_ARR);
            }
        }
        const uint32_t kvb = sb + AT_KV0 + (uint32_t)(tt & 1) * AT_STG;

        float s[8][4];
        #pragma unroll
        for (int i = 0; i < 8; i++)
            #pragma unroll
            for (int j = 0; j < 4; j++) s[i][j] = 0.f;
        #pragma unroll
        for (int ks = 0; ks < 4; ks++) {
            uint32_t kh4[4][4], kl4[4][4];
            #pragma unroll
            for (int ntp = 0; ntp < 4; ntp++) {
                uint32_t a = kvb + (uint32_t)((ntp*16 + (lane & 7) + ((lane >> 4) << 3)) * AT_ROW
                                              + ks*32 + (((lane >> 3) & 1) << 4));
                ldsm_x4(kh4[ntp], a);
                ldsm_x4(kl4[ntp], a + AT_ARR);
            }
            #pragma unroll
            for (int ntp = 0; ntp < 4; ntp++) {
                mma_bf16(s[2*ntp],   qh[ks], kh4[ntp]);
                mma_bf16(s[2*ntp+1], qh[ks], kh4[ntp] + 2);
                mma_bf16(s[2*ntp],   qh[ks], kl4[ntp]);
                mma_bf16(s[2*ntp+1], qh[ks], kl4[ntp] + 2);
                mma_bf16(s[2*ntp],   ql[ks], kh4[ntp]);
                mma_bf16(s[2*ntp+1], ql[ks], kh4[ntp] + 2);
            }
        }
        {
            int cbase = t*64 + 2*(lane & 3);
            #pragma unroll
            for (int nt = 0; nt < 8; nt++) {
                int c0 = cbase + nt*8, c1 = c0 + 1;
                if (c0 > segA || c0 <= segA - 128) s[nt][0] = -1e30f;
                if (c1 > segA || c1 <= segA - 128) s[nt][1] = -1e30f;
                if (c0 > segB || c0 <= segB - 128) s[nt][2] = -1e30f;
                if (c1 > segB || c1 <= segB - 128) s[nt][3] = -1e30f;
            }
        }
        float tmA = -1e30f, tmB = -1e30f;
        #pragma unroll
        for (int nt = 0; nt < 8; nt++) {
            tmA = fmaxf(tmA, fmaxf(s[nt][0], s[nt][1]));
            tmB = fmaxf(tmB, fmaxf(s[nt][2], s[nt][3]));
        }
        tmA = fmaxf(tmA, __shfl_xor_sync(0xffffffffu, tmA, 1));
        tmA = fmaxf(tmA, __shfl_xor_sync(0xffffffffu, tmA, 2));
        tmB = fmaxf(tmB, __shfl_xor_sync(0xffffffffu, tmB, 1));
        tmB = fmaxf(tmB, __shfl_xor_sync(0xffffffffu, tmB, 2));
        float nmA = fmaxf(mA, tmA), nmB = fmaxf(mB, tmB);
        float scA = __expf(mA - nmA), scB = __expf(mB - nmB);
        float tsA = 0.f, tsB = 0.f;
        #pragma unroll
        for (int nt = 0; nt < 8; nt++) {
            s[nt][0] = __expf(s[nt][0] - nmA);
            s[nt][1] = __expf(s[nt][1] - nmA);
            s[nt][2] = __expf(s[nt][2] - nmB);
            s[nt][3] = __expf(s[nt][3] - nmB);
            tsA += s[nt][0] + s[nt][1];
            tsB += s[nt][2] + s[nt][3];
        }
        tsA += __shfl_xor_sync(0xffffffffu, tsA, 1);
        tsA += __shfl_xor_sync(0xffffffffu, tsA, 2);
        tsB += __shfl_xor_sync(0xffffffffu, tsB, 1);
        tsB += __shfl_xor_sync(0xffffffffu, tsB, 2);
        lA = lA * scA + tsA;
        lB = lB * scB + tsB;
        #pragma unroll
        for (int nt = 0; nt < 8; nt++) {
            o[nt][0] *= scA; o[nt][1] *= scA;
            o[nt][2] *= scB; o[nt][3] *= scB;
        }
        mA = nmA; mB = nmB;
        #pragma unroll
        for (int kk = 0; kk < 4; kk++) {
            uint32_t ph[4];
            ph[0] = pack_bf16x2(s[2*kk][0],   s[2*kk][1]);
            ph[1] = pack_bf16x2(s[2*kk][2],   s[2*kk][3]);
            ph[2] = pack_bf16x2(s[2*kk+1][0], s[2*kk+1][1]);
            ph[3] = pack_bf16x2(s[2*kk+1][2], s[2*kk+1][3]);
            #pragma unroll
            for (int ntp = 0; ntp < 4; ntp++) {
                uint32_t vh4[4], vl4[4];
                uint32_t a = kvb + 2*AT_ARR + (uint32_t)((kk*16 + (lane & 15)) * AT_ROW
                                                        + ntp*32 + ((lane >> 4) << 4));
                ldsm_x4_t(vh4, a);
                ldsm_x4_t(vl4, a + AT_ARR);
                mma_bf16(o[2*ntp],   ph, vh4);
                mma_bf16(o[2*ntp+1], ph, vh4 + 2);
                mma_bf16(o[2*ntp],   ph, vl4);
                mma_bf16(o[2*ntp+1], ph, vl4 + 2);
            }
        }
        __syncthreads();
        if (tt + 2 < nte) load_kv(t0 + tt + 2, tt + 2);
    }

    float iA = 1.0f / lA, iB = 1.0f / lB;
    size_t rowA = ((size_t)(b*L_ + rA)) * D_;
    size_t rowB = rowA + 8 * D_;
    int cb = h*HD_ + 2*(lane & 3);
    #pragma unroll
    for (int nt = 0; nt < 8; nt++) {
        int c = cb + nt*8;
        float a0 = o[nt][0]*iA, a1 = o[nt][1]*iA;
        float b0 = o[nt][2]*iB, b1 = o[nt][3]*iB;
        unsigned short h0,l0,h1,l1;
        split1(a0,h0,l0); split1(a1,h1,l1);
        *(uint32_t*)(out_hi + rowA + c) = (uint32_t)h0 | ((uint32_t)h1 << 16);
        *(uint32_t*)(out_lo + rowA + c) = (uint32_t)l0 | ((uint32_t)l1 << 16);
        split1(b0,h0,l0); split1(b1,h1,l1);
        *(uint32_t*)(out_hi + rowB + c) = (uint32_t)h0 | ((uint32_t)h1 << 16);
        *(uint32_t*)(out_lo + rowB + c) = (uint32_t)l0 | ((uint32_t)l1 << 16);
    }
}

// ---------------------------------------------------------------------------
// Launch
// ---------------------------------------------------------------------------
static inline void split_launch(const float* src, __nv_bfloat16* hi, __nv_bfloat16* lo, size_t n) {
    int n4 = (int)(n / 4);
    split_k<<<(n4 + 255) / 256, 256>>>(src, hi, lo, n4);
}

extern "C" void kernel_launch(void* const* d_in, const int* in_sizes, int n_in,
                              void* d_out, int out_size) {
    const float* x      = (const float*)d_in[0];
    const float* memory = (const float*)d_in[1];
    const int*   seg    = (const int*)  d_in[2];
    const float* Wqkv   = (const float*)d_in[3];
    const float* bqkv   = (const float*)d_in[4];
    const float* Wo     = (const float*)d_in[5];
    const float* bo     = (const float*)d_in[6];
    const float* Wq_c   = (const float*)d_in[7];
    const float* Wkv_c  = (const float*)d_in[8];
    const float* Wo_c   = (const float*)d_in[9];
    const float* Wg     = (const float*)d_in[10];
    const float* Wu     = (const float*)d_in[11];
    const float* Wd     = (const float*)d_in[12];
    const float* n1     = (const float*)d_in[13];
    const float* n2     = (const float*)d_in[14];
    const float* n3     = (const float*)d_in[15];
    const float* nf     = (const float*)d_in[16];

    cudaFuncSetAttribute(gemm_bf16s<1>, cudaFuncAttributeMaxDynamicSharedMemorySize, GSMEM);
    cudaFuncSetAttribute(gemm_bf16s<2>, cudaFuncAttributeMaxDynamicSharedMemorySize, GSMEM);
    cudaFuncSetAttribute(gemm_bf16s<3>, cudaFuncAttributeMaxDynamicSharedMemorySize, GSMEM);
    cudaFuncSetAttribute(gemm_bf16s<4>, cudaFuncAttributeMaxDynamicSharedMemorySize, GSMEM);
    cudaFuncSetAttribute(gemm_bf16s<6>, cudaFuncAttributeMaxDynamicSharedMemorySize, GSMEM);
    cudaFuncSetAttribute(gemm_bf16s<7>, cudaFuncAttributeMaxDynamicSharedMemorySize, GSMEM);
    cudaFuncSetAttribute(self_attn_mma,  cudaFuncAttributeMaxDynamicSharedMemorySize, AT_SMEM);
    cudaFuncSetAttribute(cross_attn_mma, cudaFuncAttributeMaxDynamicSharedMemorySize, AT_SMEM);

    float *xb;
    __nv_bfloat16 *hhi, *hlo, *ahi, *alo, *chi, *clo, *gshi, *gslo, *mhi, *mlo, *whi, *wlo;
    __nv_bfloat16 *sqh, *sql, *skh, *skl, *svh, *svl;
    __nv_bfloat16 *ckh, *ckl, *cvh, *cvl;
    cudaGetSymbolAddress((void**)&xb,   g_x);
    cudaGetSymbolAddress((void**)&hhi,  g_h_hi);  cudaGetSymbolAddress((void**)&hlo,  g_h_lo);
    cudaGetSymbolAddress((void**)&ahi,  g_at_hi); cudaGetSymbolAddress((void**)&alo,  g_at_lo);
    cudaGetSymbolAddress((void**)&chi,  g_co_hi); cudaGetSymbolAddress((void**)&clo,  g_co_lo);
    cudaGetSymbolAddress((void**)&gshi, g_gs_hi); cudaGetSymbolAddress((void**)&gslo, g_gs_lo);
    cudaGetSymbolAddress((void**)&mhi,  g_m_hi);  cudaGetSymbolAddress((void**)&mlo,  g_m_lo);
    cudaGetSymbolAddress((void**)&whi,  g_w_hi);  cudaGetSymbolAddress((void**)&wlo,  g_w_lo);
    cudaGetSymbolAddress((void**)&sqh,  g_sqh);   cudaGetSymbolAddress((void**)&sql,  g_sql);
    cudaGetSymbolAddress((void**)&skh,  g_skh);   cudaGetSymbolAddress((void**)&skl,  g_skl);
    cudaGetSymbolAddress((void**)&svh,  g_svh);   cudaGetSymbolAddress((void**)&svl,  g_svl);
    cudaGetSymbolAddress((void**)&ckh,  g_ckh);   cudaGetSymbolAddress((void**)&ckl,  g_ckl);
    cudaGetSymbolAddress((void**)&cvh,  g_cvh);   cudaGetSymbolAddress((void**)&cvl,  g_cvl);

    rope_cache_k<<<256, 256>>>();
    copy_x_k<<<(M_*D_)/256, 256>>>(x);

    split_launch(Wqkv,  whi + O_WQKV, wlo + O_WQKV, NL*SZ_WQKV);
    split_launch(Wo,    whi + O_WO,   wlo + O_WO,   NL*SZ_WO);
    split_launch(Wq_c,  whi + O_WQC,  wlo + O_WQC,  NL*SZ_WQC);
    split_launch(Wkv_c, whi + O_WKVC, wlo + O_WKVC, NL*SZ_WKVC);
    split_launch(Wo_c,  whi + O_WOC,  wlo + O_WOC,  NL*SZ_WOC);
    for (int l = 0; l < NL; l++) {
        int n4 = (int)((size_t)F_*D_/4);
        split_ilv_k<<<(n4 + 255)/256, 256>>>(Wg + (size_t)l*F_*D_,
            whi + O_WGU + l*SZ_WGU, wlo + O_WGU + l*SZ_WGU, n4, D_/4, 0);
        split_ilv_k<<<(n4 + 255)/256, 256>>>(Wu + (size_t)l*F_*D_,
            whi + O_WGU + l*SZ_WGU, wlo + O_WGU + l*SZ_WGU, n4, D_/4, 1);
    }
    split_launch(Wd,    whi + O_WD,   wlo + O_WD,   NL*SZ_WD);
    split_launch(memory, mhi, mlo, (size_t)B_*S_*D_);

    // upfront: all 4 layers' cross K/V in one GEMM (layer-independent)
    gemm_bf16s<7><<<dim3(NL*2*D_/128, (B_*S_)/256), 256, GSMEM>>>(
        mhi, mlo, whi + O_WKVC, wlo + O_WKVC, nullptr, nullptr,
        ckh, ckl, cvh, cvl, nullptr, nullptr, NL*2*D_, D_);

    const dim3 self_grid(L_/64, H_, B_);
    const dim3 cross_grid(L_/64, H_, B_);

    for (int l = 0; l < NL; l++) {
        const __nv_bfloat16* wqkv_h = whi + O_WQKV + l*SZ_WQKV;
        const __nv_bfloat16* wqkv_l = wlo + O_WQKV + l*SZ_WQKV;
        const __nv_bfloat16* wo_h   = whi + O_WO   + l*SZ_WO;
        const __nv_bfloat16* wo_l   = wlo + O_WO   + l*SZ_WO;
        const __nv_bfloat16* wqc_h  = whi + O_WQC  + l*SZ_WQC;
        const __nv_bfloat16* wqc_l  = wlo + O_WQC  + l*SZ_WQC;
        const __nv_bfloat16* woc_h  = whi + O_WOC  + l*SZ_WOC;
        const __nv_bfloat16* woc_l  = wlo + O_WOC  + l*SZ_WOC;
        const __nv_bfloat16* wgu_h  = whi + O_WGU  + l*SZ_WGU;
        const __nv_bfloat16* wgu_l  = wlo + O_WGU  + l*SZ_WGU;
        const __nv_bfloat16* wd_h   = whi + O_WD   + l*SZ_WD;
        const __nv_bfloat16* wd_l   = wlo + O_WD   + l*SZ_WD;

        // --- self attention block (QKV GEMM fuses bias+RoPE+split) ---
        rmsnorm_split_k<<<M_, 256>>>(xb, n1 + l*D_, hhi, hlo);
        gemm_bf16s<6><<<dim3(3*D_/128, M_/256), 256, GSMEM>>>(
            hhi, hlo, wqkv_h, wqkv_l, bqkv + l*3*D_, nullptr,
            sqh, sql, skh, skl, svh, svl, 3*D_, D_);
        self_attn_mma<<<self_grid, 128, AT_SMEM>>>(sqh, sql, skh, skl, svh, svl, ahi, alo);
        gemm_bf16s<1><<<dim3(D_/128, M_/256), 256, GSMEM>>>(
            ahi, alo, wo_h, wo_l, bo + l*D_, xb,
            nullptr, nullptr, nullptr, nullptr, nullptr, nullptr, D_, D_);

        // --- cross attention block ---
        rmsnorm_split_k<<<M_, 256>>>(xb, n2 + l*D_, hhi, hlo);
        gemm_bf16s<4><<<dim3(D_/128, M_/256), 256, GSMEM>>>(
            hhi, hlo, wqc_h, wqc_l, nullptr, nullptr,
            sqh, sql, nullptr, nullptr, nullptr, nullptr, D_, D_);
        cross_attn_mma<<<cross_grid, 128, AT_SMEM>>>(
            sqh, sql, ckh + l*CATN, ckl + l*CATN, cvh + l*CATN, cvl + l*CATN,
            seg, chi, clo);
        gemm_bf16s<2><<<dim3(D_/128, M_/256), 256, GSMEM>>>(
            chi, clo, woc_h, woc_l, nullptr, xb,
            nullptr, nullptr, nullptr, nullptr, nullptr, nullptr, D_, D_);

        // --- MLP block (fused gate|up GEMM with swiglu epilogue) ---
        rmsnorm_split_k<<<M_, 256>>>(xb, n3 + l*D_, hhi, hlo);
        gemm_bf16s<3><<<dim3(2*F_/128, M_/256), 256, GSMEM>>>(
            hhi, hlo, wgu_h, wgu_l, nullptr, nullptr,
            gshi, gslo, nullptr, nullptr, nullptr, nullptr, 2*F_, D_);
        gemm_bf16s<2><<<dim3(D_/128, M_/256), 256, GSMEM>>>(
            gshi, gslo, wd_h, wd_l, nullptr, xb,
            nullptr, nullptr, nullptr, nullptr, nullptr, nullptr, D_, F_);
    }

    rmsnorm_k<<<M_, 256>>>(xb, nf, (float*)d_out);
}

// round 13
// speedup vs baseline: 4.7708x; 1.0007x over previous
#include <cuda_runtime.h>
#include <cuda_bf16.h>
#include <math.h>
#include <stdint.h>

// Problem constants
#define NL 4
#define B_ 2
#define L_ 2048
#define S_ 256
#define D_ 1024
#define F_ 4096
#define H_ 16
#define HD_ 64
#define M_ (B_*L_)          // 4096 token rows

// Weight region sizes (elements) and offsets in the concatenated split buffer
#define SZ_WQKV ((size_t)3*D_*D_)
#define SZ_WO   ((size_t)D_*D_)
#define SZ_WQC  ((size_t)D_*D_)
#define SZ_WKVC ((size_t)2*D_*D_)
#define SZ_WOC  ((size_t)D_*D_)
#define SZ_WGU  ((size_t)2*F_*D_)     // interleaved [g0,u0,g1,u1,...] per layer
#define SZ_WD   ((size_t)D_*F_)
static const size_t O_WQKV = 0;
static const size_t O_WO   = O_WQKV + NL*SZ_WQKV;
static const size_t O_WQC  = O_WO   + NL*SZ_WO;
static const size_t O_WKVC = O_WQC  + NL*SZ_WQC;
static const size_t O_WOC  = O_WKVC + NL*SZ_WKVC;
static const size_t O_WGU  = O_WOC  + NL*SZ_WOC;
static const size_t O_WD   = O_WGU  + NL*SZ_WGU;
#define WTOT (O_WD + NL*SZ_WD)

// ---------------------------------------------------------------------------
// Scratch (device globals; no allocations allowed)
// ---------------------------------------------------------------------------
__device__ float g_x  [M_*D_];
__device__ float g_cos[L_*32];
__device__ float g_sin[L_*32];

__device__ __nv_bfloat16 g_h_hi [M_*D_],  g_h_lo [M_*D_];
__device__ __nv_bfloat16 g_at_hi[M_*D_],  g_at_lo[M_*D_];
__device__ __nv_bfloat16 g_co_hi[M_*D_],  g_co_lo[M_*D_];
__device__ __nv_bfloat16 g_gs_hi[M_*F_],  g_gs_lo[M_*F_];
__device__ __nv_bfloat16 g_m_hi [B_*S_*D_], g_m_lo[B_*S_*D_];
__device__ __nv_bfloat16 g_w_hi[WTOT], g_w_lo[WTOT];

// attention-layout split buffers: [B][H][L][64] (self q/k/v; cross q reuses q)
#define ATN ((size_t)B_*H_*L_*HD_)
__device__ __nv_bfloat16 g_sqh[ATN], g_sql[ATN];
__device__ __nv_bfloat16 g_skh[ATN], g_skl[ATN];
__device__ __nv_bfloat16 g_svh[ATN], g_svl[ATN];

// per-layer cross K/V: [NL][B][H][S][64]
#define CATN ((size_t)B_*H_*S_*HD_)
__device__ __nv_bfloat16 g_ckh[NL*CATN], g_ckl[NL*CATN];
__device__ __nv_bfloat16 g_cvh[NL*CATN], g_cvl[NL*CATN];

// ---------------------------------------------------------------------------
// bf16 split helpers
// ---------------------------------------------------------------------------
__device__ __forceinline__ void split1(float v, unsigned short& h, unsigned short& l) {
    __nv_bfloat16 hb = __float2bfloat16_rn(v);
    float r = v - __bfloat162float(hb);
    __nv_bfloat16 lb = __float2bfloat16_rn(r);
    h = __bfloat16_as_ushort(hb);
    l = __bfloat16_as_ushort(lb);
}
__device__ __forceinline__ void split_pack4(float4 v, uint2& ph, uint2& pl) {
    unsigned short h0,h1,h2,h3,l0,l1,l2,l3;
    split1(v.x,h0,l0); split1(v.y,h1,l1); split1(v.z,h2,l2); split1(v.w,h3,l3);
    ph.x = (uint32_t)h0 | ((uint32_t)h1 << 16);
    ph.y = (uint32_t)h2 | ((uint32_t)h3 << 16);
    pl.x = (uint32_t)l0 | ((uint32_t)l1 << 16);
    pl.y = (uint32_t)l2 | ((uint32_t)l3 << 16);
}

// 4-quad ILP split (exact grids: n4 multiple of 1024)
__global__ void split_k(const float* __restrict__ in, __nv_bfloat16* __restrict__ hi,
                        __nv_bfloat16* __restrict__ lo) {
    int i = blockIdx.x * 1024 + threadIdx.x;
    float4 v[4];
    #pragma unroll
    for (int j = 0; j < 4; j++) v[j] = ((const float4*)in)[i + 256*j];
    #pragma unroll
    for (int j = 0; j < 4; j++) {
        uint2 ph, pl; split_pack4(v[j], ph, pl);
        ((uint2*)hi)[i + 256*j] = ph;
        ((uint2*)lo)[i + 256*j] = pl;
    }
}

// Interleaving split for GU weights: src row r (256 quads/row) -> dst row 2r+off
__global__ void split_ilv_k(const float* __restrict__ in, __nv_bfloat16* __restrict__ hi,
                            __nv_bfloat16* __restrict__ lo, int off) {
    int i0 = blockIdx.x * 1024 + threadIdx.x;
    float4 v[4];
    #pragma unroll
    for (int j = 0; j < 4; j++) v[j] = ((const float4*)in)[i0 + 256*j];
    #pragma unroll
    for (int j = 0; j < 4; j++) {
        int i = i0 + 256*j;
        int r = i >> 8, c = i & 255;
        uint2 ph, pl; split_pack4(v[j], ph, pl);
        size_t oi = (size_t)(2*r + off) * 256 + c;
        ((uint2*)hi)[oi] = ph;
        ((uint2*)lo)[oi] = pl;
    }
}

// ---------------------------------------------------------------------------
// RoPE cache
// ---------------------------------------------------------------------------
__global__ void rope_cache_k() {
    int idx = blockIdx.x * blockDim.x + threadIdx.x;
    int l = idx >> 5, i = idx & 31;
    double inv = exp(-log(10000.0) * (double)i / 32.0);
    double f = (double)l * inv;
    g_cos[idx] = (float)cos(f);
    g_sin[idx] = (float)sin(f);
}

// ---------------------------------------------------------------------------
// RMSNorm kernels
// ---------------------------------------------------------------------------
__global__ void rmsnorm_split_k(const float* __restrict__ x, const float* __restrict__ w,
                                __nv_bfloat16* __restrict__ hi, __nv_bfloat16* __restrict__ lo) {
    int row = blockIdx.x;
    int t = threadIdx.x;
    const float4* xr = (const float4*)(x + (size_t)row * D_);
    float4 v = xr[t];
    float ss = v.x*v.x + v.y*v.y + v.z*v.z + v.w*v.w;
    #pragma unroll
    for (int off = 16; off; off >>= 1) ss += __shfl_xor_sync(0xffffffffu, ss, off);
    __shared__ float red[8];
    if ((t & 31) == 0) red[t >> 5] = ss;
    __syncthreads();
    float tot = red[0]+red[1]+red[2]+red[3]+red[4]+red[5]+red[6]+red[7];
    float rs = rsqrtf(tot * (1.0f / (float)D_) + 1e-6f);
    float4 wv = ((const float4*)w)[t];
    float4 o;
    o.x = v.x * rs * wv.x; o.y = v.y * rs * wv.y;
    o.z = v.z * rs * wv.z; o.w = v.w * rs * wv.w;
    uint2 ph, pl; split_pack4(o, ph, pl);
    ((uint2*)hi)[(size_t)row * 256 + t] = ph;
    ((uint2*)lo)[(size_t)row * 256 + t] = pl;
}

__global__ void rmsnorm_k(const float* __restrict__ x, const float* __restrict__ w,
                          float* __restrict__ o) {
    int row = blockIdx.x;
    int t = threadIdx.x;
    const float4* xr = (const float4*)(x + (size_t)row * D_);
    float4 v = xr[t];
    float ss = v.x*v.x + v.y*v.y + v.z*v.z + v.w*v.w;
    #pragma unroll
    for (int off = 16; off; off >>= 1) ss += __shfl_xor_sync(0xffffffffu, ss, off);
    __shared__ float red[8];
    if ((t & 31) == 0) red[t >> 5] = ss;
    __syncthreads();
    float tot = red[0]+red[1]+red[2]+red[3]+red[4]+red[5]+red[6]+red[7];
    float rs = rsqrtf(tot * (1.0f / (float)D_) + 1e-6f);
    float4 wv = ((const float4*)w)[t];
    float4 out;
    out.x = v.x * rs * wv.x; out.y = v.y * rs * wv.y;
    out.z = v.z * rs * wv.z; out.w = v.w * rs * wv.w;
    ((float4*)(o + (size_t)row * D_))[t] = out;
}

// ---------------------------------------------------------------------------
// mma / ldmatrix helpers
// ---------------------------------------------------------------------------
__device__ __forceinline__ void mma_bf16(float* c, const uint32_t* a, const uint32_t* b) {
    asm volatile(
        "mma.sync.aligned.m16n8k16.row.col.f32.bf16.bf16.f32 "
        "{%0,%1,%2,%3}, {%4,%5,%6,%7}, {%8,%9}, {%0,%1,%2,%3};"
        : "+f"(c[0]), "+f"(c[1]), "+f"(c[2]), "+f"(c[3])
        : "r"(a[0]), "r"(a[1]), "r"(a[2]), "r"(a[3]), "r"(b[0]), "r"(b[1]));
}
__device__ __forceinline__ void ldsm_x4(uint32_t* r, uint32_t addr) {
    asm volatile("ldmatrix.sync.aligned.m8n8.x4.shared.b16 {%0,%1,%2,%3}, [%4];"
        : "=r"(r[0]), "=r"(r[1]), "=r"(r[2]), "=r"(r[3]) : "r"(addr));
}
__device__ __forceinline__ void ldsm_x4_t(uint32_t* r, uint32_t addr) {
    asm volatile("ldmatrix.sync.aligned.m8n8.x4.trans.shared.b16 {%0,%1,%2,%3}, [%4];"
        : "=r"(r[0]), "=r"(r[1]), "=r"(r[2]), "=r"(r[3]) : "r"(addr));
}
__device__ __forceinline__ uint32_t pack_bf16x2(float lo, float hi) {
    return (uint32_t)__bfloat16_as_ushort(__float2bfloat16_rn(lo)) |
           ((uint32_t)__bfloat16_as_ushort(__float2bfloat16_rn(hi)) << 16);
}

// ---------------------------------------------------------------------------
// bf16 split-3 GEMM (NT), 256x128 CTA tile, warp tile 64x64 (8 warps, 4x2).
// MODE 1: +bias +residual(Rsrc) -> fp32 C   (Wo; layer0 reads residual from input x)
// MODE 2: +residual(Rsrc)       -> fp32 C   (Wo_c, Wd)
// MODE 3: swiglu (interleaved g|u cols) -> bf16 hi/lo [M][F]
// MODE 4: attn-q layout, x0.125         -> bf16 hi/lo [B][H][L][64]
// MODE 6: QKV: +bias, RoPE on q/k, q x0.125 -> q/k/v bf16 hi/lo [B][H][L][64]
// MODE 7: multi-layer cross-KV           -> per-layer k/v [NL][B][H][S][64]
// ---------------------------------------------------------------------------
#define G2STAGE 61440
#define G2_AL   20480
#define G2_B0   40960
#define G2_B1   51200
#define GSMEM   (3*G2STAGE)

template <int MODE>
__global__ void __launch_bounds__(256, 1)
gemm_bf16s(const __nv_bfloat16* __restrict__ Ah, const __nv_bfloat16* __restrict__ Al,
           const __nv_bfloat16* __restrict__ Wh, const __nv_bfloat16* __restrict__ Wl,
           const float* __restrict__ bias, float* __restrict__ C,
           const float* __restrict__ Rsrc,
           __nv_bfloat16* __restrict__ o1h, __nv_bfloat16* __restrict__ o1l,
           __nv_bfloat16* __restrict__ o2h, __nv_bfloat16* __restrict__ o2l,
           __nv_bfloat16* __restrict__ o3h, __nv_bfloat16* __restrict__ o3l,
           int N, int K) {
    extern __shared__ char smem[];
    const uint32_t sbase = (uint32_t)__cvta_generic_to_shared(smem);
    const int tid  = threadIdx.x;
    const int warp = tid >> 5, lane = tid & 31;
    const int wr = warp >> 1;      // 0..3 : 64-row slab
    const int wc = warp & 1;       // 0..1 : 64-col slab
    const int g  = lane >> 2;
    const int t  = lane & 3;
    const int bm = blockIdx.y, bn = blockIdx.x;

    // cp.async chunk tables: 3072 16B-chunks per stage, 12 per thread
    const __nv_bfloat16* src[12];
    uint32_t dst[12];
    #pragma unroll
    for (int i = 0; i < 12; i++) {
        int id = tid + (i << 8);
        const __nv_bfloat16* bp;
        int grow; uint32_t off; int kc;
        if (id < 2048) {
            int arr = id >> 10, rem = id & 1023;
            int row = rem >> 2; kc = rem & 3;
            bp = arr ? Al : Ah;
            grow = bm * 256 + row;
            off = (uint32_t)(arr * G2_AL + row * 80 + kc * 16);
        } else {
            int id2 = id - 2048;
            int arr = id2 >> 9, rem = id2 & 511;
            int row = rem >> 2; kc = rem & 3;
            bp = arr ? Wl : Wh;
            grow = bn * 128 + row;
            off = (uint32_t)(G2_B0 + arr * 10240 + row * 80 + kc * 16);
        }
        src[i] = bp + (size_t)grow * K + kc * 8;
        dst[i] = off;
    }

    const uint32_t arow = (uint32_t)((wr * 64 + (lane & 15)) * 80 + (lane >> 4) * 16);
    const uint32_t brow = (uint32_t)((wc * 64 + (lane & 7) + ((lane >> 4) << 3)) * 80
                                     + (((lane >> 3) & 1) << 4));

    float acc[4][8][4];
    #pragma unroll
    for (int i = 0; i < 4; i++)
        #pragma unroll
        for (int j = 0; j < 8; j++)
            #pragma unroll
            for (int r = 0; r < 4; r++) acc[i][j][r] = 0.f;

    const int nk = K >> 5;

    #pragma unroll
    for (int st = 0; st < 2; st++) {
        uint32_t s = sbase + st * G2STAGE;
        #pragma unroll
        for (int i = 0; i < 12; i++) {
            const void* p = src[i] + st * 32;
            asm volatile("cp.async.cg.shared.global [%0], [%1], 16;"
                         :: "r"(s + dst[i]), "l"(p) : "memory");
        }
        asm volatile("cp.async.commit_group;" ::: "memory");
    }

    for (int it = 0; it < nk; it++) {
        asm volatile("cp.async.wait_group 1;" ::: "memory");
        __syncthreads();
        uint32_t s = sbase + (uint32_t)(it % 3) * G2STAGE;

        #pragma unroll
        for (int ks = 0; ks < 2; ks++) {
            const uint32_t ko = ks * 32;
            uint32_t af[16], bh[16], bl[16];
            #pragma unroll
            for (int mt = 0; mt < 4; mt++) ldsm_x4(af + 4*mt, s + arow + mt*1280 + ko);
            #pragma unroll
            for (int p = 0; p < 4; p++) ldsm_x4(bh + 4*p, s + G2_B0 + brow + p*1280 + ko);
            #pragma unroll
            for (int p = 0; p < 4; p++) ldsm_x4(bl + 4*p, s + G2_B1 + brow + p*1280 + ko);
            #pragma unroll
            for (int mt = 0; mt < 4; mt++)
                #pragma unroll
                for (int nt = 0; nt < 8; nt++) mma_bf16(acc[mt][nt], af + 4*mt, bh + 2*nt);
            #pragma unroll
            for (int mt = 0; mt < 4; mt++)
                #pragma unroll
                for (int nt = 0; nt < 8; nt++) mma_bf16(acc[mt][nt], af + 4*mt, bl + 2*nt);
            #pragma unroll
            for (int mt = 0; mt < 4; mt++) ldsm_x4(af + 4*mt, s + G2_AL + arow + mt*1280 + ko);
            #pragma unroll
            for (int mt = 0; mt < 4; mt++)
                #pragma unroll
                for (int nt = 0; nt < 8; nt++) mma_bf16(acc[mt][nt], af + 4*mt, bh + 2*nt);
        }

        if (it + 2 < nk) {
            uint32_t s2 = sbase + (uint32_t)((it + 2) % 3) * G2STAGE;
            int k0 = (it + 2) * 32;
            #pragma unroll
            for (int i = 0; i < 12; i++) {
                const void* p = src[i] + k0;
                asm volatile("cp.async.cg.shared.global [%0], [%1], 16;"
                             :: "r"(s2 + dst[i]), "l"(p) : "memory");
            }
        }
        asm volatile("cp.async.commit_group;" ::: "memory");
    }

    if (MODE == 6) {
        // QKV epilogue: bias + RoPE (q,k) + split into attention layout.
        const int part = (bn * 128 + wc * 64) >> 10;
        #pragma unroll
        for (int mt = 0; mt < 4; mt++) {
            #pragma unroll
            for (int half = 0; half < 2; half++) {
                int row = bm * 256 + wr * 64 + mt * 16 + g + half * 8;
                int b = row >> 11, ltok = row & (L_ - 1);
                if (part < 2) {
                    #pragma unroll
                    for (int np = 0; np < 4; np++) {
                        int col = bn*128 + wc*64 + np*8 + 2*t;
                        int pcol = col & 1023;
                        int head = pcol >> 6;
                        int i = pcol & 31;
                        float c0 = g_cos[ltok*32 + i],     s0 = g_sin[ltok*32 + i];
                        float c1 = g_cos[ltok*32 + i + 1], s1 = g_sin[ltok*32 + i + 1];
                        float x1a = acc[mt][np  ][half*2+0] + bias[col];
                        float x1b = acc[mt][np  ][half*2+1] + bias[col+1];
                        float x2a = acc[mt][np+4][half*2+0] + bias[col+32];
                        float x2b = acc[mt][np+4][half*2+1] + bias[col+33];
                        float r1a = x1a*c0 - x2a*s0, r2a = x2a*c0 + x1a*s0;
                        float r1b = x1b*c1 - x2b*s1, r2b = x2b*c1 + x1b*s1;
                        __nv_bfloat16 *oh, *ol;
                        if (part == 0) {
                            r1a *= 0.125f; r1b *= 0.125f; r2a *= 0.125f; r2b *= 0.125f;
                            oh = o1h; ol = o1l;
                        } else { oh = o2h; ol = o2l; }
                        size_t oi = (((size_t)(b*H_ + head)) * L_ + ltok) * HD_ + i;
                        unsigned short h0, l0, h1, l1;
                        split1(r1a, h0, l0); split1(r1b, h1, l1);
                        *(uint32_t*)(oh + oi) = (uint32_t)h0 | ((uint32_t)h1 << 16);
                        *(uint32_t*)(ol + oi) = (uint32_t)l0 | ((uint32_t)l1 << 16);
                        split1(r2a, h0, l0); split1(r2b, h1, l1);
                        *(uint32_t*)(oh + oi + 32) = (uint32_t)h0 | ((uint32_t)h1 << 16);
                        *(uint32_t*)(ol + oi + 32) = (uint32_t)l0 | ((uint32_t)l1 << 16);
                    }
                } else {
                    #pragma unroll
                    for (int nt = 0; nt < 8; nt++) {
                        int col = bn*128 + wc*64 + nt*8 + 2*t;
                        int pcol = col & 1023;
                        int head = pcol >> 6, d = pcol & 63;
                        float c0 = acc[mt][nt][half*2+0] + bias[col];
                        float c1 = acc[mt][nt][half*2+1] + bias[col+1];
                        size_t oi = (((size_t)(b*H_ + head)) * L_ + ltok) * HD_ + d;
                        unsigned short h0, l0, h1, l1;
                        split1(c0, h0, l0); split1(c1, h1, l1);
                        *(uint32_t*)(o3h + oi) = (uint32_t)h0 | ((uint32_t)h1 << 16);
                        *(uint32_t*)(o3l + oi) = (uint32_t)l0 | ((uint32_t)l1 << 16);
                    }
                }
            }
        }
        return;
    }

    #pragma unroll
    for (int mt = 0; mt < 4; mt++) {
        #pragma unroll
        for (int half = 0; half < 2; half++) {
            int row = bm * 256 + wr * 64 + mt * 16 + g + half * 8;
            #pragma unroll
            for (int nt = 0; nt < 8; nt++) {
                int col = bn * 128 + wc * 64 + nt * 8 + 2 * t;
                float c0 = acc[mt][nt][half * 2 + 0];
                float c1 = acc[mt][nt][half * 2 + 1];
                if (MODE <= 2) {
                    float* dstp = C + (size_t)row * N + col;
                    const float* rp = Rsrc + (size_t)row * N + col;
                    if (MODE == 1) { c0 += bias[col]; c1 += bias[col + 1]; }
                    float2 r = *(const float2*)rp;
                    c0 += r.x; c1 += r.y;
                    *(float2*)dstp = make_float2(c0, c1);
                } else if (MODE == 3) {
                    float sg = c0 / (1.0f + expf(-c0)) * c1;
                    unsigned short hh, ll; split1(sg, hh, ll);
                    size_t oi = (size_t)row * F_ + (col >> 1);
                    o1h[oi] = __ushort_as_bfloat16(hh);
                    o1l[oi] = __ushort_as_bfloat16(ll);
                } else if (MODE == 4) {
                    int b = row >> 11, ltok = row & (L_ - 1);
                    int hd = col >> 6, d = col & 63;
                    size_t oi = (((size_t)(b*H_ + hd)) * L_ + ltok) * HD_ + d;
                    unsigned short h0, l0, h1, l1;
                    split1(c0 * 0.125f, h0, l0); split1(c1 * 0.125f, h1, l1);
                    *(uint32_t*)(o1h + oi) = (uint32_t)h0 | ((uint32_t)h1 << 16);
                    *(uint32_t*)(o1l + oi) = (uint32_t)l0 | ((uint32_t)l1 << 16);
                } else { // MODE 7: multi-layer cross-KV
                    int layer = col >> 11;
                    int c2 = col & 2047;
                    int kv = c2 >> 10;
                    int hd = (c2 >> 6) & 15, d = c2 & 63;
                    int b = row >> 8, stok = row & (S_ - 1);
                    size_t oi = (size_t)layer * CATN
                              + (((size_t)(b*H_ + hd)) * S_ + stok) * HD_ + d;
                    unsigned short h0, l0, h1, l1;
                    split1(c0, h0, l0); split1(c1, h1, l1);
                    __nv_bfloat16* ph = kv ? o2h : o1h;
                    __nv_bfloat16* pl = kv ? o2l : o1l;
                    *(uint32_t*)(ph + oi) = (uint32_t)h0 | ((uint32_t)h1 << 16);
                    *(uint32_t*)(pl + oi) = (uint32_t)l0 | ((uint32_t)l1 << 16);
                }
            }
        }
    }
}

// ---------------------------------------------------------------------------
// mma.sync flash self-attention. P·V uses Ph·Vh + Ph·Vl (Pl term dropped;
// P in [0,1] positive-sum, ~1e-4 output error, within budget).
// ---------------------------------------------------------------------------
#define AT_ROW  144
#define AT_ARR  (64*AT_ROW)
#define AT_KV0  (2*AT_ARR)
#define AT_STG  (4*AT_ARR)
#define AT_SMEM (2*AT_ARR + 2*AT_STG)

__global__ void __launch_bounds__(128, 2)
self_attn_mma(const __nv_bfloat16* __restrict__ Qh, const __nv_bfloat16* __restrict__ Ql,
              const __nv_bfloat16* __restrict__ Kh, const __nv_bfloat16* __restrict__ Kl,
              const __nv_bfloat16* __restrict__ Vh, const __nv_bfloat16* __restrict__ Vl,
              __nv_bfloat16* __restrict__ out_hi, __nv_bfloat16* __restrict__ out_lo) {
    extern __shared__ char smraw[];
    const uint32_t sb = (uint32_t)__cvta_generic_to_shared(smraw);
    const int tid = threadIdx.x, warp = tid >> 5, lane = tid & 31;
    const int h = blockIdx.y, b = blockIdx.z;
    const int qbi = (int)(gridDim.x - 1 - blockIdx.x);
    const int qb = qbi * 64;
    const int ntiles = qbi + 1;
    const size_t hb = ((size_t)(b*H_ + h)) * L_;

    #pragma unroll
    for (int i = 0; i < 8; i++) {
        int id = tid + i * 128;
        int arr = id >> 9;
        int rem = id & 511;
        int row = rem >> 3, kc = rem & 7;
        const __nv_bfloat16* p = (arr ? Ql : Qh) + (hb + qb + row) * HD_ + kc * 8;
        uint32_t d = sb + (uint32_t)(arr * AT_ARR + row * AT_ROW + kc * 16);
        asm volatile("cp.async.cg.shared.global [%0], [%1], 16;" :: "r"(d), "l"(p) : "memory");
    }
    auto load_kv = [&](int t, int slot) {
        uint32_t base = sb + AT_KV0 + (uint32_t)(slot & 1) * AT_STG;
        int k0 = t * 64;
        #pragma unroll
        for (int i = 0; i < 16; i++) {
            int id = tid + i * 128;
            int arr = id >> 9;
            int rem = id & 511;
            int row = rem >> 3, kc = rem & 7;
            const __nv_bfloat16* p = (arr==0?Kh:arr==1?Kl:arr==2?Vh:Vl) + (hb + k0 + row) * HD_ + kc * 8;
            uint32_t d = base + (uint32_t)(arr * AT_ARR + row * AT_ROW + kc * 16);
            asm volatile("cp.async.cg.shared.global [%0], [%1], 16;" :: "r"(d), "l"(p) : "memory");
        }
        asm volatile("cp.async.commit_group;" ::: "memory");
    };
    load_kv(0, 0);
    if (ntiles > 1) load_kv(1, 1);

    uint32_t qh[4][4], ql[4][4];
    float o[8][4];
    #pragma unroll
    for (int i = 0; i < 8; i++)
        #pragma unroll
        for (int j = 0; j < 4; j++) o[i][j] = 0.f;
    float mA = -1e30f, mB = -1e30f, lA = 0.f, lB = 0.f;

    for (int t = 0; t < ntiles; t++) {
        if (t + 1 < ntiles) { asm volatile("cp.async.wait_group 1;" ::: "memory"); }
        else                { asm volatile("cp.async.wait_group 0;" ::: "memory"); }
        __syncthreads();
        if (t == 0) {
            #pragma unroll
            for (int ks = 0; ks < 4; ks++) {
                uint32_t a = sb + (uint32_t)((warp*16 + (lane & 15)) * AT_ROW + ks*32 + (lane >> 4) * 16);
                ldsm_x4(qh[ks], a);
                ldsm_x4(ql[ks], a + AT_ARR);
            }
        }
        const uint32_t kvb = sb + AT_KV0 + (uint32_t)(t & 1) * AT_STG;

        float s[8][4];
        #pragma unroll
        for (int i = 0; i < 8; i++)
            #pragma unroll
            for (int j = 0; j < 4; j++) s[i][j] = 0.f;
        #pragma unroll
        for (int ks = 0; ks < 4; ks++) {
            uint32_t kh4[4][4], kl4[4][4];
            #pragma unroll
            for (int ntp = 0; ntp < 4; ntp++) {
                uint32_t a = kvb + (uint32_t)((ntp*16 + (lane & 7) + ((lane >> 4) << 3)) * AT_ROW
                                              + ks*32 + (((lane >> 3) & 1) << 4));
                ldsm_x4(kh4[ntp], a);
                ldsm_x4(kl4[ntp], a + AT_ARR);
            }
            #pragma unroll
            for (int ntp = 0; ntp < 4; ntp++) {
                mma_bf16(s[2*ntp],   qh[ks], kh4[ntp]);
                mma_bf16(s[2*ntp+1], qh[ks], kh4[ntp] + 2);
                mma_bf16(s[2*ntp],   qh[ks], kl4[ntp]);
                mma_bf16(s[2*ntp+1], qh[ks], kl4[ntp] + 2);
                mma_bf16(s[2*ntp],   ql[ks], kh4[ntp]);
                mma_bf16(s[2*ntp+1], ql[ks], kh4[ntp] + 2);
            }
        }
        if (t == ntiles - 1) {
            int rA = qb + warp*16 + (lane >> 2);
            int cbase = t*64 + 2*(lane & 3);
            #pragma unroll
            for (int nt = 0; nt < 8; nt++) {
                int c0 = cbase + nt*8, c1 = c0 + 1;
                if (c0 > rA)     s[nt][0] = -1e30f;
                if (c1 > rA)     s[nt][1] = -1e30f;
                if (c0 > rA + 8) s[nt][2] = -1e30f;
                if (c1 > rA + 8) s[nt][3] = -1e30f;
            }
        }
        float tmA = -1e30f, tmB = -1e30f;
        #pragma unroll
        for (int nt = 0; nt < 8; nt++) {
            tmA = fmaxf(tmA, fmaxf(s[nt][0], s[nt][1]));
            tmB = fmaxf(tmB, fmaxf(s[nt][2], s[nt][3]));
        }
        tmA = fmaxf(tmA, __shfl_xor_sync(0xffffffffu, tmA, 1));
        tmA = fmaxf(tmA, __shfl_xor_sync(0xffffffffu, tmA, 2));
        tmB = fmaxf(tmB, __shfl_xor_sync(0xffffffffu, tmB, 1));
        tmB = fmaxf(tmB, __shfl_xor_sync(0xffffffffu, tmB, 2));
        float nmA = fmaxf(mA, tmA), nmB = fmaxf(mB, tmB);
        float scA = __expf(mA - nmA), scB = __expf(mB - nmB);
        float tsA = 0.f, tsB = 0.f;
        #pragma unroll
        for (int nt = 0; nt < 8; nt++) {
            s[nt][0] = __expf(s[nt][0] - nmA);
            s[nt][1] = __expf(s[nt][1] - nmA);
            s[nt][2] = __expf(s[nt][2] - nmB);
            s[nt][3] = __expf(s[nt][3] - nmB);
            tsA += s[nt][0] + s[nt][1];
            tsB += s[nt][2] + s[nt][3];
        }
        tsA += __shfl_xor_sync(0xffffffffu, tsA, 1);
        tsA += __shfl_xor_sync(0xffffffffu, tsA, 2);
        tsB += __shfl_xor_sync(0xffffffffu, tsB, 1);
        tsB += __shfl_xor_sync(0xffffffffu, tsB, 2);
        lA = lA * scA + tsA;
        lB = lB * scB + tsB;
        #pragma unroll
        for (int nt = 0; nt < 8; nt++) {
            o[nt][0] *= scA; o[nt][1] *= scA;
            o[nt][2] *= scB; o[nt][3] *= scB;
        }
        mA = nmA; mB = nmB;
        #pragma unroll
        for (int kk = 0; kk < 4; kk++) {
            uint32_t ph[4];
            ph[0] = pack_bf16x2(s[2*kk][0],   s[2*kk][1]);
            ph[1] = pack_bf16x2(s[2*kk][2],   s[2*kk][3]);
            ph[2] = pack_bf16x2(s[2*kk+1][0], s[2*kk+1][1]);
            ph[3] = pack_bf16x2(s[2*kk+1][2], s[2*kk+1][3]);
            #pragma unroll
            for (int ntp = 0; ntp < 4; ntp++) {
                uint32_t vh4[4], vl4[4];
                uint32_t a = kvb + 2*AT_ARR + (uint32_t)((kk*16 + (lane & 15)) * AT_ROW
                                                        + ntp*32 + ((lane >> 4) << 4));
                ldsm_x4_t(vh4, a);
                ldsm_x4_t(vl4, a + AT_ARR);
                mma_bf16(o[2*ntp],   ph, vh4);
                mma_bf16(o[2*ntp+1], ph, vh4 + 2);
                mma_bf16(o[2*ntp],   ph, vl4);
                mma_bf16(o[2*ntp+1], ph, vl4 + 2);
            }
        }
        __syncthreads();
        if (t + 2 < ntiles) load_kv(t + 2, t + 2);
    }

    float iA = 1.0f / lA, iB = 1.0f / lB;
    int qA = qb + warp*16 + (lane >> 2);
    size_t rowA = ((size_t)(b*L_ + qA)) * D_;
    size_t rowB = rowA + 8 * D_;
    int cb = h*HD_ + 2*(lane & 3);
    #pragma unroll
    for (int nt = 0; nt < 8; nt++) {
        int c = cb + nt*8;
        float a0 = o[nt][0]*iA, a1 = o[nt][1]*iA;
        float b0 = o[nt][2]*iB, b1 = o[nt][3]*iB;
        unsigned short h0,l0,h1,l1;
        split1(a0,h0,l0); split1(a1,h1,l1);
        *(uint32_t*)(out_hi + rowA + c) = (uint32_t)h0 | ((uint32_t)h1 << 16);
        *(uint32_t*)(out_lo + rowA + c) = (uint32_t)l0 | ((uint32_t)l1 << 16);
        split1(b0,h0,l0); split1(b1,h1,l1);
        *(uint32_t*)(out_hi + rowB + c) = (uint32_t)h0 | ((uint32_t)h1 << 16);
        *(uint32_t*)(out_lo + rowB + c) = (uint32_t)l0 | ((uint32_t)l1 << 16);
    }
}

// ---------------------------------------------------------------------------
// mma.sync cross-attention with tile-range skipping (seg_ids sorted).
// ---------------------------------------------------------------------------
__global__ void __launch_bounds__(128, 2)
cross_attn_mma(const __nv_bfloat16* __restrict__ Qh, const __nv_bfloat16* __restrict__ Ql,
               const __nv_bfloat16* __restrict__ Kh, const __nv_bfloat16* __restrict__ Kl,
               const __nv_bfloat16* __restrict__ Vh, const __nv_bfloat16* __restrict__ Vl,
               const int* __restrict__ seg_ids,
               __nv_bfloat16* __restrict__ out_hi, __nv_bfloat16* __restrict__ out_lo) {
    extern __shared__ char smraw[];
    const uint32_t sb = (uint32_t)__cvta_generic_to_shared(smraw);
    const int tid = threadIdx.x, warp = tid >> 5, lane = tid & 31;
    const int h = blockIdx.y, b = blockIdx.z;
    const int qb = (int)blockIdx.x * 64;
    const size_t hbQ = ((size_t)(b*H_ + h)) * L_;
    const size_t hbK = ((size_t)(b*H_ + h)) * S_;

    const int rA = qb + warp*16 + (lane >> 2);
    const int segA = seg_ids[b*L_ + rA];
    const int segB = seg_ids[b*L_ + rA + 8];

    const int segF = seg_ids[b*L_ + qb];
    const int segL = seg_ids[b*L_ + qb + 63];
    int t0 = (segF - 127) >> 6; if (t0 < 0) t0 = 0;
    int t1 = segL >> 6;
    const int nte = t1 - t0 + 1;

    #pragma unroll
    for (int i = 0; i < 8; i++) {
        int id = tid + i * 128;
        int arr = id >> 9;
        int rem = id & 511;
        int row = rem >> 3, kc = rem & 7;
        const __nv_bfloat16* p = (arr ? Ql : Qh) + (hbQ + qb + row) * HD_ + kc * 8;
        uint32_t d = sb + (uint32_t)(arr * AT_ARR + row * AT_ROW + kc * 16);
        asm volatile("cp.async.cg.shared.global [%0], [%1], 16;" :: "r"(d), "l"(p) : "memory");
    }
    auto load_kv = [&](int t, int slot) {
        uint32_t base = sb + AT_KV0 + (uint32_t)(slot & 1) * AT_STG;
        int k0 = t * 64;
        #pragma unroll
        for (int i = 0; i < 16; i++) {
            int id = tid + i * 128;
            int arr = id >> 9;
            int rem = id & 511;
            int row = rem >> 3, kc = rem & 7;
            const __nv_bfloat16* p = (arr==0?Kh:arr==1?Kl:arr==2?Vh:Vl) + (hbK + k0 + row) * HD_ + kc * 8;
            uint32_t d = base + (uint32_t)(arr * AT_ARR + row * AT_ROW + kc * 16);
            asm volatile("cp.async.cg.shared.global [%0], [%1], 16;" :: "r"(d), "l"(p) : "memory");
        }
        asm volatile("cp.async.commit_group;" ::: "memory");
    };
    load_kv(t0, 0);
    if (nte > 1) load_kv(t0 + 1, 1);

    uint32_t qh[4][4], ql[4][4];
    float o[8][4];
    #pragma unroll
    for (int i = 0; i < 8; i++)
        #pragma unroll
        for (int j = 0; j < 4; j++) o[i][j] = 0.f;
    float mA = -1e30f, mB = -1e30f, lA = 0.f, lB = 0.f;

    for (int tt = 0; tt < nte; tt++) {
        const int t = t0 + tt;
        if (tt + 1 < nte) { asm volatile("cp.async.wait_group 1;" ::: "memory"); }
        else              { asm volatile("cp.async.wait_group 0;" ::: "memory"); }
        __syncthreads();
        if (tt == 0) {
            #pragma unroll
            for (int ks = 0; ks < 4; ks++) {
                uint32_t a = sb + (uint32_t)((warp*16 + (lane & 15)) * AT_ROW + ks*32 + (lane >> 4) * 16);
                ldsm_x4(qh[ks], a);
                ldsm_x4(ql[ks], a + AT_ARR);
            }
        }
        const uint32_t kvb = sb + AT_KV0 + (uint32_t)(tt & 1) * AT_STG;

        float s[8][4];
        #pragma unroll
        for (int i = 0; i < 8; i++)
            #pragma unroll
            for (int j = 0; j < 4; j++) s[i][j] = 0.f;
        #pragma unroll
        for (int ks = 0; ks < 4; ks++) {
            uint32_t kh4[4][4], kl4[4][4];
            #pragma unroll
            for (int ntp = 0; ntp < 4; ntp++) {
                uint32_t a = kvb + (uint32_t)((ntp*16 + (lane & 7) + ((lane >> 4) << 3)) * AT_ROW
                                              + ks*32 + (((lane >> 3) & 1) << 4));
                ldsm_x4(kh4[ntp], a);
                ldsm_x4(kl4[ntp], a + AT_ARR);
            }
            #pragma unroll
            for (int ntp = 0; ntp < 4; ntp++) {
                mma_bf16(s[2*ntp],   qh[ks], kh4[ntp]);
                mma_bf16(s[2*ntp+1], qh[ks], kh4[ntp] + 2);
                mma_bf16(s[2*ntp],   qh[ks], kl4[ntp]);
                mma_bf16(s[2*ntp+1], qh[ks], kl4[ntp] + 2);
                mma_bf16(s[2*ntp],   ql[ks], kh4[ntp]);
                mma_bf16(s[2*ntp+1], ql[ks], kh4[ntp] + 2);
            }
        }
        {
            int cbase = t*64 + 2*(lane & 3);
            #pragma unroll
            for (int nt = 0; nt < 8; nt++) {
                int c0 = cbase + nt*8, c1 = c0 + 1;
                if (c0 > segA || c0 <= segA - 128) s[nt][0] = -1e30f;
                if (c1 > segA || c1 <= segA - 128) s[nt][1] = -1e30f;
                if (c0 > segB || c0 <= segB - 128) s[nt][2] = -1e30f;
                if (c1 > segB || c1 <= segB - 128) s[nt][3] = -1e30f;
            }
        }
        float tmA = -1e30f, tmB = -1e30f;
        #pragma unroll
        for (int nt = 0; nt < 8; nt++) {
            tmA = fmaxf(tmA, fmaxf(s[nt][0], s[nt][1]));
            tmB = fmaxf(tmB, fmaxf(s[nt][2], s[nt][3]));
        }
        tmA = fmaxf(tmA, __shfl_xor_sync(0xffffffffu, tmA, 1));
        tmA = fmaxf(tmA, __shfl_xor_sync(0xffffffffu, tmA, 2));
        tmB = fmaxf(tmB, __shfl_xor_sync(0xffffffffu, tmB, 1));
        tmB = fmaxf(tmB, __shfl_xor_sync(0xffffffffu, tmB, 2));
        float nmA = fmaxf(mA, tmA), nmB = fmaxf(mB, tmB);
        float scA = __expf(mA - nmA), scB = __expf(mB - nmB);
        float tsA = 0.f, tsB = 0.f;
        #pragma unroll
        for (int nt = 0; nt < 8; nt++) {
            s[nt][0] = __expf(s[nt][0] - nmA);
            s[nt][1] = __expf(s[nt][1] - nmA);
            s[nt][2] = __expf(s[nt][2] - nmB);
            s[nt][3] = __expf(s[nt][3] - nmB);
            tsA += s[nt][0] + s[nt][1];
            tsB += s[nt][2] + s[nt][3];
        }
        tsA += __shfl_xor_sync(0xffffffffu, tsA, 1);
        tsA += __shfl_xor_sync(0xffffffffu, tsA, 2);
        tsB += __shfl_xor_sync(0xffffffffu, tsB, 1);
        tsB += __shfl_xor_sync(0xffffffffu, tsB, 2);
        lA = lA * scA + tsA;
        lB = lB * scB + tsB;
        #pragma unroll
        for (int nt = 0; nt < 8; nt++) {
            o[nt][0] *= scA; o[nt][1] *= scA;
            o[nt][2] *= scB; o[nt][3] *= scB;
        }
        mA = nmA; mB = nmB;
        #pragma unroll
        for (int kk = 0; kk < 4; kk++) {
            uint32_t ph[4];
            ph[0] = pack_bf16x2(s[2*kk][0],   s[2*kk][1]);
            ph[1] = pack_bf16x2(s[2*kk][2],   s[2*kk][3]);
            ph[2] = pack_bf16x2(s[2*kk+1][0], s[2*kk+1][1]);
            ph[3] = pack_bf16x2(s[2*kk+1][2], s[2*kk+1][3]);
            #pragma unroll
            for (int ntp = 0; ntp < 4; ntp++) {
                uint32_t vh4[4], vl4[4];
                uint32_t a = kvb + 2*AT_ARR + (uint32_t)((kk*16 + (lane & 15)) * AT_ROW
                                                        + ntp*32 + ((lane >> 4) << 4));
                ldsm_x4_t(vh4, a);
                ldsm_x4_t(vl4, a + AT_ARR);
                mma_bf16(o[2*ntp],   ph, vh4);
                mma_bf16(o[2*ntp+1], ph, vh4 + 2);
                mma_bf16(o[2*ntp],   ph, vl4);
                mma_bf16(o[2*ntp+1], ph, vl4 + 2);
            }
        }
        __syncthreads();
        if (tt + 2 < nte) load_kv(t0 + tt + 2, tt + 2);
    }

    float iA = 1.0f / lA, iB = 1.0f / lB;
    size_t rowA = ((size_t)(b*L_ + rA)) * D_;
    size_t rowB = rowA + 8 * D_;
    int cb = h*HD_ + 2*(lane & 3);
    #pragma unroll
    for (int nt = 0; nt < 8; nt++) {
        int c = cb + nt*8;
        float a0 = o[nt][0]*iA, a1 = o[nt][1]*iA;
        float b0 = o[nt][2]*iB, b1 = o[nt][3]*iB;
        unsigned short h0,l0,h1,l1;
        split1(a0,h0,l0); split1(a1,h1,l1);
        *(uint32_t*)(out_hi + rowA + c) = (uint32_t)h0 | ((uint32_t)h1 << 16);
        *(uint32_t*)(out_lo + rowA + c) = (uint32_t)l0 | ((uint32_t)l1 << 16);
        split1(b0,h0,l0); split1(b1,h1,l1);
        *(uint32_t*)(out_hi + rowB + c) = (uint32_t)h0 | ((uint32_t)h1 << 16);
        *(uint32_t*)(out_lo + rowB + c) = (uint32_t)l0 | ((uint32_t)l1 << 16);
    }
}

// ---------------------------------------------------------------------------
// Launch
// ---------------------------------------------------------------------------
static inline void split_launch(const float* src, __nv_bfloat16* hi, __nv_bfloat16* lo, size_t n) {
    int n4 = (int)(n / 4);
    split_k<<<n4 / 1024, 256>>>(src, hi, lo);
}

extern "C" void kernel_launch(void* const* d_in, const int* in_sizes, int n_in,
                              void* d_out, int out_size) {
    const float* x      = (const float*)d_in[0];
    const float* memory = (const float*)d_in[1];
    const int*   seg    = (const int*)  d_in[2];
    const float* Wqkv   = (const float*)d_in[3];
    const float* bqkv   = (const float*)d_in[4];
    const float* Wo     = (const float*)d_in[5];
    const float* bo     = (const float*)d_in[6];
    const float* Wq_c   = (const float*)d_in[7];
    const float* Wkv_c  = (const float*)d_in[8];
    const float* Wo_c   = (const float*)d_in[9];
    const float* Wg     = (const float*)d_in[10];
    const float* Wu     = (const float*)d_in[11];
    const float* Wd     = (const float*)d_in[12];
    const float* n1     = (const float*)d_in[13];
    const float* n2     = (const float*)d_in[14];
    const float* n3     = (const float*)d_in[15];
    const float* nf     = (const float*)d_in[16];

    cudaFuncSetAttribute(gemm_bf16s<1>, cudaFuncAttributeMaxDynamicSharedMemorySize, GSMEM);
    cudaFuncSetAttribute(gemm_bf16s<2>, cudaFuncAttributeMaxDynamicSharedMemorySize, GSMEM);
    cudaFuncSetAttribute(gemm_bf16s<3>, cudaFuncAttributeMaxDynamicSharedMemorySize, GSMEM);
    cudaFuncSetAttribute(gemm_bf16s<4>, cudaFuncAttributeMaxDynamicSharedMemorySize, GSMEM);
    cudaFuncSetAttribute(gemm_bf16s<6>, cudaFuncAttributeMaxDynamicSharedMemorySize, GSMEM);
    cudaFuncSetAttribute(gemm_bf16s<7>, cudaFuncAttributeMaxDynamicSharedMemorySize, GSMEM);
    cudaFuncSetAttribute(self_attn_mma,  cudaFuncAttributeMaxDynamicSharedMemorySize, AT_SMEM);
    cudaFuncSetAttribute(cross_attn_mma, cudaFuncAttributeMaxDynamicSharedMemorySize, AT_SMEM);

    float *xb;
    __nv_bfloat16 *hhi, *hlo, *ahi, *alo, *chi, *clo, *gshi, *gslo, *mhi, *mlo, *whi, *wlo;
    __nv_bfloat16 *sqh, *sql, *skh, *skl, *svh, *svl;
    __nv_bfloat16 *ckh, *ckl, *cvh, *cvl;
    cudaGetSymbolAddress((void**)&xb,   g_x);
    cudaGetSymbolAddress((void**)&hhi,  g_h_hi);  cudaGetSymbolAddress((void**)&hlo,  g_h_lo);
    cudaGetSymbolAddress((void**)&ahi,  g_at_hi); cudaGetSymbolAddress((void**)&alo,  g_at_lo);
    cudaGetSymbolAddress((void**)&chi,  g_co_hi); cudaGetSymbolAddress((void**)&clo,  g_co_lo);
    cudaGetSymbolAddress((void**)&gshi, g_gs_hi); cudaGetSymbolAddress((void**)&gslo, g_gs_lo);
    cudaGetSymbolAddress((void**)&mhi,  g_m_hi);  cudaGetSymbolAddress((void**)&mlo,  g_m_lo);
    cudaGetSymbolAddress((void**)&whi,  g_w_hi);  cudaGetSymbolAddress((void**)&wlo,  g_w_lo);
    cudaGetSymbolAddress((void**)&sqh,  g_sqh);   cudaGetSymbolAddress((void**)&sql,  g_sql);
    cudaGetSymbolAddress((void**)&skh,  g_skh);   cudaGetSymbolAddress((void**)&skl,  g_skl);
    cudaGetSymbolAddress((void**)&svh,  g_svh);   cudaGetSymbolAddress((void**)&svl,  g_svl);
    cudaGetSymbolAddress((void**)&ckh,  g_ckh);   cudaGetSymbolAddress((void**)&ckl,  g_ckl);
    cudaGetSymbolAddress((void**)&cvh,  g_cvh);   cudaGetSymbolAddress((void**)&cvl,  g_cvl);

    rope_cache_k<<<256, 256>>>();

    split_launch(Wqkv,  whi + O_WQKV, wlo + O_WQKV, NL*SZ_WQKV);
    split_launch(Wo,    whi + O_WO,   wlo + O_WO,   NL*SZ_WO);
    split_launch(Wq_c,  whi + O_WQC,  wlo + O_WQC,  NL*SZ_WQC);
    split_launch(Wkv_c, whi + O_WKVC, wlo + O_WKVC, NL*SZ_WKVC);
    split_launch(Wo_c,  whi + O_WOC,  wlo + O_WOC,  NL*SZ_WOC);
    for (int l = 0; l < NL; l++) {
        int blocks = (int)((size_t)F_*D_/4/1024);
        split_ilv_k<<<blocks, 256>>>(Wg + (size_t)l*F_*D_,
            whi + O_WGU + l*SZ_WGU, wlo + O_WGU + l*SZ_WGU, 0);
        split_ilv_k<<<blocks, 256>>>(Wu + (size_t)l*F_*D_,
            whi + O_WGU + l*SZ_WGU, wlo + O_WGU + l*SZ_WGU, 1);
    }
    split_launch(Wd,    whi + O_WD,   wlo + O_WD,   NL*SZ_WD);
    split_launch(memory, mhi, mlo, (size_t)B_*S_*D_);

    // upfront: all 4 layers' cross K/V in one GEMM (layer-independent)
    gemm_bf16s<7><<<dim3(NL*2*D_/128, (B_*S_)/256), 256, GSMEM>>>(
        mhi, mlo, whi + O_WKVC, wlo + O_WKVC, nullptr, nullptr, nullptr,
        ckh, ckl, cvh, cvl, nullptr, nullptr, NL*2*D_, D_);

    const dim3 self_grid(L_/64, H_, B_);
    const dim3 cross_grid(L_/64, H_, B_);

    for (int l = 0; l < NL; l++) {
        const __nv_bfloat16* wqkv_h = whi + O_WQKV + l*SZ_WQKV;
        const __nv_bfloat16* wqkv_l = wlo + O_WQKV + l*SZ_WQKV;
        const __nv_bfloat16* wo_h   = whi + O_WO   + l*SZ_WO;
        const __nv_bfloat16* wo_l   = wlo + O_WO   + l*SZ_WO;
        const __nv_bfloat16* wqc_h  = whi + O_WQC  + l*SZ_WQC;
        const __nv_bfloat16* wqc_l  = wlo + O_WQC  + l*SZ_WQC;
        const __nv_bfloat16* woc_h  = whi + O_WOC  + l*SZ_WOC;
        const __nv_bfloat16* woc_l  = wlo + O_WOC  + l*SZ_WOC;
        const __nv_bfloat16* wgu_h  = whi + O_WGU  + l*SZ_WGU;
        const __nv_bfloat16* wgu_l  = wlo + O_WGU  + l*SZ_WGU;
        const __nv_bfloat16* wd_h   = whi + O_WD   + l*SZ_WD;
        const __nv_bfloat16* wd_l   = wlo + O_WD   + l*SZ_WD;

        const float* xsrc = (l == 0) ? x : xb;    // residual stream source

        // --- self attention block (QKV GEMM fuses bias+RoPE+split) ---
        rmsnorm_split_k<<<M_, 256>>>(xsrc, n1 + l*D_, hhi, hlo);
        gemm_bf16s<6><<<dim3(3*D_/128, M_/256), 256, GSMEM>>>(
            hhi, hlo, wqkv_h, wqkv_l, bqkv + l*3*D_, nullptr, nullptr,
            sqh, sql, skh, skl, svh, svl, 3*D_, D_);
        self_attn_mma<<<self_grid, 128, AT_SMEM>>>(sqh, sql, skh, skl, svh, svl, ahi, alo);
        gemm_bf16s<1><<<dim3(D_/128, M_/256), 256, GSMEM>>>(
            ahi, alo, wo_h, wo_l, bo + l*D_, xb, xsrc,
            nullptr, nullptr, nullptr, nullptr, nullptr, nullptr, D_, D_);

        // --- cross attention block ---
        rmsnorm_split_k<<<M_, 256>>>(xb, n2 + l*D_, hhi, hlo);
        gemm_bf16s<4><<<dim3(D_/128, M_/256), 256, GSMEM>>>(
            hhi, hlo, wqc_h, wqc_l, nullptr, nullptr, nullptr,
            sqh, sql, nullptr, nullptr, nullptr, nullptr, D_, D_);
        cross_attn_mma<<<cross_grid, 128, AT_SMEM>>>(
            sqh, sql, ckh + l*CATN, ckl + l*CATN, cvh + l*CATN, cvl + l*CATN,
            seg, chi, clo);
        gemm_bf16s<2><<<dim3(D_/128, M_/256), 256, GSMEM>>>(
            chi, clo, woc_h, woc_l, nullptr, xb, xb,
            nullptr, nullptr, nullptr, nullptr, nullptr, nullptr, D_, D_);

        // --- MLP block (fused gate|up GEMM with swiglu epilogue) ---
        rmsnorm_split_k<<<M_, 256>>>(xb, n3 + l*D_, hhi, hlo);
        gemm_bf16s<3><<<dim3(2*F_/128, M_/256), 256, GSMEM>>>(
            hhi, hlo, wgu_h, wgu_l, nullptr, nullptr, nullptr,
            gshi, gslo, nullptr, nullptr, nullptr, nullptr, 2*F_, D_);
        gemm_bf16s<2><<<dim3(D_/128, M_/256), 256, GSMEM>>>(
            gshi, gslo, wd_h, wd_l, nullptr, xb, xb,
            nullptr, nullptr, nullptr, nullptr, nullptr, nullptr, D_, F_);
    }

    rmsnorm_k<<<M_, 256>>>(xb, nf, (float*)d_out);
}